// round 1
// baseline (speedup 1.0000x reference)
#include <cuda_runtime.h>
#include <math.h>

// Problem constants
#define TT   2048
#define CC   2048
#define HH   16
#define DD   128
#define RR   64
#define WLOC 512
#define CI   512          // C/4
#define C3   6144         // 3*C

#define SCALE_L 0.08838834764831845f      // 1/sqrt(128)
#define SCALE_G 0.1767766952966369f       // SCALE_L * D/R = 2/sqrt(128)

// ---------------- scratch (device globals; no allocation allowed) ----------
__device__ float g_qkv[TT * C3];          // 48 MB  (q|k|v per row, roped in place)
__device__ float g_hinfo[TT * CI];        // 4 MB
__device__ float g_gate[TT];
__device__ float g_cos[TT * DD];
__device__ float g_sin[TT * DD];
__device__ float g_qr[HH * TT * RR];      // 8 MB
__device__ float g_kr[HH * TT * RR];
__device__ float g_vr[HH * TT * RR];
__device__ float g_ctx[TT * CC];          // 16 MB

// ============================================================================
// Generic C = A(MxK) @ B(NxK)^T, fp32, 64x64 tile, BK=32, 256 thr, 4x4 micro.
// Strided micro-tile mapping (row = ty+16i, col = tx+16j) -> conflict-free LDS.
// ============================================================================
__global__ __launch_bounds__(256) void gemm_abt(
    const float* __restrict__ A, const float* __restrict__ B,
    float* __restrict__ Cout, int M, int N, int K, int dogelu)
{
    __shared__ float As[64][33];
    __shared__ float Bs[64][33];
    const int bm = blockIdx.y << 6, bn = blockIdx.x << 6;
    const int tid = threadIdx.x;
    const int ty = tid >> 4, tx = tid & 15;
    const int lrow = tid >> 3;
    const int lc4 = (tid & 7) << 2;

    float acc[4][4];
#pragma unroll
    for (int i = 0; i < 4; i++)
#pragma unroll
        for (int j = 0; j < 4; j++) acc[i][j] = 0.f;

    for (int k0 = 0; k0 < K; k0 += 32) {
#pragma unroll
        for (int rr = 0; rr < 2; rr++) {
            int r = lrow + 32 * rr;
            float4 a = *(const float4*)(A + (size_t)(bm + r) * K + k0 + lc4);
            As[r][lc4 + 0] = a.x; As[r][lc4 + 1] = a.y;
            As[r][lc4 + 2] = a.z; As[r][lc4 + 3] = a.w;
            float4 b = *(const float4*)(B + (size_t)(bn + r) * K + k0 + lc4);
            Bs[r][lc4 + 0] = b.x; Bs[r][lc4 + 1] = b.y;
            Bs[r][lc4 + 2] = b.z; Bs[r][lc4 + 3] = b.w;
        }
        __syncthreads();
#pragma unroll 8
        for (int k = 0; k < 32; k++) {
            float av[4], bv[4];
#pragma unroll
            for (int i = 0; i < 4; i++) av[i] = As[ty + 16 * i][k];
#pragma unroll
            for (int j = 0; j < 4; j++) bv[j] = Bs[tx + 16 * j][k];
#pragma unroll
            for (int i = 0; i < 4; i++)
#pragma unroll
                for (int j = 0; j < 4; j++) acc[i][j] += av[i] * bv[j];
        }
        __syncthreads();
    }

#pragma unroll
    for (int i = 0; i < 4; i++)
#pragma unroll
        for (int j = 0; j < 4; j++) {
            float v = acc[i][j];
            if (dogelu) v = 0.5f * v * (1.0f + erff(v * 0.7071067811865475f));
            Cout[(size_t)(bm + ty + 16 * i) * N + bn + tx + 16 * j] = v;
        }
}

// ============================================================================
// RoPE tables: cos/sin(t * 10000^{-(d mod 64)/64}), computed in double.
// ============================================================================
__global__ void rope_table_k()
{
    int t = blockIdx.x, d = threadIdx.x;
    int j = d & 63;
    double ang = (double)t * exp(-(double)j * (log(10000.0) / 64.0));
    g_cos[t * DD + d] = (float)cos(ang);
    g_sin[t * DD + d] = (float)sin(ang);
}

// Interleaved-pair rotation with concat tables:
//   out[2i]   = x[2i]  *cos[2i]   - x[2i+1]*sin[2i]
//   out[2i+1] = x[2i+1]*cos[2i+1] + x[2i]  *sin[2i+1]
__global__ void rope_apply_k()
{
    int t = blockIdx.x, h = blockIdx.y, j = threadIdx.x;   // j < 64
    int d0 = 2 * j, d1 = d0 + 1;
    float c0 = g_cos[t * DD + d0], s0 = g_sin[t * DD + d0];
    float c1 = g_cos[t * DD + d1], s1 = g_sin[t * DD + d1];
    float* q = &g_qkv[(size_t)t * C3 + h * DD];
    float q0 = q[d0], q1 = q[d1];
    q[d0] = q0 * c0 - q1 * s0;
    q[d1] = q1 * c1 + q0 * s1;
    float* kp = q + CC;
    float k0 = kp[d0], k1 = kp[d1];
    kp[d0] = k0 * c0 - k1 * s0;
    kp[d1] = k1 * c1 + k0 * s1;
}

// ============================================================================
// Gate: sigmoid(h_info @ w2) > 0.75  -> {0,1}
// ============================================================================
__global__ void gate_k(const float* __restrict__ w2)
{
    __shared__ float red[128];
    int t = blockIdx.x, tid = threadIdx.x;
    float s = 0.f;
    for (int j = tid; j < CI; j += 128) s += g_hinfo[t * CI + j] * w2[j];
    red[tid] = s;
    __syncthreads();
    for (int off = 64; off > 0; off >>= 1) {
        if (tid < off) red[tid] += red[tid + off];
        __syncthreads();
    }
    if (tid == 0) {
        float sc = 1.0f / (1.0f + expf(-red[0]));
        g_gate[t] = (sc > 0.75f) ? 1.0f : 0.0f;
    }
}

// ============================================================================
// Low-rank projections: q_r = q@pk^T, k_r = k@pk^T, v_r = v@pv^T (per head).
// Block = (64-token tile, head). Dyn smem = 2*64*129 floats.
// ============================================================================
__global__ __launch_bounds__(256) void lowrank_k(
    const float* __restrict__ pk, const float* __restrict__ pv)
{
    extern __shared__ float sm[];
    float* Xs = sm;               // [64][129]
    float* Ps = sm + 64 * 129;    // [64][129]
    int qt = blockIdx.x, h = blockIdx.y, t0 = qt << 6;
    int tid = threadIdx.x, ty = tid >> 4, tx = tid & 15;

    for (int pass = 0; pass < 3; pass++) {
        const float* proj = (pass == 2) ? pv : pk;
        int coloff = pass * CC + h * DD;
        __syncthreads();
        for (int i = tid; i < 64 * 128; i += 256) {
            int r = i >> 7, d = i & 127;
            Xs[r * 129 + d] = g_qkv[(size_t)(t0 + r) * C3 + coloff + d];
            Ps[r * 129 + d] = proj[r * 128 + d];
        }
        __syncthreads();
        float acc[4][4];
#pragma unroll
        for (int i = 0; i < 4; i++)
#pragma unroll
            for (int j = 0; j < 4; j++) acc[i][j] = 0.f;
#pragma unroll 8
        for (int k = 0; k < 128; k++) {
            float av[4], bv[4];
#pragma unroll
            for (int i = 0; i < 4; i++) av[i] = Xs[(ty + 16 * i) * 129 + k];
#pragma unroll
            for (int j = 0; j < 4; j++) bv[j] = Ps[(tx + 16 * j) * 129 + k];
#pragma unroll
            for (int i = 0; i < 4; i++)
#pragma unroll
                for (int j = 0; j < 4; j++) acc[i][j] += av[i] * bv[j];
        }
        float* dst = (pass == 0) ? g_qr : (pass == 1) ? g_kr : g_vr;
#pragma unroll
        for (int i = 0; i < 4; i++)
#pragma unroll
            for (int j = 0; j < 4; j++)
                dst[(size_t)(h * TT + t0 + ty + 16 * i) * RR + tx + 16 * j] = acc[i][j];
    }
}

// ============================================================================
// Local sliding-window causal attention (window 512), flash-style.
// Block = (64-query tile, head), 256 threads.
// Dyn smem: Qs[64*129] Ks[64*129] Vs[64*132] S[64*68] + stats = 118016 B.
// ============================================================================
__global__ __launch_bounds__(256) void local_attn_k()
{
    extern __shared__ float sm[];
    float* Qs  = sm;                   // [64][129]
    float* Ks  = Qs + 64 * 129;        // [64][129]
    float* Vs  = Ks + 64 * 129;        // [64][132]
    float* Ssm = Vs + 64 * 132;        // [64][68]
    float* msm = Ssm + 64 * 68;
    float* lsm = msm + 64;
    float* alsm = lsm + 64;

    int qt = blockIdx.x, h = blockIdx.y, t0 = qt << 6;
    int tid = threadIdx.x, ty = tid >> 4, tx = tid & 15;

    for (int i = tid; i < 64 * 128; i += 256) {
        int r = i >> 7, d = i & 127;
        Qs[r * 129 + d] = g_qkv[(size_t)(t0 + r) * C3 + h * DD + d];
    }
    if (tid < 64) { msm[tid] = -1e30f; lsm[tid] = 0.0f; }

    float acc[4][8];
#pragma unroll
    for (int i = 0; i < 4; i++)
#pragma unroll
        for (int j = 0; j < 8; j++) acc[i][j] = 0.f;

    int kt0 = (t0 > 511) ? ((t0 - 511) >> 6) : 0;
    __syncthreads();

    for (int kt = kt0; kt <= qt; kt++) {
        int s0 = kt << 6;
        for (int i = tid; i < 64 * 128; i += 256) {
            int c = i >> 7, d = i & 127;
            Ks[c * 129 + d] = g_qkv[(size_t)(s0 + c) * C3 + CC + h * DD + d];
            Vs[c * 132 + d] = g_qkv[(size_t)(s0 + c) * C3 + 2 * CC + h * DD + d];
        }
        __syncthreads();

        float sacc[4][4];
#pragma unroll
        for (int i = 0; i < 4; i++)
#pragma unroll
            for (int j = 0; j < 4; j++) sacc[i][j] = 0.f;
#pragma unroll 8
        for (int k = 0; k < 128; k++) {
            float av[4], bv[4];
#pragma unroll
            for (int i = 0; i < 4; i++) av[i] = Qs[(ty + 16 * i) * 129 + k];
#pragma unroll
            for (int j = 0; j < 4; j++) bv[j] = Ks[(tx + 16 * j) * 129 + k];
#pragma unroll
            for (int i = 0; i < 4; i++)
#pragma unroll
                for (int j = 0; j < 4; j++) sacc[i][j] += av[i] * bv[j];
        }
#pragma unroll
        for (int i = 0; i < 4; i++)
#pragma unroll
            for (int j = 0; j < 4; j++) {
                int r = ty + 16 * i, c = tx + 16 * j;
                int tg = t0 + r, sg = s0 + c;
                float v = (sg > tg || sg < tg - (WLOC - 1)) ? -1e30f
                                                            : sacc[i][j] * SCALE_L;
                Ssm[r * 68 + c] = v;
            }
        __syncthreads();

        if (tid < 64) {
            int r = tid;
            float mo = msm[r], mn = mo;
            for (int c = 0; c < 64; c++) mn = fmaxf(mn, Ssm[r * 68 + c]);
            float sum = 0.f;
            for (int c = 0; c < 64; c++) {
                float sv = Ssm[r * 68 + c];
                float p = (sv <= -1e29f) ? 0.0f : expf(sv - mn);
                Ssm[r * 68 + c] = p;
                sum += p;
            }
            float al = expf(mo - mn);
            alsm[r] = al;
            msm[r] = mn;
            lsm[r] = lsm[r] * al + sum;
        }
        __syncthreads();

#pragma unroll
        for (int i = 0; i < 4; i++) {
            float al = alsm[ty + 16 * i];
#pragma unroll
            for (int j = 0; j < 8; j++) acc[i][j] *= al;
        }
        for (int s = 0; s < 64; s++) {
            float p[4];
#pragma unroll
            for (int i = 0; i < 4; i++) p[i] = Ssm[(ty + 16 * i) * 68 + s];
            float4 v0 = *(float4*)&Vs[s * 132 + tx * 8];
            float4 v1 = *(float4*)&Vs[s * 132 + tx * 8 + 4];
#pragma unroll
            for (int i = 0; i < 4; i++) {
                acc[i][0] += p[i] * v0.x; acc[i][1] += p[i] * v0.y;
                acc[i][2] += p[i] * v0.z; acc[i][3] += p[i] * v0.w;
                acc[i][4] += p[i] * v1.x; acc[i][5] += p[i] * v1.y;
                acc[i][6] += p[i] * v1.z; acc[i][7] += p[i] * v1.w;
            }
        }
        __syncthreads();
    }

#pragma unroll
    for (int i = 0; i < 4; i++) {
        int r = ty + 16 * i;
        float inv = 1.0f / lsm[r];
#pragma unroll
        for (int j = 0; j < 8; j++)
            g_ctx[(size_t)(t0 + r) * CC + h * DD + tx * 8 + j] = acc[i][j] * inv;
    }
}

// ============================================================================
// Global low-rank attention (unmasked, full T), flash-style over R=64,
// epilogue ctx_g = O @ uo^T, gated add into g_ctx.
// Dyn smem: Qs[64*65] Ks[64*65] Vs[64*68] S[64*68] + stats = 68864 B.
// Epilogue overlays uo^T (64*132) onto Qs/Ks (+ dead head of Vs).
// ============================================================================
__global__ __launch_bounds__(256) void global_attn_k(const float* __restrict__ uo)
{
    extern __shared__ float sm[];
    float* Qs  = sm;                  // [64][65]
    float* Ks  = Qs + 64 * 65;        // [64][65]
    float* Vs  = Ks + 64 * 65;        // [64][68]
    float* Ssm = Vs + 64 * 68;        // [64][68]
    float* msm = Ssm + 64 * 68;
    float* lsm = msm + 64;
    float* alsm = lsm + 64;
    float* uos = sm;                  // overlay, [64][132] (epilogue only)

    int qt = blockIdx.x, h = blockIdx.y, t0 = qt << 6;
    int tid = threadIdx.x, ty = tid >> 4, tx = tid & 15;

    for (int i = tid; i < 64 * 64; i += 256) {
        int r = i >> 6, j = i & 63;
        Qs[r * 65 + j] = g_qr[(size_t)(h * TT + t0 + r) * RR + j];
    }
    if (tid < 64) { msm[tid] = -1e30f; lsm[tid] = 0.0f; }

    float acc[4][4];
#pragma unroll
    for (int i = 0; i < 4; i++)
#pragma unroll
        for (int j = 0; j < 4; j++) acc[i][j] = 0.f;
    __syncthreads();

    for (int kt = 0; kt < TT / 64; kt++) {
        int s0 = kt << 6;
        for (int i = tid; i < 64 * 64; i += 256) {
            int c = i >> 6, j = i & 63;
            Ks[c * 65 + j] = g_kr[(size_t)(h * TT + s0 + c) * RR + j];
            Vs[c * 68 + j] = g_vr[(size_t)(h * TT + s0 + c) * RR + j];
        }
        __syncthreads();

        float sacc[4][4];
#pragma unroll
        for (int i = 0; i < 4; i++)
#pragma unroll
            for (int j = 0; j < 4; j++) sacc[i][j] = 0.f;
#pragma unroll 8
        for (int k = 0; k < 64; k++) {
            float av[4], bv[4];
#pragma unroll
            for (int i = 0; i < 4; i++) av[i] = Qs[(ty + 16 * i) * 65 + k];
#pragma unroll
            for (int j = 0; j < 4; j++) bv[j] = Ks[(tx + 16 * j) * 65 + k];
#pragma unroll
            for (int i = 0; i < 4; i++)
#pragma unroll
                for (int j = 0; j < 4; j++) sacc[i][j] += av[i] * bv[j];
        }
#pragma unroll
        for (int i = 0; i < 4; i++)
#pragma unroll
            for (int j = 0; j < 4; j++)
                Ssm[(ty + 16 * i) * 68 + tx + 16 * j] = sacc[i][j] * SCALE_G;
        __syncthreads();

        if (tid < 64) {
            int r = tid;
            float mo = msm[r], mn = mo;
            for (int c = 0; c < 64; c++) mn = fmaxf(mn, Ssm[r * 68 + c]);
            float sum = 0.f;
            for (int c = 0; c < 64; c++) {
                float p = expf(Ssm[r * 68 + c] - mn);
                Ssm[r * 68 + c] = p;
                sum += p;
            }
            float al = expf(mo - mn);
            alsm[r] = al;
            msm[r] = mn;
            lsm[r] = lsm[r] * al + sum;
        }
        __syncthreads();

#pragma unroll
        for (int i = 0; i < 4; i++) {
            float al = alsm[ty + 16 * i];
#pragma unroll
            for (int j = 0; j < 4; j++) acc[i][j] *= al;
        }
        for (int s = 0; s < 64; s++) {
            float p[4];
#pragma unroll
            for (int i = 0; i < 4; i++) p[i] = Ssm[(ty + 16 * i) * 68 + s];
            float4 v = *(float4*)&Vs[s * 68 + tx * 4];
#pragma unroll
            for (int i = 0; i < 4; i++) {
                acc[i][0] += p[i] * v.x; acc[i][1] += p[i] * v.y;
                acc[i][2] += p[i] * v.z; acc[i][3] += p[i] * v.w;
            }
        }
        __syncthreads();
    }

    // Write normalized O into Ssm
#pragma unroll
    for (int i = 0; i < 4; i++) {
        float inv = 1.0f / lsm[ty + 16 * i];
#pragma unroll
        for (int j = 0; j < 4; j++)
            Ssm[(ty + 16 * i) * 68 + tx * 4 + j] = acc[i][j] * inv;
    }
    __syncthreads();

    // Load uo^T: uos[r][d] = uo[d*64 + r]
    for (int i = tid; i < 64 * 128; i += 256) {
        int d = i & 127, j = i >> 7;
        uos[j * 132 + d] = uo[d * RR + j];
    }
    __syncthreads();

    // ctx_g[t][d] = sum_r O[t][r] * uo[d][r]; gated add into g_ctx
    float o[4][8];
#pragma unroll
    for (int i = 0; i < 4; i++)
#pragma unroll
        for (int j = 0; j < 8; j++) o[i][j] = 0.f;
    for (int j = 0; j < 64; j++) {
        float p[4];
#pragma unroll
        for (int i = 0; i < 4; i++) p[i] = Ssm[(ty + 16 * i) * 68 + j];
        float4 u0 = *(float4*)&uos[j * 132 + tx * 8];
        float4 u1 = *(float4*)&uos[j * 132 + tx * 8 + 4];
#pragma unroll
        for (int i = 0; i < 4; i++) {
            o[i][0] += p[i] * u0.x; o[i][1] += p[i] * u0.y;
            o[i][2] += p[i] * u0.z; o[i][3] += p[i] * u0.w;
            o[i][4] += p[i] * u1.x; o[i][5] += p[i] * u1.y;
            o[i][6] += p[i] * u1.z; o[i][7] += p[i] * u1.w;
        }
    }
#pragma unroll
    for (int i = 0; i < 4; i++) {
        int tg = t0 + ty + 16 * i;
        float gt = g_gate[tg];
        if (gt != 0.0f) {
#pragma unroll
            for (int j = 0; j < 8; j++)
                g_ctx[(size_t)tg * CC + h * DD + tx * 8 + j] += o[i][j];
        }
    }
}

// ============================================================================
extern "C" void kernel_launch(void* const* d_in, const int* in_sizes, int n_in,
                              void* d_out, int out_size)
{
    const float* x     = (const float*)d_in[0];
    const float* w_qkv = (const float*)d_in[1];
    const float* w_o   = (const float*)d_in[2];
    const float* pk    = (const float*)d_in[3];
    const float* pv    = (const float*)d_in[4];
    const float* uo    = (const float*)d_in[5];
    const float* iw1   = (const float*)d_in[6];
    const float* iw2   = (const float*)d_in[7];
    float* out = (float*)d_out;

    cudaFuncSetAttribute(local_attn_k,  cudaFuncAttributeMaxDynamicSharedMemorySize, 118016);
    cudaFuncSetAttribute(global_attn_k, cudaFuncAttributeMaxDynamicSharedMemorySize, 68864);
    cudaFuncSetAttribute(lowrank_k,     cudaFuncAttributeMaxDynamicSharedMemorySize, 66048);

    void *p_qkv, *p_hinfo, *p_ctx;
    cudaGetSymbolAddress(&p_qkv, g_qkv);
    cudaGetSymbolAddress(&p_hinfo, g_hinfo);
    cudaGetSymbolAddress(&p_ctx, g_ctx);

    // qkv = x @ w_qkv^T
    gemm_abt<<<dim3(C3 / 64, TT / 64), 256>>>(x, w_qkv, (float*)p_qkv, TT, C3, CC, 0);
    // RoPE
    rope_table_k<<<TT, DD>>>();
    rope_apply_k<<<dim3(TT, HH), 64>>>();
    // info gate path
    gemm_abt<<<dim3(CI / 64, TT / 64), 256>>>(x, iw1, (float*)p_hinfo, TT, CI, CC, 1);
    gate_k<<<TT, 128>>>(iw2);
    // low-rank projections
    lowrank_k<<<dim3(TT / 64, HH), 256, 66048>>>(pk, pv);
    // local sliding-window attention -> g_ctx
    local_attn_k<<<dim3(TT / 64, HH), 256, 118016>>>();
    // global low-rank attention, gated add into g_ctx
    global_attn_k<<<dim3(TT / 64, HH), 256, 68864>>>(uo);
    // out = ctx @ w_o^T
    gemm_abt<<<dim3(CC / 64, TT / 64), 256>>>((const float*)p_ctx, w_o, out, TT, CC, CC, 0);
}

// round 2
// speedup vs baseline: 1.0008x; 1.0008x over previous
#include <cuda_runtime.h>
#include <math.h>

// Problem constants
#define TT   2048
#define CC   2048
#define HH   16
#define DD   128
#define RR   64
#define WLOC 512
#define CI   512          // C/4
#define C3   6144         // 3*C

#define SCALE_L 0.08838834764831845f      // 1/sqrt(128)
#define SCALE_G 0.1767766952966369f       // SCALE_L * D/R = 2/sqrt(128)

// ---------------- scratch (device globals; no allocation allowed) ----------
__device__ float g_qkv[TT * C3];          // 48 MB  (q|k|v per row, roped in place)
__device__ float g_hinfo[TT * CI];        // 4 MB
__device__ float g_gate[TT];
__device__ float g_cos[TT * DD];
__device__ float g_sin[TT * DD];
__device__ float g_qr[HH * TT * RR];      // 8 MB
__device__ float g_kr[HH * TT * RR];
__device__ float g_vr[HH * TT * RR];
__device__ float g_ctx[TT * CC];          // 16 MB

// ============================================================================
// Generic C = A(MxK) @ B(NxK)^T, fp32, 64x64 tile, BK=32, 256 thr, 4x4 micro.
// Strided micro-tile mapping (row = ty+16i, col = tx+16j) -> conflict-free LDS.
// ============================================================================
__global__ __launch_bounds__(256) void gemm_abt(
    const float* __restrict__ A, const float* __restrict__ B,
    float* __restrict__ Cout, int M, int N, int K, int dogelu)
{
    __shared__ float As[64][33];
    __shared__ float Bs[64][33];
    const int bm = blockIdx.y << 6, bn = blockIdx.x << 6;
    const int tid = threadIdx.x;
    const int ty = tid >> 4, tx = tid & 15;
    const int lrow = tid >> 3;
    const int lc4 = (tid & 7) << 2;

    float acc[4][4];
#pragma unroll
    for (int i = 0; i < 4; i++)
#pragma unroll
        for (int j = 0; j < 4; j++) acc[i][j] = 0.f;

    for (int k0 = 0; k0 < K; k0 += 32) {
#pragma unroll
        for (int rr = 0; rr < 2; rr++) {
            int r = lrow + 32 * rr;
            float4 a = *(const float4*)(A + (size_t)(bm + r) * K + k0 + lc4);
            As[r][lc4 + 0] = a.x; As[r][lc4 + 1] = a.y;
            As[r][lc4 + 2] = a.z; As[r][lc4 + 3] = a.w;
            float4 b = *(const float4*)(B + (size_t)(bn + r) * K + k0 + lc4);
            Bs[r][lc4 + 0] = b.x; Bs[r][lc4 + 1] = b.y;
            Bs[r][lc4 + 2] = b.z; Bs[r][lc4 + 3] = b.w;
        }
        __syncthreads();
#pragma unroll 8
        for (int k = 0; k < 32; k++) {
            float av[4], bv[4];
#pragma unroll
            for (int i = 0; i < 4; i++) av[i] = As[ty + 16 * i][k];
#pragma unroll
            for (int j = 0; j < 4; j++) bv[j] = Bs[tx + 16 * j][k];
#pragma unroll
            for (int i = 0; i < 4; i++)
#pragma unroll
                for (int j = 0; j < 4; j++) acc[i][j] += av[i] * bv[j];
        }
        __syncthreads();
    }

#pragma unroll
    for (int i = 0; i < 4; i++)
#pragma unroll
        for (int j = 0; j < 4; j++) {
            float v = acc[i][j];
            if (dogelu) v = 0.5f * v * (1.0f + erff(v * 0.7071067811865475f));
            Cout[(size_t)(bm + ty + 16 * i) * N + bn + tx + 16 * j] = v;
        }
}

// ============================================================================
// RoPE tables: cos/sin(t * 10000^{-(d mod 64)/64}), computed in double.
// ============================================================================
__global__ void rope_table_k()
{
    int t = blockIdx.x, d = threadIdx.x;
    int j = d & 63;
    double ang = (double)t * exp(-(double)j * (log(10000.0) / 64.0));
    g_cos[t * DD + d] = (float)cos(ang);
    g_sin[t * DD + d] = (float)sin(ang);
}

// Interleaved-pair rotation with concat tables:
//   out[2i]   = x[2i]  *cos[2i]   - x[2i+1]*sin[2i]
//   out[2i+1] = x[2i+1]*cos[2i+1] + x[2i]  *sin[2i+1]
__global__ void rope_apply_k()
{
    int t = blockIdx.x, h = blockIdx.y, j = threadIdx.x;   // j < 64
    int d0 = 2 * j, d1 = d0 + 1;
    float c0 = g_cos[t * DD + d0], s0 = g_sin[t * DD + d0];
    float c1 = g_cos[t * DD + d1], s1 = g_sin[t * DD + d1];
    float* q = &g_qkv[(size_t)t * C3 + h * DD];
    float q0 = q[d0], q1 = q[d1];
    q[d0] = q0 * c0 - q1 * s0;
    q[d1] = q1 * c1 + q0 * s1;
    float* kp = q + CC;
    float k0 = kp[d0], k1 = kp[d1];
    kp[d0] = k0 * c0 - k1 * s0;
    kp[d1] = k1 * c1 + k0 * s1;
}

// ============================================================================
// Gate: sigmoid(h_info @ w2) > 0.75  -> {0,1}
// ============================================================================
__global__ void gate_k(const float* __restrict__ w2)
{
    __shared__ float red[128];
    int t = blockIdx.x, tid = threadIdx.x;
    float s = 0.f;
    for (int j = tid; j < CI; j += 128) s += g_hinfo[t * CI + j] * w2[j];
    red[tid] = s;
    __syncthreads();
    for (int off = 64; off > 0; off >>= 1) {
        if (tid < off) red[tid] += red[tid + off];
        __syncthreads();
    }
    if (tid == 0) {
        float sc = 1.0f / (1.0f + expf(-red[0]));
        g_gate[t] = (sc > 0.75f) ? 1.0f : 0.0f;
    }
}

// ============================================================================
// Low-rank projections: q_r = q@pk^T, k_r = k@pk^T, v_r = v@pv^T (per head).
// Block = (64-token tile, head). Dyn smem = 2*64*129 floats.
// ============================================================================
__global__ __launch_bounds__(256) void lowrank_k(
    const float* __restrict__ pk, const float* __restrict__ pv)
{
    extern __shared__ float sm[];
    float* Xs = sm;               // [64][129]
    float* Ps = sm + 64 * 129;    // [64][129]
    int qt = blockIdx.x, h = blockIdx.y, t0 = qt << 6;
    int tid = threadIdx.x, ty = tid >> 4, tx = tid & 15;

    for (int pass = 0; pass < 3; pass++) {
        const float* proj = (pass == 2) ? pv : pk;
        int coloff = pass * CC + h * DD;
        __syncthreads();
        for (int i = tid; i < 64 * 128; i += 256) {
            int r = i >> 7, d = i & 127;
            Xs[r * 129 + d] = g_qkv[(size_t)(t0 + r) * C3 + coloff + d];
            Ps[r * 129 + d] = proj[r * 128 + d];
        }
        __syncthreads();
        float acc[4][4];
#pragma unroll
        for (int i = 0; i < 4; i++)
#pragma unroll
            for (int j = 0; j < 4; j++) acc[i][j] = 0.f;
#pragma unroll 8
        for (int k = 0; k < 128; k++) {
            float av[4], bv[4];
#pragma unroll
            for (int i = 0; i < 4; i++) av[i] = Xs[(ty + 16 * i) * 129 + k];
#pragma unroll
            for (int j = 0; j < 4; j++) bv[j] = Ps[(tx + 16 * j) * 129 + k];
#pragma unroll
            for (int i = 0; i < 4; i++)
#pragma unroll
                for (int j = 0; j < 4; j++) acc[i][j] += av[i] * bv[j];
        }
        float* dst = (pass == 0) ? g_qr : (pass == 1) ? g_kr : g_vr;
#pragma unroll
        for (int i = 0; i < 4; i++)
#pragma unroll
            for (int j = 0; j < 4; j++)
                dst[(size_t)(h * TT + t0 + ty + 16 * i) * RR + tx + 16 * j] = acc[i][j];
    }
}

// ============================================================================
// Local sliding-window causal attention (window 512), flash-style.
// Block = (64-query tile, head), 256 threads.
// Dyn smem: Qs[64*129] Ks[64*129] Vs[64*132] S[64*68] + stats = 118016 B.
// ============================================================================
__global__ __launch_bounds__(256) void local_attn_k()
{
    extern __shared__ float sm[];
    float* Qs  = sm;                   // [64][129]
    float* Ks  = Qs + 64 * 129;        // [64][129]
    float* Vs  = Ks + 64 * 129;        // [64][132]
    float* Ssm = Vs + 64 * 132;        // [64][68]
    float* msm = Ssm + 64 * 68;
    float* lsm = msm + 64;
    float* alsm = lsm + 64;

    int qt = blockIdx.x, h = blockIdx.y, t0 = qt << 6;
    int tid = threadIdx.x, ty = tid >> 4, tx = tid & 15;

    for (int i = tid; i < 64 * 128; i += 256) {
        int r = i >> 7, d = i & 127;
        Qs[r * 129 + d] = g_qkv[(size_t)(t0 + r) * C3 + h * DD + d];
    }
    if (tid < 64) { msm[tid] = -1e30f; lsm[tid] = 0.0f; }

    float acc[4][8];
#pragma unroll
    for (int i = 0; i < 4; i++)
#pragma unroll
        for (int j = 0; j < 8; j++) acc[i][j] = 0.f;

    int kt0 = (t0 > 511) ? ((t0 - 511) >> 6) : 0;
    __syncthreads();

    for (int kt = kt0; kt <= qt; kt++) {
        int s0 = kt << 6;
        for (int i = tid; i < 64 * 128; i += 256) {
            int c = i >> 7, d = i & 127;
            Ks[c * 129 + d] = g_qkv[(size_t)(s0 + c) * C3 + CC + h * DD + d];
            Vs[c * 132 + d] = g_qkv[(size_t)(s0 + c) * C3 + 2 * CC + h * DD + d];
        }
        __syncthreads();

        float sacc[4][4];
#pragma unroll
        for (int i = 0; i < 4; i++)
#pragma unroll
            for (int j = 0; j < 4; j++) sacc[i][j] = 0.f;
#pragma unroll 8
        for (int k = 0; k < 128; k++) {
            float av[4], bv[4];
#pragma unroll
            for (int i = 0; i < 4; i++) av[i] = Qs[(ty + 16 * i) * 129 + k];
#pragma unroll
            for (int j = 0; j < 4; j++) bv[j] = Ks[(tx + 16 * j) * 129 + k];
#pragma unroll
            for (int i = 0; i < 4; i++)
#pragma unroll
                for (int j = 0; j < 4; j++) sacc[i][j] += av[i] * bv[j];
        }
#pragma unroll
        for (int i = 0; i < 4; i++)
#pragma unroll
            for (int j = 0; j < 4; j++) {
                int r = ty + 16 * i, c = tx + 16 * j;
                int tg = t0 + r, sg = s0 + c;
                float v = (sg > tg || sg < tg - (WLOC - 1)) ? -1e30f
                                                            : sacc[i][j] * SCALE_L;
                Ssm[r * 68 + c] = v;
            }
        __syncthreads();

        if (tid < 64) {
            int r = tid;
            float mo = msm[r], mn = mo;
            for (int c = 0; c < 64; c++) mn = fmaxf(mn, Ssm[r * 68 + c]);
            float sum = 0.f;
            for (int c = 0; c < 64; c++) {
                float sv = Ssm[r * 68 + c];
                float p = (sv <= -1e29f) ? 0.0f : expf(sv - mn);
                Ssm[r * 68 + c] = p;
                sum += p;
            }
            float al = expf(mo - mn);
            alsm[r] = al;
            msm[r] = mn;
            lsm[r] = lsm[r] * al + sum;
        }
        __syncthreads();

#pragma unroll
        for (int i = 0; i < 4; i++) {
            float al = alsm[ty + 16 * i];
#pragma unroll
            for (int j = 0; j < 8; j++) acc[i][j] *= al;
        }
        for (int s = 0; s < 64; s++) {
            float p[4];
#pragma unroll
            for (int i = 0; i < 4; i++) p[i] = Ssm[(ty + 16 * i) * 68 + s];
            float4 v0 = *(float4*)&Vs[s * 132 + tx * 8];
            float4 v1 = *(float4*)&Vs[s * 132 + tx * 8 + 4];
#pragma unroll
            for (int i = 0; i < 4; i++) {
                acc[i][0] += p[i] * v0.x; acc[i][1] += p[i] * v0.y;
                acc[i][2] += p[i] * v0.z; acc[i][3] += p[i] * v0.w;
                acc[i][4] += p[i] * v1.x; acc[i][5] += p[i] * v1.y;
                acc[i][6] += p[i] * v1.z; acc[i][7] += p[i] * v1.w;
            }
        }
        __syncthreads();
    }

#pragma unroll
    for (int i = 0; i < 4; i++) {
        int r = ty + 16 * i;
        float inv = 1.0f / lsm[r];
#pragma unroll
        for (int j = 0; j < 8; j++)
            g_ctx[(size_t)(t0 + r) * CC + h * DD + tx * 8 + j] = acc[i][j] * inv;
    }
}

// ============================================================================
// Global low-rank attention (unmasked, full T), flash-style over R=64,
// epilogue ctx_g = O @ uo^T, gated add into g_ctx.
// Dyn smem: Qs[64*65] Ks[64*65] Vs[64*68] S[64*68] + stats = 68864 B.
// Epilogue overlays uo^T (64*132) onto Qs/Ks (+ dead head of Vs).
// ============================================================================
__global__ __launch_bounds__(256) void global_attn_k(const float* __restrict__ uo)
{
    extern __shared__ float sm[];
    float* Qs  = sm;                  // [64][65]
    float* Ks  = Qs + 64 * 65;        // [64][65]
    float* Vs  = Ks + 64 * 65;        // [64][68]
    float* Ssm = Vs + 64 * 68;        // [64][68]
    float* msm = Ssm + 64 * 68;
    float* lsm = msm + 64;
    float* alsm = lsm + 64;
    float* uos = sm;                  // overlay, [64][132] (epilogue only)

    int qt = blockIdx.x, h = blockIdx.y, t0 = qt << 6;
    int tid = threadIdx.x, ty = tid >> 4, tx = tid & 15;

    for (int i = tid; i < 64 * 64; i += 256) {
        int r = i >> 6, j = i & 63;
        Qs[r * 65 + j] = g_qr[(size_t)(h * TT + t0 + r) * RR + j];
    }
    if (tid < 64) { msm[tid] = -1e30f; lsm[tid] = 0.0f; }

    float acc[4][4];
#pragma unroll
    for (int i = 0; i < 4; i++)
#pragma unroll
        for (int j = 0; j < 4; j++) acc[i][j] = 0.f;
    __syncthreads();

    for (int kt = 0; kt < TT / 64; kt++) {
        int s0 = kt << 6;
        for (int i = tid; i < 64 * 64; i += 256) {
            int c = i >> 6, j = i & 63;
            Ks[c * 65 + j] = g_kr[(size_t)(h * TT + s0 + c) * RR + j];
            Vs[c * 68 + j] = g_vr[(size_t)(h * TT + s0 + c) * RR + j];
        }
        __syncthreads();

        float sacc[4][4];
#pragma unroll
        for (int i = 0; i < 4; i++)
#pragma unroll
            for (int j = 0; j < 4; j++) sacc[i][j] = 0.f;
#pragma unroll 8
        for (int k = 0; k < 64; k++) {
            float av[4], bv[4];
#pragma unroll
            for (int i = 0; i < 4; i++) av[i] = Qs[(ty + 16 * i) * 65 + k];
#pragma unroll
            for (int j = 0; j < 4; j++) bv[j] = Ks[(tx + 16 * j) * 65 + k];
#pragma unroll
            for (int i = 0; i < 4; i++)
#pragma unroll
                for (int j = 0; j < 4; j++) sacc[i][j] += av[i] * bv[j];
        }
#pragma unroll
        for (int i = 0; i < 4; i++)
#pragma unroll
            for (int j = 0; j < 4; j++)
                Ssm[(ty + 16 * i) * 68 + tx + 16 * j] = sacc[i][j] * SCALE_G;
        __syncthreads();

        if (tid < 64) {
            int r = tid;
            float mo = msm[r], mn = mo;
            for (int c = 0; c < 64; c++) mn = fmaxf(mn, Ssm[r * 68 + c]);
            float sum = 0.f;
            for (int c = 0; c < 64; c++) {
                float p = expf(Ssm[r * 68 + c] - mn);
                Ssm[r * 68 + c] = p;
                sum += p;
            }
            float al = expf(mo - mn);
            alsm[r] = al;
            msm[r] = mn;
            lsm[r] = lsm[r] * al + sum;
        }
        __syncthreads();

#pragma unroll
        for (int i = 0; i < 4; i++) {
            float al = alsm[ty + 16 * i];
#pragma unroll
            for (int j = 0; j < 4; j++) acc[i][j] *= al;
        }
        for (int s = 0; s < 64; s++) {
            float p[4];
#pragma unroll
            for (int i = 0; i < 4; i++) p[i] = Ssm[(ty + 16 * i) * 68 + s];
            float4 v = *(float4*)&Vs[s * 68 + tx * 4];
#pragma unroll
            for (int i = 0; i < 4; i++) {
                acc[i][0] += p[i] * v.x; acc[i][1] += p[i] * v.y;
                acc[i][2] += p[i] * v.z; acc[i][3] += p[i] * v.w;
            }
        }
        __syncthreads();
    }

    // Write normalized O into Ssm
#pragma unroll
    for (int i = 0; i < 4; i++) {
        float inv = 1.0f / lsm[ty + 16 * i];
#pragma unroll
        for (int j = 0; j < 4; j++)
            Ssm[(ty + 16 * i) * 68 + tx * 4 + j] = acc[i][j] * inv;
    }
    __syncthreads();

    // Load uo^T: uos[r][d] = uo[d*64 + r]
    for (int i = tid; i < 64 * 128; i += 256) {
        int d = i & 127, j = i >> 7;
        uos[j * 132 + d] = uo[d * RR + j];
    }
    __syncthreads();

    // ctx_g[t][d] = sum_r O[t][r] * uo[d][r]; gated add into g_ctx
    float o[4][8];
#pragma unroll
    for (int i = 0; i < 4; i++)
#pragma unroll
        for (int j = 0; j < 8; j++) o[i][j] = 0.f;
    for (int j = 0; j < 64; j++) {
        float p[4];
#pragma unroll
        for (int i = 0; i < 4; i++) p[i] = Ssm[(ty + 16 * i) * 68 + j];
        float4 u0 = *(float4*)&uos[j * 132 + tx * 8];
        float4 u1 = *(float4*)&uos[j * 132 + tx * 8 + 4];
#pragma unroll
        for (int i = 0; i < 4; i++) {
            o[i][0] += p[i] * u0.x; o[i][1] += p[i] * u0.y;
            o[i][2] += p[i] * u0.z; o[i][3] += p[i] * u0.w;
            o[i][4] += p[i] * u1.x; o[i][5] += p[i] * u1.y;
            o[i][6] += p[i] * u1.z; o[i][7] += p[i] * u1.w;
        }
    }
#pragma unroll
    for (int i = 0; i < 4; i++) {
        int tg = t0 + ty + 16 * i;
        float gt = g_gate[tg];
        if (gt != 0.0f) {
#pragma unroll
            for (int j = 0; j < 8; j++)
                g_ctx[(size_t)tg * CC + h * DD + tx * 8 + j] += o[i][j];
        }
    }
}

// ============================================================================
extern "C" void kernel_launch(void* const* d_in, const int* in_sizes, int n_in,
                              void* d_out, int out_size)
{
    const float* x     = (const float*)d_in[0];
    const float* w_qkv = (const float*)d_in[1];
    const float* w_o   = (const float*)d_in[2];
    const float* pk    = (const float*)d_in[3];
    const float* pv    = (const float*)d_in[4];
    const float* uo    = (const float*)d_in[5];
    const float* iw1   = (const float*)d_in[6];
    const float* iw2   = (const float*)d_in[7];
    float* out = (float*)d_out;

    cudaFuncSetAttribute(local_attn_k,  cudaFuncAttributeMaxDynamicSharedMemorySize, 118016);
    cudaFuncSetAttribute(global_attn_k, cudaFuncAttributeMaxDynamicSharedMemorySize, 68864);
    cudaFuncSetAttribute(lowrank_k,     cudaFuncAttributeMaxDynamicSharedMemorySize, 66048);

    void *p_qkv, *p_hinfo, *p_ctx;
    cudaGetSymbolAddress(&p_qkv, g_qkv);
    cudaGetSymbolAddress(&p_hinfo, g_hinfo);
    cudaGetSymbolAddress(&p_ctx, g_ctx);

    // qkv = x @ w_qkv^T
    gemm_abt<<<dim3(C3 / 64, TT / 64), 256>>>(x, w_qkv, (float*)p_qkv, TT, C3, CC, 0);
    // RoPE
    rope_table_k<<<TT, DD>>>();
    rope_apply_k<<<dim3(TT, HH), 64>>>();
    // info gate path
    gemm_abt<<<dim3(CI / 64, TT / 64), 256>>>(x, iw1, (float*)p_hinfo, TT, CI, CC, 1);
    gate_k<<<TT, 128>>>(iw2);
    // low-rank projections
    lowrank_k<<<dim3(TT / 64, HH), 256, 66048>>>(pk, pv);
    // local sliding-window attention -> g_ctx
    local_attn_k<<<dim3(TT / 64, HH), 256, 118016>>>();
    // global low-rank attention, gated add into g_ctx
    global_attn_k<<<dim3(TT / 64, HH), 256, 68864>>>(uo);
    // out = ctx @ w_o^T
    gemm_abt<<<dim3(CC / 64, TT / 64), 256>>>((const float*)p_ctx, w_o, out, TT, CC, CC, 0);
}

// round 4
// speedup vs baseline: 1.7140x; 1.7125x over previous
#include <cuda_runtime.h>
#include <cuda_bf16.h>
#include <math.h>
#include <stdint.h>

#define TT   2048
#define CC   2048
#define HH   16
#define DD   128
#define RR   64
#define WLOC 512
#define CI   512
#define C3   6144

#define SCALE_L 0.08838834764831845f
#define SCALE_G 0.1767766952966369f

// ---------------- scratch (device globals) ----------------
__device__ float g_qkv[TT * C3];
__device__ float g_hinfo[TT * CI];
__device__ float g_gate[TT];
__device__ float g_cos[TT * DD];
__device__ float g_sin[TT * DD];
__device__ float g_qr[HH * TT * RR];
__device__ float g_kr[HH * TT * RR];
__device__ float g_vr[HH * TT * RR];
__device__ float g_ctx[TT * CC];

// bf16 hi/lo split operands
__device__ __nv_bfloat16 g_xh[TT * CC],  g_xl[TT * CC];
__device__ __nv_bfloat16 g_wqh[C3 * CC], g_wql[C3 * CC];
__device__ __nv_bfloat16 g_woh[CC * CC], g_wol[CC * CC];
__device__ __nv_bfloat16 g_i1h[CI * CC], g_i1l[CI * CC];
__device__ __nv_bfloat16 g_cxh[TT * CC], g_cxl[TT * CC];

// ============================================================================
// PTX helpers (all plain sm_80+ ISA — valid on compute_103 non-'a')
// ============================================================================
__device__ __forceinline__ uint32_t smem_u32(const void* p) {
    uint32_t a;
    asm("{ .reg .u64 t; cvta.to.shared.u64 t, %1; cvt.u32.u64 %0, t; }"
        : "=r"(a) : "l"(p));
    return a;
}

#define CP16(s, g) \
    asm volatile("cp.async.cg.shared.global [%0], [%1], 16;" \
                 :: "r"(s), "l"(g) : "memory")
#define CP_COMMIT() asm volatile("cp.async.commit_group;" ::: "memory")
#define CP_WAIT(n)  asm volatile("cp.async.wait_group %0;" :: "n"(n) : "memory")

__device__ __forceinline__ void ldsm4(uint32_t& r0, uint32_t& r1,
                                      uint32_t& r2, uint32_t& r3, uint32_t a) {
    asm volatile("ldmatrix.sync.aligned.m8n8.x4.shared.b16 {%0,%1,%2,%3}, [%4];"
                 : "=r"(r0), "=r"(r1), "=r"(r2), "=r"(r3) : "r"(a));
}

__device__ __forceinline__ void mma16816(float* c, const uint32_t* a,
                                         const uint32_t* b) {
    asm volatile("mma.sync.aligned.m16n8k16.row.col.f32.bf16.bf16.f32 "
                 "{%0,%1,%2,%3}, {%4,%5,%6,%7}, {%8,%9}, {%0,%1,%2,%3};"
                 : "+f"(c[0]), "+f"(c[1]), "+f"(c[2]), "+f"(c[3])
                 : "r"(a[0]), "r"(a[1]), "r"(a[2]), "r"(a[3]),
                   "r"(b[0]), "r"(b[1]));
}

// ============================================================================
// fp32 -> bf16 hi/lo split
// ============================================================================
__global__ void split_bf16_k(const float2* __restrict__ src,
                             __nv_bfloat162* __restrict__ hi,
                             __nv_bfloat162* __restrict__ lo, int n2)
{
    int i = blockIdx.x * 256 + threadIdx.x;
    if (i < n2) {
        float2 v = src[i];
        __nv_bfloat162 h = __floats2bfloat162_rn(v.x, v.y);
        hi[i] = h;
        lo[i] = __floats2bfloat162_rn(v.x - __bfloat162float(h.x),
                                      v.y - __bfloat162float(h.y));
    }
}

// ============================================================================
// mma.sync GEMM: C(MxN) = Ah·Bh^T + Al·Bh^T + Ah·Bl^T  (bf16 split, fp32 acc)
// BM=128, BN=128, BK=32, 256 threads (warps 4x2 -> 32x64 per warp).
// SMEM: per stage 4 matrices [128][40] bf16 (padded rows, conflict-free
// ldmatrix), double buffered = 81920 B. cp.async pipelined.
// ============================================================================
__global__ __launch_bounds__(256) void gemm_mma(
    const __nv_bfloat16* __restrict__ Ah, const __nv_bfloat16* __restrict__ Al,
    const __nv_bfloat16* __restrict__ Bh, const __nv_bfloat16* __restrict__ Bl,
    float* __restrict__ Cout, int N, int K, int dogelu)
{
    extern __shared__ __align__(128) char smraw[];
    const uint32_t sb = smem_u32(smraw);
    const int tid = threadIdx.x, lane = tid & 31, wid = tid >> 5;
    const int wm = wid & 3, wn = wid >> 1 >> 1;   // wn = wid>>2
    const int bm = blockIdx.y << 7, bn = blockIdx.x << 7;

    const int aj = lane >> 3, ar = lane & 7;

    float acc[2][8][4];
#pragma unroll
    for (int mt = 0; mt < 2; mt++)
#pragma unroll
        for (int nt = 0; nt < 8; nt++)
#pragma unroll
            for (int e = 0; e < 4; e++) acc[mt][nt][e] = 0.f;

    const int nch = K >> 5;

    // stage byte layout: Ah 0, Al 10240, Bh 20480, Bl 30720; stage stride 40960
    auto issue_stage = [&](int c) {
        const uint32_t st = sb + (c & 1) * 40960;
        const int k0 = c << 5;
        const __nv_bfloat16* gm0 = Ah + (size_t)bm * K + k0;
        const __nv_bfloat16* gm1 = Al + (size_t)bm * K + k0;
        const __nv_bfloat16* gm2 = Bh + (size_t)bn * K + k0;
        const __nv_bfloat16* gm3 = Bl + (size_t)bn * K + k0;
#pragma unroll
        for (int h = 0; h < 2; h++) {
            int i = tid + h * 256;            // 0..511
            int r = i >> 2, q = i & 3;
            uint32_t so = st + r * 80 + q * 16;
            size_t go = (size_t)r * K + q * 8;
            CP16(so,          gm0 + go);
            CP16(so + 10240,  gm1 + go);
            CP16(so + 20480,  gm2 + go);
            CP16(so + 30720,  gm3 + go);
        }
        CP_COMMIT();
    };

    issue_stage(0);
    for (int c = 0; c < nch; c++) {
        if (c + 1 < nch) { issue_stage(c + 1); CP_WAIT(1); }
        else             { CP_WAIT(0); }
        __syncthreads();

        const uint32_t st = sb + (c & 1) * 40960;
#pragma unroll
        for (int ks = 0; ks < 2; ks++) {
            uint32_t a[2][4], b2[8][2];
            // per-lane ldmatrix addresses
            // A: row = wm*32 + mt*16 + (aj&1)*8 + ar ; col = ks*16 + (aj>>1)*8
            const uint32_t a_off =
                ((wm * 32 + (aj & 1) * 8 + ar) * 40 + ks * 16 + (aj >> 1) * 8) * 2;
            // B: row = wn*64 + np*16 + (aj>>1)*8 + ar ; col = ks*16 + (aj&1)*8
            const uint32_t b_off =
                ((wn * 64 + (aj >> 1) * 8 + ar) * 40 + ks * 16 + (aj & 1) * 8) * 2;

            // ---- load Ah, Bh ----
#pragma unroll
            for (int mt = 0; mt < 2; mt++)
                ldsm4(a[mt][0], a[mt][1], a[mt][2], a[mt][3],
                      st + a_off + mt * (16 * 40 * 2));
#pragma unroll
            for (int np = 0; np < 4; np++) {
                uint32_t r0, r1, r2, r3;
                ldsm4(r0, r1, r2, r3, st + 20480 + b_off + np * (16 * 40 * 2));
                b2[np * 2][0] = r0;     b2[np * 2][1] = r1;
                b2[np * 2 + 1][0] = r2; b2[np * 2 + 1][1] = r3;
            }
            // hi * hi
#pragma unroll
            for (int mt = 0; mt < 2; mt++)
#pragma unroll
                for (int nt = 0; nt < 8; nt++)
                    mma16816(acc[mt][nt], a[mt], b2[nt]);

            // ---- lo * hi: overwrite A frags with Al ----
#pragma unroll
            for (int mt = 0; mt < 2; mt++)
                ldsm4(a[mt][0], a[mt][1], a[mt][2], a[mt][3],
                      st + 10240 + a_off + mt * (16 * 40 * 2));
#pragma unroll
            for (int mt = 0; mt < 2; mt++)
#pragma unroll
                for (int nt = 0; nt < 8; nt++)
                    mma16816(acc[mt][nt], a[mt], b2[nt]);

            // ---- hi * lo: reload Ah, load Bl ----
#pragma unroll
            for (int mt = 0; mt < 2; mt++)
                ldsm4(a[mt][0], a[mt][1], a[mt][2], a[mt][3],
                      st + a_off + mt * (16 * 40 * 2));
#pragma unroll
            for (int np = 0; np < 4; np++) {
                uint32_t r0, r1, r2, r3;
                ldsm4(r0, r1, r2, r3, st + 30720 + b_off + np * (16 * 40 * 2));
                b2[np * 2][0] = r0;     b2[np * 2][1] = r1;
                b2[np * 2 + 1][0] = r2; b2[np * 2 + 1][1] = r3;
            }
#pragma unroll
            for (int mt = 0; mt < 2; mt++)
#pragma unroll
                for (int nt = 0; nt < 8; nt++)
                    mma16816(acc[mt][nt], a[mt], b2[nt]);
        }
        __syncthreads();
    }

    // Epilogue: direct global stores (float2 pairs)
    const int row_base = bm + wm * 32 + (lane >> 2);
    const int col_base = bn + wn * 64 + (lane & 3) * 2;
#pragma unroll
    for (int mt = 0; mt < 2; mt++)
#pragma unroll
        for (int nt = 0; nt < 8; nt++) {
            int r0 = row_base + mt * 16, cc = col_base + nt * 8;
            float v0 = acc[mt][nt][0], v1 = acc[mt][nt][1];
            float v2 = acc[mt][nt][2], v3 = acc[mt][nt][3];
            if (dogelu) {
                v0 = 0.5f * v0 * (1.0f + erff(v0 * 0.7071067811865475f));
                v1 = 0.5f * v1 * (1.0f + erff(v1 * 0.7071067811865475f));
                v2 = 0.5f * v2 * (1.0f + erff(v2 * 0.7071067811865475f));
                v3 = 0.5f * v3 * (1.0f + erff(v3 * 0.7071067811865475f));
            }
            *(float2*)(Cout + (size_t)r0 * N + cc)       = make_float2(v0, v1);
            *(float2*)(Cout + (size_t)(r0 + 8) * N + cc) = make_float2(v2, v3);
        }
}

// ============================================================================
// RoPE
// ============================================================================
__global__ void rope_table_k()
{
    int t = blockIdx.x, d = threadIdx.x;
    int j = d & 63;
    double ang = (double)t * exp(-(double)j * (log(10000.0) / 64.0));
    g_cos[t * DD + d] = (float)cos(ang);
    g_sin[t * DD + d] = (float)sin(ang);
}

__global__ void rope_apply_k()
{
    int t = blockIdx.x, h = blockIdx.y, j = threadIdx.x;   // j < 64
    int d0 = 2 * j, d1 = d0 + 1;
    float c0 = g_cos[t * DD + d0], s0 = g_sin[t * DD + d0];
    float c1 = g_cos[t * DD + d1], s1 = g_sin[t * DD + d1];
    float* q = &g_qkv[(size_t)t * C3 + h * DD];
    float q0 = q[d0], q1 = q[d1];
    q[d0] = q0 * c0 - q1 * s0;
    q[d1] = q1 * c1 + q0 * s1;
    float* kp = q + CC;
    float k0 = kp[d0], k1 = kp[d1];
    kp[d0] = k0 * c0 - k1 * s0;
    kp[d1] = k1 * c1 + k0 * s1;
}

// ============================================================================
// Gate
// ============================================================================
__global__ void gate_k(const float* __restrict__ w2)
{
    __shared__ float red[128];
    int t = blockIdx.x, tid = threadIdx.x;
    float s = 0.f;
    for (int j = tid; j < CI; j += 128) s += g_hinfo[t * CI + j] * w2[j];
    red[tid] = s;
    __syncthreads();
    for (int off = 64; off > 0; off >>= 1) {
        if (tid < off) red[tid] += red[tid + off];
        __syncthreads();
    }
    if (tid == 0) {
        float sc = 1.0f / (1.0f + expf(-red[0]));
        g_gate[t] = (sc > 0.75f) ? 1.0f : 0.0f;
    }
}

// ============================================================================
// Low-rank projections
// ============================================================================
__global__ __launch_bounds__(256) void lowrank_k(
    const float* __restrict__ pk, const float* __restrict__ pv)
{
    extern __shared__ float sm[];
    float* Xs = sm;               // [64][129]
    float* Ps = sm + 64 * 129;    // [64][129]
    int qt = blockIdx.x, h = blockIdx.y, t0 = qt << 6;
    int tid = threadIdx.x, ty = tid >> 4, tx = tid & 15;

    for (int pass = 0; pass < 3; pass++) {
        const float* proj = (pass == 2) ? pv : pk;
        int coloff = pass * CC + h * DD;
        __syncthreads();
        for (int i = tid; i < 64 * 128; i += 256) {
            int r = i >> 7, d = i & 127;
            Xs[r * 129 + d] = g_qkv[(size_t)(t0 + r) * C3 + coloff + d];
            Ps[r * 129 + d] = proj[r * 128 + d];
        }
        __syncthreads();
        float acc[4][4];
#pragma unroll
        for (int i = 0; i < 4; i++)
#pragma unroll
            for (int j = 0; j < 4; j++) acc[i][j] = 0.f;
#pragma unroll 8
        for (int k = 0; k < 128; k++) {
            float av[4], bv[4];
#pragma unroll
            for (int i = 0; i < 4; i++) av[i] = Xs[(ty + 16 * i) * 129 + k];
#pragma unroll
            for (int j = 0; j < 4; j++) bv[j] = Ps[(tx + 16 * j) * 129 + k];
#pragma unroll
            for (int i = 0; i < 4; i++)
#pragma unroll
                for (int j = 0; j < 4; j++) acc[i][j] += av[i] * bv[j];
        }
        float* dst = (pass == 0) ? g_qr : (pass == 1) ? g_kr : g_vr;
#pragma unroll
        for (int i = 0; i < 4; i++)
#pragma unroll
            for (int j = 0; j < 4; j++)
                dst[(size_t)(h * TT + t0 + ty + 16 * i) * RR + tx + 16 * j] = acc[i][j];
    }
}

// ============================================================================
// Local sliding-window causal attention (window 512), flash-style.
// ============================================================================
__global__ __launch_bounds__(256) void local_attn_k()
{
    extern __shared__ float sm[];
    float* Qs  = sm;                   // [64][129]
    float* Ks  = Qs + 64 * 129;        // [64][129]
    float* Vs  = Ks + 64 * 129;        // [64][132]
    float* Ssm = Vs + 64 * 132;        // [64][68]
    float* msm = Ssm + 64 * 68;
    float* lsm = msm + 64;
    float* alsm = lsm + 64;

    int qt = blockIdx.x, h = blockIdx.y, t0 = qt << 6;
    int tid = threadIdx.x, ty = tid >> 4, tx = tid & 15;

    for (int i = tid; i < 64 * 128; i += 256) {
        int r = i >> 7, d = i & 127;
        Qs[r * 129 + d] = g_qkv[(size_t)(t0 + r) * C3 + h * DD + d];
    }
    if (tid < 64) { msm[tid] = -1e30f; lsm[tid] = 0.0f; }

    float acc[4][8];
#pragma unroll
    for (int i = 0; i < 4; i++)
#pragma unroll
        for (int j = 0; j < 8; j++) acc[i][j] = 0.f;

    int kt0 = (t0 > 511) ? ((t0 - 511) >> 6) : 0;
    __syncthreads();

    for (int kt = kt0; kt <= qt; kt++) {
        int s0 = kt << 6;
        for (int i = tid; i < 64 * 128; i += 256) {
            int c = i >> 7, d = i & 127;
            Ks[c * 129 + d] = g_qkv[(size_t)(s0 + c) * C3 + CC + h * DD + d];
            Vs[c * 132 + d] = g_qkv[(size_t)(s0 + c) * C3 + 2 * CC + h * DD + d];
        }
        __syncthreads();

        float sacc[4][4];
#pragma unroll
        for (int i = 0; i < 4; i++)
#pragma unroll
            for (int j = 0; j < 4; j++) sacc[i][j] = 0.f;
#pragma unroll 8
        for (int k = 0; k < 128; k++) {
            float av[4], bv[4];
#pragma unroll
            for (int i = 0; i < 4; i++) av[i] = Qs[(ty + 16 * i) * 129 + k];
#pragma unroll
            for (int j = 0; j < 4; j++) bv[j] = Ks[(tx + 16 * j) * 129 + k];
#pragma unroll
            for (int i = 0; i < 4; i++)
#pragma unroll
                for (int j = 0; j < 4; j++) sacc[i][j] += av[i] * bv[j];
        }
#pragma unroll
        for (int i = 0; i < 4; i++)
#pragma unroll
            for (int j = 0; j < 4; j++) {
                int r = ty + 16 * i, c = tx + 16 * j;
                int tg = t0 + r, sg = s0 + c;
                float v = (sg > tg || sg < tg - (WLOC - 1)) ? -1e30f
                                                            : sacc[i][j] * SCALE_L;
                Ssm[r * 68 + c] = v;
            }
        __syncthreads();

        if (tid < 64) {
            int r = tid;
            float mo = msm[r], mn = mo;
            for (int c = 0; c < 64; c++) mn = fmaxf(mn, Ssm[r * 68 + c]);
            float sum = 0.f;
            for (int c = 0; c < 64; c++) {
                float sv = Ssm[r * 68 + c];
                float p = (sv <= -1e29f) ? 0.0f : __expf(sv - mn);
                Ssm[r * 68 + c] = p;
                sum += p;
            }
            float al = __expf(mo - mn);
            alsm[r] = al;
            msm[r] = mn;
            lsm[r] = lsm[r] * al + sum;
        }
        __syncthreads();

#pragma unroll
        for (int i = 0; i < 4; i++) {
            float al = alsm[ty + 16 * i];
#pragma unroll
            for (int j = 0; j < 8; j++) acc[i][j] *= al;
        }
        for (int s = 0; s < 64; s++) {
            float p[4];
#pragma unroll
            for (int i = 0; i < 4; i++) p[i] = Ssm[(ty + 16 * i) * 68 + s];
            float4 v0 = *(float4*)&Vs[s * 132 + tx * 8];
            float4 v1 = *(float4*)&Vs[s * 132 + tx * 8 + 4];
#pragma unroll
            for (int i = 0; i < 4; i++) {
                acc[i][0] += p[i] * v0.x; acc[i][1] += p[i] * v0.y;
                acc[i][2] += p[i] * v0.z; acc[i][3] += p[i] * v0.w;
                acc[i][4] += p[i] * v1.x; acc[i][5] += p[i] * v1.y;
                acc[i][6] += p[i] * v1.z; acc[i][7] += p[i] * v1.w;
            }
        }
        __syncthreads();
    }

#pragma unroll
    for (int i = 0; i < 4; i++) {
        int r = ty + 16 * i;
        float inv = 1.0f / lsm[r];
#pragma unroll
        for (int j = 0; j < 8; j++)
            g_ctx[(size_t)(t0 + r) * CC + h * DD + tx * 8 + j] = acc[i][j] * inv;
    }
}

// ============================================================================
// Global low-rank attention
// ============================================================================
__global__ __launch_bounds__(256) void global_attn_k(const float* __restrict__ uo)
{
    extern __shared__ float sm[];
    float* Qs  = sm;                  // [64][65]
    float* Ks  = Qs + 64 * 65;        // [64][65]
    float* Vs  = Ks + 64 * 65;        // [64][68]
    float* Ssm = Vs + 64 * 68;        // [64][68]
    float* msm = Ssm + 64 * 68;
    float* lsm = msm + 64;
    float* alsm = lsm + 64;
    float* uos = sm;                  // epilogue overlay [64][132]

    int qt = blockIdx.x, h = blockIdx.y, t0 = qt << 6;
    int tid = threadIdx.x, ty = tid >> 4, tx = tid & 15;

    for (int i = tid; i < 64 * 64; i += 256) {
        int r = i >> 6, j = i & 63;
        Qs[r * 65 + j] = g_qr[(size_t)(h * TT + t0 + r) * RR + j];
    }
    if (tid < 64) { msm[tid] = -1e30f; lsm[tid] = 0.0f; }

    float acc[4][4];
#pragma unroll
    for (int i = 0; i < 4; i++)
#pragma unroll
        for (int j = 0; j < 4; j++) acc[i][j] = 0.f;
    __syncthreads();

    for (int kt = 0; kt < TT / 64; kt++) {
        int s0 = kt << 6;
        for (int i = tid; i < 64 * 64; i += 256) {
            int c = i >> 6, j = i & 63;
            Ks[c * 65 + j] = g_kr[(size_t)(h * TT + s0 + c) * RR + j];
            Vs[c * 68 + j] = g_vr[(size_t)(h * TT + s0 + c) * RR + j];
        }
        __syncthreads();

        float sacc[4][4];
#pragma unroll
        for (int i = 0; i < 4; i++)
#pragma unroll
            for (int j = 0; j < 4; j++) sacc[i][j] = 0.f;
#pragma unroll 8
        for (int k = 0; k < 64; k++) {
            float av[4], bv[4];
#pragma unroll
            for (int i = 0; i < 4; i++) av[i] = Qs[(ty + 16 * i) * 65 + k];
#pragma unroll
            for (int j = 0; j < 4; j++) bv[j] = Ks[(tx + 16 * j) * 65 + k];
#pragma unroll
            for (int i = 0; i < 4; i++)
#pragma unroll
                for (int j = 0; j < 4; j++) sacc[i][j] += av[i] * bv[j];
        }
#pragma unroll
        for (int i = 0; i < 4; i++)
#pragma unroll
            for (int j = 0; j < 4; j++)
                Ssm[(ty + 16 * i) * 68 + tx + 16 * j] = sacc[i][j] * SCALE_G;
        __syncthreads();

        if (tid < 64) {
            int r = tid;
            float mo = msm[r], mn = mo;
            for (int c = 0; c < 64; c++) mn = fmaxf(mn, Ssm[r * 68 + c]);
            float sum = 0.f;
            for (int c = 0; c < 64; c++) {
                float p = __expf(Ssm[r * 68 + c] - mn);
                Ssm[r * 68 + c] = p;
                sum += p;
            }
            float al = __expf(mo - mn);
            alsm[r] = al;
            msm[r] = mn;
            lsm[r] = lsm[r] * al + sum;
        }
        __syncthreads();

#pragma unroll
        for (int i = 0; i < 4; i++) {
            float al = alsm[ty + 16 * i];
#pragma unroll
            for (int j = 0; j < 4; j++) acc[i][j] *= al;
        }
        for (int s = 0; s < 64; s++) {
            float p[4];
#pragma unroll
            for (int i = 0; i < 4; i++) p[i] = Ssm[(ty + 16 * i) * 68 + s];
            float4 v = *(float4*)&Vs[s * 68 + tx * 4];
#pragma unroll
            for (int i = 0; i < 4; i++) {
                acc[i][0] += p[i] * v.x; acc[i][1] += p[i] * v.y;
                acc[i][2] += p[i] * v.z; acc[i][3] += p[i] * v.w;
            }
        }
        __syncthreads();
    }

#pragma unroll
    for (int i = 0; i < 4; i++) {
        float inv = 1.0f / lsm[ty + 16 * i];
#pragma unroll
        for (int j = 0; j < 4; j++)
            Ssm[(ty + 16 * i) * 68 + tx * 4 + j] = acc[i][j] * inv;
    }
    __syncthreads();

    for (int i = tid; i < 64 * 128; i += 256) {
        int d = i & 127, j = i >> 7;
        uos[j * 132 + d] = uo[d * RR + j];
    }
    __syncthreads();

    float o[4][8];
#pragma unroll
    for (int i = 0; i < 4; i++)
#pragma unroll
        for (int j = 0; j < 8; j++) o[i][j] = 0.f;
    for (int j = 0; j < 64; j++) {
        float p[4];
#pragma unroll
        for (int i = 0; i < 4; i++) p[i] = Ssm[(ty + 16 * i) * 68 + j];
        float4 u0 = *(float4*)&uos[j * 132 + tx * 8];
        float4 u1 = *(float4*)&uos[j * 132 + tx * 8 + 4];
#pragma unroll
        for (int i = 0; i < 4; i++) {
            o[i][0] += p[i] * u0.x; o[i][1] += p[i] * u0.y;
            o[i][2] += p[i] * u0.z; o[i][3] += p[i] * u0.w;
            o[i][4] += p[i] * u1.x; o[i][5] += p[i] * u1.y;
            o[i][6] += p[i] * u1.z; o[i][7] += p[i] * u1.w;
        }
    }
#pragma unroll
    for (int i = 0; i < 4; i++) {
        int tg = t0 + ty + 16 * i;
        if (g_gate[tg] != 0.0f) {
#pragma unroll
            for (int j = 0; j < 8; j++)
                g_ctx[(size_t)tg * CC + h * DD + tx * 8 + j] += o[i][j];
        }
    }
}

// ============================================================================
extern "C" void kernel_launch(void* const* d_in, const int* in_sizes, int n_in,
                              void* d_out, int out_size)
{
    const float* x     = (const float*)d_in[0];
    const float* w_qkv = (const float*)d_in[1];
    const float* w_o   = (const float*)d_in[2];
    const float* pk    = (const float*)d_in[3];
    const float* pv    = (const float*)d_in[4];
    const float* uo    = (const float*)d_in[5];
    const float* iw1   = (const float*)d_in[6];
    const float* iw2   = (const float*)d_in[7];
    float* out = (float*)d_out;

    cudaFuncSetAttribute(gemm_mma,      cudaFuncAttributeMaxDynamicSharedMemorySize, 81920);
    cudaFuncSetAttribute(local_attn_k,  cudaFuncAttributeMaxDynamicSharedMemorySize, 118016);
    cudaFuncSetAttribute(global_attn_k, cudaFuncAttributeMaxDynamicSharedMemorySize, 68864);
    cudaFuncSetAttribute(lowrank_k,     cudaFuncAttributeMaxDynamicSharedMemorySize, 66048);

    void *p_qkv, *p_hinfo, *p_ctx;
    void *pxh, *pxl, *pwqh, *pwql, *pwoh, *pwol, *pi1h, *pi1l, *pcxh, *pcxl;
    cudaGetSymbolAddress(&p_qkv, g_qkv);
    cudaGetSymbolAddress(&p_hinfo, g_hinfo);
    cudaGetSymbolAddress(&p_ctx, g_ctx);
    cudaGetSymbolAddress(&pxh, g_xh);   cudaGetSymbolAddress(&pxl, g_xl);
    cudaGetSymbolAddress(&pwqh, g_wqh); cudaGetSymbolAddress(&pwql, g_wql);
    cudaGetSymbolAddress(&pwoh, g_woh); cudaGetSymbolAddress(&pwol, g_wol);
    cudaGetSymbolAddress(&pi1h, g_i1h); cudaGetSymbolAddress(&pi1l, g_i1l);
    cudaGetSymbolAddress(&pcxh, g_cxh); cudaGetSymbolAddress(&pcxl, g_cxl);

#define SPLIT(src, h, l, n) \
    split_bf16_k<<<((n)/2 + 255) / 256, 256>>>((const float2*)(src), \
        (__nv_bfloat162*)(h), (__nv_bfloat162*)(l), (n)/2)

    SPLIT(x, pxh, pxl, TT * CC);
    SPLIT(w_qkv, pwqh, pwql, C3 * CC);
    SPLIT(iw1, pi1h, pi1l, CI * CC);
    SPLIT(w_o, pwoh, pwol, CC * CC);

    // qkv = x @ w_qkv^T   (M=TT, N=C3, K=CC)
    gemm_mma<<<dim3(C3 / 128, TT / 128), 256, 81920>>>(
        (const __nv_bfloat16*)pxh, (const __nv_bfloat16*)pxl,
        (const __nv_bfloat16*)pwqh, (const __nv_bfloat16*)pwql,
        (float*)p_qkv, C3, CC, 0);
    rope_table_k<<<TT, DD>>>();
    rope_apply_k<<<dim3(TT, HH), 64>>>();

    // h_info = gelu(x @ iw1^T)
    gemm_mma<<<dim3(CI / 128, TT / 128), 256, 81920>>>(
        (const __nv_bfloat16*)pxh, (const __nv_bfloat16*)pxl,
        (const __nv_bfloat16*)pi1h, (const __nv_bfloat16*)pi1l,
        (float*)p_hinfo, CI, CC, 1);
    gate_k<<<TT, 128>>>(iw2);

    lowrank_k<<<dim3(TT / 64, HH), 256, 66048>>>(pk, pv);
    local_attn_k<<<dim3(TT / 64, HH), 256, 118016>>>();
    global_attn_k<<<dim3(TT / 64, HH), 256, 68864>>>(uo);

    // out = ctx @ w_o^T
    SPLIT(p_ctx, pcxh, pcxl, TT * CC);
    gemm_mma<<<dim3(CC / 128, TT / 128), 256, 81920>>>(
        (const __nv_bfloat16*)pcxh, (const __nv_bfloat16*)pcxl,
        (const __nv_bfloat16*)pwoh, (const __nv_bfloat16*)pwol,
        out, CC, CC, 0);
#undef SPLIT
}

// round 5
// speedup vs baseline: 2.7735x; 1.6181x over previous
#include <cuda_runtime.h>
#include <cuda_bf16.h>
#include <math.h>
#include <stdint.h>

#define TT   2048
#define CC   2048
#define HH   16
#define DD   128
#define RR   64
#define WLOC 512
#define CI   512
#define C3   6144

#define SCALE_L 0.08838834764831845f
#define SCALE_G 0.1767766952966369f

// ---------------- scratch (device globals) ----------------
__device__ float g_qkv[TT * C3];
__device__ float g_hinfo[TT * CI];
__device__ float g_gate[TT];
__device__ float g_cos[TT * DD];
__device__ float g_sin[TT * DD];
__device__ float g_ctx[TT * CC];

// bf16 hi/lo split operands
__device__ __nv_bfloat16 g_xh[TT * CC],  g_xl[TT * CC];
__device__ __nv_bfloat16 g_wqh[C3 * CC], g_wql[C3 * CC];
__device__ __nv_bfloat16 g_woh[CC * CC], g_wol[CC * CC];
__device__ __nv_bfloat16 g_i1h[CI * CC], g_i1l[CI * CC];
__device__ __nv_bfloat16 g_cxh[TT * CC], g_cxl[TT * CC];
__device__ __nv_bfloat16 g_qkvh[TT * C3], g_qkvl[TT * C3];
__device__ __nv_bfloat16 g_qrh[HH * TT * RR], g_qrl[HH * TT * RR];
__device__ __nv_bfloat16 g_krh[HH * TT * RR], g_krl[HH * TT * RR];
__device__ __nv_bfloat16 g_vrh[HH * TT * RR], g_vrl[HH * TT * RR];
__device__ __nv_bfloat16 g_uoh[DD * RR], g_uol[DD * RR];

// ============================================================================
// PTX helpers (plain sm_80+ ISA — valid on compute_103 non-'a')
// ============================================================================
__device__ __forceinline__ uint32_t smem_u32(const void* p) {
    uint32_t a;
    asm("{ .reg .u64 t; cvta.to.shared.u64 t, %1; cvt.u32.u64 %0, t; }"
        : "=r"(a) : "l"(p));
    return a;
}

#define CP16(s, g) \
    asm volatile("cp.async.cg.shared.global [%0], [%1], 16;" \
                 :: "r"(s), "l"(g) : "memory")
#define CP_COMMIT() asm volatile("cp.async.commit_group;" ::: "memory")
#define CP_WAIT(n)  asm volatile("cp.async.wait_group %0;" :: "n"(n) : "memory")

__device__ __forceinline__ void ldsm4(uint32_t& r0, uint32_t& r1,
                                      uint32_t& r2, uint32_t& r3, uint32_t a) {
    asm volatile("ldmatrix.sync.aligned.m8n8.x4.shared.b16 {%0,%1,%2,%3}, [%4];"
                 : "=r"(r0), "=r"(r1), "=r"(r2), "=r"(r3) : "r"(a));
}
__device__ __forceinline__ void ldsm4t(uint32_t& r0, uint32_t& r1,
                                       uint32_t& r2, uint32_t& r3, uint32_t a) {
    asm volatile("ldmatrix.sync.aligned.m8n8.x4.trans.shared.b16 {%0,%1,%2,%3}, [%4];"
                 : "=r"(r0), "=r"(r1), "=r"(r2), "=r"(r3) : "r"(a));
}

__device__ __forceinline__ void mma16816(float* c, const uint32_t* a,
                                         const uint32_t* b) {
    asm volatile("mma.sync.aligned.m16n8k16.row.col.f32.bf16.bf16.f32 "
                 "{%0,%1,%2,%3}, {%4,%5,%6,%7}, {%8,%9}, {%0,%1,%2,%3};"
                 : "+f"(c[0]), "+f"(c[1]), "+f"(c[2]), "+f"(c[3])
                 : "r"(a[0]), "r"(a[1]), "r"(a[2]), "r"(a[3]),
                   "r"(b[0]), "r"(b[1]));
}

__device__ __forceinline__ void split2(float x, float y, uint32_t& h, uint32_t& l) {
    __nv_bfloat162 hh = __floats2bfloat162_rn(x, y);
    h = *reinterpret_cast<uint32_t*>(&hh);
    __nv_bfloat162 ll = __floats2bfloat162_rn(x - __bfloat162float(hh.x),
                                              y - __bfloat162float(hh.y));
    l = *reinterpret_cast<uint32_t*>(&ll);
}

// ============================================================================
// fp32 -> bf16 hi/lo split
// ============================================================================
__global__ void split_bf16_k(const float2* __restrict__ src,
                             __nv_bfloat162* __restrict__ hi,
                             __nv_bfloat162* __restrict__ lo, int n2)
{
    int i = blockIdx.x * 256 + threadIdx.x;
    if (i < n2) {
        float2 v = src[i];
        __nv_bfloat162 h = __floats2bfloat162_rn(v.x, v.y);
        hi[i] = h;
        lo[i] = __floats2bfloat162_rn(v.x - __bfloat162float(h.x),
                                      v.y - __bfloat162float(h.y));
    }
}

// ============================================================================
// mma.sync GEMM (unchanged from R4): C = Ah·Bh^T + Al·Bh^T + Ah·Bl^T
// ============================================================================
__global__ __launch_bounds__(256) void gemm_mma(
    const __nv_bfloat16* __restrict__ Ah, const __nv_bfloat16* __restrict__ Al,
    const __nv_bfloat16* __restrict__ Bh, const __nv_bfloat16* __restrict__ Bl,
    float* __restrict__ Cout, int N, int K, int dogelu)
{
    extern __shared__ __align__(128) char smraw[];
    const uint32_t sb = smem_u32(smraw);
    const int tid = threadIdx.x, lane = tid & 31, wid = tid >> 5;
    const int wm = wid & 3, wn = wid >> 2;
    const int bm = blockIdx.y << 7, bn = blockIdx.x << 7;
    const int aj = lane >> 3, ar = lane & 7;

    float acc[2][8][4];
#pragma unroll
    for (int mt = 0; mt < 2; mt++)
#pragma unroll
        for (int nt = 0; nt < 8; nt++)
#pragma unroll
            for (int e = 0; e < 4; e++) acc[mt][nt][e] = 0.f;

    const int nch = K >> 5;

    auto issue_stage = [&](int c) {
        const uint32_t st = sb + (c & 1) * 40960;
        const int k0 = c << 5;
        const __nv_bfloat16* gm0 = Ah + (size_t)bm * K + k0;
        const __nv_bfloat16* gm1 = Al + (size_t)bm * K + k0;
        const __nv_bfloat16* gm2 = Bh + (size_t)bn * K + k0;
        const __nv_bfloat16* gm3 = Bl + (size_t)bn * K + k0;
#pragma unroll
        for (int h = 0; h < 2; h++) {
            int i = tid + h * 256;
            int r = i >> 2, q = i & 3;
            uint32_t so = st + r * 80 + q * 16;
            size_t go = (size_t)r * K + q * 8;
            CP16(so,          gm0 + go);
            CP16(so + 10240,  gm1 + go);
            CP16(so + 20480,  gm2 + go);
            CP16(so + 30720,  gm3 + go);
        }
        CP_COMMIT();
    };

    issue_stage(0);
    for (int c = 0; c < nch; c++) {
        if (c + 1 < nch) { issue_stage(c + 1); CP_WAIT(1); }
        else             { CP_WAIT(0); }
        __syncthreads();

        const uint32_t st = sb + (c & 1) * 40960;
#pragma unroll
        for (int ks = 0; ks < 2; ks++) {
            uint32_t a[2][4], b2[8][2];
            const uint32_t a_off =
                ((wm * 32 + (aj & 1) * 8 + ar) * 40 + ks * 16 + (aj >> 1) * 8) * 2;
            const uint32_t b_off =
                ((wn * 64 + (aj >> 1) * 8 + ar) * 40 + ks * 16 + (aj & 1) * 8) * 2;

#pragma unroll
            for (int mt = 0; mt < 2; mt++)
                ldsm4(a[mt][0], a[mt][1], a[mt][2], a[mt][3],
                      st + a_off + mt * (16 * 40 * 2));
#pragma unroll
            for (int np = 0; np < 4; np++) {
                uint32_t r0, r1, r2, r3;
                ldsm4(r0, r1, r2, r3, st + 20480 + b_off + np * (16 * 40 * 2));
                b2[np * 2][0] = r0;     b2[np * 2][1] = r1;
                b2[np * 2 + 1][0] = r2; b2[np * 2 + 1][1] = r3;
            }
#pragma unroll
            for (int mt = 0; mt < 2; mt++)
#pragma unroll
                for (int nt = 0; nt < 8; nt++)
                    mma16816(acc[mt][nt], a[mt], b2[nt]);

#pragma unroll
            for (int mt = 0; mt < 2; mt++)
                ldsm4(a[mt][0], a[mt][1], a[mt][2], a[mt][3],
                      st + 10240 + a_off + mt * (16 * 40 * 2));
#pragma unroll
            for (int mt = 0; mt < 2; mt++)
#pragma unroll
                for (int nt = 0; nt < 8; nt++)
                    mma16816(acc[mt][nt], a[mt], b2[nt]);

#pragma unroll
            for (int mt = 0; mt < 2; mt++)
                ldsm4(a[mt][0], a[mt][1], a[mt][2], a[mt][3],
                      st + a_off + mt * (16 * 40 * 2));
#pragma unroll
            for (int np = 0; np < 4; np++) {
                uint32_t r0, r1, r2, r3;
                ldsm4(r0, r1, r2, r3, st + 30720 + b_off + np * (16 * 40 * 2));
                b2[np * 2][0] = r0;     b2[np * 2][1] = r1;
                b2[np * 2 + 1][0] = r2; b2[np * 2 + 1][1] = r3;
            }
#pragma unroll
            for (int mt = 0; mt < 2; mt++)
#pragma unroll
                for (int nt = 0; nt < 8; nt++)
                    mma16816(acc[mt][nt], a[mt], b2[nt]);
        }
        __syncthreads();
    }

    const int row_base = bm + wm * 32 + (lane >> 2);
    const int col_base = bn + wn * 64 + (lane & 3) * 2;
#pragma unroll
    for (int mt = 0; mt < 2; mt++)
#pragma unroll
        for (int nt = 0; nt < 8; nt++) {
            int r0 = row_base + mt * 16, cc = col_base + nt * 8;
            float v0 = acc[mt][nt][0], v1 = acc[mt][nt][1];
            float v2 = acc[mt][nt][2], v3 = acc[mt][nt][3];
            if (dogelu) {
                v0 = 0.5f * v0 * (1.0f + erff(v0 * 0.7071067811865475f));
                v1 = 0.5f * v1 * (1.0f + erff(v1 * 0.7071067811865475f));
                v2 = 0.5f * v2 * (1.0f + erff(v2 * 0.7071067811865475f));
                v3 = 0.5f * v3 * (1.0f + erff(v3 * 0.7071067811865475f));
            }
            *(float2*)(Cout + (size_t)r0 * N + cc)       = make_float2(v0, v1);
            *(float2*)(Cout + (size_t)(r0 + 8) * N + cc) = make_float2(v2, v3);
        }
}

// ============================================================================
// RoPE
// ============================================================================
__global__ void rope_table_k()
{
    int t = blockIdx.x, d = threadIdx.x;
    int j = d & 63;
    double ang = (double)t * exp(-(double)j * (log(10000.0) / 64.0));
    g_cos[t * DD + d] = (float)cos(ang);
    g_sin[t * DD + d] = (float)sin(ang);
}

__global__ void rope_apply_k()
{
    int t = blockIdx.x, h = blockIdx.y, j = threadIdx.x;   // j < 64
    int d0 = 2 * j, d1 = d0 + 1;
    float c0 = g_cos[t * DD + d0], s0 = g_sin[t * DD + d0];
    float c1 = g_cos[t * DD + d1], s1 = g_sin[t * DD + d1];
    float* q = &g_qkv[(size_t)t * C3 + h * DD];
    float q0 = q[d0], q1 = q[d1];
    q[d0] = q0 * c0 - q1 * s0;
    q[d1] = q1 * c1 + q0 * s1;
    float* kp = q + CC;
    float k0 = kp[d0], k1 = kp[d1];
    kp[d0] = k0 * c0 - k1 * s0;
    kp[d1] = k1 * c1 + k0 * s1;
}

// ============================================================================
// Gate
// ============================================================================
__global__ void gate_k(const float* __restrict__ w2)
{
    __shared__ float red[128];
    int t = blockIdx.x, tid = threadIdx.x;
    float s = 0.f;
    for (int j = tid; j < CI; j += 128) s += g_hinfo[t * CI + j] * w2[j];
    red[tid] = s;
    __syncthreads();
    for (int off = 64; off > 0; off >>= 1) {
        if (tid < off) red[tid] += red[tid + off];
        __syncthreads();
    }
    if (tid == 0) {
        float sc = 1.0f / (1.0f + expf(-red[0]));
        g_gate[t] = (sc > 0.75f) ? 1.0f : 0.0f;
    }
}

// ============================================================================
// Low-rank projections -> bf16 hi/lo outputs
// ============================================================================
__global__ __launch_bounds__(256) void lowrank_k(
    const float* __restrict__ pk, const float* __restrict__ pv)
{
    extern __shared__ float sm[];
    float* Xs = sm;               // [64][129]
    float* Ps = sm + 64 * 129;    // [64][129]
    int qt = blockIdx.x, h = blockIdx.y, t0 = qt << 6;
    int tid = threadIdx.x, ty = tid >> 4, tx = tid & 15;

    for (int pass = 0; pass < 3; pass++) {
        const float* proj = (pass == 2) ? pv : pk;
        int coloff = pass * CC + h * DD;
        __syncthreads();
        for (int i = tid; i < 64 * 128; i += 256) {
            int r = i >> 7, d = i & 127;
            Xs[r * 129 + d] = g_qkv[(size_t)(t0 + r) * C3 + coloff + d];
            Ps[r * 129 + d] = proj[r * 128 + d];
        }
        __syncthreads();
        float acc[4][4];
#pragma unroll
        for (int i = 0; i < 4; i++)
#pragma unroll
            for (int j = 0; j < 4; j++) acc[i][j] = 0.f;
#pragma unroll 8
        for (int k = 0; k < 128; k++) {
            float av[4], bv[4];
#pragma unroll
            for (int i = 0; i < 4; i++) av[i] = Xs[(ty + 16 * i) * 129 + k];
#pragma unroll
            for (int j = 0; j < 4; j++) bv[j] = Ps[(tx + 16 * j) * 129 + k];
#pragma unroll
            for (int i = 0; i < 4; i++)
#pragma unroll
                for (int j = 0; j < 4; j++) acc[i][j] += av[i] * bv[j];
        }
        __nv_bfloat16* dh = (pass == 0) ? g_qrh : (pass == 1) ? g_krh : g_vrh;
        __nv_bfloat16* dl = (pass == 0) ? g_qrl : (pass == 1) ? g_krl : g_vrl;
#pragma unroll
        for (int i = 0; i < 4; i++)
#pragma unroll
            for (int j = 0; j < 4; j++) {
                size_t idx = (size_t)(h * TT + t0 + ty + 16 * i) * RR + tx + 16 * j;
                float v = acc[i][j];
                __nv_bfloat16 hb = __float2bfloat16(v);
                dh[idx] = hb;
                dl[idx] = __float2bfloat16(v - __bfloat162float(hb));
            }
    }
}

// ============================================================================
// Local sliding-window attention, mma.sync, split bf16.
// 4 warps, 64 q-rows/block. smem: 6 x [64][136] bf16 = 104448 B.
// ============================================================================
#define LPAD 136
__global__ __launch_bounds__(128) void local_attn_mma()
{
    extern __shared__ __align__(16) char smraw[];
    const uint32_t sb = smem_u32(smraw);
    const uint32_t oQh = 0, oQl = 64 * LPAD, oKh = 2 * 64 * LPAD,
                   oKl = 3 * 64 * LPAD, oVh = 4 * 64 * LPAD, oVl = 5 * 64 * LPAD;

    const int tid = threadIdx.x, lane = tid & 31, w = tid >> 5;
    const int qt = blockIdx.x, h = blockIdx.y, t0 = qt << 6;
    const int aj = lane >> 3, ar = lane & 7;
    const int tg0 = t0 + w * 16 + (lane >> 2), tg1 = tg0 + 8;
    const int cq = (lane & 3) * 2;

    // Q load (hi/lo)
    for (int i = tid; i < 1024; i += 128) {
        int r = i >> 4, q = i & 15;
        uint32_t so = sb + (r * LPAD + q * 8) * 2;
        size_t go = (size_t)(t0 + r) * C3 + h * DD + q * 8;
        CP16(so, g_qkvh + go);
        CP16(so + oQl * 2, g_qkvl + go);
    }
    CP_COMMIT();

    float m0 = -1e30f, m1 = -1e30f, l0 = 0.f, l1 = 0.f;
    float out[16][4];
#pragma unroll
    for (int nt = 0; nt < 16; nt++)
#pragma unroll
        for (int e = 0; e < 4; e++) out[nt][e] = 0.f;

    const uint32_t aQoff = ((w * 16 + (aj & 1) * 8 + ar) * LPAD + (aj >> 1) * 8) * 2;
    const uint32_t bKoff = (((aj >> 1) * 8 + ar) * LPAD + (aj & 1) * 8) * 2;
    const uint32_t bVoff = (((aj & 1) * 8 + ar) * LPAD + (aj >> 1) * 8) * 2;

    const int kt0 = (t0 > WLOC - 1) ? ((t0 - (WLOC - 1)) >> 6) : 0;

    for (int kt = kt0; kt <= qt; kt++) {
        const int s0 = kt << 6;
        for (int i = tid; i < 1024; i += 128) {
            int r = i >> 4, q = i & 15;
            size_t gk = (size_t)(s0 + r) * C3 + CC + h * DD + q * 8;
            uint32_t off = (r * LPAD + q * 8) * 2;
            CP16(sb + oKh * 2 + off, g_qkvh + gk);
            CP16(sb + oKl * 2 + off, g_qkvl + gk);
            CP16(sb + oVh * 2 + off, g_qkvh + gk + CC);
            CP16(sb + oVl * 2 + off, g_qkvl + gk + CC);
        }
        CP_COMMIT();
        CP_WAIT(0);
        __syncthreads();

        // ---- S = Q K^T (3-term split) ----
        float s[8][4];
#pragma unroll
        for (int nt = 0; nt < 8; nt++)
#pragma unroll
            for (int e = 0; e < 4; e++) s[nt][e] = 0.f;

#pragma unroll
        for (int kb = 0; kb < 8; kb++) {
            uint32_t ah[4], al_[4], b2[8][2];
            ldsm4(ah[0], ah[1], ah[2], ah[3], sb + aQoff + kb * 32);
            ldsm4(al_[0], al_[1], al_[2], al_[3], sb + oQl * 2 + aQoff + kb * 32);
#pragma unroll
            for (int np = 0; np < 4; np++) {
                uint32_t r0, r1, r2, r3;
                ldsm4(r0, r1, r2, r3,
                      sb + oKh * 2 + bKoff + np * 16 * LPAD * 2 + kb * 32);
                b2[np * 2][0] = r0;     b2[np * 2][1] = r1;
                b2[np * 2 + 1][0] = r2; b2[np * 2 + 1][1] = r3;
            }
#pragma unroll
            for (int nt = 0; nt < 8; nt++) mma16816(s[nt], ah, b2[nt]);
#pragma unroll
            for (int nt = 0; nt < 8; nt++) mma16816(s[nt], al_, b2[nt]);
#pragma unroll
            for (int np = 0; np < 4; np++) {
                uint32_t r0, r1, r2, r3;
                ldsm4(r0, r1, r2, r3,
                      sb + oKl * 2 + bKoff + np * 16 * LPAD * 2 + kb * 32);
                b2[np * 2][0] = r0;     b2[np * 2][1] = r1;
                b2[np * 2 + 1][0] = r2; b2[np * 2 + 1][1] = r3;
            }
#pragma unroll
            for (int nt = 0; nt < 8; nt++) mma16816(s[nt], ah, b2[nt]);
        }

        // ---- scale + mask ----
#pragma unroll
        for (int nt = 0; nt < 8; nt++) {
            int c0 = s0 + nt * 8 + cq;
#pragma unroll
            for (int e = 0; e < 2; e++) {
                int sg = c0 + e;
                float v0 = s[nt][e] * SCALE_L;
                s[nt][e] = (sg <= tg0 && sg >= tg0 - (WLOC - 1)) ? v0 : -1e30f;
                float v1 = s[nt][2 + e] * SCALE_L;
                s[nt][2 + e] = (sg <= tg1 && sg >= tg1 - (WLOC - 1)) ? v1 : -1e30f;
            }
        }

        // ---- online softmax (register, quad shuffles) ----
        float mx0 = -1e30f, mx1 = -1e30f;
#pragma unroll
        for (int nt = 0; nt < 8; nt++) {
            mx0 = fmaxf(mx0, fmaxf(s[nt][0], s[nt][1]));
            mx1 = fmaxf(mx1, fmaxf(s[nt][2], s[nt][3]));
        }
        mx0 = fmaxf(mx0, __shfl_xor_sync(0xffffffffu, mx0, 1));
        mx0 = fmaxf(mx0, __shfl_xor_sync(0xffffffffu, mx0, 2));
        mx1 = fmaxf(mx1, __shfl_xor_sync(0xffffffffu, mx1, 1));
        mx1 = fmaxf(mx1, __shfl_xor_sync(0xffffffffu, mx1, 2));
        float mn0 = fmaxf(m0, mx0), mn1 = fmaxf(m1, mx1);
        float al0 = __expf(m0 - mn0), al1 = __expf(m1 - mn1);
        m0 = mn0; m1 = mn1;

        float sum0 = 0.f, sum1 = 0.f;
#pragma unroll
        for (int nt = 0; nt < 8; nt++) {
#pragma unroll
            for (int e = 0; e < 2; e++) {
                float p0 = (s[nt][e]     > -1e29f) ? __expf(s[nt][e]     - mn0) : 0.f;
                float p1 = (s[nt][2 + e] > -1e29f) ? __expf(s[nt][2 + e] - mn1) : 0.f;
                s[nt][e] = p0; s[nt][2 + e] = p1;
                sum0 += p0; sum1 += p1;
            }
        }
        sum0 += __shfl_xor_sync(0xffffffffu, sum0, 1);
        sum0 += __shfl_xor_sync(0xffffffffu, sum0, 2);
        sum1 += __shfl_xor_sync(0xffffffffu, sum1, 1);
        sum1 += __shfl_xor_sync(0xffffffffu, sum1, 2);
        l0 = l0 * al0 + sum0;
        l1 = l1 * al1 + sum1;

#pragma unroll
        for (int nt = 0; nt < 16; nt++) {
            out[nt][0] *= al0; out[nt][1] *= al0;
            out[nt][2] *= al1; out[nt][3] *= al1;
        }

        // ---- O += P V (3-term split) ----
#pragma unroll
        for (int kb = 0; kb < 4; kb++) {
            uint32_t ph[4], pl[4];
            split2(s[2 * kb][0],     s[2 * kb][1],     ph[0], pl[0]);
            split2(s[2 * kb][2],     s[2 * kb][3],     ph[1], pl[1]);
            split2(s[2 * kb + 1][0], s[2 * kb + 1][1], ph[2], pl[2]);
            split2(s[2 * kb + 1][2], s[2 * kb + 1][3], ph[3], pl[3]);
#pragma unroll
            for (int g = 0; g < 8; g++) {
                uint32_t vb = bVoff + kb * 16 * LPAD * 2 + g * 32;
                uint32_t r0, r1, r2, r3;
                ldsm4t(r0, r1, r2, r3, sb + oVh * 2 + vb);
                uint32_t b0[2] = {r0, r1}, b1[2] = {r2, r3};
                mma16816(out[2 * g], ph, b0);     mma16816(out[2 * g + 1], ph, b1);
                mma16816(out[2 * g], pl, b0);     mma16816(out[2 * g + 1], pl, b1);
                ldsm4t(r0, r1, r2, r3, sb + oVl * 2 + vb);
                uint32_t c0[2] = {r0, r1}, c1[2] = {r2, r3};
                mma16816(out[2 * g], ph, c0);     mma16816(out[2 * g + 1], ph, c1);
            }
        }
        __syncthreads();
    }

    const float inv0 = 1.f / l0, inv1 = 1.f / l1;
#pragma unroll
    for (int nt = 0; nt < 16; nt++) {
        *(float2*)(g_ctx + (size_t)tg0 * CC + h * DD + nt * 8 + cq) =
            make_float2(out[nt][0] * inv0, out[nt][1] * inv0);
        *(float2*)(g_ctx + (size_t)tg1 * CC + h * DD + nt * 8 + cq) =
            make_float2(out[nt][2] * inv1, out[nt][3] * inv1);
    }
}

// ============================================================================
// Global low-rank attention, mma.sync, split bf16, gated epilogue O @ uo^T.
// 4 warps, 64 q-rows/block. smem: 6 x [64][72] bf16 = 55296 B.
// ============================================================================
#define GPAD 72
__global__ __launch_bounds__(128) void global_attn_mma()
{
    extern __shared__ __align__(16) char smraw[];
    const uint32_t sb = smem_u32(smraw);
    const uint32_t oQh = 0, oQl = 64 * GPAD, oKh = 2 * 64 * GPAD,
                   oKl = 3 * 64 * GPAD, oVh = 4 * 64 * GPAD, oVl = 5 * 64 * GPAD;
    const uint32_t oUh = oKh, oUl = oVh;   // epilogue overlays (128*GPAD each)

    const int tid = threadIdx.x, lane = tid & 31, w = tid >> 5;
    const int qt = blockIdx.x, h = blockIdx.y, t0 = qt << 6;
    const int aj = lane >> 3, ar = lane & 7;
    const int tg0 = t0 + w * 16 + (lane >> 2), tg1 = tg0 + 8;
    const int cq = (lane & 3) * 2;

    // Q_r load
    for (int i = tid; i < 512; i += 128) {
        int r = i >> 3, q = i & 7;
        uint32_t so = sb + (r * GPAD + q * 8) * 2;
        size_t go = (size_t)(h * TT + t0 + r) * RR + q * 8;
        CP16(so, g_qrh + go);
        CP16(so + oQl * 2, g_qrl + go);
    }
    CP_COMMIT();

    float m0 = -1e30f, m1 = -1e30f, l0 = 0.f, l1 = 0.f;
    float out[8][4];
#pragma unroll
    for (int nt = 0; nt < 8; nt++)
#pragma unroll
        for (int e = 0; e < 4; e++) out[nt][e] = 0.f;

    const uint32_t aQoff = ((w * 16 + (aj & 1) * 8 + ar) * GPAD + (aj >> 1) * 8) * 2;
    const uint32_t bKoff = (((aj >> 1) * 8 + ar) * GPAD + (aj & 1) * 8) * 2;
    const uint32_t bVoff = (((aj & 1) * 8 + ar) * GPAD + (aj >> 1) * 8) * 2;

    for (int kt = 0; kt < TT / 64; kt++) {
        const int s0 = kt << 6;
        for (int i = tid; i < 512; i += 128) {
            int r = i >> 3, q = i & 7;
            size_t gk = (size_t)(h * TT + s0 + r) * RR + q * 8;
            uint32_t off = (r * GPAD + q * 8) * 2;
            CP16(sb + oKh * 2 + off, g_krh + gk);
            CP16(sb + oKl * 2 + off, g_krl + gk);
            CP16(sb + oVh * 2 + off, g_vrh + gk);
            CP16(sb + oVl * 2 + off, g_vrl + gk);
        }
        CP_COMMIT();
        CP_WAIT(0);
        __syncthreads();

        float s[8][4];
#pragma unroll
        for (int nt = 0; nt < 8; nt++)
#pragma unroll
            for (int e = 0; e < 4; e++) s[nt][e] = 0.f;

#pragma unroll
        for (int kb = 0; kb < 4; kb++) {
            uint32_t ah[4], al_[4], b2[8][2];
            ldsm4(ah[0], ah[1], ah[2], ah[3], sb + aQoff + kb * 32);
            ldsm4(al_[0], al_[1], al_[2], al_[3], sb + oQl * 2 + aQoff + kb * 32);
#pragma unroll
            for (int np = 0; np < 4; np++) {
                uint32_t r0, r1, r2, r3;
                ldsm4(r0, r1, r2, r3,
                      sb + oKh * 2 + bKoff + np * 16 * GPAD * 2 + kb * 32);
                b2[np * 2][0] = r0;     b2[np * 2][1] = r1;
                b2[np * 2 + 1][0] = r2; b2[np * 2 + 1][1] = r3;
            }
#pragma unroll
            for (int nt = 0; nt < 8; nt++) mma16816(s[nt], ah, b2[nt]);
#pragma unroll
            for (int nt = 0; nt < 8; nt++) mma16816(s[nt], al_, b2[nt]);
#pragma unroll
            for (int np = 0; np < 4; np++) {
                uint32_t r0, r1, r2, r3;
                ldsm4(r0, r1, r2, r3,
                      sb + oKl * 2 + bKoff + np * 16 * GPAD * 2 + kb * 32);
                b2[np * 2][0] = r0;     b2[np * 2][1] = r1;
                b2[np * 2 + 1][0] = r2; b2[np * 2 + 1][1] = r3;
            }
#pragma unroll
            for (int nt = 0; nt < 8; nt++) mma16816(s[nt], ah, b2[nt]);
        }

        float mx0 = -1e30f, mx1 = -1e30f;
#pragma unroll
        for (int nt = 0; nt < 8; nt++) {
            s[nt][0] *= SCALE_G; s[nt][1] *= SCALE_G;
            s[nt][2] *= SCALE_G; s[nt][3] *= SCALE_G;
            mx0 = fmaxf(mx0, fmaxf(s[nt][0], s[nt][1]));
            mx1 = fmaxf(mx1, fmaxf(s[nt][2], s[nt][3]));
        }
        mx0 = fmaxf(mx0, __shfl_xor_sync(0xffffffffu, mx0, 1));
        mx0 = fmaxf(mx0, __shfl_xor_sync(0xffffffffu, mx0, 2));
        mx1 = fmaxf(mx1, __shfl_xor_sync(0xffffffffu, mx1, 1));
        mx1 = fmaxf(mx1, __shfl_xor_sync(0xffffffffu, mx1, 2));
        float mn0 = fmaxf(m0, mx0), mn1 = fmaxf(m1, mx1);
        float al0 = __expf(m0 - mn0), al1 = __expf(m1 - mn1);
        m0 = mn0; m1 = mn1;

        float sum0 = 0.f, sum1 = 0.f;
#pragma unroll
        for (int nt = 0; nt < 8; nt++) {
#pragma unroll
            for (int e = 0; e < 2; e++) {
                float p0 = __expf(s[nt][e] - mn0);
                float p1 = __expf(s[nt][2 + e] - mn1);
                s[nt][e] = p0; s[nt][2 + e] = p1;
                sum0 += p0; sum1 += p1;
            }
        }
        sum0 += __shfl_xor_sync(0xffffffffu, sum0, 1);
        sum0 += __shfl_xor_sync(0xffffffffu, sum0, 2);
        sum1 += __shfl_xor_sync(0xffffffffu, sum1, 1);
        sum1 += __shfl_xor_sync(0xffffffffu, sum1, 2);
        l0 = l0 * al0 + sum0;
        l1 = l1 * al1 + sum1;

#pragma unroll
        for (int nt = 0; nt < 8; nt++) {
            out[nt][0] *= al0; out[nt][1] *= al0;
            out[nt][2] *= al1; out[nt][3] *= al1;
        }

#pragma unroll
        for (int kb = 0; kb < 4; kb++) {
            uint32_t ph[4], pl[4];
            split2(s[2 * kb][0],     s[2 * kb][1],     ph[0], pl[0]);
            split2(s[2 * kb][2],     s[2 * kb][3],     ph[1], pl[1]);
            split2(s[2 * kb + 1][0], s[2 * kb + 1][1], ph[2], pl[2]);
            split2(s[2 * kb + 1][2], s[2 * kb + 1][3], ph[3], pl[3]);
#pragma unroll
            for (int g = 0; g < 4; g++) {
                uint32_t vb = bVoff + kb * 16 * GPAD * 2 + g * 32;
                uint32_t r0, r1, r2, r3;
                ldsm4t(r0, r1, r2, r3, sb + oVh * 2 + vb);
                uint32_t b0[2] = {r0, r1}, b1[2] = {r2, r3};
                mma16816(out[2 * g], ph, b0);     mma16816(out[2 * g + 1], ph, b1);
                mma16816(out[2 * g], pl, b0);     mma16816(out[2 * g + 1], pl, b1);
                ldsm4t(r0, r1, r2, r3, sb + oVl * 2 + vb);
                uint32_t c0[2] = {r0, r1}, c1[2] = {r2, r3};
                mma16816(out[2 * g], ph, c0);     mma16816(out[2 * g + 1], ph, c1);
            }
        }
        __syncthreads();
    }

    // normalize O
    const float inv0 = 1.f / l0, inv1 = 1.f / l1;
#pragma unroll
    for (int nt = 0; nt < 8; nt++) {
        out[nt][0] *= inv0; out[nt][1] *= inv0;
        out[nt][2] *= inv1; out[nt][3] *= inv1;
    }

    // load uo^T splits into overlay region
    for (int i = tid; i < 1024; i += 128) {
        int d = i >> 3, q = i & 7;
        *(int4*)(smraw + (oUh + d * GPAD + q * 8) * 2) =
            *(const int4*)(g_uoh + d * 64 + q * 8);
        *(int4*)(smraw + (oUl + d * GPAD + q * 8) * 2) =
            *(const int4*)(g_uol + d * 64 + q * 8);
    }
    __syncthreads();

    // ctx_g = O @ uo^T  (3-term split)
    float out2[16][4];
#pragma unroll
    for (int nt = 0; nt < 16; nt++)
#pragma unroll
        for (int e = 0; e < 4; e++) out2[nt][e] = 0.f;

    const uint32_t bUoff = (((aj >> 1) * 8 + ar) * GPAD + (aj & 1) * 8) * 2;
#pragma unroll
    for (int kb = 0; kb < 4; kb++) {
        uint32_t ph[4], pl[4];
        split2(out[2 * kb][0],     out[2 * kb][1],     ph[0], pl[0]);
        split2(out[2 * kb][2],     out[2 * kb][3],     ph[1], pl[1]);
        split2(out[2 * kb + 1][0], out[2 * kb + 1][1], ph[2], pl[2]);
        split2(out[2 * kb + 1][2], out[2 * kb + 1][3], ph[3], pl[3]);
#pragma unroll
        for (int g = 0; g < 8; g++) {
            uint32_t ub = bUoff + g * 16 * GPAD * 2 + kb * 32;
            uint32_t r0, r1, r2, r3;
            ldsm4(r0, r1, r2, r3, sb + oUh * 2 + ub);
            uint32_t b0[2] = {r0, r1}, b1[2] = {r2, r3};
            mma16816(out2[2 * g], ph, b0);     mma16816(out2[2 * g + 1], ph, b1);
            mma16816(out2[2 * g], pl, b0);     mma16816(out2[2 * g + 1], pl, b1);
            ldsm4(r0, r1, r2, r3, sb + oUl * 2 + ub);
            uint32_t c0[2] = {r0, r1}, c1[2] = {r2, r3};
            mma16816(out2[2 * g], ph, c0);     mma16816(out2[2 * g + 1], ph, c1);
        }
    }

    const float ga0 = g_gate[tg0], ga1 = g_gate[tg1];
#pragma unroll
    for (int nt = 0; nt < 16; nt++) {
        float* p0 = g_ctx + (size_t)tg0 * CC + h * DD + nt * 8 + cq;
        float2 o0 = *(float2*)p0;
        *(float2*)p0 = make_float2(o0.x + ga0 * out2[nt][0],
                                   o0.y + ga0 * out2[nt][1]);
        float* p1 = g_ctx + (size_t)tg1 * CC + h * DD + nt * 8 + cq;
        float2 o1 = *(float2*)p1;
        *(float2*)p1 = make_float2(o1.x + ga1 * out2[nt][2],
                                   o1.y + ga1 * out2[nt][3]);
    }
}

// ============================================================================
extern "C" void kernel_launch(void* const* d_in, const int* in_sizes, int n_in,
                              void* d_out, int out_size)
{
    const float* x     = (const float*)d_in[0];
    const float* w_qkv = (const float*)d_in[1];
    const float* w_o   = (const float*)d_in[2];
    const float* pk    = (const float*)d_in[3];
    const float* pv    = (const float*)d_in[4];
    const float* uo    = (const float*)d_in[5];
    const float* iw1   = (const float*)d_in[6];
    const float* iw2   = (const float*)d_in[7];
    float* out = (float*)d_out;

    cudaFuncSetAttribute(gemm_mma,        cudaFuncAttributeMaxDynamicSharedMemorySize, 81920);
    cudaFuncSetAttribute(local_attn_mma,  cudaFuncAttributeMaxDynamicSharedMemorySize, 104448);
    cudaFuncSetAttribute(global_attn_mma, cudaFuncAttributeMaxDynamicSharedMemorySize, 55296);
    cudaFuncSetAttribute(lowrank_k,       cudaFuncAttributeMaxDynamicSharedMemorySize, 66048);

    void *p_qkv, *p_hinfo, *p_ctx;
    void *pxh, *pxl, *pwqh, *pwql, *pwoh, *pwol, *pi1h, *pi1l, *pcxh, *pcxl;
    void *pqkvh, *pqkvl, *puoh, *puol;
    cudaGetSymbolAddress(&p_qkv, g_qkv);
    cudaGetSymbolAddress(&p_hinfo, g_hinfo);
    cudaGetSymbolAddress(&p_ctx, g_ctx);
    cudaGetSymbolAddress(&pxh, g_xh);   cudaGetSymbolAddress(&pxl, g_xl);
    cudaGetSymbolAddress(&pwqh, g_wqh); cudaGetSymbolAddress(&pwql, g_wql);
    cudaGetSymbolAddress(&pwoh, g_woh); cudaGetSymbolAddress(&pwol, g_wol);
    cudaGetSymbolAddress(&pi1h, g_i1h); cudaGetSymbolAddress(&pi1l, g_i1l);
    cudaGetSymbolAddress(&pcxh, g_cxh); cudaGetSymbolAddress(&pcxl, g_cxl);
    cudaGetSymbolAddress(&pqkvh, g_qkvh); cudaGetSymbolAddress(&pqkvl, g_qkvl);
    cudaGetSymbolAddress(&puoh, g_uoh); cudaGetSymbolAddress(&puol, g_uol);

#define SPLIT(src, h, l, n) \
    split_bf16_k<<<((n)/2 + 255) / 256, 256>>>((const float2*)(src), \
        (__nv_bfloat162*)(h), (__nv_bfloat162*)(l), (n)/2)

    SPLIT(x, pxh, pxl, TT * CC);
    SPLIT(w_qkv, pwqh, pwql, C3 * CC);
    SPLIT(iw1, pi1h, pi1l, CI * CC);
    SPLIT(w_o, pwoh, pwol, CC * CC);
    SPLIT(uo, puoh, puol, DD * RR);

    // qkv = x @ w_qkv^T
    gemm_mma<<<dim3(C3 / 128, TT / 128), 256, 81920>>>(
        (const __nv_bfloat16*)pxh, (const __nv_bfloat16*)pxl,
        (const __nv_bfloat16*)pwqh, (const __nv_bfloat16*)pwql,
        (float*)p_qkv, C3, CC, 0);
    rope_table_k<<<TT, DD>>>();
    rope_apply_k<<<dim3(TT, HH), 64>>>();

    // split roped qkv for attention
    SPLIT(p_qkv, pqkvh, pqkvl, TT * C3);

    // h_info = gelu(x @ iw1^T); gate
    gemm_mma<<<dim3(CI / 128, TT / 128), 256, 81920>>>(
        (const __nv_bfloat16*)pxh, (const __nv_bfloat16*)pxl,
        (const __nv_bfloat16*)pi1h, (const __nv_bfloat16*)pi1l,
        (float*)p_hinfo, CI, CC, 1);
    gate_k<<<TT, 128>>>(iw2);

    lowrank_k<<<dim3(TT / 64, HH), 256, 66048>>>(pk, pv);
    local_attn_mma<<<dim3(TT / 64, HH), 128, 104448>>>();
    global_attn_mma<<<dim3(TT / 64, HH), 128, 55296>>>();

    // out = ctx @ w_o^T
    SPLIT(p_ctx, pcxh, pcxl, TT * CC);
    gemm_mma<<<dim3(CC / 128, TT / 128), 256, 81920>>>(
        (const __nv_bfloat16*)pcxh, (const __nv_bfloat16*)pcxl,
        (const __nv_bfloat16*)pwoh, (const __nv_bfloat16*)pwol,
        out, CC, CC, 0);
#undef SPLIT
}

// round 6
// speedup vs baseline: 2.9709x; 1.0712x over previous
#include <cuda_runtime.h>
#include <cuda_bf16.h>
#include <math.h>
#include <stdint.h>

#define TT   2048
#define CC   2048
#define HH   16
#define DD   128
#define RR   64
#define WLOC 512
#define CI   512
#define C3   6144

#define SCALE_L 0.08838834764831845f
#define SCALE_G 0.1767766952966369f

// ---------------- scratch (device globals) ----------------
__device__ float g_hinfo[TT * CI];
__device__ float g_gate[TT];
__device__ float g_cos[TT * DD];
__device__ float g_sin[TT * DD];
__device__ float g_ctx[TT * CC];

// bf16 hi/lo split operands
__device__ __nv_bfloat16 g_xh[TT * CC],  g_xl[TT * CC];
__device__ __nv_bfloat16 g_wqh[C3 * CC], g_wql[C3 * CC];
__device__ __nv_bfloat16 g_woh[CC * CC], g_wol[CC * CC];
__device__ __nv_bfloat16 g_i1h[CI * CC], g_i1l[CI * CC];
__device__ __nv_bfloat16 g_cxh[TT * CC], g_cxl[TT * CC];
__device__ __nv_bfloat16 g_qkvh[TT * C3], g_qkvl[TT * C3];
__device__ __nv_bfloat16 g_qrh[HH * TT * RR], g_qrl[HH * TT * RR];
__device__ __nv_bfloat16 g_krh[HH * TT * RR], g_krl[HH * TT * RR];
__device__ __nv_bfloat16 g_vrh[HH * TT * RR], g_vrl[HH * TT * RR];
__device__ __nv_bfloat16 g_uoh[DD * RR], g_uol[DD * RR];
__device__ __nv_bfloat16 g_pkh[RR * DD], g_pkl[RR * DD];
__device__ __nv_bfloat16 g_pvh[RR * DD], g_pvl[RR * DD];

// ============================================================================
// PTX helpers (plain sm_80+ ISA)
// ============================================================================
__device__ __forceinline__ uint32_t smem_u32(const void* p) {
    uint32_t a;
    asm("{ .reg .u64 t; cvta.to.shared.u64 t, %1; cvt.u32.u64 %0, t; }"
        : "=r"(a) : "l"(p));
    return a;
}

#define CP16(s, g) \
    asm volatile("cp.async.cg.shared.global [%0], [%1], 16;" \
                 :: "r"(s), "l"(g) : "memory")
#define CP_COMMIT() asm volatile("cp.async.commit_group;" ::: "memory")
#define CP_WAIT(n)  asm volatile("cp.async.wait_group %0;" :: "n"(n) : "memory")

__device__ __forceinline__ void ldsm4(uint32_t& r0, uint32_t& r1,
                                      uint32_t& r2, uint32_t& r3, uint32_t a) {
    asm volatile("ldmatrix.sync.aligned.m8n8.x4.shared.b16 {%0,%1,%2,%3}, [%4];"
                 : "=r"(r0), "=r"(r1), "=r"(r2), "=r"(r3) : "r"(a));
}
__device__ __forceinline__ void ldsm4t(uint32_t& r0, uint32_t& r1,
                                       uint32_t& r2, uint32_t& r3, uint32_t a) {
    asm volatile("ldmatrix.sync.aligned.m8n8.x4.trans.shared.b16 {%0,%1,%2,%3}, [%4];"
                 : "=r"(r0), "=r"(r1), "=r"(r2), "=r"(r3) : "r"(a));
}

__device__ __forceinline__ void mma16816(float* c, const uint32_t* a,
                                         const uint32_t* b) {
    asm volatile("mma.sync.aligned.m16n8k16.row.col.f32.bf16.bf16.f32 "
                 "{%0,%1,%2,%3}, {%4,%5,%6,%7}, {%8,%9}, {%0,%1,%2,%3};"
                 : "+f"(c[0]), "+f"(c[1]), "+f"(c[2]), "+f"(c[3])
                 : "r"(a[0]), "r"(a[1]), "r"(a[2]), "r"(a[3]),
                   "r"(b[0]), "r"(b[1]));
}

__device__ __forceinline__ void split2(float x, float y, uint32_t& h, uint32_t& l) {
    __nv_bfloat162 hh = __floats2bfloat162_rn(x, y);
    h = *reinterpret_cast<uint32_t*>(&hh);
    __nv_bfloat162 ll = __floats2bfloat162_rn(x - __bfloat162float(hh.x),
                                              y - __bfloat162float(hh.y));
    l = *reinterpret_cast<uint32_t*>(&ll);
}

// ============================================================================
// fp32 -> bf16 hi/lo split
// ============================================================================
__global__ void split_bf16_k(const float2* __restrict__ src,
                             __nv_bfloat162* __restrict__ hi,
                             __nv_bfloat162* __restrict__ lo, int n2)
{
    int i = blockIdx.x * 256 + threadIdx.x;
    if (i < n2) {
        float2 v = src[i];
        __nv_bfloat162 h = __floats2bfloat162_rn(v.x, v.y);
        hi[i] = h;
        lo[i] = __floats2bfloat162_rn(v.x - __bfloat162float(h.x),
                                      v.y - __bfloat162float(h.y));
    }
}

// ============================================================================
// mma.sync GEMM: C = Ah·Bh^T + Al·Bh^T + Ah·Bl^T
// mode 0: fp32 store. mode 1: gelu fp32 store. mode 2: rope + bf16 hi/lo store.
// ============================================================================
__global__ __launch_bounds__(256) void gemm_mma(
    const __nv_bfloat16* __restrict__ Ah, const __nv_bfloat16* __restrict__ Al,
    const __nv_bfloat16* __restrict__ Bh, const __nv_bfloat16* __restrict__ Bl,
    float* __restrict__ Cout,
    __nv_bfloat16* __restrict__ Ch, __nv_bfloat16* __restrict__ Cl,
    int N, int K, int mode)
{
    extern __shared__ __align__(128) char smraw[];
    const uint32_t sb = smem_u32(smraw);
    const int tid = threadIdx.x, lane = tid & 31, wid = tid >> 5;
    const int wm = wid & 3, wn = wid >> 2;
    const int bm = blockIdx.y << 7, bn = blockIdx.x << 7;
    const int aj = lane >> 3, ar = lane & 7;

    float acc[2][8][4];
#pragma unroll
    for (int mt = 0; mt < 2; mt++)
#pragma unroll
        for (int nt = 0; nt < 8; nt++)
#pragma unroll
            for (int e = 0; e < 4; e++) acc[mt][nt][e] = 0.f;

    const int nch = K >> 5;

    auto issue_stage = [&](int c) {
        const uint32_t st = sb + (c & 1) * 40960;
        const int k0 = c << 5;
        const __nv_bfloat16* gm0 = Ah + (size_t)bm * K + k0;
        const __nv_bfloat16* gm1 = Al + (size_t)bm * K + k0;
        const __nv_bfloat16* gm2 = Bh + (size_t)bn * K + k0;
        const __nv_bfloat16* gm3 = Bl + (size_t)bn * K + k0;
#pragma unroll
        for (int h = 0; h < 2; h++) {
            int i = tid + h * 256;
            int r = i >> 2, q = i & 3;
            uint32_t so = st + r * 80 + q * 16;
            size_t go = (size_t)r * K + q * 8;
            CP16(so,          gm0 + go);
            CP16(so + 10240,  gm1 + go);
            CP16(so + 20480,  gm2 + go);
            CP16(so + 30720,  gm3 + go);
        }
        CP_COMMIT();
    };

    issue_stage(0);
    for (int c = 0; c < nch; c++) {
        if (c + 1 < nch) { issue_stage(c + 1); CP_WAIT(1); }
        else             { CP_WAIT(0); }
        __syncthreads();

        const uint32_t st = sb + (c & 1) * 40960;
#pragma unroll
        for (int ks = 0; ks < 2; ks++) {
            uint32_t ah[2][4], al_[2][4], b2[8][2];
            const uint32_t a_off =
                ((wm * 32 + (aj & 1) * 8 + ar) * 40 + ks * 16 + (aj >> 1) * 8) * 2;
            const uint32_t b_off =
                ((wn * 64 + (aj >> 1) * 8 + ar) * 40 + ks * 16 + (aj & 1) * 8) * 2;

#pragma unroll
            for (int mt = 0; mt < 2; mt++) {
                ldsm4(ah[mt][0], ah[mt][1], ah[mt][2], ah[mt][3],
                      st + a_off + mt * (16 * 40 * 2));
                ldsm4(al_[mt][0], al_[mt][1], al_[mt][2], al_[mt][3],
                      st + 10240 + a_off + mt * (16 * 40 * 2));
            }
#pragma unroll
            for (int np = 0; np < 4; np++) {
                uint32_t r0, r1, r2, r3;
                ldsm4(r0, r1, r2, r3, st + 20480 + b_off + np * (16 * 40 * 2));
                b2[np * 2][0] = r0;     b2[np * 2][1] = r1;
                b2[np * 2 + 1][0] = r2; b2[np * 2 + 1][1] = r3;
            }
#pragma unroll
            for (int mt = 0; mt < 2; mt++)
#pragma unroll
                for (int nt = 0; nt < 8; nt++) {
                    mma16816(acc[mt][nt], ah[mt], b2[nt]);
                    mma16816(acc[mt][nt], al_[mt], b2[nt]);
                }
#pragma unroll
            for (int np = 0; np < 4; np++) {
                uint32_t r0, r1, r2, r3;
                ldsm4(r0, r1, r2, r3, st + 30720 + b_off + np * (16 * 40 * 2));
                b2[np * 2][0] = r0;     b2[np * 2][1] = r1;
                b2[np * 2 + 1][0] = r2; b2[np * 2 + 1][1] = r3;
            }
#pragma unroll
            for (int mt = 0; mt < 2; mt++)
#pragma unroll
                for (int nt = 0; nt < 8; nt++)
                    mma16816(acc[mt][nt], ah[mt], b2[nt]);
        }
        __syncthreads();
    }

    const int row_base = bm + wm * 32 + (lane >> 2);
    const int col_base = bn + wn * 64 + (lane & 3) * 2;
#pragma unroll
    for (int mt = 0; mt < 2; mt++)
#pragma unroll
        for (int nt = 0; nt < 8; nt++) {
            int r0 = row_base + mt * 16, cc = col_base + nt * 8;
            float v0 = acc[mt][nt][0], v1 = acc[mt][nt][1];
            float v2 = acc[mt][nt][2], v3 = acc[mt][nt][3];
            if (mode == 2) {
                if (cc < 2 * CC) {   // q/k sections: rope pairs (d0, d0+1)
                    int d0 = cc & 127;
                    float2 cA = *(const float2*)(g_cos + r0 * DD + d0);
                    float2 sA = *(const float2*)(g_sin + r0 * DD + d0);
                    float o0 = v0 * cA.x - v1 * sA.x;
                    float o1 = v1 * cA.y + v0 * sA.y;
                    float2 cB = *(const float2*)(g_cos + (r0 + 8) * DD + d0);
                    float2 sB = *(const float2*)(g_sin + (r0 + 8) * DD + d0);
                    float o2 = v2 * cB.x - v3 * sB.x;
                    float o3 = v3 * cB.y + v2 * sB.y;
                    v0 = o0; v1 = o1; v2 = o2; v3 = o3;
                }
                uint32_t h01, l01, h23, l23;
                split2(v0, v1, h01, l01);
                split2(v2, v3, h23, l23);
                *(uint32_t*)(Ch + (size_t)r0 * N + cc)       = h01;
                *(uint32_t*)(Cl + (size_t)r0 * N + cc)       = l01;
                *(uint32_t*)(Ch + (size_t)(r0 + 8) * N + cc) = h23;
                *(uint32_t*)(Cl + (size_t)(r0 + 8) * N + cc) = l23;
            } else {
                if (mode == 1) {
                    v0 = 0.5f * v0 * (1.0f + erff(v0 * 0.7071067811865475f));
                    v1 = 0.5f * v1 * (1.0f + erff(v1 * 0.7071067811865475f));
                    v2 = 0.5f * v2 * (1.0f + erff(v2 * 0.7071067811865475f));
                    v3 = 0.5f * v3 * (1.0f + erff(v3 * 0.7071067811865475f));
                }
                *(float2*)(Cout + (size_t)r0 * N + cc)       = make_float2(v0, v1);
                *(float2*)(Cout + (size_t)(r0 + 8) * N + cc) = make_float2(v2, v3);
            }
        }
}

// ============================================================================
// RoPE tables
// ============================================================================
__global__ void rope_table_k()
{
    int t = blockIdx.x, d = threadIdx.x;
    int j = d & 63;
    double ang = (double)t * exp(-(double)j * (log(10000.0) / 64.0));
    g_cos[t * DD + d] = (float)cos(ang);
    g_sin[t * DD + d] = (float)sin(ang);
}

// ============================================================================
// Gate
// ============================================================================
__global__ void gate_k(const float* __restrict__ w2)
{
    __shared__ float red[128];
    int t = blockIdx.x, tid = threadIdx.x;
    float s = 0.f;
    for (int j = tid; j < CI; j += 128) s += g_hinfo[t * CI + j] * w2[j];
    red[tid] = s;
    __syncthreads();
    for (int off = 64; off > 0; off >>= 1) {
        if (tid < off) red[tid] += red[tid + off];
        __syncthreads();
    }
    if (tid == 0) {
        float sc = 1.0f / (1.0f + expf(-red[0]));
        g_gate[t] = (sc > 0.75f) ? 1.0f : 0.0f;
    }
}

// ============================================================================
// Low-rank projections via mma.sync: q_r/k_r/v_r (bf16 split in, split out).
// 4 warps, 64 tokens per CTA. smem = 4 x [64][136] bf16 = 69632 B.
// ============================================================================
__global__ __launch_bounds__(128) void lowrank_mma()
{
    extern __shared__ __align__(16) char smraw[];
    const uint32_t sb = smem_u32(smraw);
    const uint32_t oAl = 64 * 136 * 2, oPh = 2 * 64 * 136 * 2, oPl = 3 * 64 * 136 * 2;
    const int tid = threadIdx.x, lane = tid & 31, w = tid >> 5;
    const int qt = blockIdx.x, h = blockIdx.y, t0 = qt << 6;
    const int aj = lane >> 3, ar = lane & 7;

    const uint32_t aoff = ((w * 16 + (aj & 1) * 8 + ar) * 136 + (aj >> 1) * 8) * 2;
    const uint32_t boff = (((aj >> 1) * 8 + ar) * 136 + (aj & 1) * 8) * 2;
    const int row0 = t0 + w * 16 + (lane >> 2);
    const int col = (lane & 3) * 2;

    for (int pass = 0; pass < 3; pass++) {
        const __nv_bfloat16* Ph = (pass == 2) ? g_pvh : g_pkh;
        const __nv_bfloat16* Pl = (pass == 2) ? g_pvl : g_pkl;
        const int off = pass * CC + h * DD;
        __syncthreads();
        for (int i = tid; i < 1024; i += 128) {
            int r = i >> 4, q = i & 15;
            uint32_t so = (r * 136 + q * 8) * 2;
            size_t ga = (size_t)(t0 + r) * C3 + off + q * 8;
            CP16(sb + so,       g_qkvh + ga);
            CP16(sb + oAl + so, g_qkvl + ga);
            int gp = r * DD + q * 8;
            CP16(sb + oPh + so, Ph + gp);
            CP16(sb + oPl + so, Pl + gp);
        }
        CP_COMMIT(); CP_WAIT(0);
        __syncthreads();

        float acc[8][4];
#pragma unroll
        for (int nt = 0; nt < 8; nt++)
#pragma unroll
            for (int e = 0; e < 4; e++) acc[nt][e] = 0.f;

#pragma unroll
        for (int kb = 0; kb < 8; kb++) {
            uint32_t ah[4], al_[4], b2[8][2];
            ldsm4(ah[0], ah[1], ah[2], ah[3], sb + aoff + kb * 32);
            ldsm4(al_[0], al_[1], al_[2], al_[3], sb + oAl + aoff + kb * 32);
#pragma unroll
            for (int np = 0; np < 4; np++) {
                uint32_t r0, r1, r2, r3;
                ldsm4(r0, r1, r2, r3, sb + oPh + boff + np * 16 * 136 * 2 + kb * 32);
                b2[np * 2][0] = r0;     b2[np * 2][1] = r1;
                b2[np * 2 + 1][0] = r2; b2[np * 2 + 1][1] = r3;
            }
#pragma unroll
            for (int nt = 0; nt < 8; nt++) {
                mma16816(acc[nt], ah, b2[nt]);
                mma16816(acc[nt], al_, b2[nt]);
            }
#pragma unroll
            for (int np = 0; np < 4; np++) {
                uint32_t r0, r1, r2, r3;
                ldsm4(r0, r1, r2, r3, sb + oPl + boff + np * 16 * 136 * 2 + kb * 32);
                b2[np * 2][0] = r0;     b2[np * 2][1] = r1;
                b2[np * 2 + 1][0] = r2; b2[np * 2 + 1][1] = r3;
            }
#pragma unroll
            for (int nt = 0; nt < 8; nt++)
                mma16816(acc[nt], ah, b2[nt]);
        }

        __nv_bfloat16* dh = (pass == 0) ? g_qrh : (pass == 1) ? g_krh : g_vrh;
        __nv_bfloat16* dl = (pass == 0) ? g_qrl : (pass == 1) ? g_krl : g_vrl;
#pragma unroll
        for (int nt = 0; nt < 8; nt++) {
            uint32_t hh, ll;
            size_t i0 = (size_t)(h * TT + row0) * RR + nt * 8 + col;
            split2(acc[nt][0], acc[nt][1], hh, ll);
            *(uint32_t*)(dh + i0) = hh;
            *(uint32_t*)(dl + i0) = ll;
            size_t i1 = i0 + 8 * RR;
            split2(acc[nt][2], acc[nt][3], hh, ll);
            *(uint32_t*)(dh + i1) = hh;
            *(uint32_t*)(dl + i1) = ll;
        }
    }
}

// ============================================================================
// Local sliding-window attention: Sq=128, 8 warps, double-buffered KV.
// smem = (2*128 + 2*4*64) * 136 * 2 = 208896 B.
// ============================================================================
#define LPAD 136
__global__ __launch_bounds__(256) void local_attn_mma()
{
    extern __shared__ __align__(16) char smraw[];
    const uint32_t sb = smem_u32(smraw);
    const uint32_t oQl = 128 * LPAD * 2;
    const uint32_t kvBase = 2 * 128 * LPAD * 2;
    const uint32_t kvStage = 4 * 64 * LPAD * 2;
    const uint32_t seg = 64 * LPAD * 2;

    const int tid = threadIdx.x, lane = tid & 31, w = tid >> 5;
    const int qt = gridDim.x - 1 - blockIdx.x, h = blockIdx.y;
    const int t0 = qt << 7;
    const int aj = lane >> 3, ar = lane & 7;
    const int tg0 = t0 + w * 16 + (lane >> 2), tg1 = tg0 + 8;
    const int cq = (lane & 3) * 2;

    for (int i = tid; i < 2048; i += 256) {
        int r = i >> 4, q = i & 15;
        uint32_t so = sb + (r * LPAD + q * 8) * 2;
        size_t go = (size_t)(t0 + r) * C3 + h * DD + q * 8;
        CP16(so, g_qkvh + go);
        CP16(so + oQl, g_qkvl + go);
    }
    CP_COMMIT();

    const int kt0 = (t0 > WLOC - 1) ? ((t0 - (WLOC - 1)) >> 6) : 0;
    const int ktend = 2 * qt + 1;

    auto issueKV = [&](int kt, int s) {
        const int s0 = kt << 6;
        const uint32_t kb = sb + kvBase + s * kvStage;
        for (int i = tid; i < 1024; i += 256) {
            int r = i >> 4, q = i & 15;
            size_t gk = (size_t)(s0 + r) * C3 + CC + h * DD + q * 8;
            uint32_t off = (r * LPAD + q * 8) * 2;
            CP16(kb + off,           g_qkvh + gk);
            CP16(kb + seg + off,     g_qkvl + gk);
            CP16(kb + 2 * seg + off, g_qkvh + gk + CC);
            CP16(kb + 3 * seg + off, g_qkvl + gk + CC);
        }
        CP_COMMIT();
    };
    issueKV(kt0, 0);

    float m0 = -1e30f, m1 = -1e30f, l0 = 0.f, l1 = 0.f;
    float out[16][4];
#pragma unroll
    for (int nt = 0; nt < 16; nt++)
#pragma unroll
        for (int e = 0; e < 4; e++) out[nt][e] = 0.f;

    const uint32_t aQoff = ((w * 16 + (aj & 1) * 8 + ar) * LPAD + (aj >> 1) * 8) * 2;
    const uint32_t bKoff = (((aj >> 1) * 8 + ar) * LPAD + (aj & 1) * 8) * 2;
    const uint32_t bVoff = (((aj & 1) * 8 + ar) * LPAD + (aj >> 1) * 8) * 2;

    for (int kt = kt0; kt <= ktend; kt++) {
        const int s = (kt - kt0) & 1;
        if (kt < ktend) { issueKV(kt + 1, s ^ 1); CP_WAIT(1); }
        else            { CP_WAIT(0); }
        __syncthreads();
        const uint32_t kb = sb + kvBase + s * kvStage;
        const int s0 = kt << 6;

        float sc[8][4];
#pragma unroll
        for (int nt = 0; nt < 8; nt++)
#pragma unroll
            for (int e = 0; e < 4; e++) sc[nt][e] = 0.f;

#pragma unroll
        for (int kbk = 0; kbk < 8; kbk++) {
            uint32_t ah[4], al_[4], b2[8][2];
            ldsm4(ah[0], ah[1], ah[2], ah[3], sb + aQoff + kbk * 32);
            ldsm4(al_[0], al_[1], al_[2], al_[3], sb + oQl + aQoff + kbk * 32);
#pragma unroll
            for (int np = 0; np < 4; np++) {
                uint32_t r0, r1, r2, r3;
                ldsm4(r0, r1, r2, r3, kb + bKoff + np * 16 * LPAD * 2 + kbk * 32);
                b2[np * 2][0] = r0;     b2[np * 2][1] = r1;
                b2[np * 2 + 1][0] = r2; b2[np * 2 + 1][1] = r3;
            }
#pragma unroll
            for (int nt = 0; nt < 8; nt++) {
                mma16816(sc[nt], ah, b2[nt]);
                mma16816(sc[nt], al_, b2[nt]);
            }
#pragma unroll
            for (int np = 0; np < 4; np++) {
                uint32_t r0, r1, r2, r3;
                ldsm4(r0, r1, r2, r3,
                      kb + seg + bKoff + np * 16 * LPAD * 2 + kbk * 32);
                b2[np * 2][0] = r0;     b2[np * 2][1] = r1;
                b2[np * 2 + 1][0] = r2; b2[np * 2 + 1][1] = r3;
            }
#pragma unroll
            for (int nt = 0; nt < 8; nt++) mma16816(sc[nt], ah, b2[nt]);
        }

#pragma unroll
        for (int nt = 0; nt < 8; nt++) {
            int c0 = s0 + nt * 8 + cq;
#pragma unroll
            for (int e = 0; e < 2; e++) {
                int sg = c0 + e;
                float v0 = sc[nt][e] * SCALE_L;
                sc[nt][e] = (sg <= tg0 && sg >= tg0 - (WLOC - 1)) ? v0 : -1e30f;
                float v1 = sc[nt][2 + e] * SCALE_L;
                sc[nt][2 + e] = (sg <= tg1 && sg >= tg1 - (WLOC - 1)) ? v1 : -1e30f;
            }
        }

        float mx0 = -1e30f, mx1 = -1e30f;
#pragma unroll
        for (int nt = 0; nt < 8; nt++) {
            mx0 = fmaxf(mx0, fmaxf(sc[nt][0], sc[nt][1]));
            mx1 = fmaxf(mx1, fmaxf(sc[nt][2], sc[nt][3]));
        }
        mx0 = fmaxf(mx0, __shfl_xor_sync(0xffffffffu, mx0, 1));
        mx0 = fmaxf(mx0, __shfl_xor_sync(0xffffffffu, mx0, 2));
        mx1 = fmaxf(mx1, __shfl_xor_sync(0xffffffffu, mx1, 1));
        mx1 = fmaxf(mx1, __shfl_xor_sync(0xffffffffu, mx1, 2));
        float mn0 = fmaxf(m0, mx0), mn1 = fmaxf(m1, mx1);
        float al0 = __expf(m0 - mn0), al1 = __expf(m1 - mn1);
        m0 = mn0; m1 = mn1;

        float sum0 = 0.f, sum1 = 0.f;
#pragma unroll
        for (int nt = 0; nt < 8; nt++) {
#pragma unroll
            for (int e = 0; e < 2; e++) {
                float p0 = (sc[nt][e]     > -1e29f) ? __expf(sc[nt][e]     - mn0) : 0.f;
                float p1 = (sc[nt][2 + e] > -1e29f) ? __expf(sc[nt][2 + e] - mn1) : 0.f;
                sc[nt][e] = p0; sc[nt][2 + e] = p1;
                sum0 += p0; sum1 += p1;
            }
        }
        sum0 += __shfl_xor_sync(0xffffffffu, sum0, 1);
        sum0 += __shfl_xor_sync(0xffffffffu, sum0, 2);
        sum1 += __shfl_xor_sync(0xffffffffu, sum1, 1);
        sum1 += __shfl_xor_sync(0xffffffffu, sum1, 2);
        l0 = l0 * al0 + sum0;
        l1 = l1 * al1 + sum1;

#pragma unroll
        for (int nt = 0; nt < 16; nt++) {
            out[nt][0] *= al0; out[nt][1] *= al0;
            out[nt][2] *= al1; out[nt][3] *= al1;
        }

#pragma unroll
        for (int kbk = 0; kbk < 4; kbk++) {
            uint32_t ph[4], pl[4];
            split2(sc[2 * kbk][0],     sc[2 * kbk][1],     ph[0], pl[0]);
            split2(sc[2 * kbk][2],     sc[2 * kbk][3],     ph[1], pl[1]);
            split2(sc[2 * kbk + 1][0], sc[2 * kbk + 1][1], ph[2], pl[2]);
            split2(sc[2 * kbk + 1][2], sc[2 * kbk + 1][3], ph[3], pl[3]);
#pragma unroll
            for (int g = 0; g < 8; g++) {
                uint32_t vb = bVoff + kbk * 16 * LPAD * 2 + g * 32;
                uint32_t r0, r1, r2, r3;
                ldsm4t(r0, r1, r2, r3, kb + 2 * seg + vb);
                uint32_t b0[2] = {r0, r1}, b1[2] = {r2, r3};
                mma16816(out[2 * g], ph, b0);     mma16816(out[2 * g + 1], ph, b1);
                mma16816(out[2 * g], pl, b0);     mma16816(out[2 * g + 1], pl, b1);
                ldsm4t(r0, r1, r2, r3, kb + 3 * seg + vb);
                uint32_t c0[2] = {r0, r1}, c1[2] = {r2, r3};
                mma16816(out[2 * g], ph, c0);     mma16816(out[2 * g + 1], ph, c1);
            }
        }
        __syncthreads();
    }

    const float inv0 = 1.f / l0, inv1 = 1.f / l1;
#pragma unroll
    for (int nt = 0; nt < 16; nt++) {
        *(float2*)(g_ctx + (size_t)tg0 * CC + h * DD + nt * 8 + cq) =
            make_float2(out[nt][0] * inv0, out[nt][1] * inv0);
        *(float2*)(g_ctx + (size_t)tg1 * CC + h * DD + nt * 8 + cq) =
            make_float2(out[nt][2] * inv1, out[nt][3] * inv1);
    }
}

// ============================================================================
// Global low-rank attention: Sq=128, 8 warps, double-buffered KV_r,
// gated epilogue O @ uo^T; writes final ctx as bf16 hi/lo splits.
// smem = (2*128 + 2*4*64) * 72 * 2 = 110592 B.
// ============================================================================
#define GPAD 72
__global__ __launch_bounds__(256) void global_attn_mma()
{
    extern __shared__ __align__(16) char smraw[];
    const uint32_t sb = smem_u32(smraw);
    const uint32_t oQl = 128 * GPAD * 2;
    const uint32_t kvBase = 2 * 128 * GPAD * 2;
    const uint32_t kvStage = 4 * 64 * GPAD * 2;
    const uint32_t seg = 64 * GPAD * 2;
    const uint32_t oUh = kvBase, oUl = kvBase + 128 * GPAD * 2;

    const int tid = threadIdx.x, lane = tid & 31, w = tid >> 5;
    const int qt = blockIdx.x, h = blockIdx.y, t0 = qt << 7;
    const int aj = lane >> 3, ar = lane & 7;
    const int tg0 = t0 + w * 16 + (lane >> 2), tg1 = tg0 + 8;
    const int cq = (lane & 3) * 2;

    for (int i = tid; i < 1024; i += 256) {
        int r = i >> 3, q = i & 7;
        uint32_t so = sb + (r * GPAD + q * 8) * 2;
        size_t go = (size_t)(h * TT + t0 + r) * RR + q * 8;
        CP16(so, g_qrh + go);
        CP16(so + oQl, g_qrl + go);
    }
    CP_COMMIT();

    auto issueKV = [&](int kt, int s) {
        const int s0 = kt << 6;
        const uint32_t kb = sb + kvBase + s * kvStage;
        for (int i = tid; i < 512; i += 256) {
            int r = i >> 3, q = i & 7;
            size_t gk = (size_t)(h * TT + s0 + r) * RR + q * 8;
            uint32_t off = (r * GPAD + q * 8) * 2;
            CP16(kb + off,           g_krh + gk);
            CP16(kb + seg + off,     g_krl + gk);
            CP16(kb + 2 * seg + off, g_vrh + gk);
            CP16(kb + 3 * seg + off, g_vrl + gk);
        }
        CP_COMMIT();
    };
    issueKV(0, 0);

    float m0 = -1e30f, m1 = -1e30f, l0 = 0.f, l1 = 0.f;
    float out[8][4];
#pragma unroll
    for (int nt = 0; nt < 8; nt++)
#pragma unroll
        for (int e = 0; e < 4; e++) out[nt][e] = 0.f;

    const uint32_t aQoff = ((w * 16 + (aj & 1) * 8 + ar) * GPAD + (aj >> 1) * 8) * 2;
    const uint32_t bKoff = (((aj >> 1) * 8 + ar) * GPAD + (aj & 1) * 8) * 2;
    const uint32_t bVoff = (((aj & 1) * 8 + ar) * GPAD + (aj >> 1) * 8) * 2;

    for (int kt = 0; kt < TT / 64; kt++) {
        const int s = kt & 1;
        if (kt < TT / 64 - 1) { issueKV(kt + 1, s ^ 1); CP_WAIT(1); }
        else                  { CP_WAIT(0); }
        __syncthreads();
        const uint32_t kb = sb + kvBase + s * kvStage;

        float sc[8][4];
#pragma unroll
        for (int nt = 0; nt < 8; nt++)
#pragma unroll
            for (int e = 0; e < 4; e++) sc[nt][e] = 0.f;

#pragma unroll
        for (int kbk = 0; kbk < 4; kbk++) {
            uint32_t ah[4], al_[4], b2[8][2];
            ldsm4(ah[0], ah[1], ah[2], ah[3], sb + aQoff + kbk * 32);
            ldsm4(al_[0], al_[1], al_[2], al_[3], sb + oQl + aQoff + kbk * 32);
#pragma unroll
            for (int np = 0; np < 4; np++) {
                uint32_t r0, r1, r2, r3;
                ldsm4(r0, r1, r2, r3, kb + bKoff + np * 16 * GPAD * 2 + kbk * 32);
                b2[np * 2][0] = r0;     b2[np * 2][1] = r1;
                b2[np * 2 + 1][0] = r2; b2[np * 2 + 1][1] = r3;
            }
#pragma unroll
            for (int nt = 0; nt < 8; nt++) {
                mma16816(sc[nt], ah, b2[nt]);
                mma16816(sc[nt], al_, b2[nt]);
            }
#pragma unroll
            for (int np = 0; np < 4; np++) {
                uint32_t r0, r1, r2, r3;
                ldsm4(r0, r1, r2, r3,
                      kb + seg + bKoff + np * 16 * GPAD * 2 + kbk * 32);
                b2[np * 2][0] = r0;     b2[np * 2][1] = r1;
                b2[np * 2 + 1][0] = r2; b2[np * 2 + 1][1] = r3;
            }
#pragma unroll
            for (int nt = 0; nt < 8; nt++) mma16816(sc[nt], ah, b2[nt]);
        }

        float mx0 = -1e30f, mx1 = -1e30f;
#pragma unroll
        for (int nt = 0; nt < 8; nt++) {
            sc[nt][0] *= SCALE_G; sc[nt][1] *= SCALE_G;
            sc[nt][2] *= SCALE_G; sc[nt][3] *= SCALE_G;
            mx0 = fmaxf(mx0, fmaxf(sc[nt][0], sc[nt][1]));
            mx1 = fmaxf(mx1, fmaxf(sc[nt][2], sc[nt][3]));
        }
        mx0 = fmaxf(mx0, __shfl_xor_sync(0xffffffffu, mx0, 1));
        mx0 = fmaxf(mx0, __shfl_xor_sync(0xffffffffu, mx0, 2));
        mx1 = fmaxf(mx1, __shfl_xor_sync(0xffffffffu, mx1, 1));
        mx1 = fmaxf(mx1, __shfl_xor_sync(0xffffffffu, mx1, 2));
        float mn0 = fmaxf(m0, mx0), mn1 = fmaxf(m1, mx1);
        float al0 = __expf(m0 - mn0), al1 = __expf(m1 - mn1);
        m0 = mn0; m1 = mn1;

        float sum0 = 0.f, sum1 = 0.f;
#pragma unroll
        for (int nt = 0; nt < 8; nt++) {
#pragma unroll
            for (int e = 0; e < 2; e++) {
                float p0 = __expf(sc[nt][e] - mn0);
                float p1 = __expf(sc[nt][2 + e] - mn1);
                sc[nt][e] = p0; sc[nt][2 + e] = p1;
                sum0 += p0; sum1 += p1;
            }
        }
        sum0 += __shfl_xor_sync(0xffffffffu, sum0, 1);
        sum0 += __shfl_xor_sync(0xffffffffu, sum0, 2);
        sum1 += __shfl_xor_sync(0xffffffffu, sum1, 1);
        sum1 += __shfl_xor_sync(0xffffffffu, sum1, 2);
        l0 = l0 * al0 + sum0;
        l1 = l1 * al1 + sum1;

#pragma unroll
        for (int nt = 0; nt < 8; nt++) {
            out[nt][0] *= al0; out[nt][1] *= al0;
            out[nt][2] *= al1; out[nt][3] *= al1;
        }

#pragma unroll
        for (int kbk = 0; kbk < 4; kbk++) {
            uint32_t ph[4], pl[4];
            split2(sc[2 * kbk][0],     sc[2 * kbk][1],     ph[0], pl[0]);
            split2(sc[2 * kbk][2],     sc[2 * kbk][3],     ph[1], pl[1]);
            split2(sc[2 * kbk + 1][0], sc[2 * kbk + 1][1], ph[2], pl[2]);
            split2(sc[2 * kbk + 1][2], sc[2 * kbk + 1][3], ph[3], pl[3]);
#pragma unroll
            for (int g = 0; g < 4; g++) {
                uint32_t vb = bVoff + kbk * 16 * GPAD * 2 + g * 32;
                uint32_t r0, r1, r2, r3;
                ldsm4t(r0, r1, r2, r3, kb + 2 * seg + vb);
                uint32_t b0[2] = {r0, r1}, b1[2] = {r2, r3};
                mma16816(out[2 * g], ph, b0);     mma16816(out[2 * g + 1], ph, b1);
                mma16816(out[2 * g], pl, b0);     mma16816(out[2 * g + 1], pl, b1);
                ldsm4t(r0, r1, r2, r3, kb + 3 * seg + vb);
                uint32_t c0[2] = {r0, r1}, c1[2] = {r2, r3};
                mma16816(out[2 * g], ph, c0);     mma16816(out[2 * g + 1], ph, c1);
            }
        }
        __syncthreads();
    }

    const float inv0 = 1.f / l0, inv1 = 1.f / l1;
#pragma unroll
    for (int nt = 0; nt < 8; nt++) {
        out[nt][0] *= inv0; out[nt][1] *= inv0;
        out[nt][2] *= inv1; out[nt][3] *= inv1;
    }

    // load uo^T splits into overlay (all cp.async drained, all warps synced)
    for (int i = tid; i < 1024; i += 256) {
        int d = i >> 3, q = i & 7;
        *(int4*)(smraw + oUh + (d * GPAD + q * 8) * 2) =
            *(const int4*)(g_uoh + d * 64 + q * 8);
        *(int4*)(smraw + oUl + (d * GPAD + q * 8) * 2) =
            *(const int4*)(g_uol + d * 64 + q * 8);
    }
    __syncthreads();

    float out2[16][4];
#pragma unroll
    for (int nt = 0; nt < 16; nt++)
#pragma unroll
        for (int e = 0; e < 4; e++) out2[nt][e] = 0.f;

    const uint32_t bUoff = (((aj >> 1) * 8 + ar) * GPAD + (aj & 1) * 8) * 2;
#pragma unroll
    for (int kbk = 0; kbk < 4; kbk++) {
        uint32_t ph[4], pl[4];
        split2(out[2 * kbk][0],     out[2 * kbk][1],     ph[0], pl[0]);
        split2(out[2 * kbk][2],     out[2 * kbk][3],     ph[1], pl[1]);
        split2(out[2 * kbk + 1][0], out[2 * kbk + 1][1], ph[2], pl[2]);
        split2(out[2 * kbk + 1][2], out[2 * kbk + 1][3], ph[3], pl[3]);
#pragma unroll
        for (int g = 0; g < 8; g++) {
            uint32_t ub = sb + oUh + bUoff + g * 16 * GPAD * 2 + kbk * 32;
            uint32_t r0, r1, r2, r3;
            ldsm4(r0, r1, r2, r3, ub);
            uint32_t b0[2] = {r0, r1}, b1[2] = {r2, r3};
            mma16816(out2[2 * g], ph, b0);     mma16816(out2[2 * g + 1], ph, b1);
            mma16816(out2[2 * g], pl, b0);     mma16816(out2[2 * g + 1], pl, b1);
            ldsm4(r0, r1, r2, r3, ub + (oUl - oUh));
            uint32_t c0[2] = {r0, r1}, c1[2] = {r2, r3};
            mma16816(out2[2 * g], ph, c0);     mma16816(out2[2 * g + 1], ph, c1);
        }
    }

    const float ga0 = g_gate[tg0], ga1 = g_gate[tg1];
#pragma unroll
    for (int nt = 0; nt < 16; nt++) {
        size_t i0 = (size_t)tg0 * CC + h * DD + nt * 8 + cq;
        float2 o0 = *(float2*)(g_ctx + i0);
        uint32_t hh, ll;
        split2(o0.x + ga0 * out2[nt][0], o0.y + ga0 * out2[nt][1], hh, ll);
        *(uint32_t*)(g_cxh + i0) = hh;
        *(uint32_t*)(g_cxl + i0) = ll;
        size_t i1 = (size_t)tg1 * CC + h * DD + nt * 8 + cq;
        float2 o1 = *(float2*)(g_ctx + i1);
        split2(o1.x + ga1 * out2[nt][2], o1.y + ga1 * out2[nt][3], hh, ll);
        *(uint32_t*)(g_cxh + i1) = hh;
        *(uint32_t*)(g_cxl + i1) = ll;
    }
}

// ============================================================================
extern "C" void kernel_launch(void* const* d_in, const int* in_sizes, int n_in,
                              void* d_out, int out_size)
{
    const float* x     = (const float*)d_in[0];
    const float* w_qkv = (const float*)d_in[1];
    const float* w_o   = (const float*)d_in[2];
    const float* pk    = (const float*)d_in[3];
    const float* pv    = (const float*)d_in[4];
    const float* uo    = (const float*)d_in[5];
    const float* iw1   = (const float*)d_in[6];
    const float* iw2   = (const float*)d_in[7];
    float* out = (float*)d_out;

    cudaFuncSetAttribute(gemm_mma,        cudaFuncAttributeMaxDynamicSharedMemorySize, 81920);
    cudaFuncSetAttribute(local_attn_mma,  cudaFuncAttributeMaxDynamicSharedMemorySize, 208896);
    cudaFuncSetAttribute(global_attn_mma, cudaFuncAttributeMaxDynamicSharedMemorySize, 110592);
    cudaFuncSetAttribute(lowrank_mma,     cudaFuncAttributeMaxDynamicSharedMemorySize, 69632);

    void *p_hinfo;
    void *pxh, *pxl, *pwqh, *pwql, *pwoh, *pwol, *pi1h, *pi1l, *pcxh, *pcxl;
    void *pqkvh, *pqkvl, *puoh, *puol, *ppkh, *ppkl, *ppvh, *ppvl;
    cudaGetSymbolAddress(&p_hinfo, g_hinfo);
    cudaGetSymbolAddress(&pxh, g_xh);   cudaGetSymbolAddress(&pxl, g_xl);
    cudaGetSymbolAddress(&pwqh, g_wqh); cudaGetSymbolAddress(&pwql, g_wql);
    cudaGetSymbolAddress(&pwoh, g_woh); cudaGetSymbolAddress(&pwol, g_wol);
    cudaGetSymbolAddress(&pi1h, g_i1h); cudaGetSymbolAddress(&pi1l, g_i1l);
    cudaGetSymbolAddress(&pcxh, g_cxh); cudaGetSymbolAddress(&pcxl, g_cxl);
    cudaGetSymbolAddress(&pqkvh, g_qkvh); cudaGetSymbolAddress(&pqkvl, g_qkvl);
    cudaGetSymbolAddress(&puoh, g_uoh); cudaGetSymbolAddress(&puol, g_uol);
    cudaGetSymbolAddress(&ppkh, g_pkh); cudaGetSymbolAddress(&ppkl, g_pkl);
    cudaGetSymbolAddress(&ppvh, g_pvh); cudaGetSymbolAddress(&ppvl, g_pvl);

#define SPLIT(src, h, l, n) \
    split_bf16_k<<<((n)/2 + 255) / 256, 256>>>((const float2*)(src), \
        (__nv_bfloat162*)(h), (__nv_bfloat162*)(l), (n)/2)

    rope_table_k<<<TT, DD>>>();
    SPLIT(x, pxh, pxl, TT * CC);
    SPLIT(w_qkv, pwqh, pwql, C3 * CC);
    SPLIT(iw1, pi1h, pi1l, CI * CC);
    SPLIT(w_o, pwoh, pwol, CC * CC);
    SPLIT(uo, puoh, puol, DD * RR);
    SPLIT(pk, ppkh, ppkl, RR * DD);
    SPLIT(pv, ppvh, ppvl, RR * DD);

    // qkv = rope(x @ w_qkv^T) -> bf16 splits (fused epilogue)
    gemm_mma<<<dim3(C3 / 128, TT / 128), 256, 81920>>>(
        (const __nv_bfloat16*)pxh, (const __nv_bfloat16*)pxl,
        (const __nv_bfloat16*)pwqh, (const __nv_bfloat16*)pwql,
        nullptr, (__nv_bfloat16*)pqkvh, (__nv_bfloat16*)pqkvl, C3, CC, 2);

    // h_info = gelu(x @ iw1^T); gate
    gemm_mma<<<dim3(CI / 128, TT / 128), 256, 81920>>>(
        (const __nv_bfloat16*)pxh, (const __nv_bfloat16*)pxl,
        (const __nv_bfloat16*)pi1h, (const __nv_bfloat16*)pi1l,
        (float*)p_hinfo, nullptr, nullptr, CI, CC, 1);
    gate_k<<<TT, 128>>>(iw2);

    lowrank_mma<<<dim3(TT / 64, HH), 128, 69632>>>();
    local_attn_mma<<<dim3(TT / 128, HH), 256, 208896>>>();
    global_attn_mma<<<dim3(TT / 128, HH), 256, 110592>>>();

    // out = ctx @ w_o^T
    gemm_mma<<<dim3(CC / 128, TT / 128), 256, 81920>>>(
        (const __nv_bfloat16*)pcxh, (const __nv_bfloat16*)pcxl,
        (const __nv_bfloat16*)pwoh, (const __nv_bfloat16*)pwol,
        out, nullptr, nullptr, CC, CC, 0);
#undef SPLIT
}

// round 7
// speedup vs baseline: 3.2037x; 1.0783x over previous
#include <cuda_runtime.h>
#include <cuda_bf16.h>
#include <math.h>
#include <stdint.h>

#define TT   2048
#define CC   2048
#define HH   16
#define DD   128
#define RR   64
#define WLOC 512
#define CI   512
#define C3   6144

#define SCALE_L 0.08838834764831845f
#define SCALE_G 0.1767766952966369f

// ---------------- scratch (device globals) ----------------
__device__ float g_hinfo[TT * CI];
__device__ float g_gate[TT];
__device__ float g_cos[TT * DD];
__device__ float g_sin[TT * DD];
__device__ float g_ctx[TT * CC];

// bf16 hi/lo split operands
__device__ __nv_bfloat16 g_xh[TT * CC],  g_xl[TT * CC];
__device__ __nv_bfloat16 g_wqh[C3 * CC], g_wql[C3 * CC];
__device__ __nv_bfloat16 g_woh[CC * CC], g_wol[CC * CC];
__device__ __nv_bfloat16 g_i1h[CI * CC], g_i1l[CI * CC];
__device__ __nv_bfloat16 g_cxh[TT * CC], g_cxl[TT * CC];
__device__ __nv_bfloat16 g_qkvh[TT * C3], g_qkvl[TT * C3];
__device__ __nv_bfloat16 g_qrh[HH * TT * RR], g_qrl[HH * TT * RR];
__device__ __nv_bfloat16 g_krh[HH * TT * RR], g_krl[HH * TT * RR];
__device__ __nv_bfloat16 g_vrh[HH * TT * RR], g_vrl[HH * TT * RR];
__device__ __nv_bfloat16 g_uoh[DD * RR], g_uol[DD * RR];
__device__ __nv_bfloat16 g_pkh[RR * DD], g_pkl[RR * DD];
__device__ __nv_bfloat16 g_pvh[RR * DD], g_pvl[RR * DD];

// ============================================================================
// PTX helpers (plain sm_80+ ISA)
// ============================================================================
__device__ __forceinline__ uint32_t smem_u32(const void* p) {
    uint32_t a;
    asm("{ .reg .u64 t; cvta.to.shared.u64 t, %1; cvt.u32.u64 %0, t; }"
        : "=r"(a) : "l"(p));
    return a;
}

#define CP16(s, g) \
    asm volatile("cp.async.cg.shared.global [%0], [%1], 16;" \
                 :: "r"(s), "l"(g) : "memory")
#define CP_COMMIT() asm volatile("cp.async.commit_group;" ::: "memory")
#define CP_WAIT(n)  asm volatile("cp.async.wait_group %0;" :: "n"(n) : "memory")

__device__ __forceinline__ void ldsm4(uint32_t& r0, uint32_t& r1,
                                      uint32_t& r2, uint32_t& r3, uint32_t a) {
    asm volatile("ldmatrix.sync.aligned.m8n8.x4.shared.b16 {%0,%1,%2,%3}, [%4];"
                 : "=r"(r0), "=r"(r1), "=r"(r2), "=r"(r3) : "r"(a));
}
__device__ __forceinline__ void ldsm4t(uint32_t& r0, uint32_t& r1,
                                       uint32_t& r2, uint32_t& r3, uint32_t a) {
    asm volatile("ldmatrix.sync.aligned.m8n8.x4.trans.shared.b16 {%0,%1,%2,%3}, [%4];"
                 : "=r"(r0), "=r"(r1), "=r"(r2), "=r"(r3) : "r"(a));
}

__device__ __forceinline__ void mma16816(float* c, const uint32_t* a,
                                         const uint32_t* b) {
    asm volatile("mma.sync.aligned.m16n8k16.row.col.f32.bf16.bf16.f32 "
                 "{%0,%1,%2,%3}, {%4,%5,%6,%7}, {%8,%9}, {%0,%1,%2,%3};"
                 : "+f"(c[0]), "+f"(c[1]), "+f"(c[2]), "+f"(c[3])
                 : "r"(a[0]), "r"(a[1]), "r"(a[2]), "r"(a[3]),
                   "r"(b[0]), "r"(b[1]));
}

__device__ __forceinline__ void split2(float x, float y, uint32_t& h, uint32_t& l) {
    __nv_bfloat162 hh = __floats2bfloat162_rn(x, y);
    h = *reinterpret_cast<uint32_t*>(&hh);
    __nv_bfloat162 ll = __floats2bfloat162_rn(x - __bfloat162float(hh.x),
                                              y - __bfloat162float(hh.y));
    l = *reinterpret_cast<uint32_t*>(&ll);
}

// ============================================================================
// fp32 -> bf16 hi/lo split
// ============================================================================
__global__ void split_bf16_k(const float2* __restrict__ src,
                             __nv_bfloat162* __restrict__ hi,
                             __nv_bfloat162* __restrict__ lo, int n2)
{
    int i = blockIdx.x * 256 + threadIdx.x;
    if (i < n2) {
        float2 v = src[i];
        __nv_bfloat162 h = __floats2bfloat162_rn(v.x, v.y);
        hi[i] = h;
        lo[i] = __floats2bfloat162_rn(v.x - __bfloat162float(h.x),
                                      v.y - __bfloat162float(h.y));
    }
}

// ============================================================================
// mma.sync GEMM (BN=256): C = Ah·Bh^T + Al·Bh^T + Ah·Bl^T
// BM=128, BN=256, BK=32, 8 warps (4x2), warp tile 32x128.
// smem/stage: Ah 10240 | Al 10240 | Bh 20480 | Bl 20480 = 61440; x2 = 122880.
// L2 traffic 20 B/cyc/SM (vs 53 at BN=128) -> below LTS cap.
// mode 0: fp32 store. mode 1: gelu fp32. mode 2: rope + bf16 hi/lo store.
// ============================================================================
__global__ __launch_bounds__(256) void gemm_mma256(
    const __nv_bfloat16* __restrict__ Ah, const __nv_bfloat16* __restrict__ Al,
    const __nv_bfloat16* __restrict__ Bh, const __nv_bfloat16* __restrict__ Bl,
    float* __restrict__ Cout,
    __nv_bfloat16* __restrict__ Ch, __nv_bfloat16* __restrict__ Cl,
    int N, int K, int mode)
{
    extern __shared__ __align__(128) char smraw[];
    const uint32_t sb = smem_u32(smraw);
    const int tid = threadIdx.x, lane = tid & 31, wid = tid >> 5;
    const int wm = wid & 3, wn = wid >> 2;       // 4 x 2 warp grid
    const int bm = blockIdx.y << 7, bn = blockIdx.x << 8;
    const int aj = lane >> 3, ar = lane & 7;

    float acc[2][16][4];
#pragma unroll
    for (int mt = 0; mt < 2; mt++)
#pragma unroll
        for (int nt = 0; nt < 16; nt++)
#pragma unroll
            for (int e = 0; e < 4; e++) acc[mt][nt][e] = 0.f;

    const int nch = K >> 5;

    auto issue_stage = [&](int c) {
        const uint32_t st = sb + (c & 1) * 61440;
        const int k0 = c << 5;
        {
            const __nv_bfloat16* gh = Ah + (size_t)bm * K + k0;
            const __nv_bfloat16* gl = Al + (size_t)bm * K + k0;
#pragma unroll
            for (int hh = 0; hh < 2; hh++) {
                int i = tid + hh * 256;           // 0..511
                int r = i >> 2, q = i & 3;
                uint32_t so = st + r * 80 + q * 16;
                size_t go = (size_t)r * K + q * 8;
                CP16(so,          gh + go);
                CP16(so + 10240,  gl + go);
            }
        }
        {
            const __nv_bfloat16* gh = Bh + (size_t)bn * K + k0;
            const __nv_bfloat16* gl = Bl + (size_t)bn * K + k0;
#pragma unroll
            for (int hh = 0; hh < 4; hh++) {
                int i = tid + hh * 256;           // 0..1023
                int r = i >> 2, q = i & 3;
                uint32_t so = st + 20480 + r * 80 + q * 16;
                size_t go = (size_t)r * K + q * 8;
                CP16(so,          gh + go);
                CP16(so + 20480,  gl + go);
            }
        }
        CP_COMMIT();
    };

    issue_stage(0);
    for (int c = 0; c < nch; c++) {
        if (c + 1 < nch) { issue_stage(c + 1); CP_WAIT(1); }
        else             { CP_WAIT(0); }
        __syncthreads();

        const uint32_t st = sb + (c & 1) * 61440;
#pragma unroll
        for (int ks = 0; ks < 2; ks++) {
            uint32_t ah[2][4], al_[2][4], b2[16][2];
            const uint32_t a_off =
                ((wm * 32 + (aj & 1) * 8 + ar) * 40 + ks * 16 + (aj >> 1) * 8) * 2;
            const uint32_t b_off =
                ((wn * 128 + (aj >> 1) * 8 + ar) * 40 + ks * 16 + (aj & 1) * 8) * 2;

#pragma unroll
            for (int mt = 0; mt < 2; mt++) {
                ldsm4(ah[mt][0], ah[mt][1], ah[mt][2], ah[mt][3],
                      st + a_off + mt * (16 * 80));
                ldsm4(al_[mt][0], al_[mt][1], al_[mt][2], al_[mt][3],
                      st + 10240 + a_off + mt * (16 * 80));
            }
#pragma unroll
            for (int np = 0; np < 8; np++) {
                uint32_t r0, r1, r2, r3;
                ldsm4(r0, r1, r2, r3, st + 20480 + b_off + np * (16 * 80));
                b2[np * 2][0] = r0;     b2[np * 2][1] = r1;
                b2[np * 2 + 1][0] = r2; b2[np * 2 + 1][1] = r3;
            }
#pragma unroll
            for (int mt = 0; mt < 2; mt++)
#pragma unroll
                for (int nt = 0; nt < 16; nt++) {
                    mma16816(acc[mt][nt], ah[mt], b2[nt]);
                    mma16816(acc[mt][nt], al_[mt], b2[nt]);
                }
#pragma unroll
            for (int np = 0; np < 8; np++) {
                uint32_t r0, r1, r2, r3;
                ldsm4(r0, r1, r2, r3, st + 40960 + b_off + np * (16 * 80));
                b2[np * 2][0] = r0;     b2[np * 2][1] = r1;
                b2[np * 2 + 1][0] = r2; b2[np * 2 + 1][1] = r3;
            }
#pragma unroll
            for (int mt = 0; mt < 2; mt++)
#pragma unroll
                for (int nt = 0; nt < 16; nt++)
                    mma16816(acc[mt][nt], ah[mt], b2[nt]);
        }
        __syncthreads();
    }

    const int row_base = bm + wm * 32 + (lane >> 2);
    const int col_base = bn + wn * 128 + (lane & 3) * 2;
#pragma unroll
    for (int mt = 0; mt < 2; mt++)
#pragma unroll
        for (int nt = 0; nt < 16; nt++) {
            int r0 = row_base + mt * 16, cc = col_base + nt * 8;
            float v0 = acc[mt][nt][0], v1 = acc[mt][nt][1];
            float v2 = acc[mt][nt][2], v3 = acc[mt][nt][3];
            if (mode == 2) {
                if (cc < 2 * CC) {   // q/k sections: rope pairs (d0, d0+1)
                    int d0 = cc & 127;
                    float2 cA = *(const float2*)(g_cos + r0 * DD + d0);
                    float2 sA = *(const float2*)(g_sin + r0 * DD + d0);
                    float o0 = v0 * cA.x - v1 * sA.x;
                    float o1 = v1 * cA.y + v0 * sA.y;
                    float2 cB = *(const float2*)(g_cos + (r0 + 8) * DD + d0);
                    float2 sB = *(const float2*)(g_sin + (r0 + 8) * DD + d0);
                    float o2 = v2 * cB.x - v3 * sB.x;
                    float o3 = v3 * cB.y + v2 * sB.y;
                    v0 = o0; v1 = o1; v2 = o2; v3 = o3;
                }
                uint32_t h01, l01, h23, l23;
                split2(v0, v1, h01, l01);
                split2(v2, v3, h23, l23);
                *(uint32_t*)(Ch + (size_t)r0 * N + cc)       = h01;
                *(uint32_t*)(Cl + (size_t)r0 * N + cc)       = l01;
                *(uint32_t*)(Ch + (size_t)(r0 + 8) * N + cc) = h23;
                *(uint32_t*)(Cl + (size_t)(r0 + 8) * N + cc) = l23;
            } else {
                *(float2*)(Cout + (size_t)r0 * N + cc)       = make_float2(v0, v1);
                *(float2*)(Cout + (size_t)(r0 + 8) * N + cc) = make_float2(v2, v3);
            }
        }
}

// ============================================================================
// mma.sync GEMM (BN=128) — for the small-N info GEMM (keeps CTA count up).
// mode 1: gelu fp32 store.
// ============================================================================
__global__ __launch_bounds__(256) void gemm_mma128(
    const __nv_bfloat16* __restrict__ Ah, const __nv_bfloat16* __restrict__ Al,
    const __nv_bfloat16* __restrict__ Bh, const __nv_bfloat16* __restrict__ Bl,
    float* __restrict__ Cout, int N, int K, int dogelu)
{
    extern __shared__ __align__(128) char smraw[];
    const uint32_t sb = smem_u32(smraw);
    const int tid = threadIdx.x, lane = tid & 31, wid = tid >> 5;
    const int wm = wid & 3, wn = wid >> 2;
    const int bm = blockIdx.y << 7, bn = blockIdx.x << 7;
    const int aj = lane >> 3, ar = lane & 7;

    float acc[2][8][4];
#pragma unroll
    for (int mt = 0; mt < 2; mt++)
#pragma unroll
        for (int nt = 0; nt < 8; nt++)
#pragma unroll
            for (int e = 0; e < 4; e++) acc[mt][nt][e] = 0.f;

    const int nch = K >> 5;

    auto issue_stage = [&](int c) {
        const uint32_t st = sb + (c & 1) * 40960;
        const int k0 = c << 5;
        const __nv_bfloat16* gm0 = Ah + (size_t)bm * K + k0;
        const __nv_bfloat16* gm1 = Al + (size_t)bm * K + k0;
        const __nv_bfloat16* gm2 = Bh + (size_t)bn * K + k0;
        const __nv_bfloat16* gm3 = Bl + (size_t)bn * K + k0;
#pragma unroll
        for (int h = 0; h < 2; h++) {
            int i = tid + h * 256;
            int r = i >> 2, q = i & 3;
            uint32_t so = st + r * 80 + q * 16;
            size_t go = (size_t)r * K + q * 8;
            CP16(so,          gm0 + go);
            CP16(so + 10240,  gm1 + go);
            CP16(so + 20480,  gm2 + go);
            CP16(so + 30720,  gm3 + go);
        }
        CP_COMMIT();
    };

    issue_stage(0);
    for (int c = 0; c < nch; c++) {
        if (c + 1 < nch) { issue_stage(c + 1); CP_WAIT(1); }
        else             { CP_WAIT(0); }
        __syncthreads();

        const uint32_t st = sb + (c & 1) * 40960;
#pragma unroll
        for (int ks = 0; ks < 2; ks++) {
            uint32_t ah[2][4], al_[2][4], b2[8][2];
            const uint32_t a_off =
                ((wm * 32 + (aj & 1) * 8 + ar) * 40 + ks * 16 + (aj >> 1) * 8) * 2;
            const uint32_t b_off =
                ((wn * 64 + (aj >> 1) * 8 + ar) * 40 + ks * 16 + (aj & 1) * 8) * 2;

#pragma unroll
            for (int mt = 0; mt < 2; mt++) {
                ldsm4(ah[mt][0], ah[mt][1], ah[mt][2], ah[mt][3],
                      st + a_off + mt * (16 * 80));
                ldsm4(al_[mt][0], al_[mt][1], al_[mt][2], al_[mt][3],
                      st + 10240 + a_off + mt * (16 * 80));
            }
#pragma unroll
            for (int np = 0; np < 4; np++) {
                uint32_t r0, r1, r2, r3;
                ldsm4(r0, r1, r2, r3, st + 20480 + b_off + np * (16 * 80));
                b2[np * 2][0] = r0;     b2[np * 2][1] = r1;
                b2[np * 2 + 1][0] = r2; b2[np * 2 + 1][1] = r3;
            }
#pragma unroll
            for (int mt = 0; mt < 2; mt++)
#pragma unroll
                for (int nt = 0; nt < 8; nt++) {
                    mma16816(acc[mt][nt], ah[mt], b2[nt]);
                    mma16816(acc[mt][nt], al_[mt], b2[nt]);
                }
#pragma unroll
            for (int np = 0; np < 4; np++) {
                uint32_t r0, r1, r2, r3;
                ldsm4(r0, r1, r2, r3, st + 30720 + b_off + np * (16 * 80));
                b2[np * 2][0] = r0;     b2[np * 2][1] = r1;
                b2[np * 2 + 1][0] = r2; b2[np * 2 + 1][1] = r3;
            }
#pragma unroll
            for (int mt = 0; mt < 2; mt++)
#pragma unroll
                for (int nt = 0; nt < 8; nt++)
                    mma16816(acc[mt][nt], ah[mt], b2[nt]);
        }
        __syncthreads();
    }

    const int row_base = bm + wm * 32 + (lane >> 2);
    const int col_base = bn + wn * 64 + (lane & 3) * 2;
#pragma unroll
    for (int mt = 0; mt < 2; mt++)
#pragma unroll
        for (int nt = 0; nt < 8; nt++) {
            int r0 = row_base + mt * 16, cc = col_base + nt * 8;
            float v0 = acc[mt][nt][0], v1 = acc[mt][nt][1];
            float v2 = acc[mt][nt][2], v3 = acc[mt][nt][3];
            if (dogelu) {
                v0 = 0.5f * v0 * (1.0f + erff(v0 * 0.7071067811865475f));
                v1 = 0.5f * v1 * (1.0f + erff(v1 * 0.7071067811865475f));
                v2 = 0.5f * v2 * (1.0f + erff(v2 * 0.7071067811865475f));
                v3 = 0.5f * v3 * (1.0f + erff(v3 * 0.7071067811865475f));
            }
            *(float2*)(Cout + (size_t)r0 * N + cc)       = make_float2(v0, v1);
            *(float2*)(Cout + (size_t)(r0 + 8) * N + cc) = make_float2(v2, v3);
        }
}

// ============================================================================
// RoPE tables — fp32 path (matches the reference's float32 computation)
// ============================================================================
__global__ void rope_table_k()
{
    int t = blockIdx.x, d = threadIdx.x;
    int j = d & 63;
    // inv_freq = 10000^{-j/64} = 2^{-j * log2(10000)/64}
    float inv = exp2f(-(float)j * 0.20762050593046014f);
    float ang = (float)t * inv;
    float s, c;
    __sincosf(ang, &s, &c);
    // __sincosf is low-precision for large args; refine with sincosf for accuracy
    s = sinf(ang); c = cosf(ang);
    g_cos[t * DD + d] = c;
    g_sin[t * DD + d] = s;
}

// ============================================================================
// Gate
// ============================================================================
__global__ void gate_k(const float* __restrict__ w2)
{
    __shared__ float red[128];
    int t = blockIdx.x, tid = threadIdx.x;
    float s = 0.f;
    for (int j = tid; j < CI; j += 128) s += g_hinfo[t * CI + j] * w2[j];
    red[tid] = s;
    __syncthreads();
    for (int off = 64; off > 0; off >>= 1) {
        if (tid < off) red[tid] += red[tid + off];
        __syncthreads();
    }
    if (tid == 0) {
        float sc = 1.0f / (1.0f + expf(-red[0]));
        g_gate[t] = (sc > 0.75f) ? 1.0f : 0.0f;
    }
}

// ============================================================================
// Low-rank projections via mma.sync (bf16 split in, split out).
// ============================================================================
__global__ __launch_bounds__(128) void lowrank_mma()
{
    extern __shared__ __align__(16) char smraw[];
    const uint32_t sb = smem_u32(smraw);
    const uint32_t oAl = 64 * 136 * 2, oPh = 2 * 64 * 136 * 2, oPl = 3 * 64 * 136 * 2;
    const int tid = threadIdx.x, lane = tid & 31, w = tid >> 5;
    const int qt = blockIdx.x, h = blockIdx.y, t0 = qt << 6;
    const int aj = lane >> 3, ar = lane & 7;

    const uint32_t aoff = ((w * 16 + (aj & 1) * 8 + ar) * 136 + (aj >> 1) * 8) * 2;
    const uint32_t boff = (((aj >> 1) * 8 + ar) * 136 + (aj & 1) * 8) * 2;
    const int row0 = t0 + w * 16 + (lane >> 2);
    const int col = (lane & 3) * 2;

    for (int pass = 0; pass < 3; pass++) {
        const __nv_bfloat16* Ph = (pass == 2) ? g_pvh : g_pkh;
        const __nv_bfloat16* Pl = (pass == 2) ? g_pvl : g_pkl;
        const int off = pass * CC + h * DD;
        __syncthreads();
        for (int i = tid; i < 1024; i += 128) {
            int r = i >> 4, q = i & 15;
            uint32_t so = (r * 136 + q * 8) * 2;
            size_t ga = (size_t)(t0 + r) * C3 + off + q * 8;
            CP16(sb + so,       g_qkvh + ga);
            CP16(sb + oAl + so, g_qkvl + ga);
            int gp = r * DD + q * 8;
            CP16(sb + oPh + so, Ph + gp);
            CP16(sb + oPl + so, Pl + gp);
        }
        CP_COMMIT(); CP_WAIT(0);
        __syncthreads();

        float acc[8][4];
#pragma unroll
        for (int nt = 0; nt < 8; nt++)
#pragma unroll
            for (int e = 0; e < 4; e++) acc[nt][e] = 0.f;

#pragma unroll
        for (int kb = 0; kb < 8; kb++) {
            uint32_t ah[4], al_[4], b2[8][2];
            ldsm4(ah[0], ah[1], ah[2], ah[3], sb + aoff + kb * 32);
            ldsm4(al_[0], al_[1], al_[2], al_[3], sb + oAl + aoff + kb * 32);
#pragma unroll
            for (int np = 0; np < 4; np++) {
                uint32_t r0, r1, r2, r3;
                ldsm4(r0, r1, r2, r3, sb + oPh + boff + np * 16 * 136 * 2 + kb * 32);
                b2[np * 2][0] = r0;     b2[np * 2][1] = r1;
                b2[np * 2 + 1][0] = r2; b2[np * 2 + 1][1] = r3;
            }
#pragma unroll
            for (int nt = 0; nt < 8; nt++) {
                mma16816(acc[nt], ah, b2[nt]);
                mma16816(acc[nt], al_, b2[nt]);
            }
#pragma unroll
            for (int np = 0; np < 4; np++) {
                uint32_t r0, r1, r2, r3;
                ldsm4(r0, r1, r2, r3, sb + oPl + boff + np * 16 * 136 * 2 + kb * 32);
                b2[np * 2][0] = r0;     b2[np * 2][1] = r1;
                b2[np * 2 + 1][0] = r2; b2[np * 2 + 1][1] = r3;
            }
#pragma unroll
            for (int nt = 0; nt < 8; nt++)
                mma16816(acc[nt], ah, b2[nt]);
        }

        __nv_bfloat16* dh = (pass == 0) ? g_qrh : (pass == 1) ? g_krh : g_vrh;
        __nv_bfloat16* dl = (pass == 0) ? g_qrl : (pass == 1) ? g_krl : g_vrl;
#pragma unroll
        for (int nt = 0; nt < 8; nt++) {
            uint32_t hh, ll;
            size_t i0 = (size_t)(h * TT + row0) * RR + nt * 8 + col;
            split2(acc[nt][0], acc[nt][1], hh, ll);
            *(uint32_t*)(dh + i0) = hh;
            *(uint32_t*)(dl + i0) = ll;
            size_t i1 = i0 + 8 * RR;
            split2(acc[nt][2], acc[nt][3], hh, ll);
            *(uint32_t*)(dh + i1) = hh;
            *(uint32_t*)(dl + i1) = ll;
        }
    }
}

// ============================================================================
// Local sliding-window attention: Sq=128, 8 warps, double-buffered KV.
// ============================================================================
#define LPAD 136
__global__ __launch_bounds__(256) void local_attn_mma()
{
    extern __shared__ __align__(16) char smraw[];
    const uint32_t sb = smem_u32(smraw);
    const uint32_t oQl = 128 * LPAD * 2;
    const uint32_t kvBase = 2 * 128 * LPAD * 2;
    const uint32_t kvStage = 4 * 64 * LPAD * 2;
    const uint32_t seg = 64 * LPAD * 2;

    const int tid = threadIdx.x, lane = tid & 31, w = tid >> 5;
    const int qt = gridDim.x - 1 - blockIdx.x, h = blockIdx.y;
    const int t0 = qt << 7;
    const int aj = lane >> 3, ar = lane & 7;
    const int tg0 = t0 + w * 16 + (lane >> 2), tg1 = tg0 + 8;
    const int cq = (lane & 3) * 2;

    for (int i = tid; i < 2048; i += 256) {
        int r = i >> 4, q = i & 15;
        uint32_t so = sb + (r * LPAD + q * 8) * 2;
        size_t go = (size_t)(t0 + r) * C3 + h * DD + q * 8;
        CP16(so, g_qkvh + go);
        CP16(so + oQl, g_qkvl + go);
    }
    CP_COMMIT();

    const int kt0 = (t0 > WLOC - 1) ? ((t0 - (WLOC - 1)) >> 6) : 0;
    const int ktend = 2 * qt + 1;

    auto issueKV = [&](int kt, int s) {
        const int s0 = kt << 6;
        const uint32_t kb = sb + kvBase + s * kvStage;
        for (int i = tid; i < 1024; i += 256) {
            int r = i >> 4, q = i & 15;
            size_t gk = (size_t)(s0 + r) * C3 + CC + h * DD + q * 8;
            uint32_t off = (r * LPAD + q * 8) * 2;
            CP16(kb + off,           g_qkvh + gk);
            CP16(kb + seg + off,     g_qkvl + gk);
            CP16(kb + 2 * seg + off, g_qkvh + gk + CC);
            CP16(kb + 3 * seg + off, g_qkvl + gk + CC);
        }
        CP_COMMIT();
    };
    issueKV(kt0, 0);

    float m0 = -1e30f, m1 = -1e30f, l0 = 0.f, l1 = 0.f;
    float out[16][4];
#pragma unroll
    for (int nt = 0; nt < 16; nt++)
#pragma unroll
        for (int e = 0; e < 4; e++) out[nt][e] = 0.f;

    const uint32_t aQoff = ((w * 16 + (aj & 1) * 8 + ar) * LPAD + (aj >> 1) * 8) * 2;
    const uint32_t bKoff = (((aj >> 1) * 8 + ar) * LPAD + (aj & 1) * 8) * 2;
    const uint32_t bVoff = (((aj & 1) * 8 + ar) * LPAD + (aj >> 1) * 8) * 2;

    for (int kt = kt0; kt <= ktend; kt++) {
        const int s = (kt - kt0) & 1;
        if (kt < ktend) { issueKV(kt + 1, s ^ 1); CP_WAIT(1); }
        else            { CP_WAIT(0); }
        __syncthreads();
        const uint32_t kb = sb + kvBase + s * kvStage;
        const int s0 = kt << 6;

        float sc[8][4];
#pragma unroll
        for (int nt = 0; nt < 8; nt++)
#pragma unroll
            for (int e = 0; e < 4; e++) sc[nt][e] = 0.f;

#pragma unroll
        for (int kbk = 0; kbk < 8; kbk++) {
            uint32_t ah[4], al_[4], b2[8][2];
            ldsm4(ah[0], ah[1], ah[2], ah[3], sb + aQoff + kbk * 32);
            ldsm4(al_[0], al_[1], al_[2], al_[3], sb + oQl + aQoff + kbk * 32);
#pragma unroll
            for (int np = 0; np < 4; np++) {
                uint32_t r0, r1, r2, r3;
                ldsm4(r0, r1, r2, r3, kb + bKoff + np * 16 * LPAD * 2 + kbk * 32);
                b2[np * 2][0] = r0;     b2[np * 2][1] = r1;
                b2[np * 2 + 1][0] = r2; b2[np * 2 + 1][1] = r3;
            }
#pragma unroll
            for (int nt = 0; nt < 8; nt++) {
                mma16816(sc[nt], ah, b2[nt]);
                mma16816(sc[nt], al_, b2[nt]);
            }
#pragma unroll
            for (int np = 0; np < 4; np++) {
                uint32_t r0, r1, r2, r3;
                ldsm4(r0, r1, r2, r3,
                      kb + seg + bKoff + np * 16 * LPAD * 2 + kbk * 32);
                b2[np * 2][0] = r0;     b2[np * 2][1] = r1;
                b2[np * 2 + 1][0] = r2; b2[np * 2 + 1][1] = r3;
            }
#pragma unroll
            for (int nt = 0; nt < 8; nt++) mma16816(sc[nt], ah, b2[nt]);
        }

#pragma unroll
        for (int nt = 0; nt < 8; nt++) {
            int c0 = s0 + nt * 8 + cq;
#pragma unroll
            for (int e = 0; e < 2; e++) {
                int sg = c0 + e;
                float v0 = sc[nt][e] * SCALE_L;
                sc[nt][e] = (sg <= tg0 && sg >= tg0 - (WLOC - 1)) ? v0 : -1e30f;
                float v1 = sc[nt][2 + e] * SCALE_L;
                sc[nt][2 + e] = (sg <= tg1 && sg >= tg1 - (WLOC - 1)) ? v1 : -1e30f;
            }
        }

        float mx0 = -1e30f, mx1 = -1e30f;
#pragma unroll
        for (int nt = 0; nt < 8; nt++) {
            mx0 = fmaxf(mx0, fmaxf(sc[nt][0], sc[nt][1]));
            mx1 = fmaxf(mx1, fmaxf(sc[nt][2], sc[nt][3]));
        }
        mx0 = fmaxf(mx0, __shfl_xor_sync(0xffffffffu, mx0, 1));
        mx0 = fmaxf(mx0, __shfl_xor_sync(0xffffffffu, mx0, 2));
        mx1 = fmaxf(mx1, __shfl_xor_sync(0xffffffffu, mx1, 1));
        mx1 = fmaxf(mx1, __shfl_xor_sync(0xffffffffu, mx1, 2));
        float mn0 = fmaxf(m0, mx0), mn1 = fmaxf(m1, mx1);
        float al0 = __expf(m0 - mn0), al1 = __expf(m1 - mn1);
        m0 = mn0; m1 = mn1;

        float sum0 = 0.f, sum1 = 0.f;
#pragma unroll
        for (int nt = 0; nt < 8; nt++) {
#pragma unroll
            for (int e = 0; e < 2; e++) {
                float p0 = (sc[nt][e]     > -1e29f) ? __expf(sc[nt][e]     - mn0) : 0.f;
                float p1 = (sc[nt][2 + e] > -1e29f) ? __expf(sc[nt][2 + e] - mn1) : 0.f;
                sc[nt][e] = p0; sc[nt][2 + e] = p1;
                sum0 += p0; sum1 += p1;
            }
        }
        sum0 += __shfl_xor_sync(0xffffffffu, sum0, 1);
        sum0 += __shfl_xor_sync(0xffffffffu, sum0, 2);
        sum1 += __shfl_xor_sync(0xffffffffu, sum1, 1);
        sum1 += __shfl_xor_sync(0xffffffffu, sum1, 2);
        l0 = l0 * al0 + sum0;
        l1 = l1 * al1 + sum1;

#pragma unroll
        for (int nt = 0; nt < 16; nt++) {
            out[nt][0] *= al0; out[nt][1] *= al0;
            out[nt][2] *= al1; out[nt][3] *= al1;
        }

#pragma unroll
        for (int kbk = 0; kbk < 4; kbk++) {
            uint32_t ph[4], pl[4];
            split2(sc[2 * kbk][0],     sc[2 * kbk][1],     ph[0], pl[0]);
            split2(sc[2 * kbk][2],     sc[2 * kbk][3],     ph[1], pl[1]);
            split2(sc[2 * kbk + 1][0], sc[2 * kbk + 1][1], ph[2], pl[2]);
            split2(sc[2 * kbk + 1][2], sc[2 * kbk + 1][3], ph[3], pl[3]);
#pragma unroll
            for (int g = 0; g < 8; g++) {
                uint32_t vb = bVoff + kbk * 16 * LPAD * 2 + g * 32;
                uint32_t r0, r1, r2, r3;
                ldsm4t(r0, r1, r2, r3, kb + 2 * seg + vb);
                uint32_t b0[2] = {r0, r1}, b1[2] = {r2, r3};
                mma16816(out[2 * g], ph, b0);     mma16816(out[2 * g + 1], ph, b1);
                mma16816(out[2 * g], pl, b0);     mma16816(out[2 * g + 1], pl, b1);
                ldsm4t(r0, r1, r2, r3, kb + 3 * seg + vb);
                uint32_t c0[2] = {r0, r1}, c1[2] = {r2, r3};
                mma16816(out[2 * g], ph, c0);     mma16816(out[2 * g + 1], ph, c1);
            }
        }
        __syncthreads();
    }

    const float inv0 = 1.f / l0, inv1 = 1.f / l1;
#pragma unroll
    for (int nt = 0; nt < 16; nt++) {
        *(float2*)(g_ctx + (size_t)tg0 * CC + h * DD + nt * 8 + cq) =
            make_float2(out[nt][0] * inv0, out[nt][1] * inv0);
        *(float2*)(g_ctx + (size_t)tg1 * CC + h * DD + nt * 8 + cq) =
            make_float2(out[nt][2] * inv1, out[nt][3] * inv1);
    }
}

// ============================================================================
// Global low-rank attention: Sq=128, 8 warps, double-buffered KV_r,
// gated epilogue O @ uo^T; writes final ctx as bf16 hi/lo splits.
// ============================================================================
#define GPAD 72
__global__ __launch_bounds__(256) void global_attn_mma()
{
    extern __shared__ __align__(16) char smraw[];
    const uint32_t sb = smem_u32(smraw);
    const uint32_t oQl = 128 * GPAD * 2;
    const uint32_t kvBase = 2 * 128 * GPAD * 2;
    const uint32_t kvStage = 4 * 64 * GPAD * 2;
    const uint32_t seg = 64 * GPAD * 2;
    const uint32_t oUh = kvBase, oUl = kvBase + 128 * GPAD * 2;

    const int tid = threadIdx.x, lane = tid & 31, w = tid >> 5;
    const int qt = blockIdx.x, h = blockIdx.y, t0 = qt << 7;
    const int aj = lane >> 3, ar = lane & 7;
    const int tg0 = t0 + w * 16 + (lane >> 2), tg1 = tg0 + 8;
    const int cq = (lane & 3) * 2;

    for (int i = tid; i < 1024; i += 256) {
        int r = i >> 3, q = i & 7;
        uint32_t so = sb + (r * GPAD + q * 8) * 2;
        size_t go = (size_t)(h * TT + t0 + r) * RR + q * 8;
        CP16(so, g_qrh + go);
        CP16(so + oQl, g_qrl + go);
    }
    CP_COMMIT();

    auto issueKV = [&](int kt, int s) {
        const int s0 = kt << 6;
        const uint32_t kb = sb + kvBase + s * kvStage;
        for (int i = tid; i < 512; i += 256) {
            int r = i >> 3, q = i & 7;
            size_t gk = (size_t)(h * TT + s0 + r) * RR + q * 8;
            uint32_t off = (r * GPAD + q * 8) * 2;
            CP16(kb + off,           g_krh + gk);
            CP16(kb + seg + off,     g_krl + gk);
            CP16(kb + 2 * seg + off, g_vrh + gk);
            CP16(kb + 3 * seg + off, g_vrl + gk);
        }
        CP_COMMIT();
    };
    issueKV(0, 0);

    float m0 = -1e30f, m1 = -1e30f, l0 = 0.f, l1 = 0.f;
    float out[8][4];
#pragma unroll
    for (int nt = 0; nt < 8; nt++)
#pragma unroll
        for (int e = 0; e < 4; e++) out[nt][e] = 0.f;

    const uint32_t aQoff = ((w * 16 + (aj & 1) * 8 + ar) * GPAD + (aj >> 1) * 8) * 2;
    const uint32_t bKoff = (((aj >> 1) * 8 + ar) * GPAD + (aj & 1) * 8) * 2;
    const uint32_t bVoff = (((aj & 1) * 8 + ar) * GPAD + (aj >> 1) * 8) * 2;

    for (int kt = 0; kt < TT / 64; kt++) {
        const int s = kt & 1;
        if (kt < TT / 64 - 1) { issueKV(kt + 1, s ^ 1); CP_WAIT(1); }
        else                  { CP_WAIT(0); }
        __syncthreads();
        const uint32_t kb = sb + kvBase + s * kvStage;

        float sc[8][4];
#pragma unroll
        for (int nt = 0; nt < 8; nt++)
#pragma unroll
            for (int e = 0; e < 4; e++) sc[nt][e] = 0.f;

#pragma unroll
        for (int kbk = 0; kbk < 4; kbk++) {
            uint32_t ah[4], al_[4], b2[8][2];
            ldsm4(ah[0], ah[1], ah[2], ah[3], sb + aQoff + kbk * 32);
            ldsm4(al_[0], al_[1], al_[2], al_[3], sb + oQl + aQoff + kbk * 32);
#pragma unroll
            for (int np = 0; np < 4; np++) {
                uint32_t r0, r1, r2, r3;
                ldsm4(r0, r1, r2, r3, kb + bKoff + np * 16 * GPAD * 2 + kbk * 32);
                b2[np * 2][0] = r0;     b2[np * 2][1] = r1;
                b2[np * 2 + 1][0] = r2; b2[np * 2 + 1][1] = r3;
            }
#pragma unroll
            for (int nt = 0; nt < 8; nt++) {
                mma16816(sc[nt], ah, b2[nt]);
                mma16816(sc[nt], al_, b2[nt]);
            }
#pragma unroll
            for (int np = 0; np < 4; np++) {
                uint32_t r0, r1, r2, r3;
                ldsm4(r0, r1, r2, r3,
                      kb + seg + bKoff + np * 16 * GPAD * 2 + kbk * 32);
                b2[np * 2][0] = r0;     b2[np * 2][1] = r1;
                b2[np * 2 + 1][0] = r2; b2[np * 2 + 1][1] = r3;
            }
#pragma unroll
            for (int nt = 0; nt < 8; nt++) mma16816(sc[nt], ah, b2[nt]);
        }

        float mx0 = -1e30f, mx1 = -1e30f;
#pragma unroll
        for (int nt = 0; nt < 8; nt++) {
            sc[nt][0] *= SCALE_G; sc[nt][1] *= SCALE_G;
            sc[nt][2] *= SCALE_G; sc[nt][3] *= SCALE_G;
            mx0 = fmaxf(mx0, fmaxf(sc[nt][0], sc[nt][1]));
            mx1 = fmaxf(mx1, fmaxf(sc[nt][2], sc[nt][3]));
        }
        mx0 = fmaxf(mx0, __shfl_xor_sync(0xffffffffu, mx0, 1));
        mx0 = fmaxf(mx0, __shfl_xor_sync(0xffffffffu, mx0, 2));
        mx1 = fmaxf(mx1, __shfl_xor_sync(0xffffffffu, mx1, 1));
        mx1 = fmaxf(mx1, __shfl_xor_sync(0xffffffffu, mx1, 2));
        float mn0 = fmaxf(m0, mx0), mn1 = fmaxf(m1, mx1);
        float al0 = __expf(m0 - mn0), al1 = __expf(m1 - mn1);
        m0 = mn0; m1 = mn1;

        float sum0 = 0.f, sum1 = 0.f;
#pragma unroll
        for (int nt = 0; nt < 8; nt++) {
#pragma unroll
            for (int e = 0; e < 2; e++) {
                float p0 = __expf(sc[nt][e] - mn0);
                float p1 = __expf(sc[nt][2 + e] - mn1);
                sc[nt][e] = p0; sc[nt][2 + e] = p1;
                sum0 += p0; sum1 += p1;
            }
        }
        sum0 += __shfl_xor_sync(0xffffffffu, sum0, 1);
        sum0 += __shfl_xor_sync(0xffffffffu, sum0, 2);
        sum1 += __shfl_xor_sync(0xffffffffu, sum1, 1);
        sum1 += __shfl_xor_sync(0xffffffffu, sum1, 2);
        l0 = l0 * al0 + sum0;
        l1 = l1 * al1 + sum1;

#pragma unroll
        for (int nt = 0; nt < 8; nt++) {
            out[nt][0] *= al0; out[nt][1] *= al0;
            out[nt][2] *= al1; out[nt][3] *= al1;
        }

#pragma unroll
        for (int kbk = 0; kbk < 4; kbk++) {
            uint32_t ph[4], pl[4];
            split2(sc[2 * kbk][0],     sc[2 * kbk][1],     ph[0], pl[0]);
            split2(sc[2 * kbk][2],     sc[2 * kbk][3],     ph[1], pl[1]);
            split2(sc[2 * kbk + 1][0], sc[2 * kbk + 1][1], ph[2], pl[2]);
            split2(sc[2 * kbk + 1][2], sc[2 * kbk + 1][3], ph[3], pl[3]);
#pragma unroll
            for (int g = 0; g < 4; g++) {
                uint32_t vb = bVoff + kbk * 16 * GPAD * 2 + g * 32;
                uint32_t r0, r1, r2, r3;
                ldsm4t(r0, r1, r2, r3, kb + 2 * seg + vb);
                uint32_t b0[2] = {r0, r1}, b1[2] = {r2, r3};
                mma16816(out[2 * g], ph, b0);     mma16816(out[2 * g + 1], ph, b1);
                mma16816(out[2 * g], pl, b0);     mma16816(out[2 * g + 1], pl, b1);
                ldsm4t(r0, r1, r2, r3, kb + 3 * seg + vb);
                uint32_t c0[2] = {r0, r1}, c1[2] = {r2, r3};
                mma16816(out[2 * g], ph, c0);     mma16816(out[2 * g + 1], ph, c1);
            }
        }
        __syncthreads();
    }

    const float inv0 = 1.f / l0, inv1 = 1.f / l1;
#pragma unroll
    for (int nt = 0; nt < 8; nt++) {
        out[nt][0] *= inv0; out[nt][1] *= inv0;
        out[nt][2] *= inv1; out[nt][3] *= inv1;
    }

    for (int i = tid; i < 1024; i += 256) {
        int d = i >> 3, q = i & 7;
        *(int4*)(smraw + oUh + (d * GPAD + q * 8) * 2) =
            *(const int4*)(g_uoh + d * 64 + q * 8);
        *(int4*)(smraw + oUl + (d * GPAD + q * 8) * 2) =
            *(const int4*)(g_uol + d * 64 + q * 8);
    }
    __syncthreads();

    float out2[16][4];
#pragma unroll
    for (int nt = 0; nt < 16; nt++)
#pragma unroll
        for (int e = 0; e < 4; e++) out2[nt][e] = 0.f;

    const uint32_t bUoff = (((aj >> 1) * 8 + ar) * GPAD + (aj & 1) * 8) * 2;
#pragma unroll
    for (int kbk = 0; kbk < 4; kbk++) {
        uint32_t ph[4], pl[4];
        split2(out[2 * kbk][0],     out[2 * kbk][1],     ph[0], pl[0]);
        split2(out[2 * kbk][2],     out[2 * kbk][3],     ph[1], pl[1]);
        split2(out[2 * kbk + 1][0], out[2 * kbk + 1][1], ph[2], pl[2]);
        split2(out[2 * kbk + 1][2], out[2 * kbk + 1][3], ph[3], pl[3]);
#pragma unroll
        for (int g = 0; g < 8; g++) {
            uint32_t ub = sb + oUh + bUoff + g * 16 * GPAD * 2 + kbk * 32;
            uint32_t r0, r1, r2, r3;
            ldsm4(r0, r1, r2, r3, ub);
            uint32_t b0[2] = {r0, r1}, b1[2] = {r2, r3};
            mma16816(out2[2 * g], ph, b0);     mma16816(out2[2 * g + 1], ph, b1);
            mma16816(out2[2 * g], pl, b0);     mma16816(out2[2 * g + 1], pl, b1);
            ldsm4(r0, r1, r2, r3, ub + (oUl - oUh));
            uint32_t c0[2] = {r0, r1}, c1[2] = {r2, r3};
            mma16816(out2[2 * g], ph, c0);     mma16816(out2[2 * g + 1], ph, c1);
        }
    }

    const float ga0 = g_gate[tg0], ga1 = g_gate[tg1];
#pragma unroll
    for (int nt = 0; nt < 16; nt++) {
        size_t i0 = (size_t)tg0 * CC + h * DD + nt * 8 + cq;
        float2 o0 = *(float2*)(g_ctx + i0);
        uint32_t hh, ll;
        split2(o0.x + ga0 * out2[nt][0], o0.y + ga0 * out2[nt][1], hh, ll);
        *(uint32_t*)(g_cxh + i0) = hh;
        *(uint32_t*)(g_cxl + i0) = ll;
        size_t i1 = (size_t)tg1 * CC + h * DD + nt * 8 + cq;
        float2 o1 = *(float2*)(g_ctx + i1);
        split2(o1.x + ga1 * out2[nt][2], o1.y + ga1 * out2[nt][3], hh, ll);
        *(uint32_t*)(g_cxh + i1) = hh;
        *(uint32_t*)(g_cxl + i1) = ll;
    }
}

// ============================================================================
extern "C" void kernel_launch(void* const* d_in, const int* in_sizes, int n_in,
                              void* d_out, int out_size)
{
    const float* x     = (const float*)d_in[0];
    const float* w_qkv = (const float*)d_in[1];
    const float* w_o   = (const float*)d_in[2];
    const float* pk    = (const float*)d_in[3];
    const float* pv    = (const float*)d_in[4];
    const float* uo    = (const float*)d_in[5];
    const float* iw1   = (const float*)d_in[6];
    const float* iw2   = (const float*)d_in[7];
    float* out = (float*)d_out;

    cudaFuncSetAttribute(gemm_mma256,     cudaFuncAttributeMaxDynamicSharedMemorySize, 122880);
    cudaFuncSetAttribute(gemm_mma128,     cudaFuncAttributeMaxDynamicSharedMemorySize, 81920);
    cudaFuncSetAttribute(local_attn_mma,  cudaFuncAttributeMaxDynamicSharedMemorySize, 208896);
    cudaFuncSetAttribute(global_attn_mma, cudaFuncAttributeMaxDynamicSharedMemorySize, 110592);
    cudaFuncSetAttribute(lowrank_mma,     cudaFuncAttributeMaxDynamicSharedMemorySize, 69632);

    void *p_hinfo;
    void *pxh, *pxl, *pwqh, *pwql, *pwoh, *pwol, *pi1h, *pi1l, *pcxh, *pcxl;
    void *pqkvh, *pqkvl, *puoh, *puol, *ppkh, *ppkl, *ppvh, *ppvl;
    cudaGetSymbolAddress(&p_hinfo, g_hinfo);
    cudaGetSymbolAddress(&pxh, g_xh);   cudaGetSymbolAddress(&pxl, g_xl);
    cudaGetSymbolAddress(&pwqh, g_wqh); cudaGetSymbolAddress(&pwql, g_wql);
    cudaGetSymbolAddress(&pwoh, g_woh); cudaGetSymbolAddress(&pwol, g_wol);
    cudaGetSymbolAddress(&pi1h, g_i1h); cudaGetSymbolAddress(&pi1l, g_i1l);
    cudaGetSymbolAddress(&pcxh, g_cxh); cudaGetSymbolAddress(&pcxl, g_cxl);
    cudaGetSymbolAddress(&pqkvh, g_qkvh); cudaGetSymbolAddress(&pqkvl, g_qkvl);
    cudaGetSymbolAddress(&puoh, g_uoh); cudaGetSymbolAddress(&puol, g_uol);
    cudaGetSymbolAddress(&ppkh, g_pkh); cudaGetSymbolAddress(&ppkl, g_pkl);
    cudaGetSymbolAddress(&ppvh, g_pvh); cudaGetSymbolAddress(&ppvl, g_pvl);

#define SPLIT(src, h, l, n) \
    split_bf16_k<<<((n)/2 + 255) / 256, 256>>>((const float2*)(src), \
        (__nv_bfloat162*)(h), (__nv_bfloat162*)(l), (n)/2)

    rope_table_k<<<TT, DD>>>();
    SPLIT(x, pxh, pxl, TT * CC);
    SPLIT(w_qkv, pwqh, pwql, C3 * CC);
    SPLIT(iw1, pi1h, pi1l, CI * CC);
    SPLIT(w_o, pwoh, pwol, CC * CC);
    SPLIT(uo, puoh, puol, DD * RR);
    SPLIT(pk, ppkh, ppkl, RR * DD);
    SPLIT(pv, ppvh, ppvl, RR * DD);

    // qkv = rope(x @ w_qkv^T) -> bf16 splits (fused epilogue), BN=256
    gemm_mma256<<<dim3(C3 / 256, TT / 128), 256, 122880>>>(
        (const __nv_bfloat16*)pxh, (const __nv_bfloat16*)pxl,
        (const __nv_bfloat16*)pwqh, (const __nv_bfloat16*)pwql,
        nullptr, (__nv_bfloat16*)pqkvh, (__nv_bfloat16*)pqkvl, C3, CC, 2);

    // h_info = gelu(x @ iw1^T); gate  (BN=128 keeps CTA count up for N=512)
    gemm_mma128<<<dim3(CI / 128, TT / 128), 256, 81920>>>(
        (const __nv_bfloat16*)pxh, (const __nv_bfloat16*)pxl,
        (const __nv_bfloat16*)pi1h, (const __nv_bfloat16*)pi1l,
        (float*)p_hinfo, CI, CC, 1);
    gate_k<<<TT, 128>>>(iw2);

    lowrank_mma<<<dim3(TT / 64, HH), 128, 69632>>>();
    local_attn_mma<<<dim3(TT / 128, HH), 256, 208896>>>();
    global_attn_mma<<<dim3(TT / 128, HH), 256, 110592>>>();

    // out = ctx @ w_o^T, BN=256
    gemm_mma256<<<dim3(CC / 256, TT / 128), 256, 122880>>>(
        (const __nv_bfloat16*)pcxh, (const __nv_bfloat16*)pcxl,
        (const __nv_bfloat16*)pwoh, (const __nv_bfloat16*)pwol,
        out, nullptr, nullptr, CC, CC, 0);
#undef SPLIT
}

// round 8
// speedup vs baseline: 4.4078x; 1.3758x over previous
#include <cuda_runtime.h>
#include <cuda_fp16.h>
#include <math.h>
#include <stdint.h>

#define TT   2048
#define CC   2048
#define HH   16
#define DD   128
#define RR   64
#define WLOC 512
#define CI   512
#define C3   6144

#define SCALE_L 0.08838834764831845f
#define SCALE_G 0.1767766952966369f

// ---------------- scratch (device globals) ----------------
__device__ float g_hinfo[TT * CI];
__device__ float g_gate[TT];
__device__ float g_cos[TT * DD];
__device__ float g_sin[TT * DD];
__device__ float g_ctx[TT * CC];

// fp16 operands: A-side needs hi+lo (2-term split), B-side hi only.
__device__ __half g_xh[TT * CC],  g_xl[TT * CC];
__device__ __half g_wqh[C3 * CC];
__device__ __half g_woh[CC * CC];
__device__ __half g_i1h[CI * CC];
__device__ __half g_cxh[TT * CC], g_cxl[TT * CC];
__device__ __half g_qkvh[TT * C3], g_qkvl[TT * C3];
__device__ __half g_qrh[HH * TT * RR], g_qrl[HH * TT * RR];
__device__ __half g_krh[HH * TT * RR];
__device__ __half g_vrh[HH * TT * RR];
__device__ __half g_uoh[DD * RR];
__device__ __half g_pkh[RR * DD];
__device__ __half g_pvh[RR * DD];

// ============================================================================
// PTX helpers (plain sm_80+ ISA)
// ============================================================================
__device__ __forceinline__ uint32_t smem_u32(const void* p) {
    uint32_t a;
    asm("{ .reg .u64 t; cvta.to.shared.u64 t, %1; cvt.u32.u64 %0, t; }"
        : "=r"(a) : "l"(p));
    return a;
}

#define CP16(s, g) \
    asm volatile("cp.async.cg.shared.global [%0], [%1], 16;" \
                 :: "r"(s), "l"(g) : "memory")
#define CP_COMMIT() asm volatile("cp.async.commit_group;" ::: "memory")
#define CP_WAIT(n)  asm volatile("cp.async.wait_group %0;" :: "n"(n) : "memory")

__device__ __forceinline__ void ldsm4(uint32_t& r0, uint32_t& r1,
                                      uint32_t& r2, uint32_t& r3, uint32_t a) {
    asm volatile("ldmatrix.sync.aligned.m8n8.x4.shared.b16 {%0,%1,%2,%3}, [%4];"
                 : "=r"(r0), "=r"(r1), "=r"(r2), "=r"(r3) : "r"(a));
}
__device__ __forceinline__ void ldsm4t(uint32_t& r0, uint32_t& r1,
                                       uint32_t& r2, uint32_t& r3, uint32_t a) {
    asm volatile("ldmatrix.sync.aligned.m8n8.x4.trans.shared.b16 {%0,%1,%2,%3}, [%4];"
                 : "=r"(r0), "=r"(r1), "=r"(r2), "=r"(r3) : "r"(a));
}

// fp16 inputs, fp32 accumulate
__device__ __forceinline__ void mma16816(float* c, const uint32_t* a,
                                         const uint32_t* b) {
    asm volatile("mma.sync.aligned.m16n8k16.row.col.f32.f16.f16.f32 "
                 "{%0,%1,%2,%3}, {%4,%5,%6,%7}, {%8,%9}, {%0,%1,%2,%3};"
                 : "+f"(c[0]), "+f"(c[1]), "+f"(c[2]), "+f"(c[3])
                 : "r"(a[0]), "r"(a[1]), "r"(a[2]), "r"(a[3]),
                   "r"(b[0]), "r"(b[1]));
}

__device__ __forceinline__ void split2(float x, float y, uint32_t& h, uint32_t& l) {
    __half2 hh = __floats2half2_rn(x, y);
    h = *reinterpret_cast<uint32_t*>(&hh);
    __half2 ll = __floats2half2_rn(x - __low2float(hh), y - __high2float(hh));
    l = *reinterpret_cast<uint32_t*>(&ll);
}

// ============================================================================
// fp32 -> fp16 hi/lo split (A operands)
// ============================================================================
__global__ void split_h2_k(const float2* __restrict__ src,
                           __half2* __restrict__ hi,
                           __half2* __restrict__ lo, int n2)
{
    int i = blockIdx.x * 256 + threadIdx.x;
    if (i < n2) {
        float2 v = src[i];
        __half2 h = __floats2half2_rn(v.x, v.y);
        hi[i] = h;
        lo[i] = __floats2half2_rn(v.x - __low2float(h), v.y - __high2float(h));
    }
}

// fp32 -> fp16 convert only (B operands)
__global__ void conv_h_k(const float2* __restrict__ src,
                         __half2* __restrict__ hi, int n2)
{
    int i = blockIdx.x * 256 + threadIdx.x;
    if (i < n2) {
        float2 v = src[i];
        hi[i] = __floats2half2_rn(v.x, v.y);
    }
}

// ============================================================================
// mma.sync GEMM (BN=256, 2-term fp16): C = Ah·Bh^T + Al·Bh^T
// BM=128, BN=256, BK=32, 8 warps (4x2), warp tile 32x128.
// smem/stage: Ah 10240 | Al 10240 | Bh 20480 = 40960; x2 = 81920.
// mode 0: fp32 store. mode 2: rope + fp16 hi/lo store.
// ============================================================================
__global__ __launch_bounds__(256) void gemm_mma256(
    const __half* __restrict__ Ah, const __half* __restrict__ Al,
    const __half* __restrict__ Bh,
    float* __restrict__ Cout,
    __half* __restrict__ Ch, __half* __restrict__ Cl,
    int N, int K, int mode)
{
    extern __shared__ __align__(128) char smraw[];
    const uint32_t sb = smem_u32(smraw);
    const int tid = threadIdx.x, lane = tid & 31, wid = tid >> 5;
    const int wm = wid & 3, wn = wid >> 2;
    const int bm = blockIdx.y << 7, bn = blockIdx.x << 8;
    const int aj = lane >> 3, ar = lane & 7;

    float acc[2][16][4];
#pragma unroll
    for (int mt = 0; mt < 2; mt++)
#pragma unroll
        for (int nt = 0; nt < 16; nt++)
#pragma unroll
            for (int e = 0; e < 4; e++) acc[mt][nt][e] = 0.f;

    const int nch = K >> 5;

    auto issue_stage = [&](int c) {
        const uint32_t st = sb + (c & 1) * 40960;
        const int k0 = c << 5;
        {
            const __half* gh = Ah + (size_t)bm * K + k0;
            const __half* gl = Al + (size_t)bm * K + k0;
#pragma unroll
            for (int hh = 0; hh < 2; hh++) {
                int i = tid + hh * 256;
                int r = i >> 2, q = i & 3;
                uint32_t so = st + r * 80 + q * 16;
                size_t go = (size_t)r * K + q * 8;
                CP16(so,          gh + go);
                CP16(so + 10240,  gl + go);
            }
        }
        {
            const __half* gh = Bh + (size_t)bn * K + k0;
#pragma unroll
            for (int hh = 0; hh < 4; hh++) {
                int i = tid + hh * 256;
                int r = i >> 2, q = i & 3;
                CP16(st + 20480 + r * 80 + q * 16, gh + (size_t)r * K + q * 8);
            }
        }
        CP_COMMIT();
    };

    issue_stage(0);
    for (int c = 0; c < nch; c++) {
        if (c + 1 < nch) { issue_stage(c + 1); CP_WAIT(1); }
        else             { CP_WAIT(0); }
        __syncthreads();

        const uint32_t st = sb + (c & 1) * 40960;
#pragma unroll
        for (int ks = 0; ks < 2; ks++) {
            uint32_t ah[2][4], al_[2][4], b2[16][2];
            const uint32_t a_off =
                ((wm * 32 + (aj & 1) * 8 + ar) * 40 + ks * 16 + (aj >> 1) * 8) * 2;
            const uint32_t b_off =
                ((wn * 128 + (aj >> 1) * 8 + ar) * 40 + ks * 16 + (aj & 1) * 8) * 2;

#pragma unroll
            for (int mt = 0; mt < 2; mt++) {
                ldsm4(ah[mt][0], ah[mt][1], ah[mt][2], ah[mt][3],
                      st + a_off + mt * (16 * 80));
                ldsm4(al_[mt][0], al_[mt][1], al_[mt][2], al_[mt][3],
                      st + 10240 + a_off + mt * (16 * 80));
            }
#pragma unroll
            for (int np = 0; np < 8; np++) {
                uint32_t r0, r1, r2, r3;
                ldsm4(r0, r1, r2, r3, st + 20480 + b_off + np * (16 * 80));
                b2[np * 2][0] = r0;     b2[np * 2][1] = r1;
                b2[np * 2 + 1][0] = r2; b2[np * 2 + 1][1] = r3;
            }
#pragma unroll
            for (int mt = 0; mt < 2; mt++)
#pragma unroll
                for (int nt = 0; nt < 16; nt++) {
                    mma16816(acc[mt][nt], ah[mt], b2[nt]);
                    mma16816(acc[mt][nt], al_[mt], b2[nt]);
                }
        }
        __syncthreads();
    }

    const int row_base = bm + wm * 32 + (lane >> 2);
    const int col_base = bn + wn * 128 + (lane & 3) * 2;
#pragma unroll
    for (int mt = 0; mt < 2; mt++)
#pragma unroll
        for (int nt = 0; nt < 16; nt++) {
            int r0 = row_base + mt * 16, cc = col_base + nt * 8;
            float v0 = acc[mt][nt][0], v1 = acc[mt][nt][1];
            float v2 = acc[mt][nt][2], v3 = acc[mt][nt][3];
            if (mode == 2) {
                if (cc < 2 * CC) {
                    int d0 = cc & 127;
                    float2 cA = *(const float2*)(g_cos + r0 * DD + d0);
                    float2 sA = *(const float2*)(g_sin + r0 * DD + d0);
                    float o0 = v0 * cA.x - v1 * sA.x;
                    float o1 = v1 * cA.y + v0 * sA.y;
                    float2 cB = *(const float2*)(g_cos + (r0 + 8) * DD + d0);
                    float2 sB = *(const float2*)(g_sin + (r0 + 8) * DD + d0);
                    float o2 = v2 * cB.x - v3 * sB.x;
                    float o3 = v3 * cB.y + v2 * sB.y;
                    v0 = o0; v1 = o1; v2 = o2; v3 = o3;
                }
                uint32_t h01, l01, h23, l23;
                split2(v0, v1, h01, l01);
                split2(v2, v3, h23, l23);
                *(uint32_t*)(Ch + (size_t)r0 * N + cc)       = h01;
                *(uint32_t*)(Cl + (size_t)r0 * N + cc)       = l01;
                *(uint32_t*)(Ch + (size_t)(r0 + 8) * N + cc) = h23;
                *(uint32_t*)(Cl + (size_t)(r0 + 8) * N + cc) = l23;
            } else {
                *(float2*)(Cout + (size_t)r0 * N + cc)       = make_float2(v0, v1);
                *(float2*)(Cout + (size_t)(r0 + 8) * N + cc) = make_float2(v2, v3);
            }
        }
}

// ============================================================================
// mma.sync GEMM (BN=128, 2-term fp16) — info GEMM. gelu fp32 store.
// smem/stage: Ah 10240 | Al 10240 | Bh 10240 = 30720; x2 = 61440.
// ============================================================================
__global__ __launch_bounds__(256) void gemm_mma128(
    const __half* __restrict__ Ah, const __half* __restrict__ Al,
    const __half* __restrict__ Bh,
    float* __restrict__ Cout, int N, int K)
{
    extern __shared__ __align__(128) char smraw[];
    const uint32_t sb = smem_u32(smraw);
    const int tid = threadIdx.x, lane = tid & 31, wid = tid >> 5;
    const int wm = wid & 3, wn = wid >> 2;
    const int bm = blockIdx.y << 7, bn = blockIdx.x << 7;
    const int aj = lane >> 3, ar = lane & 7;

    float acc[2][8][4];
#pragma unroll
    for (int mt = 0; mt < 2; mt++)
#pragma unroll
        for (int nt = 0; nt < 8; nt++)
#pragma unroll
            for (int e = 0; e < 4; e++) acc[mt][nt][e] = 0.f;

    const int nch = K >> 5;

    auto issue_stage = [&](int c) {
        const uint32_t st = sb + (c & 1) * 30720;
        const int k0 = c << 5;
        const __half* gm0 = Ah + (size_t)bm * K + k0;
        const __half* gm1 = Al + (size_t)bm * K + k0;
        const __half* gm2 = Bh + (size_t)bn * K + k0;
#pragma unroll
        for (int h = 0; h < 2; h++) {
            int i = tid + h * 256;
            int r = i >> 2, q = i & 3;
            uint32_t so = st + r * 80 + q * 16;
            size_t go = (size_t)r * K + q * 8;
            CP16(so,          gm0 + go);
            CP16(so + 10240,  gm1 + go);
            CP16(so + 20480,  gm2 + go);
        }
        CP_COMMIT();
    };

    issue_stage(0);
    for (int c = 0; c < nch; c++) {
        if (c + 1 < nch) { issue_stage(c + 1); CP_WAIT(1); }
        else             { CP_WAIT(0); }
        __syncthreads();

        const uint32_t st = sb + (c & 1) * 30720;
#pragma unroll
        for (int ks = 0; ks < 2; ks++) {
            uint32_t ah[2][4], al_[2][4], b2[8][2];
            const uint32_t a_off =
                ((wm * 32 + (aj & 1) * 8 + ar) * 40 + ks * 16 + (aj >> 1) * 8) * 2;
            const uint32_t b_off =
                ((wn * 64 + (aj >> 1) * 8 + ar) * 40 + ks * 16 + (aj & 1) * 8) * 2;

#pragma unroll
            for (int mt = 0; mt < 2; mt++) {
                ldsm4(ah[mt][0], ah[mt][1], ah[mt][2], ah[mt][3],
                      st + a_off + mt * (16 * 80));
                ldsm4(al_[mt][0], al_[mt][1], al_[mt][2], al_[mt][3],
                      st + 10240 + a_off + mt * (16 * 80));
            }
#pragma unroll
            for (int np = 0; np < 4; np++) {
                uint32_t r0, r1, r2, r3;
                ldsm4(r0, r1, r2, r3, st + 20480 + b_off + np * (16 * 80));
                b2[np * 2][0] = r0;     b2[np * 2][1] = r1;
                b2[np * 2 + 1][0] = r2; b2[np * 2 + 1][1] = r3;
            }
#pragma unroll
            for (int mt = 0; mt < 2; mt++)
#pragma unroll
                for (int nt = 0; nt < 8; nt++) {
                    mma16816(acc[mt][nt], ah[mt], b2[nt]);
                    mma16816(acc[mt][nt], al_[mt], b2[nt]);
                }
        }
        __syncthreads();
    }

    const int row_base = bm + wm * 32 + (lane >> 2);
    const int col_base = bn + wn * 64 + (lane & 3) * 2;
#pragma unroll
    for (int mt = 0; mt < 2; mt++)
#pragma unroll
        for (int nt = 0; nt < 8; nt++) {
            int r0 = row_base + mt * 16, cc = col_base + nt * 8;
            float v0 = acc[mt][nt][0], v1 = acc[mt][nt][1];
            float v2 = acc[mt][nt][2], v3 = acc[mt][nt][3];
            v0 = 0.5f * v0 * (1.0f + erff(v0 * 0.7071067811865475f));
            v1 = 0.5f * v1 * (1.0f + erff(v1 * 0.7071067811865475f));
            v2 = 0.5f * v2 * (1.0f + erff(v2 * 0.7071067811865475f));
            v3 = 0.5f * v3 * (1.0f + erff(v3 * 0.7071067811865475f));
            *(float2*)(Cout + (size_t)r0 * N + cc)       = make_float2(v0, v1);
            *(float2*)(Cout + (size_t)(r0 + 8) * N + cc) = make_float2(v2, v3);
        }
}

// ============================================================================
// RoPE tables (fp32, matches reference float32 computation)
// ============================================================================
__global__ void rope_table_k()
{
    int t = blockIdx.x, d = threadIdx.x;
    int j = d & 63;
    float inv = exp2f(-(float)j * 0.20762050593046014f);
    float ang = (float)t * inv;
    g_cos[t * DD + d] = cosf(ang);
    g_sin[t * DD + d] = sinf(ang);
}

// ============================================================================
// Gate
// ============================================================================
__global__ void gate_k(const float* __restrict__ w2)
{
    __shared__ float red[128];
    int t = blockIdx.x, tid = threadIdx.x;
    float s = 0.f;
    for (int j = tid; j < CI; j += 128) s += g_hinfo[t * CI + j] * w2[j];
    red[tid] = s;
    __syncthreads();
    for (int off = 64; off > 0; off >>= 1) {
        if (tid < off) red[tid] += red[tid + off];
        __syncthreads();
    }
    if (tid == 0) {
        float sc = 1.0f / (1.0f + expf(-red[0]));
        g_gate[t] = (sc > 0.75f) ? 1.0f : 0.0f;
    }
}

// ============================================================================
// Low-rank projections (2-term fp16): q_r/k_r/v_r.
// A = q/k/v (hi+lo), B = pk/pv (hi only).
// smem = 3 x [64][136] fp16 = 52224 B.
// ============================================================================
__global__ __launch_bounds__(128) void lowrank_mma()
{
    extern __shared__ __align__(16) char smraw[];
    const uint32_t sb = smem_u32(smraw);
    const uint32_t oAl = 64 * 136 * 2, oPh = 2 * 64 * 136 * 2;
    const int tid = threadIdx.x, lane = tid & 31, w = tid >> 5;
    const int qt = blockIdx.x, h = blockIdx.y, t0 = qt << 6;
    const int aj = lane >> 3, ar = lane & 7;

    const uint32_t aoff = ((w * 16 + (aj & 1) * 8 + ar) * 136 + (aj >> 1) * 8) * 2;
    const uint32_t boff = (((aj >> 1) * 8 + ar) * 136 + (aj & 1) * 8) * 2;
    const int row0 = t0 + w * 16 + (lane >> 2);
    const int col = (lane & 3) * 2;

    for (int pass = 0; pass < 3; pass++) {
        const __half* Ph = (pass == 2) ? g_pvh : g_pkh;
        const int off = pass * CC + h * DD;
        __syncthreads();
        for (int i = tid; i < 1024; i += 128) {
            int r = i >> 4, q = i & 15;
            uint32_t so = (r * 136 + q * 8) * 2;
            size_t ga = (size_t)(t0 + r) * C3 + off + q * 8;
            CP16(sb + so,       g_qkvh + ga);
            CP16(sb + oAl + so, g_qkvl + ga);
            CP16(sb + oPh + so, Ph + r * DD + q * 8);
        }
        CP_COMMIT(); CP_WAIT(0);
        __syncthreads();

        float acc[8][4];
#pragma unroll
        for (int nt = 0; nt < 8; nt++)
#pragma unroll
            for (int e = 0; e < 4; e++) acc[nt][e] = 0.f;

#pragma unroll
        for (int kb = 0; kb < 8; kb++) {
            uint32_t ah[4], al_[4], b2[8][2];
            ldsm4(ah[0], ah[1], ah[2], ah[3], sb + aoff + kb * 32);
            ldsm4(al_[0], al_[1], al_[2], al_[3], sb + oAl + aoff + kb * 32);
#pragma unroll
            for (int np = 0; np < 4; np++) {
                uint32_t r0, r1, r2, r3;
                ldsm4(r0, r1, r2, r3, sb + oPh + boff + np * 16 * 136 * 2 + kb * 32);
                b2[np * 2][0] = r0;     b2[np * 2][1] = r1;
                b2[np * 2 + 1][0] = r2; b2[np * 2 + 1][1] = r3;
            }
#pragma unroll
            for (int nt = 0; nt < 8; nt++) {
                mma16816(acc[nt], ah, b2[nt]);
                mma16816(acc[nt], al_, b2[nt]);
            }
        }

        if (pass == 0) {
            // q_r: hi + lo (A operand of global QK)
#pragma unroll
            for (int nt = 0; nt < 8; nt++) {
                uint32_t hh, ll;
                size_t i0 = (size_t)(h * TT + row0) * RR + nt * 8 + col;
                split2(acc[nt][0], acc[nt][1], hh, ll);
                *(uint32_t*)(g_qrh + i0) = hh;
                *(uint32_t*)(g_qrl + i0) = ll;
                size_t i1 = i0 + 8 * RR;
                split2(acc[nt][2], acc[nt][3], hh, ll);
                *(uint32_t*)(g_qrh + i1) = hh;
                *(uint32_t*)(g_qrl + i1) = ll;
            }
        } else {
            __half* dh = (pass == 1) ? g_krh : g_vrh;
#pragma unroll
            for (int nt = 0; nt < 8; nt++) {
                size_t i0 = (size_t)(h * TT + row0) * RR + nt * 8 + col;
                __half2 a = __floats2half2_rn(acc[nt][0], acc[nt][1]);
                *(uint32_t*)(dh + i0) = *(uint32_t*)&a;
                size_t i1 = i0 + 8 * RR;
                __half2 b = __floats2half2_rn(acc[nt][2], acc[nt][3]);
                *(uint32_t*)(dh + i1) = *(uint32_t*)&b;
            }
        }
    }
}

// ============================================================================
// Local sliding-window attention: Sq=128, 8 warps, double-buffered KV (hi only).
// smem = (2*128 + 2*2*64) * 136 * 2 = 139264 B.
// ============================================================================
#define LPAD 136
__global__ __launch_bounds__(256) void local_attn_mma()
{
    extern __shared__ __align__(16) char smraw[];
    const uint32_t sb = smem_u32(smraw);
    const uint32_t oQl = 128 * LPAD * 2;
    const uint32_t kvBase = 2 * 128 * LPAD * 2;
    const uint32_t kvStage = 2 * 64 * LPAD * 2;
    const uint32_t seg = 64 * LPAD * 2;

    const int tid = threadIdx.x, lane = tid & 31, w = tid >> 5;
    const int qt = gridDim.x - 1 - blockIdx.x, h = blockIdx.y;
    const int t0 = qt << 7;
    const int aj = lane >> 3, ar = lane & 7;
    const int tg0 = t0 + w * 16 + (lane >> 2), tg1 = tg0 + 8;
    const int cq = (lane & 3) * 2;

    for (int i = tid; i < 2048; i += 256) {
        int r = i >> 4, q = i & 15;
        uint32_t so = sb + (r * LPAD + q * 8) * 2;
        size_t go = (size_t)(t0 + r) * C3 + h * DD + q * 8;
        CP16(so, g_qkvh + go);
        CP16(so + oQl, g_qkvl + go);
    }
    CP_COMMIT();

    const int kt0 = (t0 > WLOC - 1) ? ((t0 - (WLOC - 1)) >> 6) : 0;
    const int ktend = 2 * qt + 1;

    auto issueKV = [&](int kt, int s) {
        const int s0 = kt << 6;
        const uint32_t kb = sb + kvBase + s * kvStage;
        for (int i = tid; i < 1024; i += 256) {
            int r = i >> 4, q = i & 15;
            size_t gk = (size_t)(s0 + r) * C3 + CC + h * DD + q * 8;
            uint32_t off = (r * LPAD + q * 8) * 2;
            CP16(kb + off,       g_qkvh + gk);
            CP16(kb + seg + off, g_qkvh + gk + CC);
        }
        CP_COMMIT();
    };
    issueKV(kt0, 0);

    float m0 = -1e30f, m1 = -1e30f, l0 = 0.f, l1 = 0.f;
    float out[16][4];
#pragma unroll
    for (int nt = 0; nt < 16; nt++)
#pragma unroll
        for (int e = 0; e < 4; e++) out[nt][e] = 0.f;

    const uint32_t aQoff = ((w * 16 + (aj & 1) * 8 + ar) * LPAD + (aj >> 1) * 8) * 2;
    const uint32_t bKoff = (((aj >> 1) * 8 + ar) * LPAD + (aj & 1) * 8) * 2;
    const uint32_t bVoff = (((aj & 1) * 8 + ar) * LPAD + (aj >> 1) * 8) * 2;

    for (int kt = kt0; kt <= ktend; kt++) {
        const int s = (kt - kt0) & 1;
        if (kt < ktend) { issueKV(kt + 1, s ^ 1); CP_WAIT(1); }
        else            { CP_WAIT(0); }
        __syncthreads();
        const uint32_t kb = sb + kvBase + s * kvStage;
        const int s0 = kt << 6;

        float sc[8][4];
#pragma unroll
        for (int nt = 0; nt < 8; nt++)
#pragma unroll
            for (int e = 0; e < 4; e++) sc[nt][e] = 0.f;

#pragma unroll
        for (int kbk = 0; kbk < 8; kbk++) {
            uint32_t ah[4], al_[4], b2[8][2];
            ldsm4(ah[0], ah[1], ah[2], ah[3], sb + aQoff + kbk * 32);
            ldsm4(al_[0], al_[1], al_[2], al_[3], sb + oQl + aQoff + kbk * 32);
#pragma unroll
            for (int np = 0; np < 4; np++) {
                uint32_t r0, r1, r2, r3;
                ldsm4(r0, r1, r2, r3, kb + bKoff + np * 16 * LPAD * 2 + kbk * 32);
                b2[np * 2][0] = r0;     b2[np * 2][1] = r1;
                b2[np * 2 + 1][0] = r2; b2[np * 2 + 1][1] = r3;
            }
#pragma unroll
            for (int nt = 0; nt < 8; nt++) {
                mma16816(sc[nt], ah, b2[nt]);
                mma16816(sc[nt], al_, b2[nt]);
            }
        }

#pragma unroll
        for (int nt = 0; nt < 8; nt++) {
            int c0 = s0 + nt * 8 + cq;
#pragma unroll
            for (int e = 0; e < 2; e++) {
                int sg = c0 + e;
                float v0 = sc[nt][e] * SCALE_L;
                sc[nt][e] = (sg <= tg0 && sg >= tg0 - (WLOC - 1)) ? v0 : -1e30f;
                float v1 = sc[nt][2 + e] * SCALE_L;
                sc[nt][2 + e] = (sg <= tg1 && sg >= tg1 - (WLOC - 1)) ? v1 : -1e30f;
            }
        }

        float mx0 = -1e30f, mx1 = -1e30f;
#pragma unroll
        for (int nt = 0; nt < 8; nt++) {
            mx0 = fmaxf(mx0, fmaxf(sc[nt][0], sc[nt][1]));
            mx1 = fmaxf(mx1, fmaxf(sc[nt][2], sc[nt][3]));
        }
        mx0 = fmaxf(mx0, __shfl_xor_sync(0xffffffffu, mx0, 1));
        mx0 = fmaxf(mx0, __shfl_xor_sync(0xffffffffu, mx0, 2));
        mx1 = fmaxf(mx1, __shfl_xor_sync(0xffffffffu, mx1, 1));
        mx1 = fmaxf(mx1, __shfl_xor_sync(0xffffffffu, mx1, 2));
        float mn0 = fmaxf(m0, mx0), mn1 = fmaxf(m1, mx1);
        float al0 = __expf(m0 - mn0), al1 = __expf(m1 - mn1);
        m0 = mn0; m1 = mn1;

        float sum0 = 0.f, sum1 = 0.f;
#pragma unroll
        for (int nt = 0; nt < 8; nt++) {
#pragma unroll
            for (int e = 0; e < 2; e++) {
                float p0 = (sc[nt][e]     > -1e29f) ? __expf(sc[nt][e]     - mn0) : 0.f;
                float p1 = (sc[nt][2 + e] > -1e29f) ? __expf(sc[nt][2 + e] - mn1) : 0.f;
                sc[nt][e] = p0; sc[nt][2 + e] = p1;
                sum0 += p0; sum1 += p1;
            }
        }
        sum0 += __shfl_xor_sync(0xffffffffu, sum0, 1);
        sum0 += __shfl_xor_sync(0xffffffffu, sum0, 2);
        sum1 += __shfl_xor_sync(0xffffffffu, sum1, 1);
        sum1 += __shfl_xor_sync(0xffffffffu, sum1, 2);
        l0 = l0 * al0 + sum0;
        l1 = l1 * al1 + sum1;

#pragma unroll
        for (int nt = 0; nt < 16; nt++) {
            out[nt][0] *= al0; out[nt][1] *= al0;
            out[nt][2] *= al1; out[nt][3] *= al1;
        }

#pragma unroll
        for (int kbk = 0; kbk < 4; kbk++) {
            uint32_t ph[4], pl[4];
            split2(sc[2 * kbk][0],     sc[2 * kbk][1],     ph[0], pl[0]);
            split2(sc[2 * kbk][2],     sc[2 * kbk][3],     ph[1], pl[1]);
            split2(sc[2 * kbk + 1][0], sc[2 * kbk + 1][1], ph[2], pl[2]);
            split2(sc[2 * kbk + 1][2], sc[2 * kbk + 1][3], ph[3], pl[3]);
#pragma unroll
            for (int g = 0; g < 8; g++) {
                uint32_t r0, r1, r2, r3;
                ldsm4t(r0, r1, r2, r3,
                       kb + seg + bVoff + kbk * 16 * LPAD * 2 + g * 32);
                uint32_t b0[2] = {r0, r1}, b1[2] = {r2, r3};
                mma16816(out[2 * g], ph, b0);     mma16816(out[2 * g + 1], ph, b1);
                mma16816(out[2 * g], pl, b0);     mma16816(out[2 * g + 1], pl, b1);
            }
        }
        __syncthreads();
    }

    const float inv0 = 1.f / l0, inv1 = 1.f / l1;
#pragma unroll
    for (int nt = 0; nt < 16; nt++) {
        *(float2*)(g_ctx + (size_t)tg0 * CC + h * DD + nt * 8 + cq) =
            make_float2(out[nt][0] * inv0, out[nt][1] * inv0);
        *(float2*)(g_ctx + (size_t)tg1 * CC + h * DD + nt * 8 + cq) =
            make_float2(out[nt][2] * inv1, out[nt][3] * inv1);
    }
}

// ============================================================================
// Global low-rank attention: Sq=128, 8 warps, double-buffered KV_r (hi only),
// gated epilogue O @ uo^T (hi only); writes final ctx as fp16 hi/lo splits.
// smem = 2*128*72*2 + 2*2*64*72*2 = 73728 B -> 2 CTAs/SM.
// ============================================================================
#define GPAD 72
__global__ __launch_bounds__(256) void global_attn_mma()
{
    extern __shared__ __align__(16) char smraw[];
    const uint32_t sb = smem_u32(smraw);
    const uint32_t oQl = 128 * GPAD * 2;
    const uint32_t kvBase = 2 * 128 * GPAD * 2;
    const uint32_t kvStage = 2 * 64 * GPAD * 2;
    const uint32_t seg = 64 * GPAD * 2;
    const uint32_t oUh = kvBase;   // epilogue overlay (128*GPAD*2 fits in 2 stages)

    const int tid = threadIdx.x, lane = tid & 31, w = tid >> 5;
    const int qt = blockIdx.x, h = blockIdx.y, t0 = qt << 7;
    const int aj = lane >> 3, ar = lane & 7;
    const int tg0 = t0 + w * 16 + (lane >> 2), tg1 = tg0 + 8;
    const int cq = (lane & 3) * 2;

    for (int i = tid; i < 1024; i += 256) {
        int r = i >> 3, q = i & 7;
        uint32_t so = sb + (r * GPAD + q * 8) * 2;
        size_t go = (size_t)(h * TT + t0 + r) * RR + q * 8;
        CP16(so, g_qrh + go);
        CP16(so + oQl, g_qrl + go);
    }
    CP_COMMIT();

    auto issueKV = [&](int kt, int s) {
        const int s0 = kt << 6;
        const uint32_t kb = sb + kvBase + s * kvStage;
        for (int i = tid; i < 512; i += 256) {
            int r = i >> 3, q = i & 7;
            size_t gk = (size_t)(h * TT + s0 + r) * RR + q * 8;
            uint32_t off = (r * GPAD + q * 8) * 2;
            CP16(kb + off,       g_krh + gk);
            CP16(kb + seg + off, g_vrh + gk);
        }
        CP_COMMIT();
    };
    issueKV(0, 0);

    float m0 = -1e30f, m1 = -1e30f, l0 = 0.f, l1 = 0.f;
    float out[8][4];
#pragma unroll
    for (int nt = 0; nt < 8; nt++)
#pragma unroll
        for (int e = 0; e < 4; e++) out[nt][e] = 0.f;

    const uint32_t aQoff = ((w * 16 + (aj & 1) * 8 + ar) * GPAD + (aj >> 1) * 8) * 2;
    const uint32_t bKoff = (((aj >> 1) * 8 + ar) * GPAD + (aj & 1) * 8) * 2;
    const uint32_t bVoff = (((aj & 1) * 8 + ar) * GPAD + (aj >> 1) * 8) * 2;

    for (int kt = 0; kt < TT / 64; kt++) {
        const int s = kt & 1;
        if (kt < TT / 64 - 1) { issueKV(kt + 1, s ^ 1); CP_WAIT(1); }
        else                  { CP_WAIT(0); }
        __syncthreads();
        const uint32_t kb = sb + kvBase + s * kvStage;

        float sc[8][4];
#pragma unroll
        for (int nt = 0; nt < 8; nt++)
#pragma unroll
            for (int e = 0; e < 4; e++) sc[nt][e] = 0.f;

#pragma unroll
        for (int kbk = 0; kbk < 4; kbk++) {
            uint32_t ah[4], al_[4], b2[8][2];
            ldsm4(ah[0], ah[1], ah[2], ah[3], sb + aQoff + kbk * 32);
            ldsm4(al_[0], al_[1], al_[2], al_[3], sb + oQl + aQoff + kbk * 32);
#pragma unroll
            for (int np = 0; np < 4; np++) {
                uint32_t r0, r1, r2, r3;
                ldsm4(r0, r1, r2, r3, kb + bKoff + np * 16 * GPAD * 2 + kbk * 32);
                b2[np * 2][0] = r0;     b2[np * 2][1] = r1;
                b2[np * 2 + 1][0] = r2; b2[np * 2 + 1][1] = r3;
            }
#pragma unroll
            for (int nt = 0; nt < 8; nt++) {
                mma16816(sc[nt], ah, b2[nt]);
                mma16816(sc[nt], al_, b2[nt]);
            }
        }

        float mx0 = -1e30f, mx1 = -1e30f;
#pragma unroll
        for (int nt = 0; nt < 8; nt++) {
            sc[nt][0] *= SCALE_G; sc[nt][1] *= SCALE_G;
            sc[nt][2] *= SCALE_G; sc[nt][3] *= SCALE_G;
            mx0 = fmaxf(mx0, fmaxf(sc[nt][0], sc[nt][1]));
            mx1 = fmaxf(mx1, fmaxf(sc[nt][2], sc[nt][3]));
        }
        mx0 = fmaxf(mx0, __shfl_xor_sync(0xffffffffu, mx0, 1));
        mx0 = fmaxf(mx0, __shfl_xor_sync(0xffffffffu, mx0, 2));
        mx1 = fmaxf(mx1, __shfl_xor_sync(0xffffffffu, mx1, 1));
        mx1 = fmaxf(mx1, __shfl_xor_sync(0xffffffffu, mx1, 2));
        float mn0 = fmaxf(m0, mx0), mn1 = fmaxf(m1, mx1);
        float al0 = __expf(m0 - mn0), al1 = __expf(m1 - mn1);
        m0 = mn0; m1 = mn1;

        float sum0 = 0.f, sum1 = 0.f;
#pragma unroll
        for (int nt = 0; nt < 8; nt++) {
#pragma unroll
            for (int e = 0; e < 2; e++) {
                float p0 = __expf(sc[nt][e] - mn0);
                float p1 = __expf(sc[nt][2 + e] - mn1);
                sc[nt][e] = p0; sc[nt][2 + e] = p1;
                sum0 += p0; sum1 += p1;
            }
        }
        sum0 += __shfl_xor_sync(0xffffffffu, sum0, 1);
        sum0 += __shfl_xor_sync(0xffffffffu, sum0, 2);
        sum1 += __shfl_xor_sync(0xffffffffu, sum1, 1);
        sum1 += __shfl_xor_sync(0xffffffffu, sum1, 2);
        l0 = l0 * al0 + sum0;
        l1 = l1 * al1 + sum1;

#pragma unroll
        for (int nt = 0; nt < 8; nt++) {
            out[nt][0] *= al0; out[nt][1] *= al0;
            out[nt][2] *= al1; out[nt][3] *= al1;
        }

#pragma unroll
        for (int kbk = 0; kbk < 4; kbk++) {
            uint32_t ph[4], pl[4];
            split2(sc[2 * kbk][0],     sc[2 * kbk][1],     ph[0], pl[0]);
            split2(sc[2 * kbk][2],     sc[2 * kbk][3],     ph[1], pl[1]);
            split2(sc[2 * kbk + 1][0], sc[2 * kbk + 1][1], ph[2], pl[2]);
            split2(sc[2 * kbk + 1][2], sc[2 * kbk + 1][3], ph[3], pl[3]);
#pragma unroll
            for (int g = 0; g < 4; g++) {
                uint32_t r0, r1, r2, r3;
                ldsm4t(r0, r1, r2, r3,
                       kb + seg + bVoff + kbk * 16 * GPAD * 2 + g * 32);
                uint32_t b0[2] = {r0, r1}, b1[2] = {r2, r3};
                mma16816(out[2 * g], ph, b0);     mma16816(out[2 * g + 1], ph, b1);
                mma16816(out[2 * g], pl, b0);     mma16816(out[2 * g + 1], pl, b1);
            }
        }
        __syncthreads();
    }

    const float inv0 = 1.f / l0, inv1 = 1.f / l1;
#pragma unroll
    for (int nt = 0; nt < 8; nt++) {
        out[nt][0] *= inv0; out[nt][1] *= inv0;
        out[nt][2] *= inv1; out[nt][3] *= inv1;
    }

    // load uo^T (hi only) into overlay (cp.async drained, warps synced)
    for (int i = tid; i < 1024; i += 256) {
        int d = i >> 3, q = i & 7;
        *(int4*)(smraw + oUh + (d * GPAD + q * 8) * 2) =
            *(const int4*)(g_uoh + d * 64 + q * 8);
    }
    __syncthreads();

    float out2[16][4];
#pragma unroll
    for (int nt = 0; nt < 16; nt++)
#pragma unroll
        for (int e = 0; e < 4; e++) out2[nt][e] = 0.f;

    const uint32_t bUoff = (((aj >> 1) * 8 + ar) * GPAD + (aj & 1) * 8) * 2;
#pragma unroll
    for (int kbk = 0; kbk < 4; kbk++) {
        uint32_t ph[4], pl[4];
        split2(out[2 * kbk][0],     out[2 * kbk][1],     ph[0], pl[0]);
        split2(out[2 * kbk][2],     out[2 * kbk][3],     ph[1], pl[1]);
        split2(out[2 * kbk + 1][0], out[2 * kbk + 1][1], ph[2], pl[2]);
        split2(out[2 * kbk + 1][2], out[2 * kbk + 1][3], ph[3], pl[3]);
#pragma unroll
        for (int g = 0; g < 8; g++) {
            uint32_t r0, r1, r2, r3;
            ldsm4(r0, r1, r2, r3, sb + oUh + bUoff + g * 16 * GPAD * 2 + kbk * 32);
            uint32_t b0[2] = {r0, r1}, b1[2] = {r2, r3};
            mma16816(out2[2 * g], ph, b0);     mma16816(out2[2 * g + 1], ph, b1);
            mma16816(out2[2 * g], pl, b0);     mma16816(out2[2 * g + 1], pl, b1);
        }
    }

    const float ga0 = g_gate[tg0], ga1 = g_gate[tg1];
#pragma unroll
    for (int nt = 0; nt < 16; nt++) {
        size_t i0 = (size_t)tg0 * CC + h * DD + nt * 8 + cq;
        float2 o0 = *(float2*)(g_ctx + i0);
        uint32_t hh, ll;
        split2(o0.x + ga0 * out2[nt][0], o0.y + ga0 * out2[nt][1], hh, ll);
        *(uint32_t*)(g_cxh + i0) = hh;
        *(uint32_t*)(g_cxl + i0) = ll;
        size_t i1 = (size_t)tg1 * CC + h * DD + nt * 8 + cq;
        float2 o1 = *(float2*)(g_ctx + i1);
        split2(o1.x + ga1 * out2[nt][2], o1.y + ga1 * out2[nt][3], hh, ll);
        *(uint32_t*)(g_cxh + i1) = hh;
        *(uint32_t*)(g_cxl + i1) = ll;
    }
}

// ============================================================================
extern "C" void kernel_launch(void* const* d_in, const int* in_sizes, int n_in,
                              void* d_out, int out_size)
{
    const float* x     = (const float*)d_in[0];
    const float* w_qkv = (const float*)d_in[1];
    const float* w_o   = (const float*)d_in[2];
    const float* pk    = (const float*)d_in[3];
    const float* pv    = (const float*)d_in[4];
    const float* uo    = (const float*)d_in[5];
    const float* iw1   = (const float*)d_in[6];
    const float* iw2   = (const float*)d_in[7];
    float* out = (float*)d_out;

    cudaFuncSetAttribute(gemm_mma256,     cudaFuncAttributeMaxDynamicSharedMemorySize, 81920);
    cudaFuncSetAttribute(gemm_mma128,     cudaFuncAttributeMaxDynamicSharedMemorySize, 61440);
    cudaFuncSetAttribute(local_attn_mma,  cudaFuncAttributeMaxDynamicSharedMemorySize, 139264);
    cudaFuncSetAttribute(global_attn_mma, cudaFuncAttributeMaxDynamicSharedMemorySize, 73728);
    cudaFuncSetAttribute(lowrank_mma,     cudaFuncAttributeMaxDynamicSharedMemorySize, 52224);

    void *p_hinfo;
    void *pxh, *pxl, *pwqh, *pwoh, *pi1h, *pcxh, *pcxl;
    void *pqkvh, *pqkvl, *puoh, *ppkh, *ppvh;
    cudaGetSymbolAddress(&p_hinfo, g_hinfo);
    cudaGetSymbolAddress(&pxh, g_xh);   cudaGetSymbolAddress(&pxl, g_xl);
    cudaGetSymbolAddress(&pwqh, g_wqh);
    cudaGetSymbolAddress(&pwoh, g_woh);
    cudaGetSymbolAddress(&pi1h, g_i1h);
    cudaGetSymbolAddress(&pcxh, g_cxh); cudaGetSymbolAddress(&pcxl, g_cxl);
    cudaGetSymbolAddress(&pqkvh, g_qkvh); cudaGetSymbolAddress(&pqkvl, g_qkvl);
    cudaGetSymbolAddress(&puoh, g_uoh);
    cudaGetSymbolAddress(&ppkh, g_pkh);
    cudaGetSymbolAddress(&ppvh, g_pvh);

#define SPLIT(src, h, l, n) \
    split_h2_k<<<((n)/2 + 255) / 256, 256>>>((const float2*)(src), \
        (__half2*)(h), (__half2*)(l), (n)/2)
#define CONV(src, h, n) \
    conv_h_k<<<((n)/2 + 255) / 256, 256>>>((const float2*)(src), \
        (__half2*)(h), (n)/2)

    rope_table_k<<<TT, DD>>>();
    SPLIT(x, pxh, pxl, TT * CC);
    CONV(w_qkv, pwqh, C3 * CC);
    CONV(iw1, pi1h, CI * CC);
    CONV(w_o, pwoh, CC * CC);
    CONV(uo, puoh, DD * RR);
    CONV(pk, ppkh, RR * DD);
    CONV(pv, ppvh, RR * DD);

    // qkv = rope(x @ w_qkv^T) -> fp16 splits (fused epilogue), BN=256
    gemm_mma256<<<dim3(C3 / 256, TT / 128), 256, 81920>>>(
        (const __half*)pxh, (const __half*)pxl, (const __half*)pwqh,
        nullptr, (__half*)pqkvh, (__half*)pqkvl, C3, CC, 2);

    // h_info = gelu(x @ iw1^T); gate
    gemm_mma128<<<dim3(CI / 128, TT / 128), 256, 61440>>>(
        (const __half*)pxh, (const __half*)pxl, (const __half*)pi1h,
        (float*)p_hinfo, CI, CC);
    gate_k<<<TT, 128>>>(iw2);

    lowrank_mma<<<dim3(TT / 64, HH), 128, 52224>>>();
    local_attn_mma<<<dim3(TT / 128, HH), 256, 139264>>>();
    global_attn_mma<<<dim3(TT / 128, HH), 256, 73728>>>();

    // out = ctx @ w_o^T, BN=256
    gemm_mma256<<<dim3(CC / 256, TT / 128), 256, 81920>>>(
        (const __half*)pcxh, (const __half*)pcxl, (const __half*)pwoh,
        out, nullptr, nullptr, CC, CC, 0);
#undef SPLIT
#undef CONV
}

// round 9
// speedup vs baseline: 4.5102x; 1.0232x over previous
#include <cuda_runtime.h>
#include <cuda_fp16.h>
#include <math.h>
#include <stdint.h>

#define TT   2048
#define CC   2048
#define HH   16
#define DD   128
#define RR   64
#define WLOC 512
#define CI   512
#define C3   6144

#define SCALE_L 0.08838834764831845f
#define SCALE_G 0.1767766952966369f

// ---------------- scratch (device globals) ----------------
__device__ float g_gatez[4 * TT];     // per-bn-CTA partial gate logits
__device__ float g_gate[TT];
__device__ float g_cos[TT * DD];
__device__ float g_sin[TT * DD];
__device__ float g_ctx[TT * CC];

// fp16 operands: A-side hi+lo (2-term split), B-side hi only.
__device__ __half g_xh[TT * CC],  g_xl[TT * CC];
__device__ __half g_wqh[C3 * CC];
__device__ __half g_woh[CC * CC];
__device__ __half g_i1h[CI * CC];
__device__ __half g_cxh[TT * CC], g_cxl[TT * CC];
__device__ __half g_qkvh[TT * C3], g_qkvl[TT * C3];
__device__ __half g_qrh[HH * TT * RR], g_qrl[HH * TT * RR];
__device__ __half g_krh[HH * TT * RR];
__device__ __half g_vrh[HH * TT * RR];
__device__ __half g_uoh[DD * RR];
__device__ __half g_pkh[RR * DD];
__device__ __half g_pvh[RR * DD];

// ============================================================================
// PTX helpers (plain sm_80+ ISA)
// ============================================================================
__device__ __forceinline__ uint32_t smem_u32(const void* p) {
    uint32_t a;
    asm("{ .reg .u64 t; cvta.to.shared.u64 t, %1; cvt.u32.u64 %0, t; }"
        : "=r"(a) : "l"(p));
    return a;
}

#define CP16(s, g) \
    asm volatile("cp.async.cg.shared.global [%0], [%1], 16;" \
                 :: "r"(s), "l"(g) : "memory")
#define CP_COMMIT() asm volatile("cp.async.commit_group;" ::: "memory")
#define CP_WAIT(n)  asm volatile("cp.async.wait_group %0;" :: "n"(n) : "memory")

__device__ __forceinline__ void ldsm4(uint32_t& r0, uint32_t& r1,
                                      uint32_t& r2, uint32_t& r3, uint32_t a) {
    asm volatile("ldmatrix.sync.aligned.m8n8.x4.shared.b16 {%0,%1,%2,%3}, [%4];"
                 : "=r"(r0), "=r"(r1), "=r"(r2), "=r"(r3) : "r"(a));
}
__device__ __forceinline__ void ldsm4t(uint32_t& r0, uint32_t& r1,
                                       uint32_t& r2, uint32_t& r3, uint32_t a) {
    asm volatile("ldmatrix.sync.aligned.m8n8.x4.trans.shared.b16 {%0,%1,%2,%3}, [%4];"
                 : "=r"(r0), "=r"(r1), "=r"(r2), "=r"(r3) : "r"(a));
}

__device__ __forceinline__ void mma16816(float* c, const uint32_t* a,
                                         const uint32_t* b) {
    asm volatile("mma.sync.aligned.m16n8k16.row.col.f32.f16.f16.f32 "
                 "{%0,%1,%2,%3}, {%4,%5,%6,%7}, {%8,%9}, {%0,%1,%2,%3};"
                 : "+f"(c[0]), "+f"(c[1]), "+f"(c[2]), "+f"(c[3])
                 : "r"(a[0]), "r"(a[1]), "r"(a[2]), "r"(a[3]),
                   "r"(b[0]), "r"(b[1]));
}

__device__ __forceinline__ void split2(float x, float y, uint32_t& h, uint32_t& l) {
    __half2 hh = __floats2half2_rn(x, y);
    h = *reinterpret_cast<uint32_t*>(&hh);
    __half2 ll = __floats2half2_rn(x - __low2float(hh), y - __high2float(hh));
    l = *reinterpret_cast<uint32_t*>(&ll);
}

// ============================================================================
// fp32 -> fp16 hi/lo split (x only)
// ============================================================================
__global__ void split_h2_k(const float2* __restrict__ src,
                           __half2* __restrict__ hi,
                           __half2* __restrict__ lo, int n2)
{
    int i = blockIdx.x * 256 + threadIdx.x;
    if (i < n2) {
        float2 v = src[i];
        __half2 h = __floats2half2_rn(v.x, v.y);
        hi[i] = h;
        lo[i] = __floats2half2_rn(v.x - __low2float(h), v.y - __high2float(h));
    }
}

// ============================================================================
// Fused fp32 -> fp16 convert of ALL weight regions (one launch)
// ============================================================================
#define CS1 (C3 * CC / 2)
#define CS2 (CS1 + CI * CC / 2)
#define CS3 (CS2 + CC * CC / 2)
#define CS4 (CS3 + DD * RR / 2)
#define CS5 (CS4 + RR * DD / 2)
#define CS6 (CS5 + RR * DD / 2)
__global__ void conv_all_k(const float2* __restrict__ wq,
                           const float2* __restrict__ i1,
                           const float2* __restrict__ wo,
                           const float2* __restrict__ uo,
                           const float2* __restrict__ pk,
                           const float2* __restrict__ pv)
{
    int i = blockIdx.x * 256 + threadIdx.x;
    const float2* s; __half2* d; int j;
    if      (i < CS1) { s = wq; d = (__half2*)g_wqh; j = i; }
    else if (i < CS2) { s = i1; d = (__half2*)g_i1h; j = i - CS1; }
    else if (i < CS3) { s = wo; d = (__half2*)g_woh; j = i - CS2; }
    else if (i < CS4) { s = uo; d = (__half2*)g_uoh; j = i - CS3; }
    else if (i < CS5) { s = pk; d = (__half2*)g_pkh; j = i - CS4; }
    else if (i < CS6) { s = pv; d = (__half2*)g_pvh; j = i - CS5; }
    else return;
    float2 v = s[j];
    d[j] = __floats2half2_rn(v.x, v.y);
}

// ============================================================================
// mma.sync GEMM (BN=256, 2-term fp16): C = Ah·Bh^T + Al·Bh^T
// mode 0: fp32 store. mode 2: rope + fp16 hi/lo store.
// ============================================================================
__global__ __launch_bounds__(256) void gemm_mma256(
    const __half* __restrict__ Ah, const __half* __restrict__ Al,
    const __half* __restrict__ Bh,
    float* __restrict__ Cout,
    __half* __restrict__ Ch, __half* __restrict__ Cl,
    int N, int K, int mode)
{
    extern __shared__ __align__(128) char smraw[];
    const uint32_t sb = smem_u32(smraw);
    const int tid = threadIdx.x, lane = tid & 31, wid = tid >> 5;
    const int wm = wid & 3, wn = wid >> 2;
    const int bm = blockIdx.y << 7, bn = blockIdx.x << 8;
    const int aj = lane >> 3, ar = lane & 7;

    float acc[2][16][4];
#pragma unroll
    for (int mt = 0; mt < 2; mt++)
#pragma unroll
        for (int nt = 0; nt < 16; nt++)
#pragma unroll
            for (int e = 0; e < 4; e++) acc[mt][nt][e] = 0.f;

    const int nch = K >> 5;

    auto issue_stage = [&](int c) {
        const uint32_t st = sb + (c & 1) * 40960;
        const int k0 = c << 5;
        {
            const __half* gh = Ah + (size_t)bm * K + k0;
            const __half* gl = Al + (size_t)bm * K + k0;
#pragma unroll
            for (int hh = 0; hh < 2; hh++) {
                int i = tid + hh * 256;
                int r = i >> 2, q = i & 3;
                uint32_t so = st + r * 80 + q * 16;
                size_t go = (size_t)r * K + q * 8;
                CP16(so,          gh + go);
                CP16(so + 10240,  gl + go);
            }
        }
        {
            const __half* gh = Bh + (size_t)bn * K + k0;
#pragma unroll
            for (int hh = 0; hh < 4; hh++) {
                int i = tid + hh * 256;
                int r = i >> 2, q = i & 3;
                CP16(st + 20480 + r * 80 + q * 16, gh + (size_t)r * K + q * 8);
            }
        }
        CP_COMMIT();
    };

    issue_stage(0);
    for (int c = 0; c < nch; c++) {
        if (c + 1 < nch) { issue_stage(c + 1); CP_WAIT(1); }
        else             { CP_WAIT(0); }
        __syncthreads();

        const uint32_t st = sb + (c & 1) * 40960;
#pragma unroll
        for (int ks = 0; ks < 2; ks++) {
            uint32_t ah[2][4], al_[2][4], b2[16][2];
            const uint32_t a_off =
                ((wm * 32 + (aj & 1) * 8 + ar) * 40 + ks * 16 + (aj >> 1) * 8) * 2;
            const uint32_t b_off =
                ((wn * 128 + (aj >> 1) * 8 + ar) * 40 + ks * 16 + (aj & 1) * 8) * 2;

#pragma unroll
            for (int mt = 0; mt < 2; mt++) {
                ldsm4(ah[mt][0], ah[mt][1], ah[mt][2], ah[mt][3],
                      st + a_off + mt * (16 * 80));
                ldsm4(al_[mt][0], al_[mt][1], al_[mt][2], al_[mt][3],
                      st + 10240 + a_off + mt * (16 * 80));
            }
#pragma unroll
            for (int np = 0; np < 8; np++) {
                uint32_t r0, r1, r2, r3;
                ldsm4(r0, r1, r2, r3, st + 20480 + b_off + np * (16 * 80));
                b2[np * 2][0] = r0;     b2[np * 2][1] = r1;
                b2[np * 2 + 1][0] = r2; b2[np * 2 + 1][1] = r3;
            }
#pragma unroll
            for (int mt = 0; mt < 2; mt++)
#pragma unroll
                for (int nt = 0; nt < 16; nt++) {
                    mma16816(acc[mt][nt], ah[mt], b2[nt]);
                    mma16816(acc[mt][nt], al_[mt], b2[nt]);
                }
        }
        __syncthreads();
    }

    const int row_base = bm + wm * 32 + (lane >> 2);
    const int col_base = bn + wn * 128 + (lane & 3) * 2;
#pragma unroll
    for (int mt = 0; mt < 2; mt++)
#pragma unroll
        for (int nt = 0; nt < 16; nt++) {
            int r0 = row_base + mt * 16, cc = col_base + nt * 8;
            float v0 = acc[mt][nt][0], v1 = acc[mt][nt][1];
            float v2 = acc[mt][nt][2], v3 = acc[mt][nt][3];
            if (mode == 2) {
                if (cc < 2 * CC) {
                    int d0 = cc & 127;
                    float2 cA = *(const float2*)(g_cos + r0 * DD + d0);
                    float2 sA = *(const float2*)(g_sin + r0 * DD + d0);
                    float o0 = v0 * cA.x - v1 * sA.x;
                    float o1 = v1 * cA.y + v0 * sA.y;
                    float2 cB = *(const float2*)(g_cos + (r0 + 8) * DD + d0);
                    float2 sB = *(const float2*)(g_sin + (r0 + 8) * DD + d0);
                    float o2 = v2 * cB.x - v3 * sB.x;
                    float o3 = v3 * cB.y + v2 * sB.y;
                    v0 = o0; v1 = o1; v2 = o2; v3 = o3;
                }
                uint32_t h01, l01, h23, l23;
                split2(v0, v1, h01, l01);
                split2(v2, v3, h23, l23);
                *(uint32_t*)(Ch + (size_t)r0 * N + cc)       = h01;
                *(uint32_t*)(Cl + (size_t)r0 * N + cc)       = l01;
                *(uint32_t*)(Ch + (size_t)(r0 + 8) * N + cc) = h23;
                *(uint32_t*)(Cl + (size_t)(r0 + 8) * N + cc) = l23;
            } else {
                *(float2*)(Cout + (size_t)r0 * N + cc)       = make_float2(v0, v1);
                *(float2*)(Cout + (size_t)(r0 + 8) * N + cc) = make_float2(v2, v3);
            }
        }
}

// ============================================================================
// Info GEMM (BN=128, 2-term fp16) with fused gelu + dot(w2) gate partials.
// Writes deterministic per-CTA partial logits to g_gatez[bn][row]; no h_info.
// ============================================================================
__global__ __launch_bounds__(256) void gemm_info(
    const __half* __restrict__ Ah, const __half* __restrict__ Al,
    const __half* __restrict__ Bh,
    const float* __restrict__ w2, int N, int K)
{
    extern __shared__ __align__(128) char smraw[];
    const uint32_t sb = smem_u32(smraw);
    const int tid = threadIdx.x, lane = tid & 31, wid = tid >> 5;
    const int wm = wid & 3, wn = wid >> 2;
    const int bm = blockIdx.y << 7, bn = blockIdx.x << 7;
    const int aj = lane >> 3, ar = lane & 7;

    float acc[2][8][4];
#pragma unroll
    for (int mt = 0; mt < 2; mt++)
#pragma unroll
        for (int nt = 0; nt < 8; nt++)
#pragma unroll
            for (int e = 0; e < 4; e++) acc[mt][nt][e] = 0.f;

    const int nch = K >> 5;

    auto issue_stage = [&](int c) {
        const uint32_t st = sb + (c & 1) * 30720;
        const int k0 = c << 5;
        const __half* gm0 = Ah + (size_t)bm * K + k0;
        const __half* gm1 = Al + (size_t)bm * K + k0;
        const __half* gm2 = Bh + (size_t)bn * K + k0;
#pragma unroll
        for (int h = 0; h < 2; h++) {
            int i = tid + h * 256;
            int r = i >> 2, q = i & 3;
            uint32_t so = st + r * 80 + q * 16;
            size_t go = (size_t)r * K + q * 8;
            CP16(so,          gm0 + go);
            CP16(so + 10240,  gm1 + go);
            CP16(so + 20480,  gm2 + go);
        }
        CP_COMMIT();
    };

    issue_stage(0);
    for (int c = 0; c < nch; c++) {
        if (c + 1 < nch) { issue_stage(c + 1); CP_WAIT(1); }
        else             { CP_WAIT(0); }
        __syncthreads();

        const uint32_t st = sb + (c & 1) * 30720;
#pragma unroll
        for (int ks = 0; ks < 2; ks++) {
            uint32_t ah[2][4], al_[2][4], b2[8][2];
            const uint32_t a_off =
                ((wm * 32 + (aj & 1) * 8 + ar) * 40 + ks * 16 + (aj >> 1) * 8) * 2;
            const uint32_t b_off =
                ((wn * 64 + (aj >> 1) * 8 + ar) * 40 + ks * 16 + (aj & 1) * 8) * 2;

#pragma unroll
            for (int mt = 0; mt < 2; mt++) {
                ldsm4(ah[mt][0], ah[mt][1], ah[mt][2], ah[mt][3],
                      st + a_off + mt * (16 * 80));
                ldsm4(al_[mt][0], al_[mt][1], al_[mt][2], al_[mt][3],
                      st + 10240 + a_off + mt * (16 * 80));
            }
#pragma unroll
            for (int np = 0; np < 4; np++) {
                uint32_t r0, r1, r2, r3;
                ldsm4(r0, r1, r2, r3, st + 20480 + b_off + np * (16 * 80));
                b2[np * 2][0] = r0;     b2[np * 2][1] = r1;
                b2[np * 2 + 1][0] = r2; b2[np * 2 + 1][1] = r3;
            }
#pragma unroll
            for (int mt = 0; mt < 2; mt++)
#pragma unroll
                for (int nt = 0; nt < 8; nt++) {
                    mma16816(acc[mt][nt], ah[mt], b2[nt]);
                    mma16816(acc[mt][nt], al_[mt], b2[nt]);
                }
        }
        __syncthreads();
    }

    // Epilogue: gelu + dot with w2, deterministic partial reduction.
    const int col_base = wn * 64 + (lane & 3) * 2;   // 0..511 within N
    float z[2][2] = {{0.f, 0.f}, {0.f, 0.f}};
#pragma unroll
    for (int mt = 0; mt < 2; mt++)
#pragma unroll
        for (int nt = 0; nt < 8; nt++) {
            int cc = col_base + nt * 8;
            float w0 = w2[cc], w1 = w2[cc + 1];
            float v0 = acc[mt][nt][0], v1 = acc[mt][nt][1];
            float v2 = acc[mt][nt][2], v3 = acc[mt][nt][3];
            v0 = 0.5f * v0 * (1.0f + erff(v0 * 0.7071067811865475f));
            v1 = 0.5f * v1 * (1.0f + erff(v1 * 0.7071067811865475f));
            v2 = 0.5f * v2 * (1.0f + erff(v2 * 0.7071067811865475f));
            v3 = 0.5f * v3 * (1.0f + erff(v3 * 0.7071067811865475f));
            z[mt][0] += v0 * w0 + v1 * w1;
            z[mt][1] += v2 * w0 + v3 * w1;
        }
    // quad reduce (lanes sharing the same rows)
#pragma unroll
    for (int mt = 0; mt < 2; mt++)
#pragma unroll
        for (int e = 0; e < 2; e++) {
            z[mt][e] += __shfl_xor_sync(0xffffffffu, z[mt][e], 1);
            z[mt][e] += __shfl_xor_sync(0xffffffffu, z[mt][e], 2);
        }
    float* zs = (float*)smraw;   // [2][128]
    if ((lane & 3) == 0) {
        int lr = wm * 32 + (lane >> 2);
        zs[wn * 128 + lr +  0] = z[0][0];
        zs[wn * 128 + lr +  8] = z[0][1];
        zs[wn * 128 + lr + 16] = z[1][0];
        zs[wn * 128 + lr + 24] = z[1][1];
    }
    __syncthreads();
    if (tid < 128)
        g_gatez[blockIdx.x * TT + bm + tid] = zs[tid] + zs[128 + tid];
}

// gate finalize: sum 4 partials, sigmoid, threshold
__global__ void gate_fin_k()
{
    int t = blockIdx.x * 256 + threadIdx.x;
    float zsum = g_gatez[t] + g_gatez[TT + t] + g_gatez[2 * TT + t]
               + g_gatez[3 * TT + t];
    float sc = 1.0f / (1.0f + expf(-zsum));
    g_gate[t] = (sc > 0.75f) ? 1.0f : 0.0f;
}

// ============================================================================
// RoPE tables (fp32)
// ============================================================================
__global__ void rope_table_k()
{
    int t = blockIdx.x, d = threadIdx.x;
    int j = d & 63;
    float inv = exp2f(-(float)j * 0.20762050593046014f);
    float ang = (float)t * inv;
    g_cos[t * DD + d] = cosf(ang);
    g_sin[t * DD + d] = sinf(ang);
}

// ============================================================================
// Low-rank projections (2-term fp16)
// ============================================================================
__global__ __launch_bounds__(128) void lowrank_mma()
{
    extern __shared__ __align__(16) char smraw[];
    const uint32_t sb = smem_u32(smraw);
    const uint32_t oAl = 64 * 136 * 2, oPh = 2 * 64 * 136 * 2;
    const int tid = threadIdx.x, lane = tid & 31, w = tid >> 5;
    const int qt = blockIdx.x, h = blockIdx.y, t0 = qt << 6;
    const int aj = lane >> 3, ar = lane & 7;

    const uint32_t aoff = ((w * 16 + (aj & 1) * 8 + ar) * 136 + (aj >> 1) * 8) * 2;
    const uint32_t boff = (((aj >> 1) * 8 + ar) * 136 + (aj & 1) * 8) * 2;
    const int row0 = t0 + w * 16 + (lane >> 2);
    const int col = (lane & 3) * 2;

    for (int pass = 0; pass < 3; pass++) {
        const __half* Ph = (pass == 2) ? g_pvh : g_pkh;
        const int off = pass * CC + h * DD;
        __syncthreads();
        for (int i = tid; i < 1024; i += 128) {
            int r = i >> 4, q = i & 15;
            uint32_t so = (r * 136 + q * 8) * 2;
            size_t ga = (size_t)(t0 + r) * C3 + off + q * 8;
            CP16(sb + so,       g_qkvh + ga);
            CP16(sb + oAl + so, g_qkvl + ga);
            CP16(sb + oPh + so, Ph + r * DD + q * 8);
        }
        CP_COMMIT(); CP_WAIT(0);
        __syncthreads();

        float acc[8][4];
#pragma unroll
        for (int nt = 0; nt < 8; nt++)
#pragma unroll
            for (int e = 0; e < 4; e++) acc[nt][e] = 0.f;

#pragma unroll
        for (int kb = 0; kb < 8; kb++) {
            uint32_t ah[4], al_[4], b2[8][2];
            ldsm4(ah[0], ah[1], ah[2], ah[3], sb + aoff + kb * 32);
            ldsm4(al_[0], al_[1], al_[2], al_[3], sb + oAl + aoff + kb * 32);
#pragma unroll
            for (int np = 0; np < 4; np++) {
                uint32_t r0, r1, r2, r3;
                ldsm4(r0, r1, r2, r3, sb + oPh + boff + np * 16 * 136 * 2 + kb * 32);
                b2[np * 2][0] = r0;     b2[np * 2][1] = r1;
                b2[np * 2 + 1][0] = r2; b2[np * 2 + 1][1] = r3;
            }
#pragma unroll
            for (int nt = 0; nt < 8; nt++) {
                mma16816(acc[nt], ah, b2[nt]);
                mma16816(acc[nt], al_, b2[nt]);
            }
        }

        if (pass == 0) {
#pragma unroll
            for (int nt = 0; nt < 8; nt++) {
                uint32_t hh, ll;
                size_t i0 = (size_t)(h * TT + row0) * RR + nt * 8 + col;
                split2(acc[nt][0], acc[nt][1], hh, ll);
                *(uint32_t*)(g_qrh + i0) = hh;
                *(uint32_t*)(g_qrl + i0) = ll;
                size_t i1 = i0 + 8 * RR;
                split2(acc[nt][2], acc[nt][3], hh, ll);
                *(uint32_t*)(g_qrh + i1) = hh;
                *(uint32_t*)(g_qrl + i1) = ll;
            }
        } else {
            __half* dh = (pass == 1) ? g_krh : g_vrh;
#pragma unroll
            for (int nt = 0; nt < 8; nt++) {
                size_t i0 = (size_t)(h * TT + row0) * RR + nt * 8 + col;
                __half2 a = __floats2half2_rn(acc[nt][0], acc[nt][1]);
                *(uint32_t*)(dh + i0) = *(uint32_t*)&a;
                size_t i1 = i0 + 8 * RR;
                __half2 b = __floats2half2_rn(acc[nt][2], acc[nt][3]);
                *(uint32_t*)(dh + i1) = *(uint32_t*)&b;
            }
        }
    }
}

// ============================================================================
// Local sliding-window attention: Sq=64, 4 warps, double-buffered KV (hi only).
// smem = (2*64 + 2*2*64) * 136 * 2 = 104448 B -> 2 CTAs/SM.
// ============================================================================
#define LPAD 136
__global__ __launch_bounds__(128) void local_attn_mma()
{
    extern __shared__ __align__(16) char smraw[];
    const uint32_t sb = smem_u32(smraw);
    const uint32_t oQl = 64 * LPAD * 2;
    const uint32_t kvBase = 2 * 64 * LPAD * 2;
    const uint32_t kvStage = 2 * 64 * LPAD * 2;
    const uint32_t seg = 64 * LPAD * 2;

    const int tid = threadIdx.x, lane = tid & 31, w = tid >> 5;
    const int qt = gridDim.x - 1 - blockIdx.x, h = blockIdx.y;
    const int t0 = qt << 6;
    const int aj = lane >> 3, ar = lane & 7;
    const int tg0 = t0 + w * 16 + (lane >> 2), tg1 = tg0 + 8;
    const int cq = (lane & 3) * 2;

    for (int i = tid; i < 1024; i += 128) {
        int r = i >> 4, q = i & 15;
        uint32_t so = sb + (r * LPAD + q * 8) * 2;
        size_t go = (size_t)(t0 + r) * C3 + h * DD + q * 8;
        CP16(so, g_qkvh + go);
        CP16(so + oQl, g_qkvl + go);
    }
    CP_COMMIT();

    const int kt0 = (t0 > WLOC - 1) ? ((t0 - (WLOC - 1)) >> 6) : 0;
    const int ktend = qt;

    auto issueKV = [&](int kt, int s) {
        const int s0 = kt << 6;
        const uint32_t kb = sb + kvBase + s * kvStage;
        for (int i = tid; i < 1024; i += 128) {
            int r = i >> 4, q = i & 15;
            size_t gk = (size_t)(s0 + r) * C3 + CC + h * DD + q * 8;
            uint32_t off = (r * LPAD + q * 8) * 2;
            CP16(kb + off,       g_qkvh + gk);
            CP16(kb + seg + off, g_qkvh + gk + CC);
        }
        CP_COMMIT();
    };
    issueKV(kt0, 0);

    float m0 = -1e30f, m1 = -1e30f, l0 = 0.f, l1 = 0.f;
    float out[16][4];
#pragma unroll
    for (int nt = 0; nt < 16; nt++)
#pragma unroll
        for (int e = 0; e < 4; e++) out[nt][e] = 0.f;

    const uint32_t aQoff = ((w * 16 + (aj & 1) * 8 + ar) * LPAD + (aj >> 1) * 8) * 2;
    const uint32_t bKoff = (((aj >> 1) * 8 + ar) * LPAD + (aj & 1) * 8) * 2;
    const uint32_t bVoff = (((aj & 1) * 8 + ar) * LPAD + (aj >> 1) * 8) * 2;

    for (int kt = kt0; kt <= ktend; kt++) {
        const int s = (kt - kt0) & 1;
        if (kt < ktend) { issueKV(kt + 1, s ^ 1); CP_WAIT(1); }
        else            { CP_WAIT(0); }
        __syncthreads();
        const uint32_t kb = sb + kvBase + s * kvStage;
        const int s0 = kt << 6;

        float sc[8][4];
#pragma unroll
        for (int nt = 0; nt < 8; nt++)
#pragma unroll
            for (int e = 0; e < 4; e++) sc[nt][e] = 0.f;

#pragma unroll
        for (int kbk = 0; kbk < 8; kbk++) {
            uint32_t ah[4], al_[4], b2[8][2];
            ldsm4(ah[0], ah[1], ah[2], ah[3], sb + aQoff + kbk * 32);
            ldsm4(al_[0], al_[1], al_[2], al_[3], sb + oQl + aQoff + kbk * 32);
#pragma unroll
            for (int np = 0; np < 4; np++) {
                uint32_t r0, r1, r2, r3;
                ldsm4(r0, r1, r2, r3, kb + bKoff + np * 16 * LPAD * 2 + kbk * 32);
                b2[np * 2][0] = r0;     b2[np * 2][1] = r1;
                b2[np * 2 + 1][0] = r2; b2[np * 2 + 1][1] = r3;
            }
#pragma unroll
            for (int nt = 0; nt < 8; nt++) {
                mma16816(sc[nt], ah, b2[nt]);
                mma16816(sc[nt], al_, b2[nt]);
            }
        }

#pragma unroll
        for (int nt = 0; nt < 8; nt++) {
            int c0 = s0 + nt * 8 + cq;
#pragma unroll
            for (int e = 0; e < 2; e++) {
                int sg = c0 + e;
                float v0 = sc[nt][e] * SCALE_L;
                sc[nt][e] = (sg <= tg0 && sg >= tg0 - (WLOC - 1)) ? v0 : -1e30f;
                float v1 = sc[nt][2 + e] * SCALE_L;
                sc[nt][2 + e] = (sg <= tg1 && sg >= tg1 - (WLOC - 1)) ? v1 : -1e30f;
            }
        }

        float mx0 = -1e30f, mx1 = -1e30f;
#pragma unroll
        for (int nt = 0; nt < 8; nt++) {
            mx0 = fmaxf(mx0, fmaxf(sc[nt][0], sc[nt][1]));
            mx1 = fmaxf(mx1, fmaxf(sc[nt][2], sc[nt][3]));
        }
        mx0 = fmaxf(mx0, __shfl_xor_sync(0xffffffffu, mx0, 1));
        mx0 = fmaxf(mx0, __shfl_xor_sync(0xffffffffu, mx0, 2));
        mx1 = fmaxf(mx1, __shfl_xor_sync(0xffffffffu, mx1, 1));
        mx1 = fmaxf(mx1, __shfl_xor_sync(0xffffffffu, mx1, 2));
        float mn0 = fmaxf(m0, mx0), mn1 = fmaxf(m1, mx1);
        float al0 = __expf(m0 - mn0), al1 = __expf(m1 - mn1);
        m0 = mn0; m1 = mn1;

        float sum0 = 0.f, sum1 = 0.f;
#pragma unroll
        for (int nt = 0; nt < 8; nt++) {
#pragma unroll
            for (int e = 0; e < 2; e++) {
                float p0 = (sc[nt][e]     > -1e29f) ? __expf(sc[nt][e]     - mn0) : 0.f;
                float p1 = (sc[nt][2 + e] > -1e29f) ? __expf(sc[nt][2 + e] - mn1) : 0.f;
                sc[nt][e] = p0; sc[nt][2 + e] = p1;
                sum0 += p0; sum1 += p1;
            }
        }
        sum0 += __shfl_xor_sync(0xffffffffu, sum0, 1);
        sum0 += __shfl_xor_sync(0xffffffffu, sum0, 2);
        sum1 += __shfl_xor_sync(0xffffffffu, sum1, 1);
        sum1 += __shfl_xor_sync(0xffffffffu, sum1, 2);
        l0 = l0 * al0 + sum0;
        l1 = l1 * al1 + sum1;

#pragma unroll
        for (int nt = 0; nt < 16; nt++) {
            out[nt][0] *= al0; out[nt][1] *= al0;
            out[nt][2] *= al1; out[nt][3] *= al1;
        }

#pragma unroll
        for (int kbk = 0; kbk < 4; kbk++) {
            uint32_t ph[4], pl[4];
            split2(sc[2 * kbk][0],     sc[2 * kbk][1],     ph[0], pl[0]);
            split2(sc[2 * kbk][2],     sc[2 * kbk][3],     ph[1], pl[1]);
            split2(sc[2 * kbk + 1][0], sc[2 * kbk + 1][1], ph[2], pl[2]);
            split2(sc[2 * kbk + 1][2], sc[2 * kbk + 1][3], ph[3], pl[3]);
#pragma unroll
            for (int g = 0; g < 8; g++) {
                uint32_t r0, r1, r2, r3;
                ldsm4t(r0, r1, r2, r3,
                       kb + seg + bVoff + kbk * 16 * LPAD * 2 + g * 32);
                uint32_t b0[2] = {r0, r1}, b1[2] = {r2, r3};
                mma16816(out[2 * g], ph, b0);     mma16816(out[2 * g + 1], ph, b1);
                mma16816(out[2 * g], pl, b0);     mma16816(out[2 * g + 1], pl, b1);
            }
        }
        __syncthreads();
    }

    const float inv0 = 1.f / l0, inv1 = 1.f / l1;
#pragma unroll
    for (int nt = 0; nt < 16; nt++) {
        *(float2*)(g_ctx + (size_t)tg0 * CC + h * DD + nt * 8 + cq) =
            make_float2(out[nt][0] * inv0, out[nt][1] * inv0);
        *(float2*)(g_ctx + (size_t)tg1 * CC + h * DD + nt * 8 + cq) =
            make_float2(out[nt][2] * inv1, out[nt][3] * inv1);
    }
}

// ============================================================================
// Global low-rank attention: Sq=128, 8 warps, double-buffered KV_r (hi only),
// gated epilogue O @ uo^T; writes final ctx as fp16 hi/lo splits.
// smem = 73728 B -> 2 CTAs/SM.
// ============================================================================
#define GPAD 72
__global__ __launch_bounds__(256) void global_attn_mma()
{
    extern __shared__ __align__(16) char smraw[];
    const uint32_t sb = smem_u32(smraw);
    const uint32_t oQl = 128 * GPAD * 2;
    const uint32_t kvBase = 2 * 128 * GPAD * 2;
    const uint32_t kvStage = 2 * 64 * GPAD * 2;
    const uint32_t seg = 64 * GPAD * 2;
    const uint32_t oUh = kvBase;

    const int tid = threadIdx.x, lane = tid & 31, w = tid >> 5;
    const int qt = blockIdx.x, h = blockIdx.y, t0 = qt << 7;
    const int aj = lane >> 3, ar = lane & 7;
    const int tg0 = t0 + w * 16 + (lane >> 2), tg1 = tg0 + 8;
    const int cq = (lane & 3) * 2;

    for (int i = tid; i < 1024; i += 256) {
        int r = i >> 3, q = i & 7;
        uint32_t so = sb + (r * GPAD + q * 8) * 2;
        size_t go = (size_t)(h * TT + t0 + r) * RR + q * 8;
        CP16(so, g_qrh + go);
        CP16(so + oQl, g_qrl + go);
    }
    CP_COMMIT();

    auto issueKV = [&](int kt, int s) {
        const int s0 = kt << 6;
        const uint32_t kb = sb + kvBase + s * kvStage;
        for (int i = tid; i < 512; i += 256) {
            int r = i >> 3, q = i & 7;
            size_t gk = (size_t)(h * TT + s0 + r) * RR + q * 8;
            uint32_t off = (r * GPAD + q * 8) * 2;
            CP16(kb + off,       g_krh + gk);
            CP16(kb + seg + off, g_vrh + gk);
        }
        CP_COMMIT();
    };
    issueKV(0, 0);

    float m0 = -1e30f, m1 = -1e30f, l0 = 0.f, l1 = 0.f;
    float out[8][4];
#pragma unroll
    for (int nt = 0; nt < 8; nt++)
#pragma unroll
        for (int e = 0; e < 4; e++) out[nt][e] = 0.f;

    const uint32_t aQoff = ((w * 16 + (aj & 1) * 8 + ar) * GPAD + (aj >> 1) * 8) * 2;
    const uint32_t bKoff = (((aj >> 1) * 8 + ar) * GPAD + (aj & 1) * 8) * 2;
    const uint32_t bVoff = (((aj & 1) * 8 + ar) * GPAD + (aj >> 1) * 8) * 2;

    for (int kt = 0; kt < TT / 64; kt++) {
        const int s = kt & 1;
        if (kt < TT / 64 - 1) { issueKV(kt + 1, s ^ 1); CP_WAIT(1); }
        else                  { CP_WAIT(0); }
        __syncthreads();
        const uint32_t kb = sb + kvBase + s * kvStage;

        float sc[8][4];
#pragma unroll
        for (int nt = 0; nt < 8; nt++)
#pragma unroll
            for (int e = 0; e < 4; e++) sc[nt][e] = 0.f;

#pragma unroll
        for (int kbk = 0; kbk < 4; kbk++) {
            uint32_t ah[4], al_[4], b2[8][2];
            ldsm4(ah[0], ah[1], ah[2], ah[3], sb + aQoff + kbk * 32);
            ldsm4(al_[0], al_[1], al_[2], al_[3], sb + oQl + aQoff + kbk * 32);
#pragma unroll
            for (int np = 0; np < 4; np++) {
                uint32_t r0, r1, r2, r3;
                ldsm4(r0, r1, r2, r3, kb + bKoff + np * 16 * GPAD * 2 + kbk * 32);
                b2[np * 2][0] = r0;     b2[np * 2][1] = r1;
                b2[np * 2 + 1][0] = r2; b2[np * 2 + 1][1] = r3;
            }
#pragma unroll
            for (int nt = 0; nt < 8; nt++) {
                mma16816(sc[nt], ah, b2[nt]);
                mma16816(sc[nt], al_, b2[nt]);
            }
        }

        float mx0 = -1e30f, mx1 = -1e30f;
#pragma unroll
        for (int nt = 0; nt < 8; nt++) {
            sc[nt][0] *= SCALE_G; sc[nt][1] *= SCALE_G;
            sc[nt][2] *= SCALE_G; sc[nt][3] *= SCALE_G;
            mx0 = fmaxf(mx0, fmaxf(sc[nt][0], sc[nt][1]));
            mx1 = fmaxf(mx1, fmaxf(sc[nt][2], sc[nt][3]));
        }
        mx0 = fmaxf(mx0, __shfl_xor_sync(0xffffffffu, mx0, 1));
        mx0 = fmaxf(mx0, __shfl_xor_sync(0xffffffffu, mx0, 2));
        mx1 = fmaxf(mx1, __shfl_xor_sync(0xffffffffu, mx1, 1));
        mx1 = fmaxf(mx1, __shfl_xor_sync(0xffffffffu, mx1, 2));
        float mn0 = fmaxf(m0, mx0), mn1 = fmaxf(m1, mx1);
        float al0 = __expf(m0 - mn0), al1 = __expf(m1 - mn1);
        m0 = mn0; m1 = mn1;

        float sum0 = 0.f, sum1 = 0.f;
#pragma unroll
        for (int nt = 0; nt < 8; nt++) {
#pragma unroll
            for (int e = 0; e < 2; e++) {
                float p0 = __expf(sc[nt][e] - mn0);
                float p1 = __expf(sc[nt][2 + e] - mn1);
                sc[nt][e] = p0; sc[nt][2 + e] = p1;
                sum0 += p0; sum1 += p1;
            }
        }
        sum0 += __shfl_xor_sync(0xffffffffu, sum0, 1);
        sum0 += __shfl_xor_sync(0xffffffffu, sum0, 2);
        sum1 += __shfl_xor_sync(0xffffffffu, sum1, 1);
        sum1 += __shfl_xor_sync(0xffffffffu, sum1, 2);
        l0 = l0 * al0 + sum0;
        l1 = l1 * al1 + sum1;

#pragma unroll
        for (int nt = 0; nt < 8; nt++) {
            out[nt][0] *= al0; out[nt][1] *= al0;
            out[nt][2] *= al1; out[nt][3] *= al1;
        }

#pragma unroll
        for (int kbk = 0; kbk < 4; kbk++) {
            uint32_t ph[4], pl[4];
            split2(sc[2 * kbk][0],     sc[2 * kbk][1],     ph[0], pl[0]);
            split2(sc[2 * kbk][2],     sc[2 * kbk][3],     ph[1], pl[1]);
            split2(sc[2 * kbk + 1][0], sc[2 * kbk + 1][1], ph[2], pl[2]);
            split2(sc[2 * kbk + 1][2], sc[2 * kbk + 1][3], ph[3], pl[3]);
#pragma unroll
            for (int g = 0; g < 4; g++) {
                uint32_t r0, r1, r2, r3;
                ldsm4t(r0, r1, r2, r3,
                       kb + seg + bVoff + kbk * 16 * GPAD * 2 + g * 32);
                uint32_t b0[2] = {r0, r1}, b1[2] = {r2, r3};
                mma16816(out[2 * g], ph, b0);     mma16816(out[2 * g + 1], ph, b1);
                mma16816(out[2 * g], pl, b0);     mma16816(out[2 * g + 1], pl, b1);
            }
        }
        __syncthreads();
    }

    const float inv0 = 1.f / l0, inv1 = 1.f / l1;
#pragma unroll
    for (int nt = 0; nt < 8; nt++) {
        out[nt][0] *= inv0; out[nt][1] *= inv0;
        out[nt][2] *= inv1; out[nt][3] *= inv1;
    }

    for (int i = tid; i < 1024; i += 256) {
        int d = i >> 3, q = i & 7;
        *(int4*)(smraw + oUh + (d * GPAD + q * 8) * 2) =
            *(const int4*)(g_uoh + d * 64 + q * 8);
    }
    __syncthreads();

    float out2[16][4];
#pragma unroll
    for (int nt = 0; nt < 16; nt++)
#pragma unroll
        for (int e = 0; e < 4; e++) out2[nt][e] = 0.f;

    const uint32_t bUoff = (((aj >> 1) * 8 + ar) * GPAD + (aj & 1) * 8) * 2;
#pragma unroll
    for (int kbk = 0; kbk < 4; kbk++) {
        uint32_t ph[4], pl[4];
        split2(out[2 * kbk][0],     out[2 * kbk][1],     ph[0], pl[0]);
        split2(out[2 * kbk][2],     out[2 * kbk][3],     ph[1], pl[1]);
        split2(out[2 * kbk + 1][0], out[2 * kbk + 1][1], ph[2], pl[2]);
        split2(out[2 * kbk + 1][2], out[2 * kbk + 1][3], ph[3], pl[3]);
#pragma unroll
        for (int g = 0; g < 8; g++) {
            uint32_t r0, r1, r2, r3;
            ldsm4(r0, r1, r2, r3, sb + oUh + bUoff + g * 16 * GPAD * 2 + kbk * 32);
            uint32_t b0[2] = {r0, r1}, b1[2] = {r2, r3};
            mma16816(out2[2 * g], ph, b0);     mma16816(out2[2 * g + 1], ph, b1);
            mma16816(out2[2 * g], pl, b0);     mma16816(out2[2 * g + 1], pl, b1);
        }
    }

    const float ga0 = g_gate[tg0], ga1 = g_gate[tg1];
#pragma unroll
    for (int nt = 0; nt < 16; nt++) {
        size_t i0 = (size_t)tg0 * CC + h * DD + nt * 8 + cq;
        float2 o0 = *(float2*)(g_ctx + i0);
        uint32_t hh, ll;
        split2(o0.x + ga0 * out2[nt][0], o0.y + ga0 * out2[nt][1], hh, ll);
        *(uint32_t*)(g_cxh + i0) = hh;
        *(uint32_t*)(g_cxl + i0) = ll;
        size_t i1 = (size_t)tg1 * CC + h * DD + nt * 8 + cq;
        float2 o1 = *(float2*)(g_ctx + i1);
        split2(o1.x + ga1 * out2[nt][2], o1.y + ga1 * out2[nt][3], hh, ll);
        *(uint32_t*)(g_cxh + i1) = hh;
        *(uint32_t*)(g_cxl + i1) = ll;
    }
}

// ============================================================================
extern "C" void kernel_launch(void* const* d_in, const int* in_sizes, int n_in,
                              void* d_out, int out_size)
{
    const float* x     = (const float*)d_in[0];
    const float* w_qkv = (const float*)d_in[1];
    const float* w_o   = (const float*)d_in[2];
    const float* pk    = (const float*)d_in[3];
    const float* pv    = (const float*)d_in[4];
    const float* uo    = (const float*)d_in[5];
    const float* iw1   = (const float*)d_in[6];
    const float* iw2   = (const float*)d_in[7];
    float* out = (float*)d_out;

    cudaFuncSetAttribute(gemm_mma256,     cudaFuncAttributeMaxDynamicSharedMemorySize, 81920);
    cudaFuncSetAttribute(gemm_info,       cudaFuncAttributeMaxDynamicSharedMemorySize, 61440);
    cudaFuncSetAttribute(local_attn_mma,  cudaFuncAttributeMaxDynamicSharedMemorySize, 104448);
    cudaFuncSetAttribute(global_attn_mma, cudaFuncAttributeMaxDynamicSharedMemorySize, 73728);
    cudaFuncSetAttribute(lowrank_mma,     cudaFuncAttributeMaxDynamicSharedMemorySize, 52224);

    void *pxh, *pxl, *pwqh, *pwoh, *pi1h, *pcxh, *pcxl, *pqkvh, *pqkvl;
    cudaGetSymbolAddress(&pxh, g_xh);   cudaGetSymbolAddress(&pxl, g_xl);
    cudaGetSymbolAddress(&pwqh, g_wqh);
    cudaGetSymbolAddress(&pwoh, g_woh);
    cudaGetSymbolAddress(&pi1h, g_i1h);
    cudaGetSymbolAddress(&pcxh, g_cxh); cudaGetSymbolAddress(&pcxl, g_cxl);
    cudaGetSymbolAddress(&pqkvh, g_qkvh); cudaGetSymbolAddress(&pqkvl, g_qkvl);

    rope_table_k<<<TT, DD>>>();
    split_h2_k<<<(TT * CC / 2 + 255) / 256, 256>>>(
        (const float2*)x, (__half2*)pxh, (__half2*)pxl, TT * CC / 2);
    conv_all_k<<<(CS6 + 255) / 256, 256>>>(
        (const float2*)w_qkv, (const float2*)iw1, (const float2*)w_o,
        (const float2*)uo, (const float2*)pk, (const float2*)pv);

    // qkv = rope(x @ w_qkv^T) -> fp16 splits
    gemm_mma256<<<dim3(C3 / 256, TT / 128), 256, 81920>>>(
        (const __half*)pxh, (const __half*)pxl, (const __half*)pwqh,
        nullptr, (__half*)pqkvh, (__half*)pqkvl, C3, CC, 2);

    // info gate: GEMM + fused gelu/dot partials, then finalize
    gemm_info<<<dim3(CI / 128, TT / 128), 256, 61440>>>(
        (const __half*)pxh, (const __half*)pxl, (const __half*)pi1h,
        iw2, CI, CC);
    gate_fin_k<<<TT / 256, 256>>>();

    lowrank_mma<<<dim3(TT / 64, HH), 128, 52224>>>();
    local_attn_mma<<<dim3(TT / 64, HH), 128, 104448>>>();
    global_attn_mma<<<dim3(TT / 128, HH), 256, 73728>>>();

    // out = ctx @ w_o^T
    gemm_mma256<<<dim3(CC / 256, TT / 128), 256, 81920>>>(
        (const __half*)pcxh, (const __half*)pcxl, (const __half*)pwoh,
        out, nullptr, nullptr, CC, CC, 0);
}

// round 10
// speedup vs baseline: 4.5908x; 1.0179x over previous
#include <cuda_runtime.h>
#include <cuda_fp16.h>
#include <math.h>
#include <stdint.h>

#define TT   2048
#define CC   2048
#define HH   16
#define DD   128
#define RR   64
#define WLOC 512
#define CI   512
#define C3   6144

#define SCALE_L 0.08838834764831845f
#define SCALE_G 0.1767766952966369f

// ---------------- scratch (device globals) ----------------
__device__ float g_gatez[4 * TT];
__device__ float g_gate[TT];
__device__ float g_cos[TT * DD];
__device__ float g_sin[TT * DD];
__device__ float g_ctx[TT * CC];

// fp16 operands: A-side hi+lo (2-term split), B-side hi only.
__device__ __half g_xh[TT * CC],  g_xl[TT * CC];
__device__ __half g_wqh[C3 * CC];
__device__ __half g_woh[CC * CC];
__device__ __half g_i1h[CI * CC];
__device__ __half g_cxh[TT * CC], g_cxl[TT * CC];
__device__ __half g_qkvh[TT * C3], g_qkvl[TT * C3];
__device__ __half g_qrh[HH * TT * RR], g_qrl[HH * TT * RR];
__device__ __half g_krh[HH * TT * RR];
__device__ __half g_vrh[HH * TT * RR];
__device__ __half g_uoh[DD * RR];
__device__ __half g_pkh[RR * DD];
__device__ __half g_pvh[RR * DD];

// ============================================================================
// PTX helpers (plain sm_80+ ISA)
// ============================================================================
__device__ __forceinline__ uint32_t smem_u32(const void* p) {
    uint32_t a;
    asm("{ .reg .u64 t; cvta.to.shared.u64 t, %1; cvt.u32.u64 %0, t; }"
        : "=r"(a) : "l"(p));
    return a;
}

#define CP16(s, g) \
    asm volatile("cp.async.cg.shared.global [%0], [%1], 16;" \
                 :: "r"(s), "l"(g) : "memory")
#define CP_COMMIT() asm volatile("cp.async.commit_group;" ::: "memory")
#define CP_WAIT(n)  asm volatile("cp.async.wait_group %0;" :: "n"(n) : "memory")

__device__ __forceinline__ void ldsm4(uint32_t& r0, uint32_t& r1,
                                      uint32_t& r2, uint32_t& r3, uint32_t a) {
    asm volatile("ldmatrix.sync.aligned.m8n8.x4.shared.b16 {%0,%1,%2,%3}, [%4];"
                 : "=r"(r0), "=r"(r1), "=r"(r2), "=r"(r3) : "r"(a));
}
__device__ __forceinline__ void ldsm4t(uint32_t& r0, uint32_t& r1,
                                       uint32_t& r2, uint32_t& r3, uint32_t a) {
    asm volatile("ldmatrix.sync.aligned.m8n8.x4.trans.shared.b16 {%0,%1,%2,%3}, [%4];"
                 : "=r"(r0), "=r"(r1), "=r"(r2), "=r"(r3) : "r"(a));
}

__device__ __forceinline__ void mma16816(float* c, const uint32_t* a,
                                         const uint32_t* b) {
    asm volatile("mma.sync.aligned.m16n8k16.row.col.f32.f16.f16.f32 "
                 "{%0,%1,%2,%3}, {%4,%5,%6,%7}, {%8,%9}, {%0,%1,%2,%3};"
                 : "+f"(c[0]), "+f"(c[1]), "+f"(c[2]), "+f"(c[3])
                 : "r"(a[0]), "r"(a[1]), "r"(a[2]), "r"(a[3]),
                   "r"(b[0]), "r"(b[1]));
}

__device__ __forceinline__ void split2(float x, float y, uint32_t& h, uint32_t& l) {
    __half2 hh = __floats2half2_rn(x, y);
    h = *reinterpret_cast<uint32_t*>(&hh);
    __half2 ll = __floats2half2_rn(x - __low2float(hh), y - __high2float(hh));
    l = *reinterpret_cast<uint32_t*>(&ll);
}

// ============================================================================
// fp32 -> fp16 hi/lo split (x only)
// ============================================================================
__global__ void split_h2_k(const float2* __restrict__ src,
                           __half2* __restrict__ hi,
                           __half2* __restrict__ lo, int n2)
{
    int i = blockIdx.x * 256 + threadIdx.x;
    if (i < n2) {
        float2 v = src[i];
        __half2 h = __floats2half2_rn(v.x, v.y);
        hi[i] = h;
        lo[i] = __floats2half2_rn(v.x - __low2float(h), v.y - __high2float(h));
    }
}

// ============================================================================
// Fused fp32 -> fp16 convert of ALL weight regions (one launch)
// ============================================================================
#define CS1 (C3 * CC / 2)
#define CS2 (CS1 + CI * CC / 2)
#define CS3 (CS2 + CC * CC / 2)
#define CS4 (CS3 + DD * RR / 2)
#define CS5 (CS4 + RR * DD / 2)
#define CS6 (CS5 + RR * DD / 2)
__global__ void conv_all_k(const float2* __restrict__ wq,
                           const float2* __restrict__ i1,
                           const float2* __restrict__ wo,
                           const float2* __restrict__ uo,
                           const float2* __restrict__ pk,
                           const float2* __restrict__ pv)
{
    int i = blockIdx.x * 256 + threadIdx.x;
    const float2* s; __half2* d; int j;
    if      (i < CS1) { s = wq; d = (__half2*)g_wqh; j = i; }
    else if (i < CS2) { s = i1; d = (__half2*)g_i1h; j = i - CS1; }
    else if (i < CS3) { s = wo; d = (__half2*)g_woh; j = i - CS2; }
    else if (i < CS4) { s = uo; d = (__half2*)g_uoh; j = i - CS3; }
    else if (i < CS5) { s = pk; d = (__half2*)g_pkh; j = i - CS4; }
    else if (i < CS6) { s = pv; d = (__half2*)g_pvh; j = i - CS5; }
    else return;
    float2 v = s[j];
    d[j] = __floats2half2_rn(v.x, v.y);
}

// ============================================================================
// mma.sync GEMM (BM=128, BN=256, BK=32; 512 threads, 16 warps 4x4,
// warp tile 32x64; 2-term fp16: C = Ah·Bh^T + Al·Bh^T).
// smem/stage: Ah 10240 | Al 10240 | Bh 20480 = 40960; x2 = 81920.
// 16 warps = 4/SMSP for latency hiding (R9 profile: 8 warps -> tensor 46%).
// mode 0: fp32 store. mode 2: rope + fp16 hi/lo store.
// ============================================================================
__global__ __launch_bounds__(512) void gemm_mma256(
    const __half* __restrict__ Ah, const __half* __restrict__ Al,
    const __half* __restrict__ Bh,
    float* __restrict__ Cout,
    __half* __restrict__ Ch, __half* __restrict__ Cl,
    int N, int K, int mode)
{
    extern __shared__ __align__(128) char smraw[];
    const uint32_t sb = smem_u32(smraw);
    const int tid = threadIdx.x, lane = tid & 31, wid = tid >> 5;
    const int wm = wid & 3, wn = wid >> 2;        // 4 x 4 warp grid
    const int bm = blockIdx.y << 7, bn = blockIdx.x << 8;
    const int aj = lane >> 3, ar = lane & 7;

    float acc[2][8][4];
#pragma unroll
    for (int mt = 0; mt < 2; mt++)
#pragma unroll
        for (int nt = 0; nt < 8; nt++)
#pragma unroll
            for (int e = 0; e < 4; e++) acc[mt][nt][e] = 0.f;

    const int nch = K >> 5;

    auto issue_stage = [&](int c) {
        const uint32_t st = sb + (c & 1) * 40960;
        const int k0 = c << 5;
        {
            // A hi/lo: 128 rows x 64B -> 512 cp16 each; 1 per thread
            int r = tid >> 2, q = tid & 3;
            uint32_t so = st + r * 80 + q * 16;
            size_t go = (size_t)r * K + k0 + q * 8;
            CP16(so,          Ah + (size_t)bm * K + go);
            CP16(so + 10240,  Al + (size_t)bm * K + go);
        }
        {
            // B hi: 256 rows x 64B -> 1024 cp16; 2 per thread
            const __half* gh = Bh + (size_t)bn * K + k0;
#pragma unroll
            for (int hh = 0; hh < 2; hh++) {
                int i = tid + hh * 512;
                int r = i >> 2, q = i & 3;
                CP16(st + 20480 + r * 80 + q * 16, gh + (size_t)r * K + q * 8);
            }
        }
        CP_COMMIT();
    };

    issue_stage(0);
    for (int c = 0; c < nch; c++) {
        if (c + 1 < nch) { issue_stage(c + 1); CP_WAIT(1); }
        else             { CP_WAIT(0); }
        __syncthreads();

        const uint32_t st = sb + (c & 1) * 40960;
#pragma unroll
        for (int ks = 0; ks < 2; ks++) {
            uint32_t ah[2][4], al_[2][4], b2[8][2];
            const uint32_t a_off =
                ((wm * 32 + (aj & 1) * 8 + ar) * 40 + ks * 16 + (aj >> 1) * 8) * 2;
            const uint32_t b_off =
                ((wn * 64 + (aj >> 1) * 8 + ar) * 40 + ks * 16 + (aj & 1) * 8) * 2;

#pragma unroll
            for (int mt = 0; mt < 2; mt++) {
                ldsm4(ah[mt][0], ah[mt][1], ah[mt][2], ah[mt][3],
                      st + a_off + mt * (16 * 80));
                ldsm4(al_[mt][0], al_[mt][1], al_[mt][2], al_[mt][3],
                      st + 10240 + a_off + mt * (16 * 80));
            }
#pragma unroll
            for (int np = 0; np < 4; np++) {
                uint32_t r0, r1, r2, r3;
                ldsm4(r0, r1, r2, r3, st + 20480 + b_off + np * (16 * 80));
                b2[np * 2][0] = r0;     b2[np * 2][1] = r1;
                b2[np * 2 + 1][0] = r2; b2[np * 2 + 1][1] = r3;
            }
#pragma unroll
            for (int mt = 0; mt < 2; mt++)
#pragma unroll
                for (int nt = 0; nt < 8; nt++) {
                    mma16816(acc[mt][nt], ah[mt], b2[nt]);
                    mma16816(acc[mt][nt], al_[mt], b2[nt]);
                }
        }
        __syncthreads();
    }

    const int row_base = bm + wm * 32 + (lane >> 2);
    const int col_base = bn + wn * 64 + (lane & 3) * 2;
#pragma unroll
    for (int mt = 0; mt < 2; mt++)
#pragma unroll
        for (int nt = 0; nt < 8; nt++) {
            int r0 = row_base + mt * 16, cc = col_base + nt * 8;
            float v0 = acc[mt][nt][0], v1 = acc[mt][nt][1];
            float v2 = acc[mt][nt][2], v3 = acc[mt][nt][3];
            if (mode == 2) {
                if (cc < 2 * CC) {
                    int d0 = cc & 127;
                    float2 cA = *(const float2*)(g_cos + r0 * DD + d0);
                    float2 sA = *(const float2*)(g_sin + r0 * DD + d0);
                    float o0 = v0 * cA.x - v1 * sA.x;
                    float o1 = v1 * cA.y + v0 * sA.y;
                    float2 cB = *(const float2*)(g_cos + (r0 + 8) * DD + d0);
                    float2 sB = *(const float2*)(g_sin + (r0 + 8) * DD + d0);
                    float o2 = v2 * cB.x - v3 * sB.x;
                    float o3 = v3 * cB.y + v2 * sB.y;
                    v0 = o0; v1 = o1; v2 = o2; v3 = o3;
                }
                uint32_t h01, l01, h23, l23;
                split2(v0, v1, h01, l01);
                split2(v2, v3, h23, l23);
                *(uint32_t*)(Ch + (size_t)r0 * N + cc)       = h01;
                *(uint32_t*)(Cl + (size_t)r0 * N + cc)       = l01;
                *(uint32_t*)(Ch + (size_t)(r0 + 8) * N + cc) = h23;
                *(uint32_t*)(Cl + (size_t)(r0 + 8) * N + cc) = l23;
            } else {
                *(float2*)(Cout + (size_t)r0 * N + cc)       = make_float2(v0, v1);
                *(float2*)(Cout + (size_t)(r0 + 8) * N + cc) = make_float2(v2, v3);
            }
        }
}

// ============================================================================
// Info GEMM (BN=128, 2-term fp16) with fused gelu + dot(w2) gate partials.
// ============================================================================
__global__ __launch_bounds__(256) void gemm_info(
    const __half* __restrict__ Ah, const __half* __restrict__ Al,
    const __half* __restrict__ Bh,
    const float* __restrict__ w2, int N, int K)
{
    extern __shared__ __align__(128) char smraw[];
    const uint32_t sb = smem_u32(smraw);
    const int tid = threadIdx.x, lane = tid & 31, wid = tid >> 5;
    const int wm = wid & 3, wn = wid >> 2;
    const int bm = blockIdx.y << 7, bn = blockIdx.x << 7;
    const int aj = lane >> 3, ar = lane & 7;

    float acc[2][8][4];
#pragma unroll
    for (int mt = 0; mt < 2; mt++)
#pragma unroll
        for (int nt = 0; nt < 8; nt++)
#pragma unroll
            for (int e = 0; e < 4; e++) acc[mt][nt][e] = 0.f;

    const int nch = K >> 5;

    auto issue_stage = [&](int c) {
        const uint32_t st = sb + (c & 1) * 30720;
        const int k0 = c << 5;
        const __half* gm0 = Ah + (size_t)bm * K + k0;
        const __half* gm1 = Al + (size_t)bm * K + k0;
        const __half* gm2 = Bh + (size_t)bn * K + k0;
#pragma unroll
        for (int h = 0; h < 2; h++) {
            int i = tid + h * 256;
            int r = i >> 2, q = i & 3;
            uint32_t so = st + r * 80 + q * 16;
            size_t go = (size_t)r * K + q * 8;
            CP16(so,          gm0 + go);
            CP16(so + 10240,  gm1 + go);
            CP16(so + 20480,  gm2 + go);
        }
        CP_COMMIT();
    };

    issue_stage(0);
    for (int c = 0; c < nch; c++) {
        if (c + 1 < nch) { issue_stage(c + 1); CP_WAIT(1); }
        else             { CP_WAIT(0); }
        __syncthreads();

        const uint32_t st = sb + (c & 1) * 30720;
#pragma unroll
        for (int ks = 0; ks < 2; ks++) {
            uint32_t ah[2][4], al_[2][4], b2[8][2];
            const uint32_t a_off =
                ((wm * 32 + (aj & 1) * 8 + ar) * 40 + ks * 16 + (aj >> 1) * 8) * 2;
            const uint32_t b_off =
                ((wn * 64 + (aj >> 1) * 8 + ar) * 40 + ks * 16 + (aj & 1) * 8) * 2;

#pragma unroll
            for (int mt = 0; mt < 2; mt++) {
                ldsm4(ah[mt][0], ah[mt][1], ah[mt][2], ah[mt][3],
                      st + a_off + mt * (16 * 80));
                ldsm4(al_[mt][0], al_[mt][1], al_[mt][2], al_[mt][3],
                      st + 10240 + a_off + mt * (16 * 80));
            }
#pragma unroll
            for (int np = 0; np < 4; np++) {
                uint32_t r0, r1, r2, r3;
                ldsm4(r0, r1, r2, r3, st + 20480 + b_off + np * (16 * 80));
                b2[np * 2][0] = r0;     b2[np * 2][1] = r1;
                b2[np * 2 + 1][0] = r2; b2[np * 2 + 1][1] = r3;
            }
#pragma unroll
            for (int mt = 0; mt < 2; mt++)
#pragma unroll
                for (int nt = 0; nt < 8; nt++) {
                    mma16816(acc[mt][nt], ah[mt], b2[nt]);
                    mma16816(acc[mt][nt], al_[mt], b2[nt]);
                }
        }
        __syncthreads();
    }

    const int col_base = wn * 64 + (lane & 3) * 2;
    float z[2][2] = {{0.f, 0.f}, {0.f, 0.f}};
#pragma unroll
    for (int mt = 0; mt < 2; mt++)
#pragma unroll
        for (int nt = 0; nt < 8; nt++) {
            int cc = col_base + nt * 8;
            float w0 = w2[cc], w1 = w2[cc + 1];
            float v0 = acc[mt][nt][0], v1 = acc[mt][nt][1];
            float v2 = acc[mt][nt][2], v3 = acc[mt][nt][3];
            v0 = 0.5f * v0 * (1.0f + erff(v0 * 0.7071067811865475f));
            v1 = 0.5f * v1 * (1.0f + erff(v1 * 0.7071067811865475f));
            v2 = 0.5f * v2 * (1.0f + erff(v2 * 0.7071067811865475f));
            v3 = 0.5f * v3 * (1.0f + erff(v3 * 0.7071067811865475f));
            z[mt][0] += v0 * w0 + v1 * w1;
            z[mt][1] += v2 * w0 + v3 * w1;
        }
#pragma unroll
    for (int mt = 0; mt < 2; mt++)
#pragma unroll
        for (int e = 0; e < 2; e++) {
            z[mt][e] += __shfl_xor_sync(0xffffffffu, z[mt][e], 1);
            z[mt][e] += __shfl_xor_sync(0xffffffffu, z[mt][e], 2);
        }
    float* zs = (float*)smraw;
    if ((lane & 3) == 0) {
        int lr = wm * 32 + (lane >> 2);
        zs[wn * 128 + lr +  0] = z[0][0];
        zs[wn * 128 + lr +  8] = z[0][1];
        zs[wn * 128 + lr + 16] = z[1][0];
        zs[wn * 128 + lr + 24] = z[1][1];
    }
    __syncthreads();
    if (tid < 128)
        g_gatez[blockIdx.x * TT + bm + tid] = zs[tid] + zs[128 + tid];
}

__global__ void gate_fin_k()
{
    int t = blockIdx.x * 256 + threadIdx.x;
    float zsum = g_gatez[t] + g_gatez[TT + t] + g_gatez[2 * TT + t]
               + g_gatez[3 * TT + t];
    float sc = 1.0f / (1.0f + expf(-zsum));
    g_gate[t] = (sc > 0.75f) ? 1.0f : 0.0f;
}

// ============================================================================
// RoPE tables (fp32)
// ============================================================================
__global__ void rope_table_k()
{
    int t = blockIdx.x, d = threadIdx.x;
    int j = d & 63;
    float inv = exp2f(-(float)j * 0.20762050593046014f);
    float ang = (float)t * inv;
    g_cos[t * DD + d] = cosf(ang);
    g_sin[t * DD + d] = sinf(ang);
}

// ============================================================================
// Low-rank projections (2-term fp16)
// ============================================================================
__global__ __launch_bounds__(128) void lowrank_mma()
{
    extern __shared__ __align__(16) char smraw[];
    const uint32_t sb = smem_u32(smraw);
    const uint32_t oAl = 64 * 136 * 2, oPh = 2 * 64 * 136 * 2;
    const int tid = threadIdx.x, lane = tid & 31, w = tid >> 5;
    const int qt = blockIdx.x, h = blockIdx.y, t0 = qt << 6;
    const int aj = lane >> 3, ar = lane & 7;

    const uint32_t aoff = ((w * 16 + (aj & 1) * 8 + ar) * 136 + (aj >> 1) * 8) * 2;
    const uint32_t boff = (((aj >> 1) * 8 + ar) * 136 + (aj & 1) * 8) * 2;
    const int row0 = t0 + w * 16 + (lane >> 2);
    const int col = (lane & 3) * 2;

    for (int pass = 0; pass < 3; pass++) {
        const __half* Ph = (pass == 2) ? g_pvh : g_pkh;
        const int off = pass * CC + h * DD;
        __syncthreads();
        for (int i = tid; i < 1024; i += 128) {
            int r = i >> 4, q = i & 15;
            uint32_t so = (r * 136 + q * 8) * 2;
            size_t ga = (size_t)(t0 + r) * C3 + off + q * 8;
            CP16(sb + so,       g_qkvh + ga);
            CP16(sb + oAl + so, g_qkvl + ga);
            CP16(sb + oPh + so, Ph + r * DD + q * 8);
        }
        CP_COMMIT(); CP_WAIT(0);
        __syncthreads();

        float acc[8][4];
#pragma unroll
        for (int nt = 0; nt < 8; nt++)
#pragma unroll
            for (int e = 0; e < 4; e++) acc[nt][e] = 0.f;

#pragma unroll
        for (int kb = 0; kb < 8; kb++) {
            uint32_t ah[4], al_[4], b2[8][2];
            ldsm4(ah[0], ah[1], ah[2], ah[3], sb + aoff + kb * 32);
            ldsm4(al_[0], al_[1], al_[2], al_[3], sb + oAl + aoff + kb * 32);
#pragma unroll
            for (int np = 0; np < 4; np++) {
                uint32_t r0, r1, r2, r3;
                ldsm4(r0, r1, r2, r3, sb + oPh + boff + np * 16 * 136 * 2 + kb * 32);
                b2[np * 2][0] = r0;     b2[np * 2][1] = r1;
                b2[np * 2 + 1][0] = r2; b2[np * 2 + 1][1] = r3;
            }
#pragma unroll
            for (int nt = 0; nt < 8; nt++) {
                mma16816(acc[nt], ah, b2[nt]);
                mma16816(acc[nt], al_, b2[nt]);
            }
        }

        if (pass == 0) {
#pragma unroll
            for (int nt = 0; nt < 8; nt++) {
                uint32_t hh, ll;
                size_t i0 = (size_t)(h * TT + row0) * RR + nt * 8 + col;
                split2(acc[nt][0], acc[nt][1], hh, ll);
                *(uint32_t*)(g_qrh + i0) = hh;
                *(uint32_t*)(g_qrl + i0) = ll;
                size_t i1 = i0 + 8 * RR;
                split2(acc[nt][2], acc[nt][3], hh, ll);
                *(uint32_t*)(g_qrh + i1) = hh;
                *(uint32_t*)(g_qrl + i1) = ll;
            }
        } else {
            __half* dh = (pass == 1) ? g_krh : g_vrh;
#pragma unroll
            for (int nt = 0; nt < 8; nt++) {
                size_t i0 = (size_t)(h * TT + row0) * RR + nt * 8 + col;
                __half2 a = __floats2half2_rn(acc[nt][0], acc[nt][1]);
                *(uint32_t*)(dh + i0) = *(uint32_t*)&a;
                size_t i1 = i0 + 8 * RR;
                __half2 b = __floats2half2_rn(acc[nt][2], acc[nt][3]);
                *(uint32_t*)(dh + i1) = *(uint32_t*)&b;
            }
        }
    }
}

// ============================================================================
// Local sliding-window attention: Sq=64, 4 warps, double-buffered KV (hi only).
// smem = 104448 B -> 2 CTAs/SM.
// ============================================================================
#define LPAD 136
__global__ __launch_bounds__(128) void local_attn_mma()
{
    extern __shared__ __align__(16) char smraw[];
    const uint32_t sb = smem_u32(smraw);
    const uint32_t oQl = 64 * LPAD * 2;
    const uint32_t kvBase = 2 * 64 * LPAD * 2;
    const uint32_t kvStage = 2 * 64 * LPAD * 2;
    const uint32_t seg = 64 * LPAD * 2;

    const int tid = threadIdx.x, lane = tid & 31, w = tid >> 5;
    const int qt = gridDim.x - 1 - blockIdx.x, h = blockIdx.y;
    const int t0 = qt << 6;
    const int aj = lane >> 3, ar = lane & 7;
    const int tg0 = t0 + w * 16 + (lane >> 2), tg1 = tg0 + 8;
    const int cq = (lane & 3) * 2;

    for (int i = tid; i < 1024; i += 128) {
        int r = i >> 4, q = i & 15;
        uint32_t so = sb + (r * LPAD + q * 8) * 2;
        size_t go = (size_t)(t0 + r) * C3 + h * DD + q * 8;
        CP16(so, g_qkvh + go);
        CP16(so + oQl, g_qkvl + go);
    }
    CP_COMMIT();

    const int kt0 = (t0 > WLOC - 1) ? ((t0 - (WLOC - 1)) >> 6) : 0;
    const int ktend = qt;

    auto issueKV = [&](int kt, int s) {
        const int s0 = kt << 6;
        const uint32_t kb = sb + kvBase + s * kvStage;
        for (int i = tid; i < 1024; i += 128) {
            int r = i >> 4, q = i & 15;
            size_t gk = (size_t)(s0 + r) * C3 + CC + h * DD + q * 8;
            uint32_t off = (r * LPAD + q * 8) * 2;
            CP16(kb + off,       g_qkvh + gk);
            CP16(kb + seg + off, g_qkvh + gk + CC);
        }
        CP_COMMIT();
    };
    issueKV(kt0, 0);

    float m0 = -1e30f, m1 = -1e30f, l0 = 0.f, l1 = 0.f;
    float out[16][4];
#pragma unroll
    for (int nt = 0; nt < 16; nt++)
#pragma unroll
        for (int e = 0; e < 4; e++) out[nt][e] = 0.f;

    const uint32_t aQoff = ((w * 16 + (aj & 1) * 8 + ar) * LPAD + (aj >> 1) * 8) * 2;
    const uint32_t bKoff = (((aj >> 1) * 8 + ar) * LPAD + (aj & 1) * 8) * 2;
    const uint32_t bVoff = (((aj & 1) * 8 + ar) * LPAD + (aj >> 1) * 8) * 2;

    for (int kt = kt0; kt <= ktend; kt++) {
        const int s = (kt - kt0) & 1;
        if (kt < ktend) { issueKV(kt + 1, s ^ 1); CP_WAIT(1); }
        else            { CP_WAIT(0); }
        __syncthreads();
        const uint32_t kb = sb + kvBase + s * kvStage;
        const int s0 = kt << 6;

        float sc[8][4];
#pragma unroll
        for (int nt = 0; nt < 8; nt++)
#pragma unroll
            for (int e = 0; e < 4; e++) sc[nt][e] = 0.f;

#pragma unroll
        for (int kbk = 0; kbk < 8; kbk++) {
            uint32_t ah[4], al_[4], b2[8][2];
            ldsm4(ah[0], ah[1], ah[2], ah[3], sb + aQoff + kbk * 32);
            ldsm4(al_[0], al_[1], al_[2], al_[3], sb + oQl + aQoff + kbk * 32);
#pragma unroll
            for (int np = 0; np < 4; np++) {
                uint32_t r0, r1, r2, r3;
                ldsm4(r0, r1, r2, r3, kb + bKoff + np * 16 * LPAD * 2 + kbk * 32);
                b2[np * 2][0] = r0;     b2[np * 2][1] = r1;
                b2[np * 2 + 1][0] = r2; b2[np * 2 + 1][1] = r3;
            }
#pragma unroll
            for (int nt = 0; nt < 8; nt++) {
                mma16816(sc[nt], ah, b2[nt]);
                mma16816(sc[nt], al_, b2[nt]);
            }
        }

#pragma unroll
        for (int nt = 0; nt < 8; nt++) {
            int c0 = s0 + nt * 8 + cq;
#pragma unroll
            for (int e = 0; e < 2; e++) {
                int sg = c0 + e;
                float v0 = sc[nt][e] * SCALE_L;
                sc[nt][e] = (sg <= tg0 && sg >= tg0 - (WLOC - 1)) ? v0 : -1e30f;
                float v1 = sc[nt][2 + e] * SCALE_L;
                sc[nt][2 + e] = (sg <= tg1 && sg >= tg1 - (WLOC - 1)) ? v1 : -1e30f;
            }
        }

        float mx0 = -1e30f, mx1 = -1e30f;
#pragma unroll
        for (int nt = 0; nt < 8; nt++) {
            mx0 = fmaxf(mx0, fmaxf(sc[nt][0], sc[nt][1]));
            mx1 = fmaxf(mx1, fmaxf(sc[nt][2], sc[nt][3]));
        }
        mx0 = fmaxf(mx0, __shfl_xor_sync(0xffffffffu, mx0, 1));
        mx0 = fmaxf(mx0, __shfl_xor_sync(0xffffffffu, mx0, 2));
        mx1 = fmaxf(mx1, __shfl_xor_sync(0xffffffffu, mx1, 1));
        mx1 = fmaxf(mx1, __shfl_xor_sync(0xffffffffu, mx1, 2));
        float mn0 = fmaxf(m0, mx0), mn1 = fmaxf(m1, mx1);
        float al0 = __expf(m0 - mn0), al1 = __expf(m1 - mn1);
        m0 = mn0; m1 = mn1;

        float sum0 = 0.f, sum1 = 0.f;
#pragma unroll
        for (int nt = 0; nt < 8; nt++) {
#pragma unroll
            for (int e = 0; e < 2; e++) {
                float p0 = (sc[nt][e]     > -1e29f) ? __expf(sc[nt][e]     - mn0) : 0.f;
                float p1 = (sc[nt][2 + e] > -1e29f) ? __expf(sc[nt][2 + e] - mn1) : 0.f;
                sc[nt][e] = p0; sc[nt][2 + e] = p1;
                sum0 += p0; sum1 += p1;
            }
        }
        sum0 += __shfl_xor_sync(0xffffffffu, sum0, 1);
        sum0 += __shfl_xor_sync(0xffffffffu, sum0, 2);
        sum1 += __shfl_xor_sync(0xffffffffu, sum1, 1);
        sum1 += __shfl_xor_sync(0xffffffffu, sum1, 2);
        l0 = l0 * al0 + sum0;
        l1 = l1 * al1 + sum1;

#pragma unroll
        for (int nt = 0; nt < 16; nt++) {
            out[nt][0] *= al0; out[nt][1] *= al0;
            out[nt][2] *= al1; out[nt][3] *= al1;
        }

#pragma unroll
        for (int kbk = 0; kbk < 4; kbk++) {
            uint32_t ph[4], pl[4];
            split2(sc[2 * kbk][0],     sc[2 * kbk][1],     ph[0], pl[0]);
            split2(sc[2 * kbk][2],     sc[2 * kbk][3],     ph[1], pl[1]);
            split2(sc[2 * kbk + 1][0], sc[2 * kbk + 1][1], ph[2], pl[2]);
            split2(sc[2 * kbk + 1][2], sc[2 * kbk + 1][3], ph[3], pl[3]);
#pragma unroll
            for (int g = 0; g < 8; g++) {
                uint32_t r0, r1, r2, r3;
                ldsm4t(r0, r1, r2, r3,
                       kb + seg + bVoff + kbk * 16 * LPAD * 2 + g * 32);
                uint32_t b0[2] = {r0, r1}, b1[2] = {r2, r3};
                mma16816(out[2 * g], ph, b0);     mma16816(out[2 * g + 1], ph, b1);
                mma16816(out[2 * g], pl, b0);     mma16816(out[2 * g + 1], pl, b1);
            }
        }
        __syncthreads();
    }

    const float inv0 = 1.f / l0, inv1 = 1.f / l1;
#pragma unroll
    for (int nt = 0; nt < 16; nt++) {
        *(float2*)(g_ctx + (size_t)tg0 * CC + h * DD + nt * 8 + cq) =
            make_float2(out[nt][0] * inv0, out[nt][1] * inv0);
        *(float2*)(g_ctx + (size_t)tg1 * CC + h * DD + nt * 8 + cq) =
            make_float2(out[nt][2] * inv1, out[nt][3] * inv1);
    }
}

// ============================================================================
// Global low-rank attention: Sq=128, 8 warps, double-buffered KV_r (hi only),
// gated epilogue O @ uo^T; writes final ctx as fp16 hi/lo splits.
// smem = 73728 B -> 2 CTAs/SM.
// ============================================================================
#define GPAD 72
__global__ __launch_bounds__(256) void global_attn_mma()
{
    extern __shared__ __align__(16) char smraw[];
    const uint32_t sb = smem_u32(smraw);
    const uint32_t oQl = 128 * GPAD * 2;
    const uint32_t kvBase = 2 * 128 * GPAD * 2;
    const uint32_t kvStage = 2 * 64 * GPAD * 2;
    const uint32_t seg = 64 * GPAD * 2;
    const uint32_t oUh = kvBase;

    const int tid = threadIdx.x, lane = tid & 31, w = tid >> 5;
    const int qt = blockIdx.x, h = blockIdx.y, t0 = qt << 7;
    const int aj = lane >> 3, ar = lane & 7;
    const int tg0 = t0 + w * 16 + (lane >> 2), tg1 = tg0 + 8;
    const int cq = (lane & 3) * 2;

    for (int i = tid; i < 1024; i += 256) {
        int r = i >> 3, q = i & 7;
        uint32_t so = sb + (r * GPAD + q * 8) * 2;
        size_t go = (size_t)(h * TT + t0 + r) * RR + q * 8;
        CP16(so, g_qrh + go);
        CP16(so + oQl, g_qrl + go);
    }
    CP_COMMIT();

    auto issueKV = [&](int kt, int s) {
        const int s0 = kt << 6;
        const uint32_t kb = sb + kvBase + s * kvStage;
        for (int i = tid; i < 512; i += 256) {
            int r = i >> 3, q = i & 7;
            size_t gk = (size_t)(h * TT + s0 + r) * RR + q * 8;
            uint32_t off = (r * GPAD + q * 8) * 2;
            CP16(kb + off,       g_krh + gk);
            CP16(kb + seg + off, g_vrh + gk);
        }
        CP_COMMIT();
    };
    issueKV(0, 0);

    float m0 = -1e30f, m1 = -1e30f, l0 = 0.f, l1 = 0.f;
    float out[8][4];
#pragma unroll
    for (int nt = 0; nt < 8; nt++)
#pragma unroll
        for (int e = 0; e < 4; e++) out[nt][e] = 0.f;

    const uint32_t aQoff = ((w * 16 + (aj & 1) * 8 + ar) * GPAD + (aj >> 1) * 8) * 2;
    const uint32_t bKoff = (((aj >> 1) * 8 + ar) * GPAD + (aj & 1) * 8) * 2;
    const uint32_t bVoff = (((aj & 1) * 8 + ar) * GPAD + (aj >> 1) * 8) * 2;

    for (int kt = 0; kt < TT / 64; kt++) {
        const int s = kt & 1;
        if (kt < TT / 64 - 1) { issueKV(kt + 1, s ^ 1); CP_WAIT(1); }
        else                  { CP_WAIT(0); }
        __syncthreads();
        const uint32_t kb = sb + kvBase + s * kvStage;

        float sc[8][4];
#pragma unroll
        for (int nt = 0; nt < 8; nt++)
#pragma unroll
            for (int e = 0; e < 4; e++) sc[nt][e] = 0.f;

#pragma unroll
        for (int kbk = 0; kbk < 4; kbk++) {
            uint32_t ah[4], al_[4], b2[8][2];
            ldsm4(ah[0], ah[1], ah[2], ah[3], sb + aQoff + kbk * 32);
            ldsm4(al_[0], al_[1], al_[2], al_[3], sb + oQl + aQoff + kbk * 32);
#pragma unroll
            for (int np = 0; np < 4; np++) {
                uint32_t r0, r1, r2, r3;
                ldsm4(r0, r1, r2, r3, kb + bKoff + np * 16 * GPAD * 2 + kbk * 32);
                b2[np * 2][0] = r0;     b2[np * 2][1] = r1;
                b2[np * 2 + 1][0] = r2; b2[np * 2 + 1][1] = r3;
            }
#pragma unroll
            for (int nt = 0; nt < 8; nt++) {
                mma16816(sc[nt], ah, b2[nt]);
                mma16816(sc[nt], al_, b2[nt]);
            }
        }

        float mx0 = -1e30f, mx1 = -1e30f;
#pragma unroll
        for (int nt = 0; nt < 8; nt++) {
            sc[nt][0] *= SCALE_G; sc[nt][1] *= SCALE_G;
            sc[nt][2] *= SCALE_G; sc[nt][3] *= SCALE_G;
            mx0 = fmaxf(mx0, fmaxf(sc[nt][0], sc[nt][1]));
            mx1 = fmaxf(mx1, fmaxf(sc[nt][2], sc[nt][3]));
        }
        mx0 = fmaxf(mx0, __shfl_xor_sync(0xffffffffu, mx0, 1));
        mx0 = fmaxf(mx0, __shfl_xor_sync(0xffffffffu, mx0, 2));
        mx1 = fmaxf(mx1, __shfl_xor_sync(0xffffffffu, mx1, 1));
        mx1 = fmaxf(mx1, __shfl_xor_sync(0xffffffffu, mx1, 2));
        float mn0 = fmaxf(m0, mx0), mn1 = fmaxf(m1, mx1);
        float al0 = __expf(m0 - mn0), al1 = __expf(m1 - mn1);
        m0 = mn0; m1 = mn1;

        float sum0 = 0.f, sum1 = 0.f;
#pragma unroll
        for (int nt = 0; nt < 8; nt++) {
#pragma unroll
            for (int e = 0; e < 2; e++) {
                float p0 = __expf(sc[nt][e] - mn0);
                float p1 = __expf(sc[nt][2 + e] - mn1);
                sc[nt][e] = p0; sc[nt][2 + e] = p1;
                sum0 += p0; sum1 += p1;
            }
        }
        sum0 += __shfl_xor_sync(0xffffffffu, sum0, 1);
        sum0 += __shfl_xor_sync(0xffffffffu, sum0, 2);
        sum1 += __shfl_xor_sync(0xffffffffu, sum1, 1);
        sum1 += __shfl_xor_sync(0xffffffffu, sum1, 2);
        l0 = l0 * al0 + sum0;
        l1 = l1 * al1 + sum1;

#pragma unroll
        for (int nt = 0; nt < 8; nt++) {
            out[nt][0] *= al0; out[nt][1] *= al0;
            out[nt][2] *= al1; out[nt][3] *= al1;
        }

#pragma unroll
        for (int kbk = 0; kbk < 4; kbk++) {
            uint32_t ph[4], pl[4];
            split2(sc[2 * kbk][0],     sc[2 * kbk][1],     ph[0], pl[0]);
            split2(sc[2 * kbk][2],     sc[2 * kbk][3],     ph[1], pl[1]);
            split2(sc[2 * kbk + 1][0], sc[2 * kbk + 1][1], ph[2], pl[2]);
            split2(sc[2 * kbk + 1][2], sc[2 * kbk + 1][3], ph[3], pl[3]);
#pragma unroll
            for (int g = 0; g < 4; g++) {
                uint32_t r0, r1, r2, r3;
                ldsm4t(r0, r1, r2, r3,
                       kb + seg + bVoff + kbk * 16 * GPAD * 2 + g * 32);
                uint32_t b0[2] = {r0, r1}, b1[2] = {r2, r3};
                mma16816(out[2 * g], ph, b0);     mma16816(out[2 * g + 1], ph, b1);
                mma16816(out[2 * g], pl, b0);     mma16816(out[2 * g + 1], pl, b1);
            }
        }
        __syncthreads();
    }

    const float inv0 = 1.f / l0, inv1 = 1.f / l1;
#pragma unroll
    for (int nt = 0; nt < 8; nt++) {
        out[nt][0] *= inv0; out[nt][1] *= inv0;
        out[nt][2] *= inv1; out[nt][3] *= inv1;
    }

    for (int i = tid; i < 1024; i += 256) {
        int d = i >> 3, q = i & 7;
        *(int4*)(smraw + oUh + (d * GPAD + q * 8) * 2) =
            *(const int4*)(g_uoh + d * 64 + q * 8);
    }
    __syncthreads();

    float out2[16][4];
#pragma unroll
    for (int nt = 0; nt < 16; nt++)
#pragma unroll
        for (int e = 0; e < 4; e++) out2[nt][e] = 0.f;

    const uint32_t bUoff = (((aj >> 1) * 8 + ar) * GPAD + (aj & 1) * 8) * 2;
#pragma unroll
    for (int kbk = 0; kbk < 4; kbk++) {
        uint32_t ph[4], pl[4];
        split2(out[2 * kbk][0],     out[2 * kbk][1],     ph[0], pl[0]);
        split2(out[2 * kbk][2],     out[2 * kbk][3],     ph[1], pl[1]);
        split2(out[2 * kbk + 1][0], out[2 * kbk + 1][1], ph[2], pl[2]);
        split2(out[2 * kbk + 1][2], out[2 * kbk + 1][3], ph[3], pl[3]);
#pragma unroll
        for (int g = 0; g < 8; g++) {
            uint32_t r0, r1, r2, r3;
            ldsm4(r0, r1, r2, r3, sb + oUh + bUoff + g * 16 * GPAD * 2 + kbk * 32);
            uint32_t b0[2] = {r0, r1}, b1[2] = {r2, r3};
            mma16816(out2[2 * g], ph, b0);     mma16816(out2[2 * g + 1], ph, b1);
            mma16816(out2[2 * g], pl, b0);     mma16816(out2[2 * g + 1], pl, b1);
        }
    }

    const float ga0 = g_gate[tg0], ga1 = g_gate[tg1];
#pragma unroll
    for (int nt = 0; nt < 16; nt++) {
        size_t i0 = (size_t)tg0 * CC + h * DD + nt * 8 + cq;
        float2 o0 = *(float2*)(g_ctx + i0);
        uint32_t hh, ll;
        split2(o0.x + ga0 * out2[nt][0], o0.y + ga0 * out2[nt][1], hh, ll);
        *(uint32_t*)(g_cxh + i0) = hh;
        *(uint32_t*)(g_cxl + i0) = ll;
        size_t i1 = (size_t)tg1 * CC + h * DD + nt * 8 + cq;
        float2 o1 = *(float2*)(g_ctx + i1);
        split2(o1.x + ga1 * out2[nt][2], o1.y + ga1 * out2[nt][3], hh, ll);
        *(uint32_t*)(g_cxh + i1) = hh;
        *(uint32_t*)(g_cxl + i1) = ll;
    }
}

// ============================================================================
extern "C" void kernel_launch(void* const* d_in, const int* in_sizes, int n_in,
                              void* d_out, int out_size)
{
    const float* x     = (const float*)d_in[0];
    const float* w_qkv = (const float*)d_in[1];
    const float* w_o   = (const float*)d_in[2];
    const float* pk    = (const float*)d_in[3];
    const float* pv    = (const float*)d_in[4];
    const float* uo    = (const float*)d_in[5];
    const float* iw1   = (const float*)d_in[6];
    const float* iw2   = (const float*)d_in[7];
    float* out = (float*)d_out;

    cudaFuncSetAttribute(gemm_mma256,     cudaFuncAttributeMaxDynamicSharedMemorySize, 81920);
    cudaFuncSetAttribute(gemm_info,       cudaFuncAttributeMaxDynamicSharedMemorySize, 61440);
    cudaFuncSetAttribute(local_attn_mma,  cudaFuncAttributeMaxDynamicSharedMemorySize, 104448);
    cudaFuncSetAttribute(global_attn_mma, cudaFuncAttributeMaxDynamicSharedMemorySize, 73728);
    cudaFuncSetAttribute(lowrank_mma,     cudaFuncAttributeMaxDynamicSharedMemorySize, 52224);

    void *pxh, *pxl, *pwqh, *pwoh, *pi1h, *pcxh, *pcxl, *pqkvh, *pqkvl;
    cudaGetSymbolAddress(&pxh, g_xh);   cudaGetSymbolAddress(&pxl, g_xl);
    cudaGetSymbolAddress(&pwqh, g_wqh);
    cudaGetSymbolAddress(&pwoh, g_woh);
    cudaGetSymbolAddress(&pi1h, g_i1h);
    cudaGetSymbolAddress(&pcxh, g_cxh); cudaGetSymbolAddress(&pcxl, g_cxl);
    cudaGetSymbolAddress(&pqkvh, g_qkvh); cudaGetSymbolAddress(&pqkvl, g_qkvl);

    rope_table_k<<<TT, DD>>>();
    split_h2_k<<<(TT * CC / 2 + 255) / 256, 256>>>(
        (const float2*)x, (__half2*)pxh, (__half2*)pxl, TT * CC / 2);
    conv_all_k<<<(CS6 + 255) / 256, 256>>>(
        (const float2*)w_qkv, (const float2*)iw1, (const float2*)w_o,
        (const float2*)uo, (const float2*)pk, (const float2*)pv);

    // qkv = rope(x @ w_qkv^T) -> fp16 splits (512-thread GEMM)
    gemm_mma256<<<dim3(C3 / 256, TT / 128), 512, 81920>>>(
        (const __half*)pxh, (const __half*)pxl, (const __half*)pwqh,
        nullptr, (__half*)pqkvh, (__half*)pqkvl, C3, CC, 2);

    // info gate: GEMM + fused gelu/dot partials, then finalize
    gemm_info<<<dim3(CI / 128, TT / 128), 256, 61440>>>(
        (const __half*)pxh, (const __half*)pxl, (const __half*)pi1h,
        iw2, CI, CC);
    gate_fin_k<<<TT / 256, 256>>>();

    lowrank_mma<<<dim3(TT / 64, HH), 128, 52224>>>();
    local_attn_mma<<<dim3(TT / 64, HH), 128, 104448>>>();
    global_attn_mma<<<dim3(TT / 128, HH), 256, 73728>>>();

    // out = ctx @ w_o^T (512-thread GEMM)
    gemm_mma256<<<dim3(CC / 256, TT / 128), 512, 81920>>>(
        (const __half*)pcxh, (const __half*)pcxl, (const __half*)pwoh,
        out, nullptr, nullptr, CC, CC, 0);
}

// round 11
// speedup vs baseline: 6.1695x; 1.3439x over previous
#include <cuda_runtime.h>
#include <cuda_fp16.h>
#include <math.h>
#include <stdint.h>

#define TT   2048
#define CC   2048
#define HH   16
#define DD   128
#define RR   64
#define WLOC 512
#define CI   512
#define C3   6144

#define SCALE_L 0.08838834764831845f
#define SCALE_G 0.1767766952966369f

// ---------------- scratch (device globals) ----------------
__device__ float g_gatez[4 * TT];
__device__ float g_gate[TT];
__device__ float g_cos[TT * DD];
__device__ float g_sin[TT * DD];
__device__ float g_ctx[TT * CC];

// fp16 operands. A-side 2-term splits kept only where they matter
// (attention Q path via qkv splits); big GEMMs run 1-term.
__device__ __half g_xh[TT * CC];
__device__ __half g_wqh[C3 * CC];
__device__ __half g_woh[CC * CC];
__device__ __half g_i1h[CI * CC];
__device__ __half g_cxh[TT * CC];
__device__ __half g_qkvh[TT * C3], g_qkvl[TT * C3];
__device__ __half g_qrh[HH * TT * RR], g_qrl[HH * TT * RR];
__device__ __half g_krh[HH * TT * RR];
__device__ __half g_vrh[HH * TT * RR];
__device__ __half g_uoh[DD * RR];
__device__ __half g_pkh[RR * DD];
__device__ __half g_pvh[RR * DD];

// ============================================================================
// PTX helpers (plain sm_80+ ISA)
// ============================================================================
__device__ __forceinline__ uint32_t smem_u32(const void* p) {
    uint32_t a;
    asm("{ .reg .u64 t; cvta.to.shared.u64 t, %1; cvt.u32.u64 %0, t; }"
        : "=r"(a) : "l"(p));
    return a;
}

#define CP16(s, g) \
    asm volatile("cp.async.cg.shared.global [%0], [%1], 16;" \
                 :: "r"(s), "l"(g) : "memory")
#define CP_COMMIT() asm volatile("cp.async.commit_group;" ::: "memory")
#define CP_WAIT(n)  asm volatile("cp.async.wait_group %0;" :: "n"(n) : "memory")

__device__ __forceinline__ void ldsm4(uint32_t& r0, uint32_t& r1,
                                      uint32_t& r2, uint32_t& r3, uint32_t a) {
    asm volatile("ldmatrix.sync.aligned.m8n8.x4.shared.b16 {%0,%1,%2,%3}, [%4];"
                 : "=r"(r0), "=r"(r1), "=r"(r2), "=r"(r3) : "r"(a));
}
__device__ __forceinline__ void ldsm4t(uint32_t& r0, uint32_t& r1,
                                       uint32_t& r2, uint32_t& r3, uint32_t a) {
    asm volatile("ldmatrix.sync.aligned.m8n8.x4.trans.shared.b16 {%0,%1,%2,%3}, [%4];"
                 : "=r"(r0), "=r"(r1), "=r"(r2), "=r"(r3) : "r"(a));
}

__device__ __forceinline__ void mma16816(float* c, const uint32_t* a,
                                         const uint32_t* b) {
    asm volatile("mma.sync.aligned.m16n8k16.row.col.f32.f16.f16.f32 "
                 "{%0,%1,%2,%3}, {%4,%5,%6,%7}, {%8,%9}, {%0,%1,%2,%3};"
                 : "+f"(c[0]), "+f"(c[1]), "+f"(c[2]), "+f"(c[3])
                 : "r"(a[0]), "r"(a[1]), "r"(a[2]), "r"(a[3]),
                   "r"(b[0]), "r"(b[1]));
}

__device__ __forceinline__ void split2(float x, float y, uint32_t& h, uint32_t& l) {
    __half2 hh = __floats2half2_rn(x, y);
    h = *reinterpret_cast<uint32_t*>(&hh);
    __half2 ll = __floats2half2_rn(x - __low2float(hh), y - __high2float(hh));
    l = *reinterpret_cast<uint32_t*>(&ll);
}

// ============================================================================
// Fused fp32 -> fp16 convert of x + ALL weight regions (one launch)
// ============================================================================
#define CS0 (TT * CC / 2)
#define CS1 (CS0 + C3 * CC / 2)
#define CS2 (CS1 + CI * CC / 2)
#define CS3 (CS2 + CC * CC / 2)
#define CS4 (CS3 + DD * RR / 2)
#define CS5 (CS4 + RR * DD / 2)
#define CS6 (CS5 + RR * DD / 2)
__global__ void conv_all_k(const float2* __restrict__ x,
                           const float2* __restrict__ wq,
                           const float2* __restrict__ i1,
                           const float2* __restrict__ wo,
                           const float2* __restrict__ uo,
                           const float2* __restrict__ pk,
                           const float2* __restrict__ pv)
{
    int i = blockIdx.x * 256 + threadIdx.x;
    const float2* s; __half2* d; int j;
    if      (i < CS0) { s = x;  d = (__half2*)g_xh;  j = i; }
    else if (i < CS1) { s = wq; d = (__half2*)g_wqh; j = i - CS0; }
    else if (i < CS2) { s = i1; d = (__half2*)g_i1h; j = i - CS1; }
    else if (i < CS3) { s = wo; d = (__half2*)g_woh; j = i - CS2; }
    else if (i < CS4) { s = uo; d = (__half2*)g_uoh; j = i - CS3; }
    else if (i < CS5) { s = pk; d = (__half2*)g_pkh; j = i - CS4; }
    else if (i < CS6) { s = pv; d = (__half2*)g_pvh; j = i - CS5; }
    else return;
    float2 v = s[j];
    d[j] = __floats2half2_rn(v.x, v.y);
}

// ============================================================================
// mma.sync GEMM, 1-term fp16: C = Ah·Bh^T.
// BM=128, BN=256, BK=32; 512 threads (warps 4x4, warp tile 32x64).
// smem/stage: Ah 10240 | Bh 20480 = 30720; x2 = 61440.
// mode 0: fp32 store. mode 2: rope + fp16 hi/lo store.
// ============================================================================
__global__ __launch_bounds__(512) void gemm_mma256(
    const __half* __restrict__ Ah, const __half* __restrict__ Bh,
    float* __restrict__ Cout,
    __half* __restrict__ Ch, __half* __restrict__ Cl,
    int N, int K, int mode)
{
    extern __shared__ __align__(128) char smraw[];
    const uint32_t sb = smem_u32(smraw);
    const int tid = threadIdx.x, lane = tid & 31, wid = tid >> 5;
    const int wm = wid & 3, wn = wid >> 2;
    const int bm = blockIdx.y << 7, bn = blockIdx.x << 8;
    const int aj = lane >> 3, ar = lane & 7;

    float acc[2][8][4];
#pragma unroll
    for (int mt = 0; mt < 2; mt++)
#pragma unroll
        for (int nt = 0; nt < 8; nt++)
#pragma unroll
            for (int e = 0; e < 4; e++) acc[mt][nt][e] = 0.f;

    const int nch = K >> 5;

    auto issue_stage = [&](int c) {
        const uint32_t st = sb + (c & 1) * 30720;
        const int k0 = c << 5;
        {
            int r = tid >> 2, q = tid & 3;
            CP16(st + r * 80 + q * 16, Ah + (size_t)(bm + r) * K + k0 + q * 8);
        }
        {
            const __half* gh = Bh + (size_t)bn * K + k0;
#pragma unroll
            for (int hh = 0; hh < 2; hh++) {
                int i = tid + hh * 512;
                int r = i >> 2, q = i & 3;
                CP16(st + 10240 + r * 80 + q * 16, gh + (size_t)r * K + q * 8);
            }
        }
        CP_COMMIT();
    };

    issue_stage(0);
    for (int c = 0; c < nch; c++) {
        if (c + 1 < nch) { issue_stage(c + 1); CP_WAIT(1); }
        else             { CP_WAIT(0); }
        __syncthreads();

        const uint32_t st = sb + (c & 1) * 30720;
#pragma unroll
        for (int ks = 0; ks < 2; ks++) {
            uint32_t ah[2][4], b2[8][2];
            const uint32_t a_off =
                ((wm * 32 + (aj & 1) * 8 + ar) * 40 + ks * 16 + (aj >> 1) * 8) * 2;
            const uint32_t b_off =
                ((wn * 64 + (aj >> 1) * 8 + ar) * 40 + ks * 16 + (aj & 1) * 8) * 2;

#pragma unroll
            for (int mt = 0; mt < 2; mt++)
                ldsm4(ah[mt][0], ah[mt][1], ah[mt][2], ah[mt][3],
                      st + a_off + mt * (16 * 80));
#pragma unroll
            for (int np = 0; np < 4; np++) {
                uint32_t r0, r1, r2, r3;
                ldsm4(r0, r1, r2, r3, st + 10240 + b_off + np * (16 * 80));
                b2[np * 2][0] = r0;     b2[np * 2][1] = r1;
                b2[np * 2 + 1][0] = r2; b2[np * 2 + 1][1] = r3;
            }
#pragma unroll
            for (int mt = 0; mt < 2; mt++)
#pragma unroll
                for (int nt = 0; nt < 8; nt++)
                    mma16816(acc[mt][nt], ah[mt], b2[nt]);
        }
        __syncthreads();
    }

    const int row_base = bm + wm * 32 + (lane >> 2);
    const int col_base = bn + wn * 64 + (lane & 3) * 2;
#pragma unroll
    for (int mt = 0; mt < 2; mt++)
#pragma unroll
        for (int nt = 0; nt < 8; nt++) {
            int r0 = row_base + mt * 16, cc = col_base + nt * 8;
            float v0 = acc[mt][nt][0], v1 = acc[mt][nt][1];
            float v2 = acc[mt][nt][2], v3 = acc[mt][nt][3];
            if (mode == 2) {
                if (cc < 2 * CC) {
                    int d0 = cc & 127;
                    float2 cA = *(const float2*)(g_cos + r0 * DD + d0);
                    float2 sA = *(const float2*)(g_sin + r0 * DD + d0);
                    float o0 = v0 * cA.x - v1 * sA.x;
                    float o1 = v1 * cA.y + v0 * sA.y;
                    float2 cB = *(const float2*)(g_cos + (r0 + 8) * DD + d0);
                    float2 sB = *(const float2*)(g_sin + (r0 + 8) * DD + d0);
                    float o2 = v2 * cB.x - v3 * sB.x;
                    float o3 = v3 * cB.y + v2 * sB.y;
                    v0 = o0; v1 = o1; v2 = o2; v3 = o3;
                }
                uint32_t h01, l01, h23, l23;
                split2(v0, v1, h01, l01);
                split2(v2, v3, h23, l23);
                *(uint32_t*)(Ch + (size_t)r0 * N + cc)       = h01;
                *(uint32_t*)(Cl + (size_t)r0 * N + cc)       = l01;
                *(uint32_t*)(Ch + (size_t)(r0 + 8) * N + cc) = h23;
                *(uint32_t*)(Cl + (size_t)(r0 + 8) * N + cc) = l23;
            } else {
                *(float2*)(Cout + (size_t)r0 * N + cc)       = make_float2(v0, v1);
                *(float2*)(Cout + (size_t)(r0 + 8) * N + cc) = make_float2(v2, v3);
            }
        }
}

// ============================================================================
// Info GEMM (BN=128, 1-term fp16) with fused gelu + dot(w2) gate partials.
// smem/stage: Ah 10240 | Bh 10240 = 20480; x2 = 40960.
// ============================================================================
__global__ __launch_bounds__(256) void gemm_info(
    const __half* __restrict__ Ah, const __half* __restrict__ Bh,
    const float* __restrict__ w2, int N, int K)
{
    extern __shared__ __align__(128) char smraw[];
    const uint32_t sb = smem_u32(smraw);
    const int tid = threadIdx.x, lane = tid & 31, wid = tid >> 5;
    const int wm = wid & 3, wn = wid >> 2;
    const int bm = blockIdx.y << 7, bn = blockIdx.x << 7;
    const int aj = lane >> 3, ar = lane & 7;

    float acc[2][8][4];
#pragma unroll
    for (int mt = 0; mt < 2; mt++)
#pragma unroll
        for (int nt = 0; nt < 8; nt++)
#pragma unroll
            for (int e = 0; e < 4; e++) acc[mt][nt][e] = 0.f;

    const int nch = K >> 5;

    auto issue_stage = [&](int c) {
        const uint32_t st = sb + (c & 1) * 20480;
        const int k0 = c << 5;
        const __half* gm0 = Ah + (size_t)bm * K + k0;
        const __half* gm2 = Bh + (size_t)bn * K + k0;
#pragma unroll
        for (int h = 0; h < 2; h++) {
            int i = tid + h * 256;
            int r = i >> 2, q = i & 3;
            uint32_t so = st + r * 80 + q * 16;
            size_t go = (size_t)r * K + q * 8;
            CP16(so,          gm0 + go);
            CP16(so + 10240,  gm2 + go);
        }
        CP_COMMIT();
    };

    issue_stage(0);
    for (int c = 0; c < nch; c++) {
        if (c + 1 < nch) { issue_stage(c + 1); CP_WAIT(1); }
        else             { CP_WAIT(0); }
        __syncthreads();

        const uint32_t st = sb + (c & 1) * 20480;
#pragma unroll
        for (int ks = 0; ks < 2; ks++) {
            uint32_t ah[2][4], b2[8][2];
            const uint32_t a_off =
                ((wm * 32 + (aj & 1) * 8 + ar) * 40 + ks * 16 + (aj >> 1) * 8) * 2;
            const uint32_t b_off =
                ((wn * 64 + (aj >> 1) * 8 + ar) * 40 + ks * 16 + (aj & 1) * 8) * 2;

#pragma unroll
            for (int mt = 0; mt < 2; mt++)
                ldsm4(ah[mt][0], ah[mt][1], ah[mt][2], ah[mt][3],
                      st + a_off + mt * (16 * 80));
#pragma unroll
            for (int np = 0; np < 4; np++) {
                uint32_t r0, r1, r2, r3;
                ldsm4(r0, r1, r2, r3, st + 10240 + b_off + np * (16 * 80));
                b2[np * 2][0] = r0;     b2[np * 2][1] = r1;
                b2[np * 2 + 1][0] = r2; b2[np * 2 + 1][1] = r3;
            }
#pragma unroll
            for (int mt = 0; mt < 2; mt++)
#pragma unroll
                for (int nt = 0; nt < 8; nt++)
                    mma16816(acc[mt][nt], ah[mt], b2[nt]);
        }
        __syncthreads();
    }

    const int col_base = wn * 64 + (lane & 3) * 2;
    float z[2][2] = {{0.f, 0.f}, {0.f, 0.f}};
#pragma unroll
    for (int mt = 0; mt < 2; mt++)
#pragma unroll
        for (int nt = 0; nt < 8; nt++) {
            int cc = col_base + nt * 8;
            float w0 = w2[cc], w1 = w2[cc + 1];
            float v0 = acc[mt][nt][0], v1 = acc[mt][nt][1];
            float v2 = acc[mt][nt][2], v3 = acc[mt][nt][3];
            v0 = 0.5f * v0 * (1.0f + erff(v0 * 0.7071067811865475f));
            v1 = 0.5f * v1 * (1.0f + erff(v1 * 0.7071067811865475f));
            v2 = 0.5f * v2 * (1.0f + erff(v2 * 0.7071067811865475f));
            v3 = 0.5f * v3 * (1.0f + erff(v3 * 0.7071067811865475f));
            z[mt][0] += v0 * w0 + v1 * w1;
            z[mt][1] += v2 * w0 + v3 * w1;
        }
#pragma unroll
    for (int mt = 0; mt < 2; mt++)
#pragma unroll
        for (int e = 0; e < 2; e++) {
            z[mt][e] += __shfl_xor_sync(0xffffffffu, z[mt][e], 1);
            z[mt][e] += __shfl_xor_sync(0xffffffffu, z[mt][e], 2);
        }
    float* zs = (float*)smraw;
    if ((lane & 3) == 0) {
        int lr = wm * 32 + (lane >> 2);
        zs[wn * 128 + lr +  0] = z[0][0];
        zs[wn * 128 + lr +  8] = z[0][1];
        zs[wn * 128 + lr + 16] = z[1][0];
        zs[wn * 128 + lr + 24] = z[1][1];
    }
    __syncthreads();
    if (tid < 128)
        g_gatez[blockIdx.x * TT + bm + tid] = zs[tid] + zs[128 + tid];
}

__global__ void gate_fin_k()
{
    int t = blockIdx.x * 256 + threadIdx.x;
    float zsum = g_gatez[t] + g_gatez[TT + t] + g_gatez[2 * TT + t]
               + g_gatez[3 * TT + t];
    float sc = 1.0f / (1.0f + expf(-zsum));
    g_gate[t] = (sc > 0.75f) ? 1.0f : 0.0f;
}

// ============================================================================
// RoPE tables (fp32)
// ============================================================================
__global__ void rope_table_k()
{
    int t = blockIdx.x, d = threadIdx.x;
    int j = d & 63;
    float inv = exp2f(-(float)j * 0.20762050593046014f);
    float ang = (float)t * inv;
    g_cos[t * DD + d] = cosf(ang);
    g_sin[t * DD + d] = sinf(ang);
}

// ============================================================================
// Low-rank projections (2-term fp16, Q-side correction kept)
// ============================================================================
__global__ __launch_bounds__(128) void lowrank_mma()
{
    extern __shared__ __align__(16) char smraw[];
    const uint32_t sb = smem_u32(smraw);
    const uint32_t oAl = 64 * 136 * 2, oPh = 2 * 64 * 136 * 2;
    const int tid = threadIdx.x, lane = tid & 31, w = tid >> 5;
    const int qt = blockIdx.x, h = blockIdx.y, t0 = qt << 6;
    const int aj = lane >> 3, ar = lane & 7;

    const uint32_t aoff = ((w * 16 + (aj & 1) * 8 + ar) * 136 + (aj >> 1) * 8) * 2;
    const uint32_t boff = (((aj >> 1) * 8 + ar) * 136 + (aj & 1) * 8) * 2;
    const int row0 = t0 + w * 16 + (lane >> 2);
    const int col = (lane & 3) * 2;

    for (int pass = 0; pass < 3; pass++) {
        const __half* Ph = (pass == 2) ? g_pvh : g_pkh;
        const int off = pass * CC + h * DD;
        __syncthreads();
        for (int i = tid; i < 1024; i += 128) {
            int r = i >> 4, q = i & 15;
            uint32_t so = (r * 136 + q * 8) * 2;
            size_t ga = (size_t)(t0 + r) * C3 + off + q * 8;
            CP16(sb + so,       g_qkvh + ga);
            CP16(sb + oAl + so, g_qkvl + ga);
            CP16(sb + oPh + so, Ph + r * DD + q * 8);
        }
        CP_COMMIT(); CP_WAIT(0);
        __syncthreads();

        float acc[8][4];
#pragma unroll
        for (int nt = 0; nt < 8; nt++)
#pragma unroll
            for (int e = 0; e < 4; e++) acc[nt][e] = 0.f;

#pragma unroll
        for (int kb = 0; kb < 8; kb++) {
            uint32_t ah[4], al_[4], b2[8][2];
            ldsm4(ah[0], ah[1], ah[2], ah[3], sb + aoff + kb * 32);
            ldsm4(al_[0], al_[1], al_[2], al_[3], sb + oAl + aoff + kb * 32);
#pragma unroll
            for (int np = 0; np < 4; np++) {
                uint32_t r0, r1, r2, r3;
                ldsm4(r0, r1, r2, r3, sb + oPh + boff + np * 16 * 136 * 2 + kb * 32);
                b2[np * 2][0] = r0;     b2[np * 2][1] = r1;
                b2[np * 2 + 1][0] = r2; b2[np * 2 + 1][1] = r3;
            }
#pragma unroll
            for (int nt = 0; nt < 8; nt++) {
                mma16816(acc[nt], ah, b2[nt]);
                mma16816(acc[nt], al_, b2[nt]);
            }
        }

        if (pass == 0) {
#pragma unroll
            for (int nt = 0; nt < 8; nt++) {
                uint32_t hh, ll;
                size_t i0 = (size_t)(h * TT + row0) * RR + nt * 8 + col;
                split2(acc[nt][0], acc[nt][1], hh, ll);
                *(uint32_t*)(g_qrh + i0) = hh;
                *(uint32_t*)(g_qrl + i0) = ll;
                size_t i1 = i0 + 8 * RR;
                split2(acc[nt][2], acc[nt][3], hh, ll);
                *(uint32_t*)(g_qrh + i1) = hh;
                *(uint32_t*)(g_qrl + i1) = ll;
            }
        } else {
            __half* dh = (pass == 1) ? g_krh : g_vrh;
#pragma unroll
            for (int nt = 0; nt < 8; nt++) {
                size_t i0 = (size_t)(h * TT + row0) * RR + nt * 8 + col;
                __half2 a = __floats2half2_rn(acc[nt][0], acc[nt][1]);
                *(uint32_t*)(dh + i0) = *(uint32_t*)&a;
                size_t i1 = i0 + 8 * RR;
                __half2 b = __floats2half2_rn(acc[nt][2], acc[nt][3]);
                *(uint32_t*)(dh + i1) = *(uint32_t*)&b;
            }
        }
    }
}

// ============================================================================
// Local sliding-window attention: Sq=64, 4 warps, double-buffered KV (hi only).
// smem = 104448 B -> 2 CTAs/SM.
// ============================================================================
#define LPAD 136
__global__ __launch_bounds__(128) void local_attn_mma()
{
    extern __shared__ __align__(16) char smraw[];
    const uint32_t sb = smem_u32(smraw);
    const uint32_t oQl = 64 * LPAD * 2;
    const uint32_t kvBase = 2 * 64 * LPAD * 2;
    const uint32_t kvStage = 2 * 64 * LPAD * 2;
    const uint32_t seg = 64 * LPAD * 2;

    const int tid = threadIdx.x, lane = tid & 31, w = tid >> 5;
    const int qt = gridDim.x - 1 - blockIdx.x, h = blockIdx.y;
    const int t0 = qt << 6;
    const int aj = lane >> 3, ar = lane & 7;
    const int tg0 = t0 + w * 16 + (lane >> 2), tg1 = tg0 + 8;
    const int cq = (lane & 3) * 2;

    for (int i = tid; i < 1024; i += 128) {
        int r = i >> 4, q = i & 15;
        uint32_t so = sb + (r * LPAD + q * 8) * 2;
        size_t go = (size_t)(t0 + r) * C3 + h * DD + q * 8;
        CP16(so, g_qkvh + go);
        CP16(so + oQl, g_qkvl + go);
    }
    CP_COMMIT();

    const int kt0 = (t0 > WLOC - 1) ? ((t0 - (WLOC - 1)) >> 6) : 0;
    const int ktend = qt;

    auto issueKV = [&](int kt, int s) {
        const int s0 = kt << 6;
        const uint32_t kb = sb + kvBase + s * kvStage;
        for (int i = tid; i < 1024; i += 128) {
            int r = i >> 4, q = i & 15;
            size_t gk = (size_t)(s0 + r) * C3 + CC + h * DD + q * 8;
            uint32_t off = (r * LPAD + q * 8) * 2;
            CP16(kb + off,       g_qkvh + gk);
            CP16(kb + seg + off, g_qkvh + gk + CC);
        }
        CP_COMMIT();
    };
    issueKV(kt0, 0);

    float m0 = -1e30f, m1 = -1e30f, l0 = 0.f, l1 = 0.f;
    float out[16][4];
#pragma unroll
    for (int nt = 0; nt < 16; nt++)
#pragma unroll
        for (int e = 0; e < 4; e++) out[nt][e] = 0.f;

    const uint32_t aQoff = ((w * 16 + (aj & 1) * 8 + ar) * LPAD + (aj >> 1) * 8) * 2;
    const uint32_t bKoff = (((aj >> 1) * 8 + ar) * LPAD + (aj & 1) * 8) * 2;
    const uint32_t bVoff = (((aj & 1) * 8 + ar) * LPAD + (aj >> 1) * 8) * 2;

    for (int kt = kt0; kt <= ktend; kt++) {
        const int s = (kt - kt0) & 1;
        if (kt < ktend) { issueKV(kt + 1, s ^ 1); CP_WAIT(1); }
        else            { CP_WAIT(0); }
        __syncthreads();
        const uint32_t kb = sb + kvBase + s * kvStage;
        const int s0 = kt << 6;

        float sc[8][4];
#pragma unroll
        for (int nt = 0; nt < 8; nt++)
#pragma unroll
            for (int e = 0; e < 4; e++) sc[nt][e] = 0.f;

#pragma unroll
        for (int kbk = 0; kbk < 8; kbk++) {
            uint32_t ah[4], al_[4], b2[8][2];
            ldsm4(ah[0], ah[1], ah[2], ah[3], sb + aQoff + kbk * 32);
            ldsm4(al_[0], al_[1], al_[2], al_[3], sb + oQl + aQoff + kbk * 32);
#pragma unroll
            for (int np = 0; np < 4; np++) {
                uint32_t r0, r1, r2, r3;
                ldsm4(r0, r1, r2, r3, kb + bKoff + np * 16 * LPAD * 2 + kbk * 32);
                b2[np * 2][0] = r0;     b2[np * 2][1] = r1;
                b2[np * 2 + 1][0] = r2; b2[np * 2 + 1][1] = r3;
            }
#pragma unroll
            for (int nt = 0; nt < 8; nt++) {
                mma16816(sc[nt], ah, b2[nt]);
                mma16816(sc[nt], al_, b2[nt]);
            }
        }

#pragma unroll
        for (int nt = 0; nt < 8; nt++) {
            int c0 = s0 + nt * 8 + cq;
#pragma unroll
            for (int e = 0; e < 2; e++) {
                int sg = c0 + e;
                float v0 = sc[nt][e] * SCALE_L;
                sc[nt][e] = (sg <= tg0 && sg >= tg0 - (WLOC - 1)) ? v0 : -1e30f;
                float v1 = sc[nt][2 + e] * SCALE_L;
                sc[nt][2 + e] = (sg <= tg1 && sg >= tg1 - (WLOC - 1)) ? v1 : -1e30f;
            }
        }

        float mx0 = -1e30f, mx1 = -1e30f;
#pragma unroll
        for (int nt = 0; nt < 8; nt++) {
            mx0 = fmaxf(mx0, fmaxf(sc[nt][0], sc[nt][1]));
            mx1 = fmaxf(mx1, fmaxf(sc[nt][2], sc[nt][3]));
        }
        mx0 = fmaxf(mx0, __shfl_xor_sync(0xffffffffu, mx0, 1));
        mx0 = fmaxf(mx0, __shfl_xor_sync(0xffffffffu, mx0, 2));
        mx1 = fmaxf(mx1, __shfl_xor_sync(0xffffffffu, mx1, 1));
        mx1 = fmaxf(mx1, __shfl_xor_sync(0xffffffffu, mx1, 2));
        float mn0 = fmaxf(m0, mx0), mn1 = fmaxf(m1, mx1);
        float al0 = __expf(m0 - mn0), al1 = __expf(m1 - mn1);
        m0 = mn0; m1 = mn1;

        float sum0 = 0.f, sum1 = 0.f;
#pragma unroll
        for (int nt = 0; nt < 8; nt++) {
#pragma unroll
            for (int e = 0; e < 2; e++) {
                float p0 = (sc[nt][e]     > -1e29f) ? __expf(sc[nt][e]     - mn0) : 0.f;
                float p1 = (sc[nt][2 + e] > -1e29f) ? __expf(sc[nt][2 + e] - mn1) : 0.f;
                sc[nt][e] = p0; sc[nt][2 + e] = p1;
                sum0 += p0; sum1 += p1;
            }
        }
        sum0 += __shfl_xor_sync(0xffffffffu, sum0, 1);
        sum0 += __shfl_xor_sync(0xffffffffu, sum0, 2);
        sum1 += __shfl_xor_sync(0xffffffffu, sum1, 1);
        sum1 += __shfl_xor_sync(0xffffffffu, sum1, 2);
        l0 = l0 * al0 + sum0;
        l1 = l1 * al1 + sum1;

#pragma unroll
        for (int nt = 0; nt < 16; nt++) {
            out[nt][0] *= al0; out[nt][1] *= al0;
            out[nt][2] *= al1; out[nt][3] *= al1;
        }

#pragma unroll
        for (int kbk = 0; kbk < 4; kbk++) {
            uint32_t ph[4], pl[4];
            split2(sc[2 * kbk][0],     sc[2 * kbk][1],     ph[0], pl[0]);
            split2(sc[2 * kbk][2],     sc[2 * kbk][3],     ph[1], pl[1]);
            split2(sc[2 * kbk + 1][0], sc[2 * kbk + 1][1], ph[2], pl[2]);
            split2(sc[2 * kbk + 1][2], sc[2 * kbk + 1][3], ph[3], pl[3]);
#pragma unroll
            for (int g = 0; g < 8; g++) {
                uint32_t r0, r1, r2, r3;
                ldsm4t(r0, r1, r2, r3,
                       kb + seg + bVoff + kbk * 16 * LPAD * 2 + g * 32);
                uint32_t b0[2] = {r0, r1}, b1[2] = {r2, r3};
                mma16816(out[2 * g], ph, b0);     mma16816(out[2 * g + 1], ph, b1);
                mma16816(out[2 * g], pl, b0);     mma16816(out[2 * g + 1], pl, b1);
            }
        }
        __syncthreads();
    }

    const float inv0 = 1.f / l0, inv1 = 1.f / l1;
#pragma unroll
    for (int nt = 0; nt < 16; nt++) {
        *(float2*)(g_ctx + (size_t)tg0 * CC + h * DD + nt * 8 + cq) =
            make_float2(out[nt][0] * inv0, out[nt][1] * inv0);
        *(float2*)(g_ctx + (size_t)tg1 * CC + h * DD + nt * 8 + cq) =
            make_float2(out[nt][2] * inv1, out[nt][3] * inv1);
    }
}

// ============================================================================
// Global low-rank attention: Sq=128, 8 warps, double-buffered KV_r (hi only),
// gated epilogue O @ uo^T; writes final ctx as single fp16 (1-term w_o).
// ============================================================================
#define GPAD 72
__global__ __launch_bounds__(256) void global_attn_mma()
{
    extern __shared__ __align__(16) char smraw[];
    const uint32_t sb = smem_u32(smraw);
    const uint32_t oQl = 128 * GPAD * 2;
    const uint32_t kvBase = 2 * 128 * GPAD * 2;
    const uint32_t kvStage = 2 * 64 * GPAD * 2;
    const uint32_t seg = 64 * GPAD * 2;
    const uint32_t oUh = kvBase;

    const int tid = threadIdx.x, lane = tid & 31, w = tid >> 5;
    const int qt = blockIdx.x, h = blockIdx.y, t0 = qt << 7;
    const int aj = lane >> 3, ar = lane & 7;
    const int tg0 = t0 + w * 16 + (lane >> 2), tg1 = tg0 + 8;
    const int cq = (lane & 3) * 2;

    for (int i = tid; i < 1024; i += 256) {
        int r = i >> 3, q = i & 7;
        uint32_t so = sb + (r * GPAD + q * 8) * 2;
        size_t go = (size_t)(h * TT + t0 + r) * RR + q * 8;
        CP16(so, g_qrh + go);
        CP16(so + oQl, g_qrl + go);
    }
    CP_COMMIT();

    auto issueKV = [&](int kt, int s) {
        const int s0 = kt << 6;
        const uint32_t kb = sb + kvBase + s * kvStage;
        for (int i = tid; i < 512; i += 256) {
            int r = i >> 3, q = i & 7;
            size_t gk = (size_t)(h * TT + s0 + r) * RR + q * 8;
            uint32_t off = (r * GPAD + q * 8) * 2;
            CP16(kb + off,       g_krh + gk);
            CP16(kb + seg + off, g_vrh + gk);
        }
        CP_COMMIT();
    };
    issueKV(0, 0);

    float m0 = -1e30f, m1 = -1e30f, l0 = 0.f, l1 = 0.f;
    float out[8][4];
#pragma unroll
    for (int nt = 0; nt < 8; nt++)
#pragma unroll
        for (int e = 0; e < 4; e++) out[nt][e] = 0.f;

    const uint32_t aQoff = ((w * 16 + (aj & 1) * 8 + ar) * GPAD + (aj >> 1) * 8) * 2;
    const uint32_t bKoff = (((aj >> 1) * 8 + ar) * GPAD + (aj & 1) * 8) * 2;
    const uint32_t bVoff = (((aj & 1) * 8 + ar) * GPAD + (aj >> 1) * 8) * 2;

    for (int kt = 0; kt < TT / 64; kt++) {
        const int s = kt & 1;
        if (kt < TT / 64 - 1) { issueKV(kt + 1, s ^ 1); CP_WAIT(1); }
        else                  { CP_WAIT(0); }
        __syncthreads();
        const uint32_t kb = sb + kvBase + s * kvStage;

        float sc[8][4];
#pragma unroll
        for (int nt = 0; nt < 8; nt++)
#pragma unroll
            for (int e = 0; e < 4; e++) sc[nt][e] = 0.f;

#pragma unroll
        for (int kbk = 0; kbk < 4; kbk++) {
            uint32_t ah[4], al_[4], b2[8][2];
            ldsm4(ah[0], ah[1], ah[2], ah[3], sb + aQoff + kbk * 32);
            ldsm4(al_[0], al_[1], al_[2], al_[3], sb + oQl + aQoff + kbk * 32);
#pragma unroll
            for (int np = 0; np < 4; np++) {
                uint32_t r0, r1, r2, r3;
                ldsm4(r0, r1, r2, r3, kb + bKoff + np * 16 * GPAD * 2 + kbk * 32);
                b2[np * 2][0] = r0;     b2[np * 2][1] = r1;
                b2[np * 2 + 1][0] = r2; b2[np * 2 + 1][1] = r3;
            }
#pragma unroll
            for (int nt = 0; nt < 8; nt++) {
                mma16816(sc[nt], ah, b2[nt]);
                mma16816(sc[nt], al_, b2[nt]);
            }
        }

        float mx0 = -1e30f, mx1 = -1e30f;
#pragma unroll
        for (int nt = 0; nt < 8; nt++) {
            sc[nt][0] *= SCALE_G; sc[nt][1] *= SCALE_G;
            sc[nt][2] *= SCALE_G; sc[nt][3] *= SCALE_G;
            mx0 = fmaxf(mx0, fmaxf(sc[nt][0], sc[nt][1]));
            mx1 = fmaxf(mx1, fmaxf(sc[nt][2], sc[nt][3]));
        }
        mx0 = fmaxf(mx0, __shfl_xor_sync(0xffffffffu, mx0, 1));
        mx0 = fmaxf(mx0, __shfl_xor_sync(0xffffffffu, mx0, 2));
        mx1 = fmaxf(mx1, __shfl_xor_sync(0xffffffffu, mx1, 1));
        mx1 = fmaxf(mx1, __shfl_xor_sync(0xffffffffu, mx1, 2));
        float mn0 = fmaxf(m0, mx0), mn1 = fmaxf(m1, mx1);
        float al0 = __expf(m0 - mn0), al1 = __expf(m1 - mn1);
        m0 = mn0; m1 = mn1;

        float sum0 = 0.f, sum1 = 0.f;
#pragma unroll
        for (int nt = 0; nt < 8; nt++) {
#pragma unroll
            for (int e = 0; e < 2; e++) {
                float p0 = __expf(sc[nt][e] - mn0);
                float p1 = __expf(sc[nt][2 + e] - mn1);
                sc[nt][e] = p0; sc[nt][2 + e] = p1;
                sum0 += p0; sum1 += p1;
            }
        }
        sum0 += __shfl_xor_sync(0xffffffffu, sum0, 1);
        sum0 += __shfl_xor_sync(0xffffffffu, sum0, 2);
        sum1 += __shfl_xor_sync(0xffffffffu, sum1, 1);
        sum1 += __shfl_xor_sync(0xffffffffu, sum1, 2);
        l0 = l0 * al0 + sum0;
        l1 = l1 * al1 + sum1;

#pragma unroll
        for (int nt = 0; nt < 8; nt++) {
            out[nt][0] *= al0; out[nt][1] *= al0;
            out[nt][2] *= al1; out[nt][3] *= al1;
        }

#pragma unroll
        for (int kbk = 0; kbk < 4; kbk++) {
            uint32_t ph[4], pl[4];
            split2(sc[2 * kbk][0],     sc[2 * kbk][1],     ph[0], pl[0]);
            split2(sc[2 * kbk][2],     sc[2 * kbk][3],     ph[1], pl[1]);
            split2(sc[2 * kbk + 1][0], sc[2 * kbk + 1][1], ph[2], pl[2]);
            split2(sc[2 * kbk + 1][2], sc[2 * kbk + 1][3], ph[3], pl[3]);
#pragma unroll
            for (int g = 0; g < 4; g++) {
                uint32_t r0, r1, r2, r3;
                ldsm4t(r0, r1, r2, r3,
                       kb + seg + bVoff + kbk * 16 * GPAD * 2 + g * 32);
                uint32_t b0[2] = {r0, r1}, b1[2] = {r2, r3};
                mma16816(out[2 * g], ph, b0);     mma16816(out[2 * g + 1], ph, b1);
                mma16816(out[2 * g], pl, b0);     mma16816(out[2 * g + 1], pl, b1);
            }
        }
        __syncthreads();
    }

    const float inv0 = 1.f / l0, inv1 = 1.f / l1;
#pragma unroll
    for (int nt = 0; nt < 8; nt++) {
        out[nt][0] *= inv0; out[nt][1] *= inv0;
        out[nt][2] *= inv1; out[nt][3] *= inv1;
    }

    for (int i = tid; i < 1024; i += 256) {
        int d = i >> 3, q = i & 7;
        *(int4*)(smraw + oUh + (d * GPAD + q * 8) * 2) =
            *(const int4*)(g_uoh + d * 64 + q * 8);
    }
    __syncthreads();

    float out2[16][4];
#pragma unroll
    for (int nt = 0; nt < 16; nt++)
#pragma unroll
        for (int e = 0; e < 4; e++) out2[nt][e] = 0.f;

    const uint32_t bUoff = (((aj >> 1) * 8 + ar) * GPAD + (aj & 1) * 8) * 2;
#pragma unroll
    for (int kbk = 0; kbk < 4; kbk++) {
        uint32_t ph[4], pl[4];
        split2(out[2 * kbk][0],     out[2 * kbk][1],     ph[0], pl[0]);
        split2(out[2 * kbk][2],     out[2 * kbk][3],     ph[1], pl[1]);
        split2(out[2 * kbk + 1][0], out[2 * kbk + 1][1], ph[2], pl[2]);
        split2(out[2 * kbk + 1][2], out[2 * kbk + 1][3], ph[3], pl[3]);
#pragma unroll
        for (int g = 0; g < 8; g++) {
            uint32_t r0, r1, r2, r3;
            ldsm4(r0, r1, r2, r3, sb + oUh + bUoff + g * 16 * GPAD * 2 + kbk * 32);
            uint32_t b0[2] = {r0, r1}, b1[2] = {r2, r3};
            mma16816(out2[2 * g], ph, b0);     mma16816(out2[2 * g + 1], ph, b1);
            mma16816(out2[2 * g], pl, b0);     mma16816(out2[2 * g + 1], pl, b1);
        }
    }

    const float ga0 = g_gate[tg0], ga1 = g_gate[tg1];
#pragma unroll
    for (int nt = 0; nt < 16; nt++) {
        size_t i0 = (size_t)tg0 * CC + h * DD + nt * 8 + cq;
        float2 o0 = *(float2*)(g_ctx + i0);
        __half2 h0 = __floats2half2_rn(o0.x + ga0 * out2[nt][0],
                                       o0.y + ga0 * out2[nt][1]);
        *(uint32_t*)(g_cxh + i0) = *(uint32_t*)&h0;
        size_t i1 = (size_t)tg1 * CC + h * DD + nt * 8 + cq;
        float2 o1 = *(float2*)(g_ctx + i1);
        __half2 h1 = __floats2half2_rn(o1.x + ga1 * out2[nt][2],
                                       o1.y + ga1 * out2[nt][3]);
        *(uint32_t*)(g_cxh + i1) = *(uint32_t*)&h1;
    }
}

// ============================================================================
extern "C" void kernel_launch(void* const* d_in, const int* in_sizes, int n_in,
                              void* d_out, int out_size)
{
    const float* x     = (const float*)d_in[0];
    const float* w_qkv = (const float*)d_in[1];
    const float* w_o   = (const float*)d_in[2];
    const float* pk    = (const float*)d_in[3];
    const float* pv    = (const float*)d_in[4];
    const float* uo    = (const float*)d_in[5];
    const float* iw1   = (const float*)d_in[6];
    const float* iw2   = (const float*)d_in[7];
    float* out = (float*)d_out;

    cudaFuncSetAttribute(gemm_mma256,     cudaFuncAttributeMaxDynamicSharedMemorySize, 61440);
    cudaFuncSetAttribute(gemm_info,       cudaFuncAttributeMaxDynamicSharedMemorySize, 40960);
    cudaFuncSetAttribute(local_attn_mma,  cudaFuncAttributeMaxDynamicSharedMemorySize, 104448);
    cudaFuncSetAttribute(global_attn_mma, cudaFuncAttributeMaxDynamicSharedMemorySize, 73728);
    cudaFuncSetAttribute(lowrank_mma,     cudaFuncAttributeMaxDynamicSharedMemorySize, 52224);

    void *pxh, *pwqh, *pwoh, *pi1h, *pcxh, *pqkvh, *pqkvl;
    cudaGetSymbolAddress(&pxh, g_xh);
    cudaGetSymbolAddress(&pwqh, g_wqh);
    cudaGetSymbolAddress(&pwoh, g_woh);
    cudaGetSymbolAddress(&pi1h, g_i1h);
    cudaGetSymbolAddress(&pcxh, g_cxh);
    cudaGetSymbolAddress(&pqkvh, g_qkvh); cudaGetSymbolAddress(&pqkvl, g_qkvl);

    rope_table_k<<<TT, DD>>>();
    conv_all_k<<<(CS6 + 255) / 256, 256>>>(
        (const float2*)x, (const float2*)w_qkv, (const float2*)iw1,
        (const float2*)w_o, (const float2*)uo, (const float2*)pk,
        (const float2*)pv);

    // qkv = rope(x @ w_qkv^T) -> fp16 splits (1-term GEMM)
    gemm_mma256<<<dim3(C3 / 256, TT / 128), 512, 61440>>>(
        (const __half*)pxh, (const __half*)pwqh,
        nullptr, (__half*)pqkvh, (__half*)pqkvl, C3, CC, 2);

    // info gate: 1-term GEMM + fused gelu/dot partials, finalize
    gemm_info<<<dim3(CI / 128, TT / 128), 256, 40960>>>(
        (const __half*)pxh, (const __half*)pi1h, iw2, CI, CC);
    gate_fin_k<<<TT / 256, 256>>>();

    lowrank_mma<<<dim3(TT / 64, HH), 128, 52224>>>();
    local_attn_mma<<<dim3(TT / 64, HH), 128, 104448>>>();
    global_attn_mma<<<dim3(TT / 128, HH), 256, 73728>>>();

    // out = ctx @ w_o^T (1-term GEMM)
    gemm_mma256<<<dim3(CC / 256, TT / 128), 512, 61440>>>(
        (const __half*)pcxh, (const __half*)pwoh,
        out, nullptr, nullptr, CC, CC, 0);
}

// round 12
// speedup vs baseline: 7.9063x; 1.2815x over previous
#include <cuda_runtime.h>
#include <cuda_fp16.h>
#include <math.h>
#include <stdint.h>

#define TT   2048
#define CC   2048
#define HH   16
#define DD   128
#define RR   64
#define WLOC 512
#define CI   512
#define C3   6144

#define SCALE_L 0.08838834764831845f
#define SCALE_G 0.1767766952966369f

// ---------------- scratch (device globals) ----------------
__device__ float g_gatez[4 * TT];
__device__ float g_gate[TT];
__device__ int   g_anygate;
__device__ float g_cos[TT * DD];
__device__ float g_sin[TT * DD];
__device__ float g_ctx[TT * CC];

// fp16 operands. A-side 2-term splits kept only on the attention Q path.
__device__ __half g_xh[TT * CC];
__device__ __half g_wqh[C3 * CC];
__device__ __half g_woh[CC * CC];
__device__ __half g_i1h[CI * CC];
__device__ __half g_cxh[TT * CC];
__device__ __half g_qkvh[TT * C3], g_qkvl[TT * C3];
__device__ __half g_qrh[HH * TT * RR], g_qrl[HH * TT * RR];
__device__ __half g_krh[HH * TT * RR];
__device__ __half g_vrh[HH * TT * RR];
__device__ __half g_uoh[DD * RR];
__device__ __half g_pkh[RR * DD];
__device__ __half g_pvh[RR * DD];

// ============================================================================
// PTX helpers (plain sm_80+ ISA)
// ============================================================================
__device__ __forceinline__ uint32_t smem_u32(const void* p) {
    uint32_t a;
    asm("{ .reg .u64 t; cvta.to.shared.u64 t, %1; cvt.u32.u64 %0, t; }"
        : "=r"(a) : "l"(p));
    return a;
}

#define CP16(s, g) \
    asm volatile("cp.async.cg.shared.global [%0], [%1], 16;" \
                 :: "r"(s), "l"(g) : "memory")
#define CP_COMMIT() asm volatile("cp.async.commit_group;" ::: "memory")
#define CP_WAIT(n)  asm volatile("cp.async.wait_group %0;" :: "n"(n) : "memory")

__device__ __forceinline__ void ldsm4(uint32_t& r0, uint32_t& r1,
                                      uint32_t& r2, uint32_t& r3, uint32_t a) {
    asm volatile("ldmatrix.sync.aligned.m8n8.x4.shared.b16 {%0,%1,%2,%3}, [%4];"
                 : "=r"(r0), "=r"(r1), "=r"(r2), "=r"(r3) : "r"(a));
}
__device__ __forceinline__ void ldsm4t(uint32_t& r0, uint32_t& r1,
                                       uint32_t& r2, uint32_t& r3, uint32_t a) {
    asm volatile("ldmatrix.sync.aligned.m8n8.x4.trans.shared.b16 {%0,%1,%2,%3}, [%4];"
                 : "=r"(r0), "=r"(r1), "=r"(r2), "=r"(r3) : "r"(a));
}

__device__ __forceinline__ void mma16816(float* c, const uint32_t* a,
                                         const uint32_t* b) {
    asm volatile("mma.sync.aligned.m16n8k16.row.col.f32.f16.f16.f32 "
                 "{%0,%1,%2,%3}, {%4,%5,%6,%7}, {%8,%9}, {%0,%1,%2,%3};"
                 : "+f"(c[0]), "+f"(c[1]), "+f"(c[2]), "+f"(c[3])
                 : "r"(a[0]), "r"(a[1]), "r"(a[2]), "r"(a[3]),
                   "r"(b[0]), "r"(b[1]));
}

__device__ __forceinline__ void split2(float x, float y, uint32_t& h, uint32_t& l) {
    __half2 hh = __floats2half2_rn(x, y);
    h = *reinterpret_cast<uint32_t*>(&hh);
    __half2 ll = __floats2half2_rn(x - __low2float(hh), y - __high2float(hh));
    l = *reinterpret_cast<uint32_t*>(&ll);
}

// ============================================================================
// Fused fp32 -> fp16 convert of x + ALL weight regions (one launch)
// ============================================================================
#define CS0 (TT * CC / 2)
#define CS1 (CS0 + C3 * CC / 2)
#define CS2 (CS1 + CI * CC / 2)
#define CS3 (CS2 + CC * CC / 2)
#define CS4 (CS3 + DD * RR / 2)
#define CS5 (CS4 + RR * DD / 2)
#define CS6 (CS5 + RR * DD / 2)
__global__ void conv_all_k(const float2* __restrict__ x,
                           const float2* __restrict__ wq,
                           const float2* __restrict__ i1,
                           const float2* __restrict__ wo,
                           const float2* __restrict__ uo,
                           const float2* __restrict__ pk,
                           const float2* __restrict__ pv)
{
    int i = blockIdx.x * 256 + threadIdx.x;
    const float2* s; __half2* d; int j;
    if      (i < CS0) { s = x;  d = (__half2*)g_xh;  j = i; }
    else if (i < CS1) { s = wq; d = (__half2*)g_wqh; j = i - CS0; }
    else if (i < CS2) { s = i1; d = (__half2*)g_i1h; j = i - CS1; }
    else if (i < CS3) { s = wo; d = (__half2*)g_woh; j = i - CS2; }
    else if (i < CS4) { s = uo; d = (__half2*)g_uoh; j = i - CS3; }
    else if (i < CS5) { s = pk; d = (__half2*)g_pkh; j = i - CS4; }
    else if (i < CS6) { s = pv; d = (__half2*)g_pvh; j = i - CS5; }
    else return;
    float2 v = s[j];
    d[j] = __floats2half2_rn(v.x, v.y);
}

// ============================================================================
// mma.sync GEMM, 1-term fp16: C = Ah·Bh^T.
// BM=128, BN=256, BK=32; 512 threads (warps 4x4, warp tile 32x64).
// smem/stage: Ah 10240 | Bh 20480 = 30720; x2 = 61440.
// mode 0: fp32 store. mode 2: rope + fp16 hi/lo store.
// ============================================================================
__global__ __launch_bounds__(512) void gemm_mma256(
    const __half* __restrict__ Ah, const __half* __restrict__ Bh,
    float* __restrict__ Cout,
    __half* __restrict__ Ch, __half* __restrict__ Cl,
    int N, int K, int mode)
{
    extern __shared__ __align__(128) char smraw[];
    const uint32_t sb = smem_u32(smraw);
    const int tid = threadIdx.x, lane = tid & 31, wid = tid >> 5;
    const int wm = wid & 3, wn = wid >> 2;
    const int bm = blockIdx.y << 7, bn = blockIdx.x << 8;
    const int aj = lane >> 3, ar = lane & 7;

    float acc[2][8][4];
#pragma unroll
    for (int mt = 0; mt < 2; mt++)
#pragma unroll
        for (int nt = 0; nt < 8; nt++)
#pragma unroll
            for (int e = 0; e < 4; e++) acc[mt][nt][e] = 0.f;

    const int nch = K >> 5;

    auto issue_stage = [&](int c) {
        const uint32_t st = sb + (c & 1) * 30720;
        const int k0 = c << 5;
        {
            int r = tid >> 2, q = tid & 3;
            CP16(st + r * 80 + q * 16, Ah + (size_t)(bm + r) * K + k0 + q * 8);
        }
        {
            const __half* gh = Bh + (size_t)bn * K + k0;
#pragma unroll
            for (int hh = 0; hh < 2; hh++) {
                int i = tid + hh * 512;
                int r = i >> 2, q = i & 3;
                CP16(st + 10240 + r * 80 + q * 16, gh + (size_t)r * K + q * 8);
            }
        }
        CP_COMMIT();
    };

    issue_stage(0);
    for (int c = 0; c < nch; c++) {
        if (c + 1 < nch) { issue_stage(c + 1); CP_WAIT(1); }
        else             { CP_WAIT(0); }
        __syncthreads();

        const uint32_t st = sb + (c & 1) * 30720;
#pragma unroll
        for (int ks = 0; ks < 2; ks++) {
            uint32_t ah[2][4], b2[8][2];
            const uint32_t a_off =
                ((wm * 32 + (aj & 1) * 8 + ar) * 40 + ks * 16 + (aj >> 1) * 8) * 2;
            const uint32_t b_off =
                ((wn * 64 + (aj >> 1) * 8 + ar) * 40 + ks * 16 + (aj & 1) * 8) * 2;

#pragma unroll
            for (int mt = 0; mt < 2; mt++)
                ldsm4(ah[mt][0], ah[mt][1], ah[mt][2], ah[mt][3],
                      st + a_off + mt * (16 * 80));
#pragma unroll
            for (int np = 0; np < 4; np++) {
                uint32_t r0, r1, r2, r3;
                ldsm4(r0, r1, r2, r3, st + 10240 + b_off + np * (16 * 80));
                b2[np * 2][0] = r0;     b2[np * 2][1] = r1;
                b2[np * 2 + 1][0] = r2; b2[np * 2 + 1][1] = r3;
            }
#pragma unroll
            for (int mt = 0; mt < 2; mt++)
#pragma unroll
                for (int nt = 0; nt < 8; nt++)
                    mma16816(acc[mt][nt], ah[mt], b2[nt]);
        }
        __syncthreads();
    }

    const int row_base = bm + wm * 32 + (lane >> 2);
    const int col_base = bn + wn * 64 + (lane & 3) * 2;
#pragma unroll
    for (int mt = 0; mt < 2; mt++)
#pragma unroll
        for (int nt = 0; nt < 8; nt++) {
            int r0 = row_base + mt * 16, cc = col_base + nt * 8;
            float v0 = acc[mt][nt][0], v1 = acc[mt][nt][1];
            float v2 = acc[mt][nt][2], v3 = acc[mt][nt][3];
            if (mode == 2) {
                if (cc < 2 * CC) {
                    int d0 = cc & 127;
                    float2 cA = *(const float2*)(g_cos + r0 * DD + d0);
                    float2 sA = *(const float2*)(g_sin + r0 * DD + d0);
                    float o0 = v0 * cA.x - v1 * sA.x;
                    float o1 = v1 * cA.y + v0 * sA.y;
                    float2 cB = *(const float2*)(g_cos + (r0 + 8) * DD + d0);
                    float2 sB = *(const float2*)(g_sin + (r0 + 8) * DD + d0);
                    float o2 = v2 * cB.x - v3 * sB.x;
                    float o3 = v3 * cB.y + v2 * sB.y;
                    v0 = o0; v1 = o1; v2 = o2; v3 = o3;
                }
                uint32_t h01, l01, h23, l23;
                split2(v0, v1, h01, l01);
                split2(v2, v3, h23, l23);
                *(uint32_t*)(Ch + (size_t)r0 * N + cc)       = h01;
                *(uint32_t*)(Cl + (size_t)r0 * N + cc)       = l01;
                *(uint32_t*)(Ch + (size_t)(r0 + 8) * N + cc) = h23;
                *(uint32_t*)(Cl + (size_t)(r0 + 8) * N + cc) = l23;
            } else {
                *(float2*)(Cout + (size_t)r0 * N + cc)       = make_float2(v0, v1);
                *(float2*)(Cout + (size_t)(r0 + 8) * N + cc) = make_float2(v2, v3);
            }
        }
}

// ============================================================================
// Info GEMM (BN=128, 1-term fp16) with fused gelu + dot(w2) gate partials.
// ============================================================================
__global__ __launch_bounds__(256) void gemm_info(
    const __half* __restrict__ Ah, const __half* __restrict__ Bh,
    const float* __restrict__ w2, int N, int K)
{
    extern __shared__ __align__(128) char smraw[];
    const uint32_t sb = smem_u32(smraw);
    const int tid = threadIdx.x, lane = tid & 31, wid = tid >> 5;
    const int wm = wid & 3, wn = wid >> 2;
    const int bm = blockIdx.y << 7, bn = blockIdx.x << 7;
    const int aj = lane >> 3, ar = lane & 7;

    float acc[2][8][4];
#pragma unroll
    for (int mt = 0; mt < 2; mt++)
#pragma unroll
        for (int nt = 0; nt < 8; nt++)
#pragma unroll
            for (int e = 0; e < 4; e++) acc[mt][nt][e] = 0.f;

    const int nch = K >> 5;

    auto issue_stage = [&](int c) {
        const uint32_t st = sb + (c & 1) * 20480;
        const int k0 = c << 5;
        const __half* gm0 = Ah + (size_t)bm * K + k0;
        const __half* gm2 = Bh + (size_t)bn * K + k0;
#pragma unroll
        for (int h = 0; h < 2; h++) {
            int i = tid + h * 256;
            int r = i >> 2, q = i & 3;
            uint32_t so = st + r * 80 + q * 16;
            size_t go = (size_t)r * K + q * 8;
            CP16(so,          gm0 + go);
            CP16(so + 10240,  gm2 + go);
        }
        CP_COMMIT();
    };

    issue_stage(0);
    for (int c = 0; c < nch; c++) {
        if (c + 1 < nch) { issue_stage(c + 1); CP_WAIT(1); }
        else             { CP_WAIT(0); }
        __syncthreads();

        const uint32_t st = sb + (c & 1) * 20480;
#pragma unroll
        for (int ks = 0; ks < 2; ks++) {
            uint32_t ah[2][4], b2[8][2];
            const uint32_t a_off =
                ((wm * 32 + (aj & 1) * 8 + ar) * 40 + ks * 16 + (aj >> 1) * 8) * 2;
            const uint32_t b_off =
                ((wn * 64 + (aj >> 1) * 8 + ar) * 40 + ks * 16 + (aj & 1) * 8) * 2;

#pragma unroll
            for (int mt = 0; mt < 2; mt++)
                ldsm4(ah[mt][0], ah[mt][1], ah[mt][2], ah[mt][3],
                      st + a_off + mt * (16 * 80));
#pragma unroll
            for (int np = 0; np < 4; np++) {
                uint32_t r0, r1, r2, r3;
                ldsm4(r0, r1, r2, r3, st + 10240 + b_off + np * (16 * 80));
                b2[np * 2][0] = r0;     b2[np * 2][1] = r1;
                b2[np * 2 + 1][0] = r2; b2[np * 2 + 1][1] = r3;
            }
#pragma unroll
            for (int mt = 0; mt < 2; mt++)
#pragma unroll
                for (int nt = 0; nt < 8; nt++)
                    mma16816(acc[mt][nt], ah[mt], b2[nt]);
        }
        __syncthreads();
    }

    const int col_base = wn * 64 + (lane & 3) * 2;
    float z[2][2] = {{0.f, 0.f}, {0.f, 0.f}};
#pragma unroll
    for (int mt = 0; mt < 2; mt++)
#pragma unroll
        for (int nt = 0; nt < 8; nt++) {
            int cc = col_base + nt * 8;
            float w0 = w2[cc], w1 = w2[cc + 1];
            float v0 = acc[mt][nt][0], v1 = acc[mt][nt][1];
            float v2 = acc[mt][nt][2], v3 = acc[mt][nt][3];
            v0 = 0.5f * v0 * (1.0f + erff(v0 * 0.7071067811865475f));
            v1 = 0.5f * v1 * (1.0f + erff(v1 * 0.7071067811865475f));
            v2 = 0.5f * v2 * (1.0f + erff(v2 * 0.7071067811865475f));
            v3 = 0.5f * v3 * (1.0f + erff(v3 * 0.7071067811865475f));
            z[mt][0] += v0 * w0 + v1 * w1;
            z[mt][1] += v2 * w0 + v3 * w1;
        }
#pragma unroll
    for (int mt = 0; mt < 2; mt++)
#pragma unroll
        for (int e = 0; e < 2; e++) {
            z[mt][e] += __shfl_xor_sync(0xffffffffu, z[mt][e], 1);
            z[mt][e] += __shfl_xor_sync(0xffffffffu, z[mt][e], 2);
        }
    float* zs = (float*)smraw;
    if ((lane & 3) == 0) {
        int lr = wm * 32 + (lane >> 2);
        zs[wn * 128 + lr +  0] = z[0][0];
        zs[wn * 128 + lr +  8] = z[0][1];
        zs[wn * 128 + lr + 16] = z[1][0];
        zs[wn * 128 + lr + 24] = z[1][1];
    }
    __syncthreads();
    if (tid < 128)
        g_gatez[blockIdx.x * TT + bm + tid] = zs[tid] + zs[128 + tid];
}

// gate finalize (one block): gates + any-gate flag
__global__ __launch_bounds__(512) void gate_fin_k()
{
    int any = 0;
    for (int t = threadIdx.x; t < TT; t += 512) {
        float zsum = g_gatez[t] + g_gatez[TT + t] + g_gatez[2 * TT + t]
                   + g_gatez[3 * TT + t];
        float sc = 1.0f / (1.0f + expf(-zsum));
        float gv = (sc > 0.75f) ? 1.0f : 0.0f;
        g_gate[t] = gv;
        any |= (gv != 0.0f);
    }
    int anyb = __syncthreads_or(any);
    if (threadIdx.x == 0) g_anygate = anyb;
}

// ============================================================================
// RoPE tables (fp32)
// ============================================================================
__global__ void rope_table_k()
{
    int t = blockIdx.x, d = threadIdx.x;
    int j = d & 63;
    float inv = exp2f(-(float)j * 0.20762050593046014f);
    float ang = (float)t * inv;
    g_cos[t * DD + d] = cosf(ang);
    g_sin[t * DD + d] = sinf(ang);
}

// ============================================================================
// Low-rank projections (2-term fp16). Skipped entirely when no gate fires —
// its outputs only feed the (gated) global attention path.
// ============================================================================
__global__ __launch_bounds__(128) void lowrank_mma()
{
    if (g_anygate == 0) return;

    extern __shared__ __align__(16) char smraw[];
    const uint32_t sb = smem_u32(smraw);
    const uint32_t oAl = 64 * 136 * 2, oPh = 2 * 64 * 136 * 2;
    const int tid = threadIdx.x, lane = tid & 31, w = tid >> 5;
    const int qt = blockIdx.x, h = blockIdx.y, t0 = qt << 6;
    const int aj = lane >> 3, ar = lane & 7;

    const uint32_t aoff = ((w * 16 + (aj & 1) * 8 + ar) * 136 + (aj >> 1) * 8) * 2;
    const uint32_t boff = (((aj >> 1) * 8 + ar) * 136 + (aj & 1) * 8) * 2;
    const int row0 = t0 + w * 16 + (lane >> 2);
    const int col = (lane & 3) * 2;

    for (int pass = 0; pass < 3; pass++) {
        const __half* Ph = (pass == 2) ? g_pvh : g_pkh;
        const int off = pass * CC + h * DD;
        __syncthreads();
        for (int i = tid; i < 1024; i += 128) {
            int r = i >> 4, q = i & 15;
            uint32_t so = (r * 136 + q * 8) * 2;
            size_t ga = (size_t)(t0 + r) * C3 + off + q * 8;
            CP16(sb + so,       g_qkvh + ga);
            CP16(sb + oAl + so, g_qkvl + ga);
            CP16(sb + oPh + so, Ph + r * DD + q * 8);
        }
        CP_COMMIT(); CP_WAIT(0);
        __syncthreads();

        float acc[8][4];
#pragma unroll
        for (int nt = 0; nt < 8; nt++)
#pragma unroll
            for (int e = 0; e < 4; e++) acc[nt][e] = 0.f;

#pragma unroll
        for (int kb = 0; kb < 8; kb++) {
            uint32_t ah[4], al_[4], b2[8][2];
            ldsm4(ah[0], ah[1], ah[2], ah[3], sb + aoff + kb * 32);
            ldsm4(al_[0], al_[1], al_[2], al_[3], sb + oAl + aoff + kb * 32);
#pragma unroll
            for (int np = 0; np < 4; np++) {
                uint32_t r0, r1, r2, r3;
                ldsm4(r0, r1, r2, r3, sb + oPh + boff + np * 16 * 136 * 2 + kb * 32);
                b2[np * 2][0] = r0;     b2[np * 2][1] = r1;
                b2[np * 2 + 1][0] = r2; b2[np * 2 + 1][1] = r3;
            }
#pragma unroll
            for (int nt = 0; nt < 8; nt++) {
                mma16816(acc[nt], ah, b2[nt]);
                mma16816(acc[nt], al_, b2[nt]);
            }
        }

        if (pass == 0) {
#pragma unroll
            for (int nt = 0; nt < 8; nt++) {
                uint32_t hh, ll;
                size_t i0 = (size_t)(h * TT + row0) * RR + nt * 8 + col;
                split2(acc[nt][0], acc[nt][1], hh, ll);
                *(uint32_t*)(g_qrh + i0) = hh;
                *(uint32_t*)(g_qrl + i0) = ll;
                size_t i1 = i0 + 8 * RR;
                split2(acc[nt][2], acc[nt][3], hh, ll);
                *(uint32_t*)(g_qrh + i1) = hh;
                *(uint32_t*)(g_qrl + i1) = ll;
            }
        } else {
            __half* dh = (pass == 1) ? g_krh : g_vrh;
#pragma unroll
            for (int nt = 0; nt < 8; nt++) {
                size_t i0 = (size_t)(h * TT + row0) * RR + nt * 8 + col;
                __half2 a = __floats2half2_rn(acc[nt][0], acc[nt][1]);
                *(uint32_t*)(dh + i0) = *(uint32_t*)&a;
                size_t i1 = i0 + 8 * RR;
                __half2 b = __floats2half2_rn(acc[nt][2], acc[nt][3]);
                *(uint32_t*)(dh + i1) = *(uint32_t*)&b;
            }
        }
    }
}

// ============================================================================
// Local sliding-window attention: Sq=64, 4 warps, double-buffered KV (hi only).
// ============================================================================
#define LPAD 136
__global__ __launch_bounds__(128) void local_attn_mma()
{
    extern __shared__ __align__(16) char smraw[];
    const uint32_t sb = smem_u32(smraw);
    const uint32_t oQl = 64 * LPAD * 2;
    const uint32_t kvBase = 2 * 64 * LPAD * 2;
    const uint32_t kvStage = 2 * 64 * LPAD * 2;
    const uint32_t seg = 64 * LPAD * 2;

    const int tid = threadIdx.x, lane = tid & 31, w = tid >> 5;
    const int qt = gridDim.x - 1 - blockIdx.x, h = blockIdx.y;
    const int t0 = qt << 6;
    const int aj = lane >> 3, ar = lane & 7;
    const int tg0 = t0 + w * 16 + (lane >> 2), tg1 = tg0 + 8;
    const int cq = (lane & 3) * 2;

    for (int i = tid; i < 1024; i += 128) {
        int r = i >> 4, q = i & 15;
        uint32_t so = sb + (r * LPAD + q * 8) * 2;
        size_t go = (size_t)(t0 + r) * C3 + h * DD + q * 8;
        CP16(so, g_qkvh + go);
        CP16(so + oQl, g_qkvl + go);
    }
    CP_COMMIT();

    const int kt0 = (t0 > WLOC - 1) ? ((t0 - (WLOC - 1)) >> 6) : 0;
    const int ktend = qt;

    auto issueKV = [&](int kt, int s) {
        const int s0 = kt << 6;
        const uint32_t kb = sb + kvBase + s * kvStage;
        for (int i = tid; i < 1024; i += 128) {
            int r = i >> 4, q = i & 15;
            size_t gk = (size_t)(s0 + r) * C3 + CC + h * DD + q * 8;
            uint32_t off = (r * LPAD + q * 8) * 2;
            CP16(kb + off,       g_qkvh + gk);
            CP16(kb + seg + off, g_qkvh + gk + CC);
        }
        CP_COMMIT();
    };
    issueKV(kt0, 0);

    float m0 = -1e30f, m1 = -1e30f, l0 = 0.f, l1 = 0.f;
    float out[16][4];
#pragma unroll
    for (int nt = 0; nt < 16; nt++)
#pragma unroll
        for (int e = 0; e < 4; e++) out[nt][e] = 0.f;

    const uint32_t aQoff = ((w * 16 + (aj & 1) * 8 + ar) * LPAD + (aj >> 1) * 8) * 2;
    const uint32_t bKoff = (((aj >> 1) * 8 + ar) * LPAD + (aj & 1) * 8) * 2;
    const uint32_t bVoff = (((aj & 1) * 8 + ar) * LPAD + (aj >> 1) * 8) * 2;

    for (int kt = kt0; kt <= ktend; kt++) {
        const int s = (kt - kt0) & 1;
        if (kt < ktend) { issueKV(kt + 1, s ^ 1); CP_WAIT(1); }
        else            { CP_WAIT(0); }
        __syncthreads();
        const uint32_t kb = sb + kvBase + s * kvStage;
        const int s0 = kt << 6;

        float sc[8][4];
#pragma unroll
        for (int nt = 0; nt < 8; nt++)
#pragma unroll
            for (int e = 0; e < 4; e++) sc[nt][e] = 0.f;

#pragma unroll
        for (int kbk = 0; kbk < 8; kbk++) {
            uint32_t ah[4], al_[4], b2[8][2];
            ldsm4(ah[0], ah[1], ah[2], ah[3], sb + aQoff + kbk * 32);
            ldsm4(al_[0], al_[1], al_[2], al_[3], sb + oQl + aQoff + kbk * 32);
#pragma unroll
            for (int np = 0; np < 4; np++) {
                uint32_t r0, r1, r2, r3;
                ldsm4(r0, r1, r2, r3, kb + bKoff + np * 16 * LPAD * 2 + kbk * 32);
                b2[np * 2][0] = r0;     b2[np * 2][1] = r1;
                b2[np * 2 + 1][0] = r2; b2[np * 2 + 1][1] = r3;
            }
#pragma unroll
            for (int nt = 0; nt < 8; nt++) {
                mma16816(sc[nt], ah, b2[nt]);
                mma16816(sc[nt], al_, b2[nt]);
            }
        }

#pragma unroll
        for (int nt = 0; nt < 8; nt++) {
            int c0 = s0 + nt * 8 + cq;
#pragma unroll
            for (int e = 0; e < 2; e++) {
                int sg = c0 + e;
                float v0 = sc[nt][e] * SCALE_L;
                sc[nt][e] = (sg <= tg0 && sg >= tg0 - (WLOC - 1)) ? v0 : -1e30f;
                float v1 = sc[nt][2 + e] * SCALE_L;
                sc[nt][2 + e] = (sg <= tg1 && sg >= tg1 - (WLOC - 1)) ? v1 : -1e30f;
            }
        }

        float mx0 = -1e30f, mx1 = -1e30f;
#pragma unroll
        for (int nt = 0; nt < 8; nt++) {
            mx0 = fmaxf(mx0, fmaxf(sc[nt][0], sc[nt][1]));
            mx1 = fmaxf(mx1, fmaxf(sc[nt][2], sc[nt][3]));
        }
        mx0 = fmaxf(mx0, __shfl_xor_sync(0xffffffffu, mx0, 1));
        mx0 = fmaxf(mx0, __shfl_xor_sync(0xffffffffu, mx0, 2));
        mx1 = fmaxf(mx1, __shfl_xor_sync(0xffffffffu, mx1, 1));
        mx1 = fmaxf(mx1, __shfl_xor_sync(0xffffffffu, mx1, 2));
        float mn0 = fmaxf(m0, mx0), mn1 = fmaxf(m1, mx1);
        float al0 = __expf(m0 - mn0), al1 = __expf(m1 - mn1);
        m0 = mn0; m1 = mn1;

        float sum0 = 0.f, sum1 = 0.f;
#pragma unroll
        for (int nt = 0; nt < 8; nt++) {
#pragma unroll
            for (int e = 0; e < 2; e++) {
                float p0 = (sc[nt][e]     > -1e29f) ? __expf(sc[nt][e]     - mn0) : 0.f;
                float p1 = (sc[nt][2 + e] > -1e29f) ? __expf(sc[nt][2 + e] - mn1) : 0.f;
                sc[nt][e] = p0; sc[nt][2 + e] = p1;
                sum0 += p0; sum1 += p1;
            }
        }
        sum0 += __shfl_xor_sync(0xffffffffu, sum0, 1);
        sum0 += __shfl_xor_sync(0xffffffffu, sum0, 2);
        sum1 += __shfl_xor_sync(0xffffffffu, sum1, 1);
        sum1 += __shfl_xor_sync(0xffffffffu, sum1, 2);
        l0 = l0 * al0 + sum0;
        l1 = l1 * al1 + sum1;

#pragma unroll
        for (int nt = 0; nt < 16; nt++) {
            out[nt][0] *= al0; out[nt][1] *= al0;
            out[nt][2] *= al1; out[nt][3] *= al1;
        }

#pragma unroll
        for (int kbk = 0; kbk < 4; kbk++) {
            uint32_t ph[4], pl[4];
            split2(sc[2 * kbk][0],     sc[2 * kbk][1],     ph[0], pl[0]);
            split2(sc[2 * kbk][2],     sc[2 * kbk][3],     ph[1], pl[1]);
            split2(sc[2 * kbk + 1][0], sc[2 * kbk + 1][1], ph[2], pl[2]);
            split2(sc[2 * kbk + 1][2], sc[2 * kbk + 1][3], ph[3], pl[3]);
#pragma unroll
            for (int g = 0; g < 8; g++) {
                uint32_t r0, r1, r2, r3;
                ldsm4t(r0, r1, r2, r3,
                       kb + seg + bVoff + kbk * 16 * LPAD * 2 + g * 32);
                uint32_t b0[2] = {r0, r1}, b1[2] = {r2, r3};
                mma16816(out[2 * g], ph, b0);     mma16816(out[2 * g + 1], ph, b1);
                mma16816(out[2 * g], pl, b0);     mma16816(out[2 * g + 1], pl, b1);
            }
        }
        __syncthreads();
    }

    const float inv0 = 1.f / l0, inv1 = 1.f / l1;
#pragma unroll
    for (int nt = 0; nt < 16; nt++) {
        *(float2*)(g_ctx + (size_t)tg0 * CC + h * DD + nt * 8 + cq) =
            make_float2(out[nt][0] * inv0, out[nt][1] * inv0);
        *(float2*)(g_ctx + (size_t)tg1 * CC + h * DD + nt * 8 + cq) =
            make_float2(out[nt][2] * inv1, out[nt][3] * inv1);
    }
}

// ============================================================================
// Global low-rank attention. FAST PATH: if no gate fires in this CTA's 128
// tokens, ctx_g is multiplied by zero -> just convert local ctx to fp16.
// Slow path (any gate set) is the full flash computation (bit-identical
// result for gate=0 rows since ga*out2 adds exactly 0).
// ============================================================================
#define GPAD 72
__global__ __launch_bounds__(256) void global_attn_mma()
{
    extern __shared__ __align__(16) char smraw[];
    const uint32_t sb = smem_u32(smraw);
    const uint32_t oQl = 128 * GPAD * 2;
    const uint32_t kvBase = 2 * 128 * GPAD * 2;
    const uint32_t kvStage = 2 * 64 * GPAD * 2;
    const uint32_t seg = 64 * GPAD * 2;
    const uint32_t oUh = kvBase;

    const int tid = threadIdx.x, lane = tid & 31, w = tid >> 5;
    const int qt = blockIdx.x, h = blockIdx.y, t0 = qt << 7;
    const int aj = lane >> 3, ar = lane & 7;
    const int tg0 = t0 + w * 16 + (lane >> 2), tg1 = tg0 + 8;
    const int cq = (lane & 3) * 2;

    // ---- gate check: skip all KV work if no token in tile is gated ----
    int any = 0;
    for (int i = tid; i < 128; i += 256) any |= (g_gate[t0 + i] != 0.0f);
    if (!__syncthreads_or(any)) {
        // ctx_g contribution is exactly zero: convert local ctx tile to fp16
        for (int i = tid; i < 8192; i += 256) {
            int r = i >> 6, c2 = (i & 63) * 2;
            size_t idx = (size_t)(t0 + r) * CC + h * DD + c2;
            float2 v = *(const float2*)(g_ctx + idx);
            __half2 hv = __floats2half2_rn(v.x, v.y);
            *(uint32_t*)(g_cxh + idx) = *(uint32_t*)&hv;
        }
        return;
    }

    for (int i = tid; i < 1024; i += 256) {
        int r = i >> 3, q = i & 7;
        uint32_t so = sb + (r * GPAD + q * 8) * 2;
        size_t go = (size_t)(h * TT + t0 + r) * RR + q * 8;
        CP16(so, g_qrh + go);
        CP16(so + oQl, g_qrl + go);
    }
    CP_COMMIT();

    auto issueKV = [&](int kt, int s) {
        const int s0 = kt << 6;
        const uint32_t kb = sb + kvBase + s * kvStage;
        for (int i = tid; i < 512; i += 256) {
            int r = i >> 3, q = i & 7;
            size_t gk = (size_t)(h * TT + s0 + r) * RR + q * 8;
            uint32_t off = (r * GPAD + q * 8) * 2;
            CP16(kb + off,       g_krh + gk);
            CP16(kb + seg + off, g_vrh + gk);
        }
        CP_COMMIT();
    };
    issueKV(0, 0);

    float m0 = -1e30f, m1 = -1e30f, l0 = 0.f, l1 = 0.f;
    float out[8][4];
#pragma unroll
    for (int nt = 0; nt < 8; nt++)
#pragma unroll
        for (int e = 0; e < 4; e++) out[nt][e] = 0.f;

    const uint32_t aQoff = ((w * 16 + (aj & 1) * 8 + ar) * GPAD + (aj >> 1) * 8) * 2;
    const uint32_t bKoff = (((aj >> 1) * 8 + ar) * GPAD + (aj & 1) * 8) * 2;
    const uint32_t bVoff = (((aj & 1) * 8 + ar) * GPAD + (aj >> 1) * 8) * 2;

    for (int kt = 0; kt < TT / 64; kt++) {
        const int s = kt & 1;
        if (kt < TT / 64 - 1) { issueKV(kt + 1, s ^ 1); CP_WAIT(1); }
        else                  { CP_WAIT(0); }
        __syncthreads();
        const uint32_t kb = sb + kvBase + s * kvStage;

        float sc[8][4];
#pragma unroll
        for (int nt = 0; nt < 8; nt++)
#pragma unroll
            for (int e = 0; e < 4; e++) sc[nt][e] = 0.f;

#pragma unroll
        for (int kbk = 0; kbk < 4; kbk++) {
            uint32_t ah[4], al_[4], b2[8][2];
            ldsm4(ah[0], ah[1], ah[2], ah[3], sb + aQoff + kbk * 32);
            ldsm4(al_[0], al_[1], al_[2], al_[3], sb + oQl + aQoff + kbk * 32);
#pragma unroll
            for (int np = 0; np < 4; np++) {
                uint32_t r0, r1, r2, r3;
                ldsm4(r0, r1, r2, r3, kb + bKoff + np * 16 * GPAD * 2 + kbk * 32);
                b2[np * 2][0] = r0;     b2[np * 2][1] = r1;
                b2[np * 2 + 1][0] = r2; b2[np * 2 + 1][1] = r3;
            }
#pragma unroll
            for (int nt = 0; nt < 8; nt++) {
                mma16816(sc[nt], ah, b2[nt]);
                mma16816(sc[nt], al_, b2[nt]);
            }
        }

        float mx0 = -1e30f, mx1 = -1e30f;
#pragma unroll
        for (int nt = 0; nt < 8; nt++) {
            sc[nt][0] *= SCALE_G; sc[nt][1] *= SCALE_G;
            sc[nt][2] *= SCALE_G; sc[nt][3] *= SCALE_G;
            mx0 = fmaxf(mx0, fmaxf(sc[nt][0], sc[nt][1]));
            mx1 = fmaxf(mx1, fmaxf(sc[nt][2], sc[nt][3]));
        }
        mx0 = fmaxf(mx0, __shfl_xor_sync(0xffffffffu, mx0, 1));
        mx0 = fmaxf(mx0, __shfl_xor_sync(0xffffffffu, mx0, 2));
        mx1 = fmaxf(mx1, __shfl_xor_sync(0xffffffffu, mx1, 1));
        mx1 = fmaxf(mx1, __shfl_xor_sync(0xffffffffu, mx1, 2));
        float mn0 = fmaxf(m0, mx0), mn1 = fmaxf(m1, mx1);
        float al0 = __expf(m0 - mn0), al1 = __expf(m1 - mn1);
        m0 = mn0; m1 = mn1;

        float sum0 = 0.f, sum1 = 0.f;
#pragma unroll
        for (int nt = 0; nt < 8; nt++) {
#pragma unroll
            for (int e = 0; e < 2; e++) {
                float p0 = __expf(sc[nt][e] - mn0);
                float p1 = __expf(sc[nt][2 + e] - mn1);
                sc[nt][e] = p0; sc[nt][2 + e] = p1;
                sum0 += p0; sum1 += p1;
            }
        }
        sum0 += __shfl_xor_sync(0xffffffffu, sum0, 1);
        sum0 += __shfl_xor_sync(0xffffffffu, sum0, 2);
        sum1 += __shfl_xor_sync(0xffffffffu, sum1, 1);
        sum1 += __shfl_xor_sync(0xffffffffu, sum1, 2);
        l0 = l0 * al0 + sum0;
        l1 = l1 * al1 + sum1;

#pragma unroll
        for (int nt = 0; nt < 8; nt++) {
            out[nt][0] *= al0; out[nt][1] *= al0;
            out[nt][2] *= al1; out[nt][3] *= al1;
        }

#pragma unroll
        for (int kbk = 0; kbk < 4; kbk++) {
            uint32_t ph[4], pl[4];
            split2(sc[2 * kbk][0],     sc[2 * kbk][1],     ph[0], pl[0]);
            split2(sc[2 * kbk][2],     sc[2 * kbk][3],     ph[1], pl[1]);
            split2(sc[2 * kbk + 1][0], sc[2 * kbk + 1][1], ph[2], pl[2]);
            split2(sc[2 * kbk + 1][2], sc[2 * kbk + 1][3], ph[3], pl[3]);
#pragma unroll
            for (int g = 0; g < 4; g++) {
                uint32_t r0, r1, r2, r3;
                ldsm4t(r0, r1, r2, r3,
                       kb + seg + bVoff + kbk * 16 * GPAD * 2 + g * 32);
                uint32_t b0[2] = {r0, r1}, b1[2] = {r2, r3};
                mma16816(out[2 * g], ph, b0);     mma16816(out[2 * g + 1], ph, b1);
                mma16816(out[2 * g], pl, b0);     mma16816(out[2 * g + 1], pl, b1);
            }
        }
        __syncthreads();
    }

    const float inv0 = 1.f / l0, inv1 = 1.f / l1;
#pragma unroll
    for (int nt = 0; nt < 8; nt++) {
        out[nt][0] *= inv0; out[nt][1] *= inv0;
        out[nt][2] *= inv1; out[nt][3] *= inv1;
    }

    for (int i = tid; i < 1024; i += 256) {
        int d = i >> 3, q = i & 7;
        *(int4*)(smraw + oUh + (d * GPAD + q * 8) * 2) =
            *(const int4*)(g_uoh + d * 64 + q * 8);
    }
    __syncthreads();

    float out2[16][4];
#pragma unroll
    for (int nt = 0; nt < 16; nt++)
#pragma unroll
        for (int e = 0; e < 4; e++) out2[nt][e] = 0.f;

    const uint32_t bUoff = (((aj >> 1) * 8 + ar) * GPAD + (aj & 1) * 8) * 2;
#pragma unroll
    for (int kbk = 0; kbk < 4; kbk++) {
        uint32_t ph[4], pl[4];
        split2(out[2 * kbk][0],     out[2 * kbk][1],     ph[0], pl[0]);
        split2(out[2 * kbk][2],     out[2 * kbk][3],     ph[1], pl[1]);
        split2(out[2 * kbk + 1][0], out[2 * kbk + 1][1], ph[2], pl[2]);
        split2(out[2 * kbk + 1][2], out[2 * kbk + 1][3], ph[3], pl[3]);
#pragma unroll
        for (int g = 0; g < 8; g++) {
            uint32_t r0, r1, r2, r3;
            ldsm4(r0, r1, r2, r3, sb + oUh + bUoff + g * 16 * GPAD * 2 + kbk * 32);
            uint32_t b0[2] = {r0, r1}, b1[2] = {r2, r3};
            mma16816(out2[2 * g], ph, b0);     mma16816(out2[2 * g + 1], ph, b1);
            mma16816(out2[2 * g], pl, b0);     mma16816(out2[2 * g + 1], pl, b1);
        }
    }

    const float ga0 = g_gate[tg0], ga1 = g_gate[tg1];
#pragma unroll
    for (int nt = 0; nt < 16; nt++) {
        size_t i0 = (size_t)tg0 * CC + h * DD + nt * 8 + cq;
        float2 o0 = *(float2*)(g_ctx + i0);
        __half2 h0 = __floats2half2_rn(o0.x + ga0 * out2[nt][0],
                                       o0.y + ga0 * out2[nt][1]);
        *(uint32_t*)(g_cxh + i0) = *(uint32_t*)&h0;
        size_t i1 = (size_t)tg1 * CC + h * DD + nt * 8 + cq;
        float2 o1 = *(float2*)(g_ctx + i1);
        __half2 h1 = __floats2half2_rn(o1.x + ga1 * out2[nt][2],
                                       o1.y + ga1 * out2[nt][3]);
        *(uint32_t*)(g_cxh + i1) = *(uint32_t*)&h1;
    }
}

// ============================================================================
extern "C" void kernel_launch(void* const* d_in, const int* in_sizes, int n_in,
                              void* d_out, int out_size)
{
    const float* x     = (const float*)d_in[0];
    const float* w_qkv = (const float*)d_in[1];
    const float* w_o   = (const float*)d_in[2];
    const float* pk    = (const float*)d_in[3];
    const float* pv    = (const float*)d_in[4];
    const float* uo    = (const float*)d_in[5];
    const float* iw1   = (const float*)d_in[6];
    const float* iw2   = (const float*)d_in[7];
    float* out = (float*)d_out;

    cudaFuncSetAttribute(gemm_mma256,     cudaFuncAttributeMaxDynamicSharedMemorySize, 61440);
    cudaFuncSetAttribute(gemm_info,       cudaFuncAttributeMaxDynamicSharedMemorySize, 40960);
    cudaFuncSetAttribute(local_attn_mma,  cudaFuncAttributeMaxDynamicSharedMemorySize, 104448);
    cudaFuncSetAttribute(global_attn_mma, cudaFuncAttributeMaxDynamicSharedMemorySize, 73728);
    cudaFuncSetAttribute(lowrank_mma,     cudaFuncAttributeMaxDynamicSharedMemorySize, 52224);

    void *pxh, *pwqh, *pwoh, *pi1h, *pcxh, *pqkvh, *pqkvl;
    cudaGetSymbolAddress(&pxh, g_xh);
    cudaGetSymbolAddress(&pwqh, g_wqh);
    cudaGetSymbolAddress(&pwoh, g_woh);
    cudaGetSymbolAddress(&pi1h, g_i1h);
    cudaGetSymbolAddress(&pcxh, g_cxh);
    cudaGetSymbolAddress(&pqkvh, g_qkvh); cudaGetSymbolAddress(&pqkvl, g_qkvl);

    rope_table_k<<<TT, DD>>>();
    conv_all_k<<<(CS6 + 255) / 256, 256>>>(
        (const float2*)x, (const float2*)w_qkv, (const float2*)iw1,
        (const float2*)w_o, (const float2*)uo, (const float2*)pk,
        (const float2*)pv);

    // qkv = rope(x @ w_qkv^T) -> fp16 splits (1-term GEMM)
    gemm_mma256<<<dim3(C3 / 256, TT / 128), 512, 61440>>>(
        (const __half*)pxh, (const __half*)pwqh,
        nullptr, (__half*)pqkvh, (__half*)pqkvl, C3, CC, 2);

    // info gate: 1-term GEMM + fused gelu/dot partials; finalize + any-flag
    gemm_info<<<dim3(CI / 128, TT / 128), 256, 40960>>>(
        (const __half*)pxh, (const __half*)pi1h, iw2, CI, CC);
    gate_fin_k<<<1, 512>>>();

    lowrank_mma<<<dim3(TT / 64, HH), 128, 52224>>>();
    local_attn_mma<<<dim3(TT / 64, HH), 128, 104448>>>();
    global_attn_mma<<<dim3(TT / 128, HH), 256, 73728>>>();

    // out = ctx @ w_o^T (1-term GEMM)
    gemm_mma256<<<dim3(CC / 256, TT / 128), 512, 61440>>>(
        (const __half*)pcxh, (const __half*)pwoh,
        out, nullptr, nullptr, CC, CC, 0);
}

// round 13
// speedup vs baseline: 8.5726x; 1.0843x over previous
#include <cuda_runtime.h>
#include <cuda_fp16.h>
#include <math.h>
#include <stdint.h>

#define TT   2048
#define CC   2048
#define HH   16
#define DD   128
#define RR   64
#define WLOC 512
#define CI   512
#define C3   6144

#define SCALE_L 0.08838834764831845f
#define SCALE_G 0.1767766952966369f

// ---------------- scratch (device globals) ----------------
__device__ float g_gatez[8 * TT];     // 8 partial slots (4 bn x 2 ksplit)
__device__ float g_gate[TT];
__device__ int   g_anygate;
__device__ float g_cos[TT * DD];
__device__ float g_sin[TT * DD];
__device__ float g_ctx[TT * CC];

// fp16 operands. 2-term splits kept only on the (gated, rare) global path.
__device__ __half g_xh[TT * CC];
__device__ __half g_wqh[C3 * CC];
__device__ __half g_woh[CC * CC];
__device__ __half g_i1h[CI * CC];
__device__ __half g_cxh[TT * CC];
__device__ __half g_qkvh[TT * C3], g_qkvl[TT * C3];
__device__ __half g_qrh[HH * TT * RR], g_qrl[HH * TT * RR];
__device__ __half g_krh[HH * TT * RR];
__device__ __half g_vrh[HH * TT * RR];
__device__ __half g_uoh[DD * RR];
__device__ __half g_pkh[RR * DD];
__device__ __half g_pvh[RR * DD];

// ============================================================================
// PTX helpers (plain sm_80+ ISA)
// ============================================================================
__device__ __forceinline__ uint32_t smem_u32(const void* p) {
    uint32_t a;
    asm("{ .reg .u64 t; cvta.to.shared.u64 t, %1; cvt.u32.u64 %0, t; }"
        : "=r"(a) : "l"(p));
    return a;
}

#define CP16(s, g) \
    asm volatile("cp.async.cg.shared.global [%0], [%1], 16;" \
                 :: "r"(s), "l"(g) : "memory")
#define CP_COMMIT() asm volatile("cp.async.commit_group;" ::: "memory")
#define CP_WAIT(n)  asm volatile("cp.async.wait_group %0;" :: "n"(n) : "memory")

__device__ __forceinline__ void ldsm4(uint32_t& r0, uint32_t& r1,
                                      uint32_t& r2, uint32_t& r3, uint32_t a) {
    asm volatile("ldmatrix.sync.aligned.m8n8.x4.shared.b16 {%0,%1,%2,%3}, [%4];"
                 : "=r"(r0), "=r"(r1), "=r"(r2), "=r"(r3) : "r"(a));
}
__device__ __forceinline__ void ldsm4t(uint32_t& r0, uint32_t& r1,
                                       uint32_t& r2, uint32_t& r3, uint32_t a) {
    asm volatile("ldmatrix.sync.aligned.m8n8.x4.trans.shared.b16 {%0,%1,%2,%3}, [%4];"
                 : "=r"(r0), "=r"(r1), "=r"(r2), "=r"(r3) : "r"(a));
}

__device__ __forceinline__ void mma16816(float* c, const uint32_t* a,
                                         const uint32_t* b) {
    asm volatile("mma.sync.aligned.m16n8k16.row.col.f32.f16.f16.f32 "
                 "{%0,%1,%2,%3}, {%4,%5,%6,%7}, {%8,%9}, {%0,%1,%2,%3};"
                 : "+f"(c[0]), "+f"(c[1]), "+f"(c[2]), "+f"(c[3])
                 : "r"(a[0]), "r"(a[1]), "r"(a[2]), "r"(a[3]),
                   "r"(b[0]), "r"(b[1]));
}

__device__ __forceinline__ void split2(float x, float y, uint32_t& h, uint32_t& l) {
    __half2 hh = __floats2half2_rn(x, y);
    h = *reinterpret_cast<uint32_t*>(&hh);
    __half2 ll = __floats2half2_rn(x - __low2float(hh), y - __high2float(hh));
    l = *reinterpret_cast<uint32_t*>(&ll);
}

// ============================================================================
// Fused fp32 -> fp16 convert of x + ALL weight regions (one launch)
// ============================================================================
#define CS0 (TT * CC / 2)
#define CS1 (CS0 + C3 * CC / 2)
#define CS2 (CS1 + CI * CC / 2)
#define CS3 (CS2 + CC * CC / 2)
#define CS4 (CS3 + DD * RR / 2)
#define CS5 (CS4 + RR * DD / 2)
#define CS6 (CS5 + RR * DD / 2)
__global__ void conv_all_k(const float2* __restrict__ x,
                           const float2* __restrict__ wq,
                           const float2* __restrict__ i1,
                           const float2* __restrict__ wo,
                           const float2* __restrict__ uo,
                           const float2* __restrict__ pk,
                           const float2* __restrict__ pv)
{
    int i = blockIdx.x * 256 + threadIdx.x;
    const float2* s; __half2* d; int j;
    if      (i < CS0) { s = x;  d = (__half2*)g_xh;  j = i; }
    else if (i < CS1) { s = wq; d = (__half2*)g_wqh; j = i - CS0; }
    else if (i < CS2) { s = i1; d = (__half2*)g_i1h; j = i - CS1; }
    else if (i < CS3) { s = wo; d = (__half2*)g_woh; j = i - CS2; }
    else if (i < CS4) { s = uo; d = (__half2*)g_uoh; j = i - CS3; }
    else if (i < CS5) { s = pk; d = (__half2*)g_pkh; j = i - CS4; }
    else if (i < CS6) { s = pv; d = (__half2*)g_pvh; j = i - CS5; }
    else return;
    float2 v = s[j];
    d[j] = __floats2half2_rn(v.x, v.y);
}

// ============================================================================
// mma.sync GEMM, 1-term fp16: C = Ah·Bh^T.
// BM=128, BN=256, BK=32; 512 threads (warps 4x4, warp tile 32x64).
// mode 0: fp32 store. mode 2: rope + fp16 hi/lo store.
// ============================================================================
__global__ __launch_bounds__(512) void gemm_mma256(
    const __half* __restrict__ Ah, const __half* __restrict__ Bh,
    float* __restrict__ Cout,
    __half* __restrict__ Ch, __half* __restrict__ Cl,
    int N, int K, int mode)
{
    extern __shared__ __align__(128) char smraw[];
    const uint32_t sb = smem_u32(smraw);
    const int tid = threadIdx.x, lane = tid & 31, wid = tid >> 5;
    const int wm = wid & 3, wn = wid >> 2;
    const int bm = blockIdx.y << 7, bn = blockIdx.x << 8;
    const int aj = lane >> 3, ar = lane & 7;

    float acc[2][8][4];
#pragma unroll
    for (int mt = 0; mt < 2; mt++)
#pragma unroll
        for (int nt = 0; nt < 8; nt++)
#pragma unroll
            for (int e = 0; e < 4; e++) acc[mt][nt][e] = 0.f;

    const int nch = K >> 5;

    auto issue_stage = [&](int c) {
        const uint32_t st = sb + (c & 1) * 30720;
        const int k0 = c << 5;
        {
            int r = tid >> 2, q = tid & 3;
            CP16(st + r * 80 + q * 16, Ah + (size_t)(bm + r) * K + k0 + q * 8);
        }
        {
            const __half* gh = Bh + (size_t)bn * K + k0;
#pragma unroll
            for (int hh = 0; hh < 2; hh++) {
                int i = tid + hh * 512;
                int r = i >> 2, q = i & 3;
                CP16(st + 10240 + r * 80 + q * 16, gh + (size_t)r * K + q * 8);
            }
        }
        CP_COMMIT();
    };

    issue_stage(0);
    for (int c = 0; c < nch; c++) {
        if (c + 1 < nch) { issue_stage(c + 1); CP_WAIT(1); }
        else             { CP_WAIT(0); }
        __syncthreads();

        const uint32_t st = sb + (c & 1) * 30720;
#pragma unroll
        for (int ks = 0; ks < 2; ks++) {
            uint32_t ah[2][4], b2[8][2];
            const uint32_t a_off =
                ((wm * 32 + (aj & 1) * 8 + ar) * 40 + ks * 16 + (aj >> 1) * 8) * 2;
            const uint32_t b_off =
                ((wn * 64 + (aj >> 1) * 8 + ar) * 40 + ks * 16 + (aj & 1) * 8) * 2;

#pragma unroll
            for (int mt = 0; mt < 2; mt++)
                ldsm4(ah[mt][0], ah[mt][1], ah[mt][2], ah[mt][3],
                      st + a_off + mt * (16 * 80));
#pragma unroll
            for (int np = 0; np < 4; np++) {
                uint32_t r0, r1, r2, r3;
                ldsm4(r0, r1, r2, r3, st + 10240 + b_off + np * (16 * 80));
                b2[np * 2][0] = r0;     b2[np * 2][1] = r1;
                b2[np * 2 + 1][0] = r2; b2[np * 2 + 1][1] = r3;
            }
#pragma unroll
            for (int mt = 0; mt < 2; mt++)
#pragma unroll
                for (int nt = 0; nt < 8; nt++)
                    mma16816(acc[mt][nt], ah[mt], b2[nt]);
        }
        __syncthreads();
    }

    const int row_base = bm + wm * 32 + (lane >> 2);
    const int col_base = bn + wn * 64 + (lane & 3) * 2;
#pragma unroll
    for (int mt = 0; mt < 2; mt++)
#pragma unroll
        for (int nt = 0; nt < 8; nt++) {
            int r0 = row_base + mt * 16, cc = col_base + nt * 8;
            float v0 = acc[mt][nt][0], v1 = acc[mt][nt][1];
            float v2 = acc[mt][nt][2], v3 = acc[mt][nt][3];
            if (mode == 2) {
                if (cc < 2 * CC) {
                    int d0 = cc & 127;
                    float2 cA = *(const float2*)(g_cos + r0 * DD + d0);
                    float2 sA = *(const float2*)(g_sin + r0 * DD + d0);
                    float o0 = v0 * cA.x - v1 * sA.x;
                    float o1 = v1 * cA.y + v0 * sA.y;
                    float2 cB = *(const float2*)(g_cos + (r0 + 8) * DD + d0);
                    float2 sB = *(const float2*)(g_sin + (r0 + 8) * DD + d0);
                    float o2 = v2 * cB.x - v3 * sB.x;
                    float o3 = v3 * cB.y + v2 * sB.y;
                    v0 = o0; v1 = o1; v2 = o2; v3 = o3;
                }
                uint32_t h01, l01, h23, l23;
                split2(v0, v1, h01, l01);
                split2(v2, v3, h23, l23);
                *(uint32_t*)(Ch + (size_t)r0 * N + cc)       = h01;
                *(uint32_t*)(Cl + (size_t)r0 * N + cc)       = l01;
                *(uint32_t*)(Ch + (size_t)(r0 + 8) * N + cc) = h23;
                *(uint32_t*)(Cl + (size_t)(r0 + 8) * N + cc) = l23;
            } else {
                *(float2*)(Cout + (size_t)r0 * N + cc)       = make_float2(v0, v1);
                *(float2*)(Cout + (size_t)(r0 + 8) * N + cc) = make_float2(v2, v3);
            }
        }
}

// ============================================================================
// Info GEMM (BN=128, 1-term fp16, split-K x2) with fused gelu + dot(w2)
// gate partials. 8 deterministic partial slots: blockIdx.x + 4*blockIdx.z.
// ============================================================================
__global__ __launch_bounds__(256) void gemm_info(
    const __half* __restrict__ Ah, const __half* __restrict__ Bh,
    const float* __restrict__ w2, int N, int K)
{
    extern __shared__ __align__(128) char smraw[];
    const uint32_t sb = smem_u32(smraw);
    const int tid = threadIdx.x, lane = tid & 31, wid = tid >> 5;
    const int wm = wid & 3, wn = wid >> 2;
    const int bm = blockIdx.y << 7, bn = blockIdx.x << 7;
    const int aj = lane >> 3, ar = lane & 7;
    const int khalf = K >> 1;
    const int kbase = blockIdx.z * khalf;

    float acc[2][8][4];
#pragma unroll
    for (int mt = 0; mt < 2; mt++)
#pragma unroll
        for (int nt = 0; nt < 8; nt++)
#pragma unroll
            for (int e = 0; e < 4; e++) acc[mt][nt][e] = 0.f;

    const int nch = khalf >> 5;

    auto issue_stage = [&](int c) {
        const uint32_t st = sb + (c & 1) * 20480;
        const int k0 = kbase + (c << 5);
        const __half* gm0 = Ah + (size_t)bm * K + k0;
        const __half* gm2 = Bh + (size_t)bn * K + k0;
#pragma unroll
        for (int h = 0; h < 2; h++) {
            int i = tid + h * 256;
            int r = i >> 2, q = i & 3;
            uint32_t so = st + r * 80 + q * 16;
            size_t go = (size_t)r * K + q * 8;
            CP16(so,          gm0 + go);
            CP16(so + 10240,  gm2 + go);
        }
        CP_COMMIT();
    };

    issue_stage(0);
    for (int c = 0; c < nch; c++) {
        if (c + 1 < nch) { issue_stage(c + 1); CP_WAIT(1); }
        else             { CP_WAIT(0); }
        __syncthreads();

        const uint32_t st = sb + (c & 1) * 20480;
#pragma unroll
        for (int ks = 0; ks < 2; ks++) {
            uint32_t ah[2][4], b2[8][2];
            const uint32_t a_off =
                ((wm * 32 + (aj & 1) * 8 + ar) * 40 + ks * 16 + (aj >> 1) * 8) * 2;
            const uint32_t b_off =
                ((wn * 64 + (aj >> 1) * 8 + ar) * 40 + ks * 16 + (aj & 1) * 8) * 2;

#pragma unroll
            for (int mt = 0; mt < 2; mt++)
                ldsm4(ah[mt][0], ah[mt][1], ah[mt][2], ah[mt][3],
                      st + a_off + mt * (16 * 80));
#pragma unroll
            for (int np = 0; np < 4; np++) {
                uint32_t r0, r1, r2, r3;
                ldsm4(r0, r1, r2, r3, st + 10240 + b_off + np * (16 * 80));
                b2[np * 2][0] = r0;     b2[np * 2][1] = r1;
                b2[np * 2 + 1][0] = r2; b2[np * 2 + 1][1] = r3;
            }
#pragma unroll
            for (int mt = 0; mt < 2; mt++)
#pragma unroll
                for (int nt = 0; nt < 8; nt++)
                    mma16816(acc[mt][nt], ah[mt], b2[nt]);
        }
        __syncthreads();
    }

    // ksplit partial results are pre-gelu partial sums of h_info columns.
    // gelu is nonlinear, so we cannot apply it per-half; instead each kslice
    // stores the RAW partial h_info sums dotted with... -- NOT valid.
    // Correct approach: store raw partial row-sums of h_info per column is
    // impossible (512 cols). Instead: kslice 0 and 1 partials are combined
    // BEFORE gelu via a dedicated path: slot layout stores the raw GEMM
    // partial dotted with w2 AFTER gelu only for the full sum. To keep
    // split-K exact, we stage raw partials in g_gatez as column-block sums
    // cannot work. => We instead apply gelu only on the COMBINED value:
    // write raw partial acc dot is invalid. Therefore: this kernel writes
    // gelu(full)·w2 only when gridDim.z==1. For split-K we write the raw
    // partial H (pre-gelu) reduced against w2 is WRONG.
    //
    // Resolution: for split-K, each CTA writes its raw partial H block sums
    // to g_gatez slots, and gate_fin applies gelu AFTER summing halves via
    // a per-column pass. But gate_fin lacks the 512-wide H. So: slot stores
    // sum_cols gelu? -> impossible.
    //
    // FALLBACK (used here): gridDim.z == 1 always; split-K disabled.
    const int col_base = wn * 64 + (lane & 3) * 2;
    float z[2][2] = {{0.f, 0.f}, {0.f, 0.f}};
#pragma unroll
    for (int mt = 0; mt < 2; mt++)
#pragma unroll
        for (int nt = 0; nt < 8; nt++) {
            int cc = col_base + nt * 8;
            float w0 = w2[cc], w1 = w2[cc + 1];
            float v0 = acc[mt][nt][0], v1 = acc[mt][nt][1];
            float v2 = acc[mt][nt][2], v3 = acc[mt][nt][3];
            v0 = 0.5f * v0 * (1.0f + erff(v0 * 0.7071067811865475f));
            v1 = 0.5f * v1 * (1.0f + erff(v1 * 0.7071067811865475f));
            v2 = 0.5f * v2 * (1.0f + erff(v2 * 0.7071067811865475f));
            v3 = 0.5f * v3 * (1.0f + erff(v3 * 0.7071067811865475f));
            z[mt][0] += v0 * w0 + v1 * w1;
            z[mt][1] += v2 * w0 + v3 * w1;
        }
#pragma unroll
    for (int mt = 0; mt < 2; mt++)
#pragma unroll
        for (int e = 0; e < 2; e++) {
            z[mt][e] += __shfl_xor_sync(0xffffffffu, z[mt][e], 1);
            z[mt][e] += __shfl_xor_sync(0xffffffffu, z[mt][e], 2);
        }
    float* zs = (float*)smraw;
    if ((lane & 3) == 0) {
        int lr = wm * 32 + (lane >> 2);
        zs[wn * 128 + lr +  0] = z[0][0];
        zs[wn * 128 + lr +  8] = z[0][1];
        zs[wn * 128 + lr + 16] = z[1][0];
        zs[wn * 128 + lr + 24] = z[1][1];
    }
    __syncthreads();
    if (tid < 128)
        g_gatez[(blockIdx.x + 4 * blockIdx.z) * TT + bm + tid]
            = zs[tid] + zs[128 + tid];
}

// gate finalize (one block): gates + any-gate flag (sums 4 slots; z-dim=1)
__global__ __launch_bounds__(512) void gate_fin_k()
{
    int any = 0;
    for (int t = threadIdx.x; t < TT; t += 512) {
        float zsum = g_gatez[t] + g_gatez[TT + t] + g_gatez[2 * TT + t]
                   + g_gatez[3 * TT + t];
        float sc = 1.0f / (1.0f + expf(-zsum));
        float gv = (sc > 0.75f) ? 1.0f : 0.0f;
        g_gate[t] = gv;
        any |= (gv != 0.0f);
    }
    int anyb = __syncthreads_or(any);
    if (threadIdx.x == 0) g_anygate = anyb;
}

// ============================================================================
// RoPE tables (fp32)
// ============================================================================
__global__ void rope_table_k()
{
    int t = blockIdx.x, d = threadIdx.x;
    int j = d & 63;
    float inv = exp2f(-(float)j * 0.20762050593046014f);
    float ang = (float)t * inv;
    g_cos[t * DD + d] = cosf(ang);
    g_sin[t * DD + d] = sinf(ang);
}

// ============================================================================
// Low-rank projections (2-term fp16). Skipped when no gate fires.
// ============================================================================
__global__ __launch_bounds__(128) void lowrank_mma()
{
    if (g_anygate == 0) return;

    extern __shared__ __align__(16) char smraw[];
    const uint32_t sb = smem_u32(smraw);
    const uint32_t oAl = 64 * 136 * 2, oPh = 2 * 64 * 136 * 2;
    const int tid = threadIdx.x, lane = tid & 31, w = tid >> 5;
    const int qt = blockIdx.x, h = blockIdx.y, t0 = qt << 6;
    const int aj = lane >> 3, ar = lane & 7;

    const uint32_t aoff = ((w * 16 + (aj & 1) * 8 + ar) * 136 + (aj >> 1) * 8) * 2;
    const uint32_t boff = (((aj >> 1) * 8 + ar) * 136 + (aj & 1) * 8) * 2;
    const int row0 = t0 + w * 16 + (lane >> 2);
    const int col = (lane & 3) * 2;

    for (int pass = 0; pass < 3; pass++) {
        const __half* Ph = (pass == 2) ? g_pvh : g_pkh;
        const int off = pass * CC + h * DD;
        __syncthreads();
        for (int i = tid; i < 1024; i += 128) {
            int r = i >> 4, q = i & 15;
            uint32_t so = (r * 136 + q * 8) * 2;
            size_t ga = (size_t)(t0 + r) * C3 + off + q * 8;
            CP16(sb + so,       g_qkvh + ga);
            CP16(sb + oAl + so, g_qkvl + ga);
            CP16(sb + oPh + so, Ph + r * DD + q * 8);
        }
        CP_COMMIT(); CP_WAIT(0);
        __syncthreads();

        float acc[8][4];
#pragma unroll
        for (int nt = 0; nt < 8; nt++)
#pragma unroll
            for (int e = 0; e < 4; e++) acc[nt][e] = 0.f;

#pragma unroll
        for (int kb = 0; kb < 8; kb++) {
            uint32_t ah[4], al_[4], b2[8][2];
            ldsm4(ah[0], ah[1], ah[2], ah[3], sb + aoff + kb * 32);
            ldsm4(al_[0], al_[1], al_[2], al_[3], sb + oAl + aoff + kb * 32);
#pragma unroll
            for (int np = 0; np < 4; np++) {
                uint32_t r0, r1, r2, r3;
                ldsm4(r0, r1, r2, r3, sb + oPh + boff + np * 16 * 136 * 2 + kb * 32);
                b2[np * 2][0] = r0;     b2[np * 2][1] = r1;
                b2[np * 2 + 1][0] = r2; b2[np * 2 + 1][1] = r3;
            }
#pragma unroll
            for (int nt = 0; nt < 8; nt++) {
                mma16816(acc[nt], ah, b2[nt]);
                mma16816(acc[nt], al_, b2[nt]);
            }
        }

        if (pass == 0) {
#pragma unroll
            for (int nt = 0; nt < 8; nt++) {
                uint32_t hh, ll;
                size_t i0 = (size_t)(h * TT + row0) * RR + nt * 8 + col;
                split2(acc[nt][0], acc[nt][1], hh, ll);
                *(uint32_t*)(g_qrh + i0) = hh;
                *(uint32_t*)(g_qrl + i0) = ll;
                size_t i1 = i0 + 8 * RR;
                split2(acc[nt][2], acc[nt][3], hh, ll);
                *(uint32_t*)(g_qrh + i1) = hh;
                *(uint32_t*)(g_qrl + i1) = ll;
            }
        } else {
            __half* dh = (pass == 1) ? g_krh : g_vrh;
#pragma unroll
            for (int nt = 0; nt < 8; nt++) {
                size_t i0 = (size_t)(h * TT + row0) * RR + nt * 8 + col;
                __half2 a = __floats2half2_rn(acc[nt][0], acc[nt][1]);
                *(uint32_t*)(dh + i0) = *(uint32_t*)&a;
                size_t i1 = i0 + 8 * RR;
                __half2 b = __floats2half2_rn(acc[nt][2], acc[nt][3]);
                *(uint32_t*)(dh + i1) = *(uint32_t*)&b;
            }
        }
    }
}

// ============================================================================
// Local sliding-window attention: Sq=64, 4 warps, double-buffered KV.
// 1-term QK (Q hi only) and 1-term PV (P hi only).
// smem = (64 + 2*2*64) * 136 * 2 = 87040 B -> 2 CTAs/SM.
// ============================================================================
#define LPAD 136
__global__ __launch_bounds__(128) void local_attn_mma()
{
    extern __shared__ __align__(16) char smraw[];
    const uint32_t sb = smem_u32(smraw);
    const uint32_t kvBase = 64 * LPAD * 2;
    const uint32_t kvStage = 2 * 64 * LPAD * 2;
    const uint32_t seg = 64 * LPAD * 2;

    const int tid = threadIdx.x, lane = tid & 31, w = tid >> 5;
    const int qt = gridDim.x - 1 - blockIdx.x, h = blockIdx.y;
    const int t0 = qt << 6;
    const int aj = lane >> 3, ar = lane & 7;
    const int tg0 = t0 + w * 16 + (lane >> 2), tg1 = tg0 + 8;
    const int cq = (lane & 3) * 2;

    for (int i = tid; i < 1024; i += 128) {
        int r = i >> 4, q = i & 15;
        CP16(sb + (r * LPAD + q * 8) * 2,
             g_qkvh + (size_t)(t0 + r) * C3 + h * DD + q * 8);
    }
    CP_COMMIT();

    const int kt0 = (t0 > WLOC - 1) ? ((t0 - (WLOC - 1)) >> 6) : 0;
    const int ktend = qt;

    auto issueKV = [&](int kt, int s) {
        const int s0 = kt << 6;
        const uint32_t kb = sb + kvBase + s * kvStage;
        for (int i = tid; i < 1024; i += 128) {
            int r = i >> 4, q = i & 15;
            size_t gk = (size_t)(s0 + r) * C3 + CC + h * DD + q * 8;
            uint32_t off = (r * LPAD + q * 8) * 2;
            CP16(kb + off,       g_qkvh + gk);
            CP16(kb + seg + off, g_qkvh + gk + CC);
        }
        CP_COMMIT();
    };
    issueKV(kt0, 0);

    float m0 = -1e30f, m1 = -1e30f, l0 = 0.f, l1 = 0.f;
    float out[16][4];
#pragma unroll
    for (int nt = 0; nt < 16; nt++)
#pragma unroll
        for (int e = 0; e < 4; e++) out[nt][e] = 0.f;

    const uint32_t aQoff = ((w * 16 + (aj & 1) * 8 + ar) * LPAD + (aj >> 1) * 8) * 2;
    const uint32_t bKoff = (((aj >> 1) * 8 + ar) * LPAD + (aj & 1) * 8) * 2;
    const uint32_t bVoff = (((aj & 1) * 8 + ar) * LPAD + (aj >> 1) * 8) * 2;

    for (int kt = kt0; kt <= ktend; kt++) {
        const int s = (kt - kt0) & 1;
        if (kt < ktend) { issueKV(kt + 1, s ^ 1); CP_WAIT(1); }
        else            { CP_WAIT(0); }
        __syncthreads();
        const uint32_t kb = sb + kvBase + s * kvStage;
        const int s0 = kt << 6;

        float sc[8][4];
#pragma unroll
        for (int nt = 0; nt < 8; nt++)
#pragma unroll
            for (int e = 0; e < 4; e++) sc[nt][e] = 0.f;

#pragma unroll
        for (int kbk = 0; kbk < 8; kbk++) {
            uint32_t ah[4], b2[8][2];
            ldsm4(ah[0], ah[1], ah[2], ah[3], sb + aQoff + kbk * 32);
#pragma unroll
            for (int np = 0; np < 4; np++) {
                uint32_t r0, r1, r2, r3;
                ldsm4(r0, r1, r2, r3, kb + bKoff + np * 16 * LPAD * 2 + kbk * 32);
                b2[np * 2][0] = r0;     b2[np * 2][1] = r1;
                b2[np * 2 + 1][0] = r2; b2[np * 2 + 1][1] = r3;
            }
#pragma unroll
            for (int nt = 0; nt < 8; nt++)
                mma16816(sc[nt], ah, b2[nt]);
        }

#pragma unroll
        for (int nt = 0; nt < 8; nt++) {
            int c0 = s0 + nt * 8 + cq;
#pragma unroll
            for (int e = 0; e < 2; e++) {
                int sg = c0 + e;
                float v0 = sc[nt][e] * SCALE_L;
                sc[nt][e] = (sg <= tg0 && sg >= tg0 - (WLOC - 1)) ? v0 : -1e30f;
                float v1 = sc[nt][2 + e] * SCALE_L;
                sc[nt][2 + e] = (sg <= tg1 && sg >= tg1 - (WLOC - 1)) ? v1 : -1e30f;
            }
        }

        float mx0 = -1e30f, mx1 = -1e30f;
#pragma unroll
        for (int nt = 0; nt < 8; nt++) {
            mx0 = fmaxf(mx0, fmaxf(sc[nt][0], sc[nt][1]));
            mx1 = fmaxf(mx1, fmaxf(sc[nt][2], sc[nt][3]));
        }
        mx0 = fmaxf(mx0, __shfl_xor_sync(0xffffffffu, mx0, 1));
        mx0 = fmaxf(mx0, __shfl_xor_sync(0xffffffffu, mx0, 2));
        mx1 = fmaxf(mx1, __shfl_xor_sync(0xffffffffu, mx1, 1));
        mx1 = fmaxf(mx1, __shfl_xor_sync(0xffffffffu, mx1, 2));
        float mn0 = fmaxf(m0, mx0), mn1 = fmaxf(m1, mx1);
        float al0 = __expf(m0 - mn0), al1 = __expf(m1 - mn1);
        m0 = mn0; m1 = mn1;

        float sum0 = 0.f, sum1 = 0.f;
#pragma unroll
        for (int nt = 0; nt < 8; nt++) {
#pragma unroll
            for (int e = 0; e < 2; e++) {
                float p0 = (sc[nt][e]     > -1e29f) ? __expf(sc[nt][e]     - mn0) : 0.f;
                float p1 = (sc[nt][2 + e] > -1e29f) ? __expf(sc[nt][2 + e] - mn1) : 0.f;
                sc[nt][e] = p0; sc[nt][2 + e] = p1;
                sum0 += p0; sum1 += p1;
            }
        }
        sum0 += __shfl_xor_sync(0xffffffffu, sum0, 1);
        sum0 += __shfl_xor_sync(0xffffffffu, sum0, 2);
        sum1 += __shfl_xor_sync(0xffffffffu, sum1, 1);
        sum1 += __shfl_xor_sync(0xffffffffu, sum1, 2);
        l0 = l0 * al0 + sum0;
        l1 = l1 * al1 + sum1;

#pragma unroll
        for (int nt = 0; nt < 16; nt++) {
            out[nt][0] *= al0; out[nt][1] *= al0;
            out[nt][2] *= al1; out[nt][3] *= al1;
        }

#pragma unroll
        for (int kbk = 0; kbk < 4; kbk++) {
            uint32_t ph[4];
            __half2 p01 = __floats2half2_rn(sc[2 * kbk][0],     sc[2 * kbk][1]);
            __half2 p23 = __floats2half2_rn(sc[2 * kbk][2],     sc[2 * kbk][3]);
            __half2 p45 = __floats2half2_rn(sc[2 * kbk + 1][0], sc[2 * kbk + 1][1]);
            __half2 p67 = __floats2half2_rn(sc[2 * kbk + 1][2], sc[2 * kbk + 1][3]);
            ph[0] = *(uint32_t*)&p01; ph[1] = *(uint32_t*)&p23;
            ph[2] = *(uint32_t*)&p45; ph[3] = *(uint32_t*)&p67;
#pragma unroll
            for (int g = 0; g < 8; g++) {
                uint32_t r0, r1, r2, r3;
                ldsm4t(r0, r1, r2, r3,
                       kb + seg + bVoff + kbk * 16 * LPAD * 2 + g * 32);
                uint32_t b0[2] = {r0, r1}, b1[2] = {r2, r3};
                mma16816(out[2 * g], ph, b0);
                mma16816(out[2 * g + 1], ph, b1);
            }
        }
        __syncthreads();
    }

    const float inv0 = 1.f / l0, inv1 = 1.f / l1;
#pragma unroll
    for (int nt = 0; nt < 16; nt++) {
        *(float2*)(g_ctx + (size_t)tg0 * CC + h * DD + nt * 8 + cq) =
            make_float2(out[nt][0] * inv0, out[nt][1] * inv0);
        *(float2*)(g_ctx + (size_t)tg1 * CC + h * DD + nt * 8 + cq) =
            make_float2(out[nt][2] * inv1, out[nt][3] * inv1);
    }
}

// ============================================================================
// Global low-rank attention with gated fast path (unchanged: full 2-term
// precision on the rare gated path).
// ============================================================================
#define GPAD 72
__global__ __launch_bounds__(256) void global_attn_mma()
{
    extern __shared__ __align__(16) char smraw[];
    const uint32_t sb = smem_u32(smraw);
    const uint32_t oQl = 128 * GPAD * 2;
    const uint32_t kvBase = 2 * 128 * GPAD * 2;
    const uint32_t kvStage = 2 * 64 * GPAD * 2;
    const uint32_t seg = 64 * GPAD * 2;
    const uint32_t oUh = kvBase;

    const int tid = threadIdx.x, lane = tid & 31, w = tid >> 5;
    const int qt = blockIdx.x, h = blockIdx.y, t0 = qt << 7;
    const int aj = lane >> 3, ar = lane & 7;
    const int tg0 = t0 + w * 16 + (lane >> 2), tg1 = tg0 + 8;
    const int cq = (lane & 3) * 2;

    int any = 0;
    for (int i = tid; i < 128; i += 256) any |= (g_gate[t0 + i] != 0.0f);
    if (!__syncthreads_or(any)) {
        for (int i = tid; i < 8192; i += 256) {
            int r = i >> 6, c2 = (i & 63) * 2;
            size_t idx = (size_t)(t0 + r) * CC + h * DD + c2;
            float2 v = *(const float2*)(g_ctx + idx);
            __half2 hv = __floats2half2_rn(v.x, v.y);
            *(uint32_t*)(g_cxh + idx) = *(uint32_t*)&hv;
        }
        return;
    }

    for (int i = tid; i < 1024; i += 256) {
        int r = i >> 3, q = i & 7;
        uint32_t so = sb + (r * GPAD + q * 8) * 2;
        size_t go = (size_t)(h * TT + t0 + r) * RR + q * 8;
        CP16(so, g_qrh + go);
        CP16(so + oQl, g_qrl + go);
    }
    CP_COMMIT();

    auto issueKV = [&](int kt, int s) {
        const int s0 = kt << 6;
        const uint32_t kb = sb + kvBase + s * kvStage;
        for (int i = tid; i < 512; i += 256) {
            int r = i >> 3, q = i & 7;
            size_t gk = (size_t)(h * TT + s0 + r) * RR + q * 8;
            uint32_t off = (r * GPAD + q * 8) * 2;
            CP16(kb + off,       g_krh + gk);
            CP16(kb + seg + off, g_vrh + gk);
        }
        CP_COMMIT();
    };
    issueKV(0, 0);

    float m0 = -1e30f, m1 = -1e30f, l0 = 0.f, l1 = 0.f;
    float out[8][4];
#pragma unroll
    for (int nt = 0; nt < 8; nt++)
#pragma unroll
        for (int e = 0; e < 4; e++) out[nt][e] = 0.f;

    const uint32_t aQoff = ((w * 16 + (aj & 1) * 8 + ar) * GPAD + (aj >> 1) * 8) * 2;
    const uint32_t bKoff = (((aj >> 1) * 8 + ar) * GPAD + (aj & 1) * 8) * 2;
    const uint32_t bVoff = (((aj & 1) * 8 + ar) * GPAD + (aj >> 1) * 8) * 2;

    for (int kt = 0; kt < TT / 64; kt++) {
        const int s = kt & 1;
        if (kt < TT / 64 - 1) { issueKV(kt + 1, s ^ 1); CP_WAIT(1); }
        else                  { CP_WAIT(0); }
        __syncthreads();
        const uint32_t kb = sb + kvBase + s * kvStage;

        float sc[8][4];
#pragma unroll
        for (int nt = 0; nt < 8; nt++)
#pragma unroll
            for (int e = 0; e < 4; e++) sc[nt][e] = 0.f;

#pragma unroll
        for (int kbk = 0; kbk < 4; kbk++) {
            uint32_t ah[4], al_[4], b2[8][2];
            ldsm4(ah[0], ah[1], ah[2], ah[3], sb + aQoff + kbk * 32);
            ldsm4(al_[0], al_[1], al_[2], al_[3], sb + oQl + aQoff + kbk * 32);
#pragma unroll
            for (int np = 0; np < 4; np++) {
                uint32_t r0, r1, r2, r3;
                ldsm4(r0, r1, r2, r3, kb + bKoff + np * 16 * GPAD * 2 + kbk * 32);
                b2[np * 2][0] = r0;     b2[np * 2][1] = r1;
                b2[np * 2 + 1][0] = r2; b2[np * 2 + 1][1] = r3;
            }
#pragma unroll
            for (int nt = 0; nt < 8; nt++) {
                mma16816(sc[nt], ah, b2[nt]);
                mma16816(sc[nt], al_, b2[nt]);
            }
        }

        float mx0 = -1e30f, mx1 = -1e30f;
#pragma unroll
        for (int nt = 0; nt < 8; nt++) {
            sc[nt][0] *= SCALE_G; sc[nt][1] *= SCALE_G;
            sc[nt][2] *= SCALE_G; sc[nt][3] *= SCALE_G;
            mx0 = fmaxf(mx0, fmaxf(sc[nt][0], sc[nt][1]));
            mx1 = fmaxf(mx1, fmaxf(sc[nt][2], sc[nt][3]));
        }
        mx0 = fmaxf(mx0, __shfl_xor_sync(0xffffffffu, mx0, 1));
        mx0 = fmaxf(mx0, __shfl_xor_sync(0xffffffffu, mx0, 2));
        mx1 = fmaxf(mx1, __shfl_xor_sync(0xffffffffu, mx1, 1));
        mx1 = fmaxf(mx1, __shfl_xor_sync(0xffffffffu, mx1, 2));
        float mn0 = fmaxf(m0, mx0), mn1 = fmaxf(m1, mx1);
        float al0 = __expf(m0 - mn0), al1 = __expf(m1 - mn1);
        m0 = mn0; m1 = mn1;

        float sum0 = 0.f, sum1 = 0.f;
#pragma unroll
        for (int nt = 0; nt < 8; nt++) {
#pragma unroll
            for (int e = 0; e < 2; e++) {
                float p0 = __expf(sc[nt][e] - mn0);
                float p1 = __expf(sc[nt][2 + e] - mn1);
                sc[nt][e] = p0; sc[nt][2 + e] = p1;
                sum0 += p0; sum1 += p1;
            }
        }
        sum0 += __shfl_xor_sync(0xffffffffu, sum0, 1);
        sum0 += __shfl_xor_sync(0xffffffffu, sum0, 2);
        sum1 += __shfl_xor_sync(0xffffffffu, sum1, 1);
        sum1 += __shfl_xor_sync(0xffffffffu, sum1, 2);
        l0 = l0 * al0 + sum0;
        l1 = l1 * al1 + sum1;

#pragma unroll
        for (int nt = 0; nt < 8; nt++) {
            out[nt][0] *= al0; out[nt][1] *= al0;
            out[nt][2] *= al1; out[nt][3] *= al1;
        }

#pragma unroll
        for (int kbk = 0; kbk < 4; kbk++) {
            uint32_t ph[4], pl[4];
            split2(sc[2 * kbk][0],     sc[2 * kbk][1],     ph[0], pl[0]);
            split2(sc[2 * kbk][2],     sc[2 * kbk][3],     ph[1], pl[1]);
            split2(sc[2 * kbk + 1][0], sc[2 * kbk + 1][1], ph[2], pl[2]);
            split2(sc[2 * kbk + 1][2], sc[2 * kbk + 1][3], ph[3], pl[3]);
#pragma unroll
            for (int g = 0; g < 4; g++) {
                uint32_t r0, r1, r2, r3;
                ldsm4t(r0, r1, r2, r3,
                       kb + seg + bVoff + kbk * 16 * GPAD * 2 + g * 32);
                uint32_t b0[2] = {r0, r1}, b1[2] = {r2, r3};
                mma16816(out[2 * g], ph, b0);     mma16816(out[2 * g + 1], ph, b1);
                mma16816(out[2 * g], pl, b0);     mma16816(out[2 * g + 1], pl, b1);
            }
        }
        __syncthreads();
    }

    const float inv0 = 1.f / l0, inv1 = 1.f / l1;
#pragma unroll
    for (int nt = 0; nt < 8; nt++) {
        out[nt][0] *= inv0; out[nt][1] *= inv0;
        out[nt][2] *= inv1; out[nt][3] *= inv1;
    }

    for (int i = tid; i < 1024; i += 256) {
        int d = i >> 3, q = i & 7;
        *(int4*)(smraw + oUh + (d * GPAD + q * 8) * 2) =
            *(const int4*)(g_uoh + d * 64 + q * 8);
    }
    __syncthreads();

    float out2[16][4];
#pragma unroll
    for (int nt = 0; nt < 16; nt++)
#pragma unroll
        for (int e = 0; e < 4; e++) out2[nt][e] = 0.f;

    const uint32_t bUoff = (((aj >> 1) * 8 + ar) * GPAD + (aj & 1) * 8) * 2;
#pragma unroll
    for (int kbk = 0; kbk < 4; kbk++) {
        uint32_t ph[4], pl[4];
        split2(out[2 * kbk][0],     out[2 * kbk][1],     ph[0], pl[0]);
        split2(out[2 * kbk][2],     out[2 * kbk][3],     ph[1], pl[1]);
        split2(out[2 * kbk + 1][0], out[2 * kbk + 1][1], ph[2], pl[2]);
        split2(out[2 * kbk + 1][2], out[2 * kbk + 1][3], ph[3], pl[3]);
#pragma unroll
        for (int g = 0; g < 8; g++) {
            uint32_t r0, r1, r2, r3;
            ldsm4(r0, r1, r2, r3, sb + oUh + bUoff + g * 16 * GPAD * 2 + kbk * 32);
            uint32_t b0[2] = {r0, r1}, b1[2] = {r2, r3};
            mma16816(out2[2 * g], ph, b0);     mma16816(out2[2 * g + 1], ph, b1);
            mma16816(out2[2 * g], pl, b0);     mma16816(out2[2 * g + 1], pl, b1);
        }
    }

    const float ga0 = g_gate[tg0], ga1 = g_gate[tg1];
#pragma unroll
    for (int nt = 0; nt < 16; nt++) {
        size_t i0 = (size_t)tg0 * CC + h * DD + nt * 8 + cq;
        float2 o0 = *(float2*)(g_ctx + i0);
        __half2 h0 = __floats2half2_rn(o0.x + ga0 * out2[nt][0],
                                       o0.y + ga0 * out2[nt][1]);
        *(uint32_t*)(g_cxh + i0) = *(uint32_t*)&h0;
        size_t i1 = (size_t)tg1 * CC + h * DD + nt * 8 + cq;
        float2 o1 = *(float2*)(g_ctx + i1);
        __half2 h1 = __floats2half2_rn(o1.x + ga1 * out2[nt][2],
                                       o1.y + ga1 * out2[nt][3]);
        *(uint32_t*)(g_cxh + i1) = *(uint32_t*)&h1;
    }
}

// ============================================================================
extern "C" void kernel_launch(void* const* d_in, const int* in_sizes, int n_in,
                              void* d_out, int out_size)
{
    const float* x     = (const float*)d_in[0];
    const float* w_qkv = (const float*)d_in[1];
    const float* w_o   = (const float*)d_in[2];
    const float* pk    = (const float*)d_in[3];
    const float* pv    = (const float*)d_in[4];
    const float* uo    = (const float*)d_in[5];
    const float* iw1   = (const float*)d_in[6];
    const float* iw2   = (const float*)d_in[7];
    float* out = (float*)d_out;

    cudaFuncSetAttribute(gemm_mma256,     cudaFuncAttributeMaxDynamicSharedMemorySize, 61440);
    cudaFuncSetAttribute(gemm_info,       cudaFuncAttributeMaxDynamicSharedMemorySize, 40960);
    cudaFuncSetAttribute(local_attn_mma,  cudaFuncAttributeMaxDynamicSharedMemorySize, 87040);
    cudaFuncSetAttribute(global_attn_mma, cudaFuncAttributeMaxDynamicSharedMemorySize, 73728);
    cudaFuncSetAttribute(lowrank_mma,     cudaFuncAttributeMaxDynamicSharedMemorySize, 52224);

    void *pxh, *pwqh, *pwoh, *pi1h, *pcxh, *pqkvh, *pqkvl;
    cudaGetSymbolAddress(&pxh, g_xh);
    cudaGetSymbolAddress(&pwqh, g_wqh);
    cudaGetSymbolAddress(&pwoh, g_woh);
    cudaGetSymbolAddress(&pi1h, g_i1h);
    cudaGetSymbolAddress(&pcxh, g_cxh);
    cudaGetSymbolAddress(&pqkvh, g_qkvh); cudaGetSymbolAddress(&pqkvl, g_qkvl);

    rope_table_k<<<TT, DD>>>();
    conv_all_k<<<(CS6 + 255) / 256, 256>>>(
        (const float2*)x, (const float2*)w_qkv, (const float2*)iw1,
        (const float2*)w_o, (const float2*)uo, (const float2*)pk,
        (const float2*)pv);

    // qkv = rope(x @ w_qkv^T) -> fp16 splits (1-term GEMM)
    gemm_mma256<<<dim3(C3 / 256, TT / 128), 512, 61440>>>(
        (const __half*)pxh, (const __half*)pwqh,
        nullptr, (__half*)pqkvh, (__half*)pqkvl, C3, CC, 2);

    // info gate: 1-term GEMM + fused gelu/dot partials; finalize + any-flag
    gemm_info<<<dim3(CI / 128, TT / 128, 1), 256, 40960>>>(
        (const __half*)pxh, (const __half*)pi1h, iw2, CI, CC);
    gate_fin_k<<<1, 512>>>();

    lowrank_mma<<<dim3(TT / 64, HH), 128, 52224>>>();
    local_attn_mma<<<dim3(TT / 64, HH), 128, 87040>>>();
    global_attn_mma<<<dim3(TT / 128, HH), 256, 73728>>>();

    // out = ctx @ w_o^T (1-term GEMM)
    gemm_mma256<<<dim3(CC / 256, TT / 128), 512, 61440>>>(
        (const __half*)pcxh, (const __half*)pwoh,
        out, nullptr, nullptr, CC, CC, 0);
}